// round 8
// baseline (speedup 1.0000x reference)
#include <cuda_runtime.h>
#include <cuda_fp16.h>
#include <math.h>
#include <stdint.h>

// ----------------------------------------------------------------------------
// Problem constants
// ----------------------------------------------------------------------------
#define B   32
#define NK  1024
#define S   16
#define D   768
#define H   8
#define DH  64
#define HD  (H*DH)    // 512
#define QKV3 (3*HD)   // 1536
#define INNER 3072
#define N_STEPS 4
#define MS  (B*S)     // 512
static __device__ __constant__ float kSCALE = 0.036084391824351615f;  // 768^-0.5

// ----------------------------------------------------------------------------
// Scratch (device globals)
// ----------------------------------------------------------------------------
__device__ __half g_xnh[B*NK*D], g_xnl[B*NK*D];
__device__ __half g_wkh [D*D],        g_wkl [D*D];
__device__ __half g_wvh [D*D],        g_wvl [D*D];
__device__ __half g_wqh [D*D],        g_wql [D*D];
__device__ __half g_wqkh[QKV3*D],     g_wqkl[QKV3*D];
__device__ __half g_woh [D*HD],       g_wol [D*HD];
__device__ __half g_w1h [2*INNER*D],  g_w1l [2*INNER*D];
__device__ __half g_w2h [D*INNER],    g_w2l [D*INNER];
__device__ __half g_qnh[MS*D],   g_qnl[MS*D];
__device__ __half g_abh[MS*D],   g_abl[MS*D];
__device__ __half g_fbh[MS*D],   g_fbl[MS*D];
__device__ __half g_innh[MS*INNER], g_innl[MS*INNER];
__device__ __half g_oah[MS*HD],  g_oal[MS*HD];
__device__ float g_k    [B*NK*D];
__device__ float g_v    [B*NK*D];
__device__ float g_slots[MS*D];
__device__ float g_attn [MS*NK];
__device__ float g_upd  [MS*D];
__device__ float g_h    [MS*D];
__device__ float g_part [4*MS*QKV3];

// ----------------------------------------------------------------------------
// FFMA2 helpers (packed fp32x2)
// ----------------------------------------------------------------------------
__device__ __forceinline__ void ffma2(unsigned long long &d,
                                      unsigned long long a,
                                      unsigned long long b) {
    asm("fma.rn.f32x2 %0, %1, %2, %0;" : "+l"(d) : "l"(a), "l"(b));
}
__device__ __forceinline__ unsigned long long pack2(float x) {
    unsigned long long r;
    asm("mov.b64 %0, {%1, %1};" : "=l"(r) : "f"(x));
    return r;
}
__device__ __forceinline__ unsigned long long packab(float a, float b) {
    unsigned long long r;
    asm("mov.b64 %0, {%1, %2};" : "=l"(r) : "f"(a), "f"(b));
    return r;
}
__device__ __forceinline__ float lo32(unsigned long long v) {
    return __uint_as_float((unsigned)(v & 0xffffffffull));
}
__device__ __forceinline__ float hi32(unsigned long long v) {
    return __uint_as_float((unsigned)(v >> 32));
}

// ----------------------------------------------------------------------------
// HMMA / cp.async helpers (baseline PTX — compiles for plain compute_103)
// ----------------------------------------------------------------------------
__device__ __forceinline__ uint32_t smem_u32(const void* p) {
    uint32_t a;
    asm("{ .reg .u64 t; cvta.to.shared.u64 t, %1; cvt.u32.u64 %0, t; }"
        : "=r"(a) : "l"(p));
    return a;
}
#define LDSM_X4(r0, r1, r2, r3, addr) \
    asm volatile("ldmatrix.sync.aligned.m8n8.x4.shared.b16 {%0,%1,%2,%3}, [%4];" \
                 : "=r"(r0), "=r"(r1), "=r"(r2), "=r"(r3) : "r"(addr))
#define LDSM_X2(r0, r1, addr) \
    asm volatile("ldmatrix.sync.aligned.m8n8.x2.shared.b16 {%0,%1}, [%2];" \
                 : "=r"(r0), "=r"(r1) : "r"(addr))
#define MMA16816(c, a, b) \
    asm volatile("mma.sync.aligned.m16n8k16.row.col.f32.f16.f16.f32 " \
                 "{%0,%1,%2,%3}, {%4,%5,%6,%7}, {%8,%9}, {%0,%1,%2,%3};" \
                 : "+f"((c)[0]), "+f"((c)[1]), "+f"((c)[2]), "+f"((c)[3]) \
                 : "r"((a)[0]), "r"((a)[1]), "r"((a)[2]), "r"((a)[3]), \
                   "r"((b)[0]), "r"((b)[1]))
#define CP_ASYNC16(dst_u32, src_ptr) \
    asm volatile("cp.async.ca.shared.global [%0], [%1], 16;" \
                 :: "r"(dst_u32), "l"(src_ptr))
#define CP_COMMIT() asm volatile("cp.async.commit_group;" ::: "memory")
#define CP_WAIT(n)  asm volatile("cp.async.wait_group %0;" :: "n"(n) : "memory")

#define PITCH 40            // halves per smem row (80 B) — conflict-free ldmatrix
#define TILEH (128 * PITCH) // halves per tile
#define TILEB (TILEH * 2)   // bytes per tile

// ----------------------------------------------------------------------------
// fp16 hi/lo HMMA GEMM, split-K, 3-stage cp.async pipeline.
// C[M,N] = A[M,K] @ Bt^T (Bt = [N][K]); partial z at C + z*M*N.
// ----------------------------------------------------------------------------
__global__ __launch_bounds__(256)
void hgemm_hilo(const __half* __restrict__ Ah, const __half* __restrict__ Al,
                const __half* __restrict__ Bth, const __half* __restrict__ Btl,
                float* __restrict__ C, int M, int N, int K)
{
    extern __shared__ __align__(16) __half dyn[];
    int tid = threadIdx.x;
    int lane = tid & 31, wid = tid >> 5;
    int wm = wid >> 2, wn = wid & 3;
    int row0 = blockIdx.y * 128, col0 = blockIdx.x * 128;
    int kb   = K / gridDim.z;
    int kbeg = blockIdx.z * kb;
    float* Cz = C + (size_t)blockIdx.z * M * N;
    int nchunk = kb / 32;

    uint32_t base = smem_u32(dyn);

    float acc[4][4][4];
    #pragma unroll
    for (int mf = 0; mf < 4; mf++)
        #pragma unroll
        for (int nf = 0; nf < 4; nf++)
            #pragma unroll
            for (int e = 0; e < 4; e++) acc[mf][nf][e] = 0.f;

    int laneAr = lane & 15, laneAk = (lane & 16) ? 8 : 0;
    int laneBr = lane & 7,  laneBk = (lane & 8)  ? 8 : 0;

    auto load_stage = [&](int c, int s) {
        uint32_t sb = base + (uint32_t)s * 4 * TILEB;
        #pragma unroll
        for (int i = 0; i < 2; i++) {
            int idx = tid + i * 256;
            int row = idx >> 2, sg = idx & 3;
            size_t ga = (size_t)(row0 + row) * K + kbeg + c * 32 + sg * 8;
            size_t gb = (size_t)(col0 + row) * K + kbeg + c * 32 + sg * 8;
            uint32_t so = (uint32_t)(row * PITCH + sg * 8) * 2;
            CP_ASYNC16(sb + 0 * TILEB + so, Ah + ga);
            CP_ASYNC16(sb + 1 * TILEB + so, Al + ga);
            CP_ASYNC16(sb + 2 * TILEB + so, Bth + gb);
            CP_ASYNC16(sb + 3 * TILEB + so, Btl + gb);
        }
    };

    load_stage(0, 0);
    CP_COMMIT();
    load_stage(1, 1);
    CP_COMMIT();
    for (int c = 0; c < nchunk; c++) {
        int s = c % 3;
        if (c + 2 < nchunk) { load_stage(c + 2, (c + 2) % 3); CP_COMMIT(); CP_WAIT(2); }
        else if (c + 1 < nchunk) { CP_WAIT(1); }
        else { CP_WAIT(0); }
        __syncthreads();
        uint32_t bAh = base + (uint32_t)s * 4 * TILEB;
        uint32_t bAl = bAh + TILEB;
        uint32_t bBh = bAl + TILEB;
        uint32_t bBl = bBh + TILEB;
        #pragma unroll
        for (int ks = 0; ks < 32; ks += 16) {
            uint32_t bh[4][2], bl[4][2];
            #pragma unroll
            for (int nf = 0; nf < 4; nf++) {
                uint32_t off = (uint32_t)((wn * 32 + nf * 8 + laneBr) * PITCH
                                          + ks + laneBk) * 2;
                LDSM_X2(bh[nf][0], bh[nf][1], bBh + off);
                LDSM_X2(bl[nf][0], bl[nf][1], bBl + off);
            }
            #pragma unroll
            for (int mf = 0; mf < 4; mf++) {
                uint32_t off = (uint32_t)((wm * 64 + mf * 16 + laneAr) * PITCH
                                          + ks + laneAk) * 2;
                uint32_t ah[4], al[4];
                LDSM_X4(ah[0], ah[1], ah[2], ah[3], bAh + off);
                LDSM_X4(al[0], al[1], al[2], al[3], bAl + off);
                #pragma unroll
                for (int nf = 0; nf < 4; nf++) {
                    MMA16816(acc[mf][nf], ah, bh[nf]);
                    MMA16816(acc[mf][nf], ah, bl[nf]);
                    MMA16816(acc[mf][nf], al, bh[nf]);
                }
            }
        }
        __syncthreads();
    }
    #pragma unroll
    for (int mf = 0; mf < 4; mf++) {
        int r = row0 + wm * 64 + mf * 16 + (lane >> 2);
        #pragma unroll
        for (int nf = 0; nf < 4; nf++) {
            int c = col0 + wn * 32 + nf * 8 + (lane & 3) * 2;
            *(float2*)(Cz + (size_t)r * N + c) =
                make_float2(acc[mf][nf][0], acc[mf][nf][1]);
            *(float2*)(Cz + (size_t)(r + 8) * N + c) =
                make_float2(acc[mf][nf][2], acc[mf][nf][3]);
        }
    }
}
#define HG_SMEM (3 * 4 * TILEB)     // 122880

// ----------------------------------------------------------------------------
// Dual-output projection, 2-stage pipelined: Ck = A@Wk^T, Cv = A@Wv^T.
// ----------------------------------------------------------------------------
__global__ __launch_bounds__(256)
void hgemm_dual(const __half* __restrict__ Ah, const __half* __restrict__ Al,
                const __half* __restrict__ Bkh, const __half* __restrict__ Bkl,
                const __half* __restrict__ Bvh, const __half* __restrict__ Bvl,
                float* __restrict__ Ck, float* __restrict__ Cv,
                int M, int N, int K)
{
    extern __shared__ __align__(16) __half dyn[];
    int tid = threadIdx.x;
    int lane = tid & 31, wid = tid >> 5;
    int wm = wid >> 2, wn = wid & 3;
    int row0 = blockIdx.y * 128, col0 = blockIdx.x * 128;
    int nchunk = K / 32;
    uint32_t base = smem_u32(dyn);

    float accK[4][4][4], accV[4][4][4];
    #pragma unroll
    for (int mf = 0; mf < 4; mf++)
        #pragma unroll
        for (int nf = 0; nf < 4; nf++)
            #pragma unroll
            for (int e = 0; e < 4; e++) { accK[mf][nf][e] = 0.f; accV[mf][nf][e] = 0.f; }

    int laneAr = lane & 15, laneAk = (lane & 16) ? 8 : 0;
    int laneBr = lane & 7,  laneBk = (lane & 8)  ? 8 : 0;

    auto load_stage = [&](int c, int s) {
        uint32_t sb = base + (uint32_t)s * 6 * TILEB;
        #pragma unroll
        for (int i = 0; i < 2; i++) {
            int idx = tid + i * 256;
            int row = idx >> 2, sg = idx & 3;
            size_t ga = (size_t)(row0 + row) * K + c * 32 + sg * 8;
            size_t gb = (size_t)(col0 + row) * K + c * 32 + sg * 8;
            uint32_t so = (uint32_t)(row * PITCH + sg * 8) * 2;
            CP_ASYNC16(sb + 0 * TILEB + so, Ah + ga);
            CP_ASYNC16(sb + 1 * TILEB + so, Al + ga);
            CP_ASYNC16(sb + 2 * TILEB + so, Bkh + gb);
            CP_ASYNC16(sb + 3 * TILEB + so, Bkl + gb);
            CP_ASYNC16(sb + 4 * TILEB + so, Bvh + gb);
            CP_ASYNC16(sb + 5 * TILEB + so, Bvl + gb);
        }
    };

    load_stage(0, 0);
    CP_COMMIT();
    for (int c = 0; c < nchunk; c++) {
        int s = c & 1;
        if (c + 1 < nchunk) { load_stage(c + 1, s ^ 1); CP_COMMIT(); CP_WAIT(1); }
        else                { CP_WAIT(0); }
        __syncthreads();
        uint32_t bAh = base + (uint32_t)s * 6 * TILEB;
        uint32_t bAl = bAh + TILEB;
        uint32_t bKh = bAl + TILEB;
        uint32_t bKl = bKh + TILEB;
        uint32_t bVh = bKl + TILEB;
        uint32_t bVl = bVh + TILEB;
        #pragma unroll
        for (int ks = 0; ks < 32; ks += 16) {
            uint32_t kh[4][2], kl[4][2], vh[4][2], vl[4][2];
            #pragma unroll
            for (int nf = 0; nf < 4; nf++) {
                uint32_t off = (uint32_t)((wn * 32 + nf * 8 + laneBr) * PITCH
                                          + ks + laneBk) * 2;
                LDSM_X2(kh[nf][0], kh[nf][1], bKh + off);
                LDSM_X2(kl[nf][0], kl[nf][1], bKl + off);
                LDSM_X2(vh[nf][0], vh[nf][1], bVh + off);
                LDSM_X2(vl[nf][0], vl[nf][1], bVl + off);
            }
            #pragma unroll
            for (int mf = 0; mf < 4; mf++) {
                uint32_t off = (uint32_t)((wm * 64 + mf * 16 + laneAr) * PITCH
                                          + ks + laneAk) * 2;
                uint32_t ah[4], al[4];
                LDSM_X4(ah[0], ah[1], ah[2], ah[3], bAh + off);
                LDSM_X4(al[0], al[1], al[2], al[3], bAl + off);
                #pragma unroll
                for (int nf = 0; nf < 4; nf++) {
                    MMA16816(accK[mf][nf], ah, kh[nf]);
                    MMA16816(accK[mf][nf], ah, kl[nf]);
                    MMA16816(accK[mf][nf], al, kh[nf]);
                    MMA16816(accV[mf][nf], ah, vh[nf]);
                    MMA16816(accV[mf][nf], ah, vl[nf]);
                    MMA16816(accV[mf][nf], al, vh[nf]);
                }
            }
        }
        __syncthreads();
    }
    #pragma unroll
    for (int mf = 0; mf < 4; mf++) {
        int r = row0 + wm * 64 + mf * 16 + (lane >> 2);
        #pragma unroll
        for (int nf = 0; nf < 4; nf++) {
            int c = col0 + wn * 32 + nf * 8 + (lane & 3) * 2;
            *(float2*)(Ck + (size_t)r * N + c) =
                make_float2(accK[mf][nf][0], accK[mf][nf][1]);
            *(float2*)(Ck + (size_t)(r + 8) * N + c) =
                make_float2(accK[mf][nf][2], accK[mf][nf][3]);
            *(float2*)(Cv + (size_t)r * N + c) =
                make_float2(accV[mf][nf][0], accV[mf][nf][1]);
            *(float2*)(Cv + (size_t)(r + 8) * N + c) =
                make_float2(accV[mf][nf][2], accV[mf][nf][3]);
        }
    }
}
#define DUAL2_SMEM (2 * 6 * TILEB)   // 122880

// ----------------------------------------------------------------------------
// W1 + GLU fused, 2-stage pipelined; emits fp16 hi/lo of u*silu(g).
// ----------------------------------------------------------------------------
__global__ __launch_bounds__(256)
void hgemm_glu(const __half* __restrict__ Ah, const __half* __restrict__ Al,
               const __half* __restrict__ W1th, const __half* __restrict__ W1tl,
               __half* __restrict__ Ih, __half* __restrict__ Il, int M)
{
    extern __shared__ __align__(16) __half dyn[];
    int tid = threadIdx.x;
    int lane = tid & 31, wid = tid >> 5;
    int wm = wid >> 2, wn = wid & 3;
    int row0 = blockIdx.y * 128, col0 = blockIdx.x * 128;
    int nchunk = D / 32;
    uint32_t base = smem_u32(dyn);

    float accU[4][4][4], accG[4][4][4];
    #pragma unroll
    for (int mf = 0; mf < 4; mf++)
        #pragma unroll
        for (int nf = 0; nf < 4; nf++)
            #pragma unroll
            for (int e = 0; e < 4; e++) { accU[mf][nf][e] = 0.f; accG[mf][nf][e] = 0.f; }

    int laneAr = lane & 15, laneAk = (lane & 16) ? 8 : 0;
    int laneBr = lane & 7,  laneBk = (lane & 8)  ? 8 : 0;

    auto load_stage = [&](int c, int s) {
        uint32_t sb = base + (uint32_t)s * 6 * TILEB;
        #pragma unroll
        for (int i = 0; i < 2; i++) {
            int idx = tid + i * 256;
            int row = idx >> 2, sg = idx & 3;
            size_t ga = (size_t)(row0 + row) * D + c * 32 + sg * 8;
            size_t gu = (size_t)(col0 + row) * D + c * 32 + sg * 8;
            size_t gg = (size_t)(col0 + row + INNER) * D + c * 32 + sg * 8;
            uint32_t so = (uint32_t)(row * PITCH + sg * 8) * 2;
            CP_ASYNC16(sb + 0 * TILEB + so, Ah + ga);
            CP_ASYNC16(sb + 1 * TILEB + so, Al + ga);
            CP_ASYNC16(sb + 2 * TILEB + so, W1th + gu);
            CP_ASYNC16(sb + 3 * TILEB + so, W1tl + gu);
            CP_ASYNC16(sb + 4 * TILEB + so, W1th + gg);
            CP_ASYNC16(sb + 5 * TILEB + so, W1tl + gg);
        }
    };

    load_stage(0, 0);
    CP_COMMIT();
    for (int c = 0; c < nchunk; c++) {
        int s = c & 1;
        if (c + 1 < nchunk) { load_stage(c + 1, s ^ 1); CP_COMMIT(); CP_WAIT(1); }
        else                { CP_WAIT(0); }
        __syncthreads();
        uint32_t bAh = base + (uint32_t)s * 6 * TILEB;
        uint32_t bAl = bAh + TILEB;
        uint32_t bUh = bAl + TILEB;
        uint32_t bUl = bUh + TILEB;
        uint32_t bGh = bUl + TILEB;
        uint32_t bGl = bGh + TILEB;
        #pragma unroll
        for (int ks = 0; ks < 32; ks += 16) {
            uint32_t uh[4][2], ul[4][2], gh[4][2], gl[4][2];
            #pragma unroll
            for (int nf = 0; nf < 4; nf++) {
                uint32_t off = (uint32_t)((wn * 32 + nf * 8 + laneBr) * PITCH
                                          + ks + laneBk) * 2;
                LDSM_X2(uh[nf][0], uh[nf][1], bUh + off);
                LDSM_X2(ul[nf][0], ul[nf][1], bUl + off);
                LDSM_X2(gh[nf][0], gh[nf][1], bGh + off);
                LDSM_X2(gl[nf][0], gl[nf][1], bGl + off);
            }
            #pragma unroll
            for (int mf = 0; mf < 4; mf++) {
                uint32_t off = (uint32_t)((wm * 64 + mf * 16 + laneAr) * PITCH
                                          + ks + laneAk) * 2;
                uint32_t ah[4], al[4];
                LDSM_X4(ah[0], ah[1], ah[2], ah[3], bAh + off);
                LDSM_X4(al[0], al[1], al[2], al[3], bAl + off);
                #pragma unroll
                for (int nf = 0; nf < 4; nf++) {
                    MMA16816(accU[mf][nf], ah, uh[nf]);
                    MMA16816(accU[mf][nf], ah, ul[nf]);
                    MMA16816(accU[mf][nf], al, uh[nf]);
                    MMA16816(accG[mf][nf], ah, gh[nf]);
                    MMA16816(accG[mf][nf], ah, gl[nf]);
                    MMA16816(accG[mf][nf], al, gh[nf]);
                }
            }
        }
        __syncthreads();
    }
    #pragma unroll
    for (int mf = 0; mf < 4; mf++) {
        int r = row0 + wm * 64 + mf * 16 + (lane >> 2);
        #pragma unroll
        for (int nf = 0; nf < 4; nf++) {
            int c = col0 + wn * 32 + nf * 8 + (lane & 3) * 2;
            #pragma unroll
            for (int half_ = 0; half_ < 2; half_++) {
                int rr = r + half_ * 8;
                float u0 = accU[mf][nf][half_ * 2], u1 = accU[mf][nf][half_ * 2 + 1];
                float gg0 = accG[mf][nf][half_ * 2], gg1 = accG[mf][nf][half_ * 2 + 1];
                float v0 = u0 * (gg0 / (1.f + expf(-gg0)));
                float v1 = u1 * (gg1 / (1.f + expf(-gg1)));
                __half h0 = __float2half_rn(v0), h1 = __float2half_rn(v1);
                __half l0 = __float2half_rn(v0 - __half2float(h0));
                __half l1 = __float2half_rn(v1 - __half2float(h1));
                *(__half2*)(Ih + (size_t)rr * INNER + c) = __halves2half2(h0, h1);
                *(__half2*)(Il + (size_t)rr * INNER + c) = __halves2half2(l0, l1);
            }
        }
    }
}

// ----------------------------------------------------------------------------
// LN reduction helper (256 threads over D=768)
// ----------------------------------------------------------------------------
__device__ __forceinline__ void ln_stats(float v0, float v1, float v2,
                                         float* sa, float* sb2,
                                         float& mean, float& rinv)
{
    float s = v0 + v1 + v2;
    float q = v0 * v0 + v1 * v1 + v2 * v2;
    int tid = threadIdx.x;
    #pragma unroll
    for (int o = 16; o > 0; o >>= 1) {
        s += __shfl_down_sync(0xffffffffu, s, o);
        q += __shfl_down_sync(0xffffffffu, q, o);
    }
    int w = tid >> 5, l = tid & 31;
    if (l == 0) { sa[w] = s; sb2[w] = q; }
    __syncthreads();
    if (tid == 0) {
        float ts = 0.f, tq = 0.f;
        #pragma unroll
        for (int k = 0; k < 8; k++) { ts += sa[k]; tq += sb2[k]; }
        sa[0] = ts; sb2[0] = tq;
    }
    __syncthreads();
    mean = sa[0] * (1.0f / D);
    float var = sb2[0] * (1.0f / D) - mean * mean;
    rinv = rsqrtf(var + 1e-5f);
    __syncthreads();
}

// LN(x) -> fp16 hi/lo
__global__ __launch_bounds__(256)
void ln_split_kernel(const float* __restrict__ in,
                     __half* __restrict__ oh, __half* __restrict__ ol,
                     const float* __restrict__ gamma, const float* __restrict__ beta)
{
    int row = blockIdx.x, tid = threadIdx.x;
    const float* x = in + (size_t)row * D;
    float v[3] = {x[tid], x[tid + 256], x[tid + 512]};
    __shared__ float sa[8], sb2[8];
    float mean, r;
    ln_stats(v[0], v[1], v[2], sa, sb2, mean, r);
    #pragma unroll
    for (int e = 0; e < 3; e++) {
        int idx = tid + e * 256;
        float y = (v[e] - mean) * r * gamma[idx] + beta[idx];
        __half hb = __float2half_rn(y);
        oh[(size_t)row * D + idx] = hb;
        ol[(size_t)row * D + idx] = __float2half_rn(y - __half2float(hb));
    }
}

// h = LN_a(slots + upd) -> hb(fp32);  LN_b(h) -> oh/ol(hi/lo)
__global__ __launch_bounds__(256)
void ln_dual_kernel(const float* __restrict__ slots, const float* __restrict__ upd,
                    float* __restrict__ hb,
                    const float* __restrict__ g1, const float* __restrict__ b1,
                    const float* __restrict__ g2, const float* __restrict__ b2,
                    __half* __restrict__ oh, __half* __restrict__ ol)
{
    int row = blockIdx.x, tid = threadIdx.x;
    const float* xs = slots + (size_t)row * D;
    const float* xu = upd + (size_t)row * D;
    float v[3];
    #pragma unroll
    for (int e = 0; e < 3; e++) v[e] = xs[tid + e * 256] + xu[tid + e * 256];
    __shared__ float sa[8], sb2[8];
    float mean, r;
    ln_stats(v[0], v[1], v[2], sa, sb2, mean, r);
    float y[3];
    #pragma unroll
    for (int e = 0; e < 3; e++) {
        int idx = tid + e * 256;
        y[e] = (v[e] - mean) * r * g1[idx] + b1[idx];
        hb[(size_t)row * D + idx] = y[e];
    }
    float mean2, r2;
    ln_stats(y[0], y[1], y[2], sa, sb2, mean2, r2);
    #pragma unroll
    for (int e = 0; e < 3; e++) {
        int idx = tid + e * 256;
        float z = (y[e] - mean2) * r2 * g2[idx] + b2[idx];
        __half hh = __float2half_rn(z);
        oh[(size_t)row * D + idx] = hh;
        ol[(size_t)row * D + idx] = __float2half_rn(z - __half2float(hh));
    }
}

// h = res + sum_{sp<4} part[sp]; res <- h; LN(h) -> oh/ol
__global__ __launch_bounds__(256)
void ln_split_red_kernel(const float* __restrict__ part, float* __restrict__ res,
                         const float* __restrict__ gamma, const float* __restrict__ beta,
                         __half* __restrict__ oh, __half* __restrict__ ol)
{
    int row = blockIdx.x, tid = threadIdx.x;
    float v[3];
    #pragma unroll
    for (int e = 0; e < 3; e++) {
        int idx = tid + e * 256;
        size_t o = (size_t)row * D + idx;
        float s = res[o];
        #pragma unroll
        for (int sp = 0; sp < 4; sp++) s += part[(size_t)sp * MS * D + o];
        v[e] = s;
        res[o] = s;
    }
    __shared__ float sa[8], sb2[8];
    float mean, r;
    ln_stats(v[0], v[1], v[2], sa, sb2, mean, r);
    #pragma unroll
    for (int e = 0; e < 3; e++) {
        int idx = tid + e * 256;
        float y = (v[e] - mean) * r * gamma[idx] + beta[idx];
        __half hb = __float2half_rn(y);
        oh[(size_t)row * D + idx] = hb;
        ol[(size_t)row * D + idx] = __float2half_rn(y - __half2float(hb));
    }
}

// h = res + sum part; slots = LN_f(h);  LN_s(slots) -> qn hi/lo (next step)
__global__ __launch_bounds__(256)
void ln_red_dual_kernel(const float* __restrict__ part, const float* __restrict__ res,
                        float* __restrict__ slots,
                        const float* __restrict__ gf, const float* __restrict__ bf,
                        const float* __restrict__ gs, const float* __restrict__ bs,
                        __half* __restrict__ qh, __half* __restrict__ ql)
{
    int row = blockIdx.x, tid = threadIdx.x;
    float v[3];
    #pragma unroll
    for (int e = 0; e < 3; e++) {
        int idx = tid + e * 256;
        size_t o = (size_t)row * D + idx;
        float s = res[o];
        #pragma unroll
        for (int sp = 0; sp < 4; sp++) s += part[(size_t)sp * MS * D + o];
        v[e] = s;
    }
    __shared__ float sa[8], sb2[8];
    float mean, r;
    ln_stats(v[0], v[1], v[2], sa, sb2, mean, r);
    float y[3];
    #pragma unroll
    for (int e = 0; e < 3; e++) {
        int idx = tid + e * 256;
        y[e] = (v[e] - mean) * r * gf[idx] + bf[idx];
        slots[(size_t)row * D + idx] = y[e];
    }
    float mean2, r2;
    ln_stats(y[0], y[1], y[2], sa, sb2, mean2, r2);
    #pragma unroll
    for (int e = 0; e < 3; e++) {
        int idx = tid + e * 256;
        float z = (y[e] - mean2) * r2 * gs[idx] + bs[idx];
        __half hh = __float2half_rn(z);
        qh[(size_t)row * D + idx] = hh;
        ql[(size_t)row * D + idx] = __float2half_rn(z - __half2float(hh));
    }
}

// transpose + fp16 hi/lo split
__global__ __launch_bounds__(256)
void wsplit_kernel(const float* __restrict__ W,
                   __half* __restrict__ Th, __half* __restrict__ Tl,
                   int Krows, int Ncols, int n_off)
{
    __shared__ float tile[32][33];
    int n0 = blockIdx.x * 32, k0 = blockIdx.y * 32;
    int t = threadIdx.x;
    int tx = t & 31, ty = t >> 5;
    #pragma unroll
    for (int i = 0; i < 4; i++)
        tile[ty + i * 8][tx] = W[(size_t)(k0 + ty + i * 8) * Ncols + n0 + tx];
    __syncthreads();
    #pragma unroll
    for (int i = 0; i < 4; i++) {
        int n = n_off + n0 + ty + i * 8;
        float v = tile[tx][ty + i * 8];
        __half hb = __float2half_rn(v);
        Th[(size_t)n * Krows + k0 + tx] = hb;
        Tl[(size_t)n * Krows + k0 + tx] = __float2half_rn(v - __half2float(hb));
    }
}

__global__ void init_slots_kernel(const float* __restrict__ noise,
                                  const float* __restrict__ mu,
                                  const float* __restrict__ ls,
                                  float* __restrict__ slots)
{
    int t = blockIdx.x * blockDim.x + threadIdx.x;
    if (t >= MS * D) return;
    int d = t % D;
    slots[t] = mu[d] + expf(ls[d]) * noise[t];
}

// ----------------------------------------------------------------------------
// dots + softmax over the slot axis; q staged once from Wq split-K partials;
// FFMA2 packed accumulators.
// dyn smem: qs2 [768*8] ull (49152B) ; ks [64*65] f32 (16640B) ; red [256] f32
// ----------------------------------------------------------------------------
#define DOTS_SMEM (49152 + 16640 + 1024)
__global__ __launch_bounds__(256)
void dots_softmax_kernel(const float* __restrict__ Qpart, const float* __restrict__ Kb,
                         float* __restrict__ attn)
{
    extern __shared__ __align__(16) char dsm[];
    unsigned long long* qs2 = (unsigned long long*)dsm;
    float* ksf = (float*)(dsm + 49152);
    float* red = (float*)(dsm + 49152 + 16640);
    int b  = blockIdx.y;
    int j0 = blockIdx.x * 64;
    int tid = threadIdx.x;
    int tx = tid & 63, ty = tid >> 6;

    // stage q pairs once: qs2[kk*8 + p] = {q[sA][kk], q[sA+4][kk]},
    // sA = (p&3) + (p>>2)*8 ; pairs feed acc[0..3] = slots ty, ty+4, ty+8, ty+12
    #pragma unroll
    for (int p = 0; p < 8; p++) {
        int sA = (p & 3) + ((p >> 2) << 3);
        size_t oA0 = ((size_t)b * S + sA) * D;
        size_t oB0 = ((size_t)b * S + sA + 4) * D;
        #pragma unroll
        for (int cch = 0; cch < 3; cch++) {
            int kk = tid + cch * 256;
            size_t oA = oA0 + kk, oB = oB0 + kk;
            float a = Qpart[oA] + Qpart[(size_t)MS * D + oA]
                    + Qpart[2 * (size_t)MS * D + oA] + Qpart[3 * (size_t)MS * D + oA];
            float v = Qpart[oB] + Qpart[(size_t)MS * D + oB]
                    + Qpart[2 * (size_t)MS * D + oB] + Qpart[3 * (size_t)MS * D + oB];
            qs2[kk * 8 + p] = packab(a, v);
        }
    }

    const float* Kp = Kb + ((size_t)b * NK + j0) * D;
    unsigned long long acc01 = 0ull, acc23 = 0ull;
    for (int k0 = 0; k0 < D; k0 += 64) {
        #pragma unroll
        for (int p = 0; p < 4; p++) {
            int e = tid + p * 256;
            int jj = e >> 4, kc = (e & 15) * 4;
            float4 v = *(const float4*)&Kp[(size_t)jj * D + k0 + kc];
            ksf[jj * 65 + kc + 0] = v.x; ksf[jj * 65 + kc + 1] = v.y;
            ksf[jj * 65 + kc + 2] = v.z; ksf[jj * 65 + kc + 3] = v.w;
        }
        __syncthreads();
        #pragma unroll
        for (int kk = 0; kk < 64; kk++) {
            unsigned long long kvp = pack2(ksf[tx * 65 + kk]);
            unsigned long long q01 = qs2[(k0 + kk) * 8 + ty];
            unsigned long long q23 = qs2[(k0 + kk) * 8 + ty + 4];
            ffma2(acc01, q01, kvp);
            ffma2(acc23, q23, kvp);
        }
        __syncthreads();
    }
    float acc[4] = {lo32(acc01) * kSCALE, hi32(acc01) * kSCALE,
                    lo32(acc23) * kSCALE, hi32(acc23) * kSCALE};
    float m = fmaxf(fmaxf(acc[0], acc[1]), fmaxf(acc[2], acc[3]));
    red[ty * 64 + tx] = m;
    __syncthreads();
    float M = fmaxf(fmaxf(red[tx], red[64 + tx]), fmaxf(red[128 + tx], red[192 + tx]));
    __syncthreads();
    float e[4]; float s = 0.f;
    #pragma unroll
    for (int r = 0; r < 4; r++) { e[r] = expf(acc[r] - M); s += e[r]; }
    red[ty * 64 + tx] = s;
    __syncthreads();
    float Ssum = red[tx] + red[64 + tx] + red[128 + tx] + red[192 + tx];
    float inv = 1.f / Ssum;
    #pragma unroll
    for (int r = 0; r < 4; r++)
        attn[((size_t)b * S + ty + r * 4) * NK + j0 + tx] = e[r] * inv + 1e-8f;
}

// updates[b,i,n] = (sum_j attn * v) / (sum_j attn)  — FFMA2 packed
__global__ __launch_bounds__(256)
void updates_kernel(const float* __restrict__ attn, const float* __restrict__ V,
                    float* __restrict__ upd)
{
    int b  = blockIdx.y;
    int n0 = blockIdx.x * 64;
    __shared__ __align__(16) unsigned long long as2[64 * 8];  // 4 KB
    __shared__ __align__(16) float vs[64][64];
    int tid = threadIdx.x;
    int tx = tid & 63, ty = tid >> 6;
    unsigned long long acc01 = 0ull, acc23 = 0ull;
    unsigned long long sum01 = 0ull, sum23 = 0ull;
    const unsigned long long ONE = pack2(1.0f);
    for (int j0 = 0; j0 < NK; j0 += 64) {
        // stage attn pairs: as2[jj*8+p] = {attn[sA][j0+jj], attn[sA+4][j0+jj]}
        #pragma unroll
        for (int i = 0; i < 2; i++) {
            int idx = tid + i * 256;
            int p = idx >> 6, jj = idx & 63;
            int sA = (p & 3) + ((p >> 2) << 3);
            float a = attn[((size_t)b * S + sA) * NK + j0 + jj];
            float v = attn[((size_t)b * S + sA + 4) * NK + j0 + jj];
            as2[jj * 8 + p] = packab(a, v);
        }
        #pragma unroll
        for (int p = 0; p < 4; p++) {
            int e = tid + p * 256;
            int jj = e >> 4, nc = (e & 15) * 4;
            *(float4*)&vs[jj][nc] =
                *(const float4*)&V[((size_t)b * NK + j0 + jj) * D + n0 + nc];
        }
        __syncthreads();
        #pragma unroll
        for (int jj = 0; jj < 64; jj++) {
            unsigned long long vvp = pack2(vs[jj][tx]);
            unsigned long long a01 = as2[jj * 8 + ty];
            unsigned long long a23 = as2[jj * 8 + ty + 4];
            ffma2(acc01, a01, vvp);
            ffma2(acc23, a23, vvp);
            ffma2(sum01, a01, ONE);
            ffma2(sum23, a23, ONE);
        }
        __syncthreads();
    }
    upd[((size_t)b * S + ty     ) * D + n0 + tx] = lo32(acc01) / lo32(sum01);
    upd[((size_t)b * S + ty +  4) * D + n0 + tx] = hi32(acc01) / hi32(sum01);
    upd[((size_t)b * S + ty +  8) * D + n0 + tx] = lo32(acc23) / lo32(sum23);
    upd[((size_t)b * S + ty + 12) * D + n0 + tx] = hi32(acc23) / hi32(sum23);
}

// encoder self-attention; reads QKV split-K partials directly
__global__ __launch_bounds__(256)
void enc_attn_kernel(const float* __restrict__ QKVpart,
                     __half* __restrict__ Oh, __half* __restrict__ Ol)
{
    int b = blockIdx.x >> 3, h = blockIdx.x & 7;
    __shared__ float qs[16][65], ks[16][65], vs[16][65];
    __shared__ float p[16][17];
    int tid = threadIdx.x;
    int i = tid >> 4, jj = tid & 15;
    {
        int r = tid >> 4, c = (tid & 15) * 4;
        size_t base = ((size_t)b * S + r) * QKV3 + h * DH + c;
        float4 vq = *(const float4*)&QKVpart[base];
        float4 vk = *(const float4*)&QKVpart[base + HD];
        float4 vv = *(const float4*)&QKVpart[base + 2 * HD];
        #pragma unroll
        for (int sp = 1; sp < 4; sp++) {
            size_t o = (size_t)sp * MS * QKV3 + base;
            float4 w;
            w = *(const float4*)&QKVpart[o];
            vq.x += w.x; vq.y += w.y; vq.z += w.z; vq.w += w.w;
            w = *(const float4*)&QKVpart[o + HD];
            vk.x += w.x; vk.y += w.y; vk.z += w.z; vk.w += w.w;
            w = *(const float4*)&QKVpart[o + 2 * HD];
            vv.x += w.x; vv.y += w.y; vv.z += w.z; vv.w += w.w;
        }
        qs[r][c] = vq.x; qs[r][c+1] = vq.y; qs[r][c+2] = vq.z; qs[r][c+3] = vq.w;
        ks[r][c] = vk.x; ks[r][c+1] = vk.y; ks[r][c+2] = vk.z; ks[r][c+3] = vk.w;
        vs[r][c] = vv.x; vs[r][c+1] = vv.y; vs[r][c+2] = vv.z; vs[r][c+3] = vv.w;
    }
    __syncthreads();
    float s = 0.f;
    #pragma unroll
    for (int d = 0; d < DH; d++) s += qs[i][d] * ks[jj][d];
    s *= 0.125f;
    p[i][jj] = s;
    __syncthreads();
    float m = -1e30f;
    #pragma unroll
    for (int t2 = 0; t2 < 16; t2++) m = fmaxf(m, p[i][t2]);
    __syncthreads();
    float e = expf(s - m);
    p[i][jj] = e;
    __syncthreads();
    float sum = 0.f;
    #pragma unroll
    for (int t2 = 0; t2 < 16; t2++) sum += p[i][t2];
    __syncthreads();
    p[i][jj] = e / sum;
    __syncthreads();
    int io = tid >> 4, dbase = (tid & 15) * 4;
    float o[4] = {0.f, 0.f, 0.f, 0.f};
    #pragma unroll
    for (int t2 = 0; t2 < 16; t2++) {
        float pp = p[io][t2];
        o[0] += pp * vs[t2][dbase + 0];
        o[1] += pp * vs[t2][dbase + 1];
        o[2] += pp * vs[t2][dbase + 2];
        o[3] += pp * vs[t2][dbase + 3];
    }
    size_t base = ((size_t)b * S + io) * HD + h * DH + dbase;
    #pragma unroll
    for (int c = 0; c < 4; c++) {
        __half hb = __float2half_rn(o[c]);
        Oh[base + c] = hb;
        Ol[base + c] = __float2half_rn(o[c] - __half2float(hb));
    }
}

// output map: per (b,i) row — sum over keys then write out[b][j][i] = attn/sum
__global__ __launch_bounds__(256)
void attn_out_kernel(const float* __restrict__ attn, float* __restrict__ out)
{
    int row = blockIdx.x;            // b*S + i
    int b = row >> 4, i = row & 15;
    const float4* p = (const float4*)(attn + (size_t)row * NK);
    int tid = threadIdx.x;
    float4 v = p[tid];
    float s = v.x + v.y + v.z + v.w;
    __shared__ float sa[8];
    #pragma unroll
    for (int o = 16; o > 0; o >>= 1) s += __shfl_down_sync(0xffffffffu, s, o);
    int w = tid >> 5, l = tid & 31;
    if (l == 0) sa[w] = s;
    __syncthreads();
    if (tid == 0) {
        float ts = 0.f;
        #pragma unroll
        for (int k = 0; k < 8; k++) ts += sa[k];
        sa[0] = ts;
    }
    __syncthreads();
    float inv = 1.f / sa[0];
    size_t ob = (size_t)b * NK * S + i;
    int j = tid * 4;
    out[ob + (size_t)(j + 0) * S] = v.x * inv;
    out[ob + (size_t)(j + 1) * S] = v.y * inv;
    out[ob + (size_t)(j + 2) * S] = v.z * inv;
    out[ob + (size_t)(j + 3) * S] = v.w * inv;
}

// ----------------------------------------------------------------------------
// Host orchestration
// ----------------------------------------------------------------------------
extern "C" void kernel_launch(void* const* d_in, const int* in_sizes, int n_in,
                              void* d_out, int out_size)
{
    const float* x       = (const float*)d_in[0];
    const float* noise   = (const float*)d_in[1];
    const float* init_mu = (const float*)d_in[2];
    const float* init_ls = (const float*)d_in[3];
    const float* Wk      = (const float*)d_in[4];
    const float* Wv      = (const float*)d_in[5];
    const float* Wq      = (const float*)d_in[6];
    const float* ni_g    = (const float*)d_in[7];
    const float* ni_b    = (const float*)d_in[8];
    const float* ns_g    = (const float*)d_in[9];
    const float* ns_b    = (const float*)d_in[10];
    const float* nica_g  = (const float*)d_in[11];
    const float* nica_b  = (const float*)d_in[12];
    const float* ln1_g   = (const float*)d_in[13];
    const float* ln1_b   = (const float*)d_in[14];
    const float* Wq_a    = (const float*)d_in[15];
    const float* Wk_a    = (const float*)d_in[16];
    const float* Wv_a    = (const float*)d_in[17];
    const float* Wo_a    = (const float*)d_in[18];
    const float* ln2_g   = (const float*)d_in[19];
    const float* ln2_b   = (const float*)d_in[20];
    const float* W1      = (const float*)d_in[21];
    const float* W2      = (const float*)d_in[22];
    const float* lnf_g   = (const float*)d_in[23];
    const float* lnf_b   = (const float*)d_in[24];

    __half *xnh, *xnl, *wkh, *wkl, *wvh, *wvl, *wqh, *wql;
    __half *wqkh, *wqkl, *woh, *wol, *w1h, *w1l, *w2h, *w2l;
    __half *qnh, *qnl, *abh, *abl, *fbh, *fbl, *innh, *innl, *oah, *oal;
    float *kb, *vb, *slots, *attn, *upd, *hb, *part;
    cudaGetSymbolAddress((void**)&xnh,  g_xnh);  cudaGetSymbolAddress((void**)&xnl,  g_xnl);
    cudaGetSymbolAddress((void**)&wkh,  g_wkh);  cudaGetSymbolAddress((void**)&wkl,  g_wkl);
    cudaGetSymbolAddress((void**)&wvh,  g_wvh);  cudaGetSymbolAddress((void**)&wvl,  g_wvl);
    cudaGetSymbolAddress((void**)&wqh,  g_wqh);  cudaGetSymbolAddress((void**)&wql,  g_wql);
    cudaGetSymbolAddress((void**)&wqkh, g_wqkh); cudaGetSymbolAddress((void**)&wqkl, g_wqkl);
    cudaGetSymbolAddress((void**)&woh,  g_woh);  cudaGetSymbolAddress((void**)&wol,  g_wol);
    cudaGetSymbolAddress((void**)&w1h,  g_w1h);  cudaGetSymbolAddress((void**)&w1l,  g_w1l);
    cudaGetSymbolAddress((void**)&w2h,  g_w2h);  cudaGetSymbolAddress((void**)&w2l,  g_w2l);
    cudaGetSymbolAddress((void**)&qnh,  g_qnh);  cudaGetSymbolAddress((void**)&qnl,  g_qnl);
    cudaGetSymbolAddress((void**)&abh,  g_abh);  cudaGetSymbolAddress((void**)&abl,  g_abl);
    cudaGetSymbolAddress((void**)&fbh,  g_fbh);  cudaGetSymbolAddress((void**)&fbl,  g_fbl);
    cudaGetSymbolAddress((void**)&innh, g_innh); cudaGetSymbolAddress((void**)&innl, g_innl);
    cudaGetSymbolAddress((void**)&oah,  g_oah);  cudaGetSymbolAddress((void**)&oal,  g_oal);
    cudaGetSymbolAddress((void**)&kb,   g_k);
    cudaGetSymbolAddress((void**)&vb,   g_v);
    cudaGetSymbolAddress((void**)&slots,g_slots);
    cudaGetSymbolAddress((void**)&attn, g_attn);
    cudaGetSymbolAddress((void**)&upd,  g_upd);
    cudaGetSymbolAddress((void**)&hb,   g_h);
    cudaGetSymbolAddress((void**)&part, g_part);

    cudaFuncSetAttribute(hgemm_hilo, cudaFuncAttributeMaxDynamicSharedMemorySize, HG_SMEM);
    cudaFuncSetAttribute(hgemm_dual, cudaFuncAttributeMaxDynamicSharedMemorySize, DUAL2_SMEM);
    cudaFuncSetAttribute(hgemm_glu,  cudaFuncAttributeMaxDynamicSharedMemorySize, DUAL2_SMEM);
    cudaFuncSetAttribute(dots_softmax_kernel,
                         cudaFuncAttributeMaxDynamicSharedMemorySize, DOTS_SMEM);

    // ---- precompute (ordered so launch #5 = hgemm_dual for ncu) ----
    wsplit_kernel<<<dim3(D / 32, D / 32), 256>>>(Wk, wkh, wkl, D, D, 0);       // 0
    wsplit_kernel<<<dim3(D / 32, D / 32), 256>>>(Wv, wvh, wvl, D, D, 0);       // 1
    ln_split_kernel<<<B * NK, 256>>>(x, xnh, xnl, ni_g, ni_b);                 // 2
    init_slots_kernel<<<(MS * D + 255) / 256, 256>>>(noise, init_mu, init_ls, slots); // 3
    wsplit_kernel<<<dim3(D / 32, D / 32), 256>>>(Wq, wqh, wql, D, D, 0);       // 4
    hgemm_dual<<<dim3(D / 128, (B * NK) / 128), 256, DUAL2_SMEM>>>(            // 5
        xnh, xnl, wkh, wkl, wvh, wvl, kb, vb, B * NK, D, D);
    wsplit_kernel<<<dim3(HD / 32, D / 32), 256>>>(Wq_a, wqkh, wqkl, D, HD, 0);
    wsplit_kernel<<<dim3(HD / 32, D / 32), 256>>>(Wk_a, wqkh, wqkl, D, HD, HD);
    wsplit_kernel<<<dim3(HD / 32, D / 32), 256>>>(Wv_a, wqkh, wqkl, D, HD, 2 * HD);
    wsplit_kernel<<<dim3(D / 32, HD / 32), 256>>>(Wo_a, woh, wol, HD, D, 0);
    wsplit_kernel<<<dim3((2 * INNER) / 32, D / 32), 256>>>(W1, w1h, w1l, D, 2 * INNER, 0);
    wsplit_kernel<<<dim3(D / 32, INNER / 32), 256>>>(W2, w2h, w2l, INNER, D, 0);
    ln_split_kernel<<<MS, 256>>>(slots, qnh, qnl, ns_g, ns_b);

    // ---- 4 slot-attention steps (11 launches each) ----
    for (int it = 0; it < N_STEPS; it++) {
        hgemm_hilo<<<dim3(D / 128, MS / 128, 4), 256, HG_SMEM>>>(qnh, qnl, wqh, wql,
                                                                 part, MS, D, D);
        dots_softmax_kernel<<<dim3(NK / 64, B), 256, DOTS_SMEM>>>(part, kb, attn);
        updates_kernel<<<dim3(D / 64, B), 256>>>(attn, vb, upd);
        ln_dual_kernel<<<MS, 256>>>(slots, upd, hb, nica_g, nica_b,
                                    ln1_g, ln1_b, abh, abl);
        hgemm_hilo<<<dim3(QKV3 / 128, MS / 128, 4), 256, HG_SMEM>>>(abh, abl, wqkh, wqkl,
                                                                    part, MS, QKV3, D);
        enc_attn_kernel<<<B * H, 256>>>(part, oah, oal);
        hgemm_hilo<<<dim3(D / 128, MS / 128, 4), 256, HG_SMEM>>>(oah, oal, woh, wol,
                                                                 part, MS, D, HD);
        ln_split_red_kernel<<<MS, 256>>>(part, hb, ln2_g, ln2_b, fbh, fbl);
        hgemm_glu<<<dim3(INNER / 128, MS / 128), 256, DUAL2_SMEM>>>(fbh, fbl, w1h, w1l,
                                                                    innh, innl, MS);
        hgemm_hilo<<<dim3(D / 128, MS / 128, 4), 256, HG_SMEM>>>(innh, innl, w2h, w2l,
                                                                 part, MS, D, INNER);
        ln_red_dual_kernel<<<MS, 256>>>(part, hb, slots, lnf_g, lnf_b,
                                        ns_g, ns_b, qnh, qnl);
    }

    // ---- outputs: slots [32,16,768], then attn_map [32,1024,16] ----
    float* out = (float*)d_out;
    cudaMemcpyAsync(out, slots, (size_t)MS * D * sizeof(float),
                    cudaMemcpyDeviceToDevice);
    attn_out_kernel<<<MS, 256>>>(attn, out + (size_t)MS * D);
}

// round 9
// speedup vs baseline: 1.0769x; 1.0769x over previous
#include <cuda_runtime.h>
#include <cuda_fp16.h>
#include <math.h>
#include <stdint.h>

// ----------------------------------------------------------------------------
// Problem constants
// ----------------------------------------------------------------------------
#define B   32
#define NK  1024
#define S   16
#define D   768
#define H   8
#define DH  64
#define HD  (H*DH)    // 512
#define QKV3 (3*HD)   // 1536
#define INNER 3072
#define N_STEPS 4
#define MS  (B*S)     // 512
static __device__ __constant__ float kSCALE = 0.036084391824351615f;  // 768^-0.5

// ----------------------------------------------------------------------------
// Scratch (device globals)
// ----------------------------------------------------------------------------
__device__ __half g_xnh[B*NK*D], g_xnl[B*NK*D];
__device__ __half g_wkh [D*D],        g_wkl [D*D];
__device__ __half g_wvh [D*D],        g_wvl [D*D];
__device__ __half g_wqh [D*D],        g_wql [D*D];
__device__ __half g_wqkh[QKV3*D],     g_wqkl[QKV3*D];
__device__ __half g_woh [D*HD],       g_wol [D*HD];
__device__ __half g_w1h [2*INNER*D],  g_w1l [2*INNER*D];
__device__ __half g_w2h [D*INNER],    g_w2l [D*INNER];
__device__ __half g_qnh[MS*D],   g_qnl[MS*D];
__device__ __half g_abh[MS*D],   g_abl[MS*D];
__device__ __half g_fbh[MS*D],   g_fbl[MS*D];
__device__ __half g_innh[MS*INNER], g_innl[MS*INNER];
__device__ __half g_oah[MS*HD],  g_oal[MS*HD];
__device__ float g_k    [B*NK*D];
__device__ float g_v    [B*NK*D];
__device__ float g_slots[MS*D];
__device__ float g_attn [MS*NK];
__device__ float g_upd  [MS*D];
__device__ float g_h    [MS*D];
__device__ float g_part [4*MS*QKV3];

// ----------------------------------------------------------------------------
// HMMA / cp.async helpers (baseline PTX — compiles for plain compute_103)
// ----------------------------------------------------------------------------
__device__ __forceinline__ uint32_t smem_u32(const void* p) {
    uint32_t a;
    asm("{ .reg .u64 t; cvta.to.shared.u64 t, %1; cvt.u32.u64 %0, t; }"
        : "=r"(a) : "l"(p));
    return a;
}
#define LDSM_X4(r0, r1, r2, r3, addr) \
    asm volatile("ldmatrix.sync.aligned.m8n8.x4.shared.b16 {%0,%1,%2,%3}, [%4];" \
                 : "=r"(r0), "=r"(r1), "=r"(r2), "=r"(r3) : "r"(addr))
#define LDSM_X2(r0, r1, addr) \
    asm volatile("ldmatrix.sync.aligned.m8n8.x2.shared.b16 {%0,%1}, [%2];" \
                 : "=r"(r0), "=r"(r1) : "r"(addr))
#define MMA16816(c, a, b) \
    asm volatile("mma.sync.aligned.m16n8k16.row.col.f32.f16.f16.f32 " \
                 "{%0,%1,%2,%3}, {%4,%5,%6,%7}, {%8,%9}, {%0,%1,%2,%3};" \
                 : "+f"((c)[0]), "+f"((c)[1]), "+f"((c)[2]), "+f"((c)[3]) \
                 : "r"((a)[0]), "r"((a)[1]), "r"((a)[2]), "r"((a)[3]), \
                   "r"((b)[0]), "r"((b)[1]))
#define CP_ASYNC16(dst_u32, src_ptr) \
    asm volatile("cp.async.ca.shared.global [%0], [%1], 16;" \
                 :: "r"(dst_u32), "l"(src_ptr))
#define CP_COMMIT() asm volatile("cp.async.commit_group;" ::: "memory")
#define CP_WAIT(n)  asm volatile("cp.async.wait_group %0;" :: "n"(n) : "memory")

#define PITCH 40            // halves per smem row (80 B) — conflict-free ldmatrix
#define TILEH (128 * PITCH) // halves per tile
#define TILEB (TILEH * 2)   // bytes per tile

// ----------------------------------------------------------------------------
// fp16 hi/lo HMMA GEMM, split-K, 2-stage cp.async double buffer.  (R7 version)
// C[M,N] = A[M,K] @ Bt^T (Bt = [N][K]); partial z at C + z*M*N.
// ----------------------------------------------------------------------------
__global__ __launch_bounds__(256)
void hgemm_hilo(const __half* __restrict__ Ah, const __half* __restrict__ Al,
                const __half* __restrict__ Bth, const __half* __restrict__ Btl,
                float* __restrict__ C, int M, int N, int K)
{
    extern __shared__ __align__(16) __half dyn[];
    int tid = threadIdx.x;
    int lane = tid & 31, wid = tid >> 5;
    int wm = wid >> 2, wn = wid & 3;
    int row0 = blockIdx.y * 128, col0 = blockIdx.x * 128;
    int kb   = K / gridDim.z;
    int kbeg = blockIdx.z * kb;
    float* Cz = C + (size_t)blockIdx.z * M * N;
    int nchunk = kb / 32;

    uint32_t base = smem_u32(dyn);

    float acc[4][4][4];
    #pragma unroll
    for (int mf = 0; mf < 4; mf++)
        #pragma unroll
        for (int nf = 0; nf < 4; nf++)
            #pragma unroll
            for (int e = 0; e < 4; e++) acc[mf][nf][e] = 0.f;

    int laneAr = lane & 15, laneAk = (lane & 16) ? 8 : 0;
    int laneBr = lane & 7,  laneBk = (lane & 8)  ? 8 : 0;

    auto load_stage = [&](int c, int s) {
        uint32_t sb = base + (uint32_t)s * 4 * TILEB;
        #pragma unroll
        for (int i = 0; i < 2; i++) {
            int idx = tid + i * 256;
            int row = idx >> 2, sg = idx & 3;
            size_t ga = (size_t)(row0 + row) * K + kbeg + c * 32 + sg * 8;
            size_t gb = (size_t)(col0 + row) * K + kbeg + c * 32 + sg * 8;
            uint32_t so = (uint32_t)(row * PITCH + sg * 8) * 2;
            CP_ASYNC16(sb + 0 * TILEB + so, Ah + ga);
            CP_ASYNC16(sb + 1 * TILEB + so, Al + ga);
            CP_ASYNC16(sb + 2 * TILEB + so, Bth + gb);
            CP_ASYNC16(sb + 3 * TILEB + so, Btl + gb);
        }
    };

    load_stage(0, 0);
    CP_COMMIT();
    for (int c = 0; c < nchunk; c++) {
        int s = c & 1;
        if (c + 1 < nchunk) { load_stage(c + 1, s ^ 1); CP_COMMIT(); CP_WAIT(1); }
        else                { CP_WAIT(0); }
        __syncthreads();
        uint32_t bAh = base + (uint32_t)s * 4 * TILEB;
        uint32_t bAl = bAh + TILEB;
        uint32_t bBh = bAl + TILEB;
        uint32_t bBl = bBh + TILEB;
        #pragma unroll
        for (int ks = 0; ks < 32; ks += 16) {
            uint32_t bh[4][2], bl[4][2];
            #pragma unroll
            for (int nf = 0; nf < 4; nf++) {
                uint32_t off = (uint32_t)((wn * 32 + nf * 8 + laneBr) * PITCH
                                          + ks + laneBk) * 2;
                LDSM_X2(bh[nf][0], bh[nf][1], bBh + off);
                LDSM_X2(bl[nf][0], bl[nf][1], bBl + off);
            }
            #pragma unroll
            for (int mf = 0; mf < 4; mf++) {
                uint32_t off = (uint32_t)((wm * 64 + mf * 16 + laneAr) * PITCH
                                          + ks + laneAk) * 2;
                uint32_t ah[4], al[4];
                LDSM_X4(ah[0], ah[1], ah[2], ah[3], bAh + off);
                LDSM_X4(al[0], al[1], al[2], al[3], bAl + off);
                #pragma unroll
                for (int nf = 0; nf < 4; nf++) {
                    MMA16816(acc[mf][nf], ah, bh[nf]);
                    MMA16816(acc[mf][nf], ah, bl[nf]);
                    MMA16816(acc[mf][nf], al, bh[nf]);
                }
            }
        }
        __syncthreads();
    }
    #pragma unroll
    for (int mf = 0; mf < 4; mf++) {
        int r = row0 + wm * 64 + mf * 16 + (lane >> 2);
        #pragma unroll
        for (int nf = 0; nf < 4; nf++) {
            int c = col0 + wn * 32 + nf * 8 + (lane & 3) * 2;
            *(float2*)(Cz + (size_t)r * N + c) =
                make_float2(acc[mf][nf][0], acc[mf][nf][1]);
            *(float2*)(Cz + (size_t)(r + 8) * N + c) =
                make_float2(acc[mf][nf][2], acc[mf][nf][3]);
        }
    }
}
#define HG_SMEM (2 * 4 * TILEB)     // 81920

// ----------------------------------------------------------------------------
// Dual-output projection, 2-stage pipelined: Ck = A@Wk^T, Cv = A@Wv^T.
// ----------------------------------------------------------------------------
__global__ __launch_bounds__(256)
void hgemm_dual(const __half* __restrict__ Ah, const __half* __restrict__ Al,
                const __half* __restrict__ Bkh, const __half* __restrict__ Bkl,
                const __half* __restrict__ Bvh, const __half* __restrict__ Bvl,
                float* __restrict__ Ck, float* __restrict__ Cv,
                int M, int N, int K)
{
    extern __shared__ __align__(16) __half dyn[];
    int tid = threadIdx.x;
    int lane = tid & 31, wid = tid >> 5;
    int wm = wid >> 2, wn = wid & 3;
    int row0 = blockIdx.y * 128, col0 = blockIdx.x * 128;
    int nchunk = K / 32;
    uint32_t base = smem_u32(dyn);

    float accK[4][4][4], accV[4][4][4];
    #pragma unroll
    for (int mf = 0; mf < 4; mf++)
        #pragma unroll
        for (int nf = 0; nf < 4; nf++)
            #pragma unroll
            for (int e = 0; e < 4; e++) { accK[mf][nf][e] = 0.f; accV[mf][nf][e] = 0.f; }

    int laneAr = lane & 15, laneAk = (lane & 16) ? 8 : 0;
    int laneBr = lane & 7,  laneBk = (lane & 8)  ? 8 : 0;

    auto load_stage = [&](int c, int s) {
        uint32_t sb = base + (uint32_t)s * 6 * TILEB;
        #pragma unroll
        for (int i = 0; i < 2; i++) {
            int idx = tid + i * 256;
            int row = idx >> 2, sg = idx & 3;
            size_t ga = (size_t)(row0 + row) * K + c * 32 + sg * 8;
            size_t gb = (size_t)(col0 + row) * K + c * 32 + sg * 8;
            uint32_t so = (uint32_t)(row * PITCH + sg * 8) * 2;
            CP_ASYNC16(sb + 0 * TILEB + so, Ah + ga);
            CP_ASYNC16(sb + 1 * TILEB + so, Al + ga);
            CP_ASYNC16(sb + 2 * TILEB + so, Bkh + gb);
            CP_ASYNC16(sb + 3 * TILEB + so, Bkl + gb);
            CP_ASYNC16(sb + 4 * TILEB + so, Bvh + gb);
            CP_ASYNC16(sb + 5 * TILEB + so, Bvl + gb);
        }
    };

    load_stage(0, 0);
    CP_COMMIT();
    for (int c = 0; c < nchunk; c++) {
        int s = c & 1;
        if (c + 1 < nchunk) { load_stage(c + 1, s ^ 1); CP_COMMIT(); CP_WAIT(1); }
        else                { CP_WAIT(0); }
        __syncthreads();
        uint32_t bAh = base + (uint32_t)s * 6 * TILEB;
        uint32_t bAl = bAh + TILEB;
        uint32_t bKh = bAl + TILEB;
        uint32_t bKl = bKh + TILEB;
        uint32_t bVh = bKl + TILEB;
        uint32_t bVl = bVh + TILEB;
        #pragma unroll
        for (int ks = 0; ks < 32; ks += 16) {
            uint32_t kh[4][2], kl[4][2], vh[4][2], vl[4][2];
            #pragma unroll
            for (int nf = 0; nf < 4; nf++) {
                uint32_t off = (uint32_t)((wn * 32 + nf * 8 + laneBr) * PITCH
                                          + ks + laneBk) * 2;
                LDSM_X2(kh[nf][0], kh[nf][1], bKh + off);
                LDSM_X2(kl[nf][0], kl[nf][1], bKl + off);
                LDSM_X2(vh[nf][0], vh[nf][1], bVh + off);
                LDSM_X2(vl[nf][0], vl[nf][1], bVl + off);
            }
            #pragma unroll
            for (int mf = 0; mf < 4; mf++) {
                uint32_t off = (uint32_t)((wm * 64 + mf * 16 + laneAr) * PITCH
                                          + ks + laneAk) * 2;
                uint32_t ah[4], al[4];
                LDSM_X4(ah[0], ah[1], ah[2], ah[3], bAh + off);
                LDSM_X4(al[0], al[1], al[2], al[3], bAl + off);
                #pragma unroll
                for (int nf = 0; nf < 4; nf++) {
                    MMA16816(accK[mf][nf], ah, kh[nf]);
                    MMA16816(accK[mf][nf], ah, kl[nf]);
                    MMA16816(accK[mf][nf], al, kh[nf]);
                    MMA16816(accV[mf][nf], ah, vh[nf]);
                    MMA16816(accV[mf][nf], ah, vl[nf]);
                    MMA16816(accV[mf][nf], al, vh[nf]);
                }
            }
        }
        __syncthreads();
    }
    #pragma unroll
    for (int mf = 0; mf < 4; mf++) {
        int r = row0 + wm * 64 + mf * 16 + (lane >> 2);
        #pragma unroll
        for (int nf = 0; nf < 4; nf++) {
            int c = col0 + wn * 32 + nf * 8 + (lane & 3) * 2;
            *(float2*)(Ck + (size_t)r * N + c) =
                make_float2(accK[mf][nf][0], accK[mf][nf][1]);
            *(float2*)(Ck + (size_t)(r + 8) * N + c) =
                make_float2(accK[mf][nf][2], accK[mf][nf][3]);
            *(float2*)(Cv + (size_t)r * N + c) =
                make_float2(accV[mf][nf][0], accV[mf][nf][1]);
            *(float2*)(Cv + (size_t)(r + 8) * N + c) =
                make_float2(accV[mf][nf][2], accV[mf][nf][3]);
        }
    }
}
#define DUAL2_SMEM (2 * 6 * TILEB)   // 122880

// ----------------------------------------------------------------------------
// W1 + GLU fused, 2-stage pipelined; emits fp16 hi/lo of u*silu(g).
// ----------------------------------------------------------------------------
__global__ __launch_bounds__(256)
void hgemm_glu(const __half* __restrict__ Ah, const __half* __restrict__ Al,
               const __half* __restrict__ W1th, const __half* __restrict__ W1tl,
               __half* __restrict__ Ih, __half* __restrict__ Il, int M)
{
    extern __shared__ __align__(16) __half dyn[];
    int tid = threadIdx.x;
    int lane = tid & 31, wid = tid >> 5;
    int wm = wid >> 2, wn = wid & 3;
    int row0 = blockIdx.y * 128, col0 = blockIdx.x * 128;
    int nchunk = D / 32;
    uint32_t base = smem_u32(dyn);

    float accU[4][4][4], accG[4][4][4];
    #pragma unroll
    for (int mf = 0; mf < 4; mf++)
        #pragma unroll
        for (int nf = 0; nf < 4; nf++)
            #pragma unroll
            for (int e = 0; e < 4; e++) { accU[mf][nf][e] = 0.f; accG[mf][nf][e] = 0.f; }

    int laneAr = lane & 15, laneAk = (lane & 16) ? 8 : 0;
    int laneBr = lane & 7,  laneBk = (lane & 8)  ? 8 : 0;

    auto load_stage = [&](int c, int s) {
        uint32_t sb = base + (uint32_t)s * 6 * TILEB;
        #pragma unroll
        for (int i = 0; i < 2; i++) {
            int idx = tid + i * 256;
            int row = idx >> 2, sg = idx & 3;
            size_t ga = (size_t)(row0 + row) * D + c * 32 + sg * 8;
            size_t gu = (size_t)(col0 + row) * D + c * 32 + sg * 8;
            size_t gg = (size_t)(col0 + row + INNER) * D + c * 32 + sg * 8;
            uint32_t so = (uint32_t)(row * PITCH + sg * 8) * 2;
            CP_ASYNC16(sb + 0 * TILEB + so, Ah + ga);
            CP_ASYNC16(sb + 1 * TILEB + so, Al + ga);
            CP_ASYNC16(sb + 2 * TILEB + so, W1th + gu);
            CP_ASYNC16(sb + 3 * TILEB + so, W1tl + gu);
            CP_ASYNC16(sb + 4 * TILEB + so, W1th + gg);
            CP_ASYNC16(sb + 5 * TILEB + so, W1tl + gg);
        }
    };

    load_stage(0, 0);
    CP_COMMIT();
    for (int c = 0; c < nchunk; c++) {
        int s = c & 1;
        if (c + 1 < nchunk) { load_stage(c + 1, s ^ 1); CP_COMMIT(); CP_WAIT(1); }
        else                { CP_WAIT(0); }
        __syncthreads();
        uint32_t bAh = base + (uint32_t)s * 6 * TILEB;
        uint32_t bAl = bAh + TILEB;
        uint32_t bUh = bAl + TILEB;
        uint32_t bUl = bUh + TILEB;
        uint32_t bGh = bUl + TILEB;
        uint32_t bGl = bGh + TILEB;
        #pragma unroll
        for (int ks = 0; ks < 32; ks += 16) {
            uint32_t uh[4][2], ul[4][2], gh[4][2], gl[4][2];
            #pragma unroll
            for (int nf = 0; nf < 4; nf++) {
                uint32_t off = (uint32_t)((wn * 32 + nf * 8 + laneBr) * PITCH
                                          + ks + laneBk) * 2;
                LDSM_X2(uh[nf][0], uh[nf][1], bUh + off);
                LDSM_X2(ul[nf][0], ul[nf][1], bUl + off);
                LDSM_X2(gh[nf][0], gh[nf][1], bGh + off);
                LDSM_X2(gl[nf][0], gl[nf][1], bGl + off);
            }
            #pragma unroll
            for (int mf = 0; mf < 4; mf++) {
                uint32_t off = (uint32_t)((wm * 64 + mf * 16 + laneAr) * PITCH
                                          + ks + laneAk) * 2;
                uint32_t ah[4], al[4];
                LDSM_X4(ah[0], ah[1], ah[2], ah[3], bAh + off);
                LDSM_X4(al[0], al[1], al[2], al[3], bAl + off);
                #pragma unroll
                for (int nf = 0; nf < 4; nf++) {
                    MMA16816(accU[mf][nf], ah, uh[nf]);
                    MMA16816(accU[mf][nf], ah, ul[nf]);
                    MMA16816(accU[mf][nf], al, uh[nf]);
                    MMA16816(accG[mf][nf], ah, gh[nf]);
                    MMA16816(accG[mf][nf], ah, gl[nf]);
                    MMA16816(accG[mf][nf], al, gh[nf]);
                }
            }
        }
        __syncthreads();
    }
    #pragma unroll
    for (int mf = 0; mf < 4; mf++) {
        int r = row0 + wm * 64 + mf * 16 + (lane >> 2);
        #pragma unroll
        for (int nf = 0; nf < 4; nf++) {
            int c = col0 + wn * 32 + nf * 8 + (lane & 3) * 2;
            #pragma unroll
            for (int half_ = 0; half_ < 2; half_++) {
                int rr = r + half_ * 8;
                float u0 = accU[mf][nf][half_ * 2], u1 = accU[mf][nf][half_ * 2 + 1];
                float gg0 = accG[mf][nf][half_ * 2], gg1 = accG[mf][nf][half_ * 2 + 1];
                float v0 = u0 * (gg0 / (1.f + expf(-gg0)));
                float v1 = u1 * (gg1 / (1.f + expf(-gg1)));
                __half h0 = __float2half_rn(v0), h1 = __float2half_rn(v1);
                __half l0 = __float2half_rn(v0 - __half2float(h0));
                __half l1 = __float2half_rn(v1 - __half2float(h1));
                *(__half2*)(Ih + (size_t)rr * INNER + c) = __halves2half2(h0, h1);
                *(__half2*)(Il + (size_t)rr * INNER + c) = __halves2half2(l0, l1);
            }
        }
    }
}

// ----------------------------------------------------------------------------
// LN reduction helper (256 threads over D=768)
// ----------------------------------------------------------------------------
__device__ __forceinline__ void ln_stats(float v0, float v1, float v2,
                                         float* sa, float* sb2,
                                         float& mean, float& rinv)
{
    float s = v0 + v1 + v2;
    float q = v0 * v0 + v1 * v1 + v2 * v2;
    int tid = threadIdx.x;
    #pragma unroll
    for (int o = 16; o > 0; o >>= 1) {
        s += __shfl_down_sync(0xffffffffu, s, o);
        q += __shfl_down_sync(0xffffffffu, q, o);
    }
    int w = tid >> 5, l = tid & 31;
    if (l == 0) { sa[w] = s; sb2[w] = q; }
    __syncthreads();
    if (tid == 0) {
        float ts = 0.f, tq = 0.f;
        #pragma unroll
        for (int k = 0; k < 8; k++) { ts += sa[k]; tq += sb2[k]; }
        sa[0] = ts; sb2[0] = tq;
    }
    __syncthreads();
    mean = sa[0] * (1.0f / D);
    float var = sb2[0] * (1.0f / D) - mean * mean;
    rinv = rsqrtf(var + 1e-5f);
    __syncthreads();
}

// LN(x) -> fp16 hi/lo
__global__ __launch_bounds__(256)
void ln_split_kernel(const float* __restrict__ in,
                     __half* __restrict__ oh, __half* __restrict__ ol,
                     const float* __restrict__ gamma, const float* __restrict__ beta)
{
    int row = blockIdx.x, tid = threadIdx.x;
    const float* x = in + (size_t)row * D;
    float v[3] = {x[tid], x[tid + 256], x[tid + 512]};
    __shared__ float sa[8], sb2[8];
    float mean, r;
    ln_stats(v[0], v[1], v[2], sa, sb2, mean, r);
    #pragma unroll
    for (int e = 0; e < 3; e++) {
        int idx = tid + e * 256;
        float y = (v[e] - mean) * r * gamma[idx] + beta[idx];
        __half hb = __float2half_rn(y);
        oh[(size_t)row * D + idx] = hb;
        ol[(size_t)row * D + idx] = __float2half_rn(y - __half2float(hb));
    }
}

// h = LN_a(slots + upd) -> hb(fp32);  LN_b(h) -> oh/ol(hi/lo)
__global__ __launch_bounds__(256)
void ln_dual_kernel(const float* __restrict__ slots, const float* __restrict__ upd,
                    float* __restrict__ hb,
                    const float* __restrict__ g1, const float* __restrict__ b1,
                    const float* __restrict__ g2, const float* __restrict__ b2,
                    __half* __restrict__ oh, __half* __restrict__ ol)
{
    int row = blockIdx.x, tid = threadIdx.x;
    const float* xs = slots + (size_t)row * D;
    const float* xu = upd + (size_t)row * D;
    float v[3];
    #pragma unroll
    for (int e = 0; e < 3; e++) v[e] = xs[tid + e * 256] + xu[tid + e * 256];
    __shared__ float sa[8], sb2[8];
    float mean, r;
    ln_stats(v[0], v[1], v[2], sa, sb2, mean, r);
    float y[3];
    #pragma unroll
    for (int e = 0; e < 3; e++) {
        int idx = tid + e * 256;
        y[e] = (v[e] - mean) * r * g1[idx] + b1[idx];
        hb[(size_t)row * D + idx] = y[e];
    }
    float mean2, r2;
    ln_stats(y[0], y[1], y[2], sa, sb2, mean2, r2);
    #pragma unroll
    for (int e = 0; e < 3; e++) {
        int idx = tid + e * 256;
        float z = (y[e] - mean2) * r2 * g2[idx] + b2[idx];
        __half hh = __float2half_rn(z);
        oh[(size_t)row * D + idx] = hh;
        ol[(size_t)row * D + idx] = __float2half_rn(z - __half2float(hh));
    }
}

// h = res + sum_{sp<4} part[sp]; res <- h; LN(h) -> oh/ol
__global__ __launch_bounds__(256)
void ln_split_red_kernel(const float* __restrict__ part, float* __restrict__ res,
                         const float* __restrict__ gamma, const float* __restrict__ beta,
                         __half* __restrict__ oh, __half* __restrict__ ol)
{
    int row = blockIdx.x, tid = threadIdx.x;
    float v[3];
    #pragma unroll
    for (int e = 0; e < 3; e++) {
        int idx = tid + e * 256;
        size_t o = (size_t)row * D + idx;
        float s = res[o];
        #pragma unroll
        for (int sp = 0; sp < 4; sp++) s += part[(size_t)sp * MS * D + o];
        v[e] = s;
        res[o] = s;
    }
    __shared__ float sa[8], sb2[8];
    float mean, r;
    ln_stats(v[0], v[1], v[2], sa, sb2, mean, r);
    #pragma unroll
    for (int e = 0; e < 3; e++) {
        int idx = tid + e * 256;
        float y = (v[e] - mean) * r * gamma[idx] + beta[idx];
        __half hb = __float2half_rn(y);
        oh[(size_t)row * D + idx] = hb;
        ol[(size_t)row * D + idx] = __float2half_rn(y - __half2float(hb));
    }
}

// h = res + sum part; slots = LN_f(h);  LN_s(slots) -> qn hi/lo (next step)
__global__ __launch_bounds__(256)
void ln_red_dual_kernel(const float* __restrict__ part, const float* __restrict__ res,
                        float* __restrict__ slots,
                        const float* __restrict__ gf, const float* __restrict__ bf,
                        const float* __restrict__ gs, const float* __restrict__ bs,
                        __half* __restrict__ qh, __half* __restrict__ ql)
{
    int row = blockIdx.x, tid = threadIdx.x;
    float v[3];
    #pragma unroll
    for (int e = 0; e < 3; e++) {
        int idx = tid + e * 256;
        size_t o = (size_t)row * D + idx;
        float s = res[o];
        #pragma unroll
        for (int sp = 0; sp < 4; sp++) s += part[(size_t)sp * MS * D + o];
        v[e] = s;
    }
    __shared__ float sa[8], sb2[8];
    float mean, r;
    ln_stats(v[0], v[1], v[2], sa, sb2, mean, r);
    float y[3];
    #pragma unroll
    for (int e = 0; e < 3; e++) {
        int idx = tid + e * 256;
        y[e] = (v[e] - mean) * r * gf[idx] + bf[idx];
        slots[(size_t)row * D + idx] = y[e];
    }
    float mean2, r2;
    ln_stats(y[0], y[1], y[2], sa, sb2, mean2, r2);
    #pragma unroll
    for (int e = 0; e < 3; e++) {
        int idx = tid + e * 256;
        float z = (y[e] - mean2) * r2 * gs[idx] + bs[idx];
        __half hh = __float2half_rn(z);
        qh[(size_t)row * D + idx] = hh;
        ql[(size_t)row * D + idx] = __float2half_rn(z - __half2float(hh));
    }
}

// transpose + fp16 hi/lo split
__global__ __launch_bounds__(256)
void wsplit_kernel(const float* __restrict__ W,
                   __half* __restrict__ Th, __half* __restrict__ Tl,
                   int Krows, int Ncols, int n_off)
{
    __shared__ float tile[32][33];
    int n0 = blockIdx.x * 32, k0 = blockIdx.y * 32;
    int t = threadIdx.x;
    int tx = t & 31, ty = t >> 5;
    #pragma unroll
    for (int i = 0; i < 4; i++)
        tile[ty + i * 8][tx] = W[(size_t)(k0 + ty + i * 8) * Ncols + n0 + tx];
    __syncthreads();
    #pragma unroll
    for (int i = 0; i < 4; i++) {
        int n = n_off + n0 + ty + i * 8;
        float v = tile[tx][ty + i * 8];
        __half hb = __float2half_rn(v);
        Th[(size_t)n * Krows + k0 + tx] = hb;
        Tl[(size_t)n * Krows + k0 + tx] = __float2half_rn(v - __half2float(hb));
    }
}

__global__ void init_slots_kernel(const float* __restrict__ noise,
                                  const float* __restrict__ mu,
                                  const float* __restrict__ ls,
                                  float* __restrict__ slots)
{
    int t = blockIdx.x * blockDim.x + threadIdx.x;
    if (t >= MS * D) return;
    int d = t % D;
    slots[t] = mu[d] + expf(ls[d]) * noise[t];
}

// ----------------------------------------------------------------------------
// dots + softmax over the slot axis; reads Wq split-K partials directly (R7)
// ----------------------------------------------------------------------------
__global__ __launch_bounds__(256)
void dots_softmax_kernel(const float* __restrict__ Qpart, const float* __restrict__ Kb,
                         float* __restrict__ attn)
{
    int b  = blockIdx.y;
    int j0 = blockIdx.x * 64;
    __shared__ __align__(16) float qs[16][64];
    __shared__ float ks[64][65];
    __shared__ float red[4][64];
    int tid = threadIdx.x;
    int tx = tid & 63, ty = tid >> 6;
    float acc[4] = {0.f, 0.f, 0.f, 0.f};
    const float* Kp = Kb + ((size_t)b * NK + j0) * D;
    for (int k0 = 0; k0 < D; k0 += 64) {
        {
            int i = tid >> 4, kc = (tid & 15) * 4;
            size_t o = ((size_t)b * S + i) * D + k0 + kc;
            float4 v = *(const float4*)&Qpart[o];
            #pragma unroll
            for (int sp = 1; sp < 4; sp++) {
                float4 w = *(const float4*)&Qpart[(size_t)sp * MS * D + o];
                v.x += w.x; v.y += w.y; v.z += w.z; v.w += w.w;
            }
            *(float4*)&qs[i][kc] = v;
        }
        #pragma unroll
        for (int p = 0; p < 4; p++) {
            int e = tid + p * 256;
            int jj = e >> 4, kc = (e & 15) * 4;
            float4 v = *(const float4*)&Kp[(size_t)jj * D + k0 + kc];
            ks[jj][kc + 0] = v.x; ks[jj][kc + 1] = v.y;
            ks[jj][kc + 2] = v.z; ks[jj][kc + 3] = v.w;
        }
        __syncthreads();
        #pragma unroll
        for (int kk = 0; kk < 64; kk++) {
            float kv = ks[tx][kk];
            acc[0] += qs[ty     ][kk] * kv;
            acc[1] += qs[ty +  4][kk] * kv;
            acc[2] += qs[ty +  8][kk] * kv;
            acc[3] += qs[ty + 12][kk] * kv;
        }
        __syncthreads();
    }
    #pragma unroll
    for (int r = 0; r < 4; r++) acc[r] *= kSCALE;
    float m = fmaxf(fmaxf(acc[0], acc[1]), fmaxf(acc[2], acc[3]));
    red[ty][tx] = m;
    __syncthreads();
    float M = fmaxf(fmaxf(red[0][tx], red[1][tx]), fmaxf(red[2][tx], red[3][tx]));
    __syncthreads();
    float e[4]; float s = 0.f;
    #pragma unroll
    for (int r = 0; r < 4; r++) { e[r] = expf(acc[r] - M); s += e[r]; }
    red[ty][tx] = s;
    __syncthreads();
    float Ssum = red[0][tx] + red[1][tx] + red[2][tx] + red[3][tx];
    float inv = 1.f / Ssum;
    #pragma unroll
    for (int r = 0; r < 4; r++)
        attn[((size_t)b * S + ty + r * 4) * NK + j0 + tx] = e[r] * inv + 1e-8f;
}

// updates[b,i,n] = (sum_j attn * v) / (sum_j attn)   (R7 scalar version)
__global__ __launch_bounds__(256)
void updates_kernel(const float* __restrict__ attn, const float* __restrict__ V,
                    float* __restrict__ upd)
{
    int b  = blockIdx.y;
    int n0 = blockIdx.x * 64;
    __shared__ __align__(16) float as_[16][64];
    __shared__ __align__(16) float vs[64][64];
    int tid = threadIdx.x;
    int tx = tid & 63, ty = tid >> 6;
    float acc[4] = {0.f, 0.f, 0.f, 0.f};
    float ssum[4] = {0.f, 0.f, 0.f, 0.f};
    for (int j0 = 0; j0 < NK; j0 += 64) {
        {
            int i = tid >> 4, jc = (tid & 15) * 4;
            *(float4*)&as_[i][jc] =
                *(const float4*)&attn[((size_t)b * S + i) * NK + j0 + jc];
        }
        #pragma unroll
        for (int p = 0; p < 4; p++) {
            int e = tid + p * 256;
            int jj = e >> 4, nc = (e & 15) * 4;
            *(float4*)&vs[jj][nc] =
                *(const float4*)&V[((size_t)b * NK + j0 + jj) * D + n0 + nc];
        }
        __syncthreads();
        #pragma unroll
        for (int jj = 0; jj < 64; jj++) {
            float vv = vs[jj][tx];
            float a0 = as_[ty][jj], a1 = as_[ty + 4][jj];
            float a2 = as_[ty + 8][jj], a3 = as_[ty + 12][jj];
            acc[0] += a0 * vv;  ssum[0] += a0;
            acc[1] += a1 * vv;  ssum[1] += a1;
            acc[2] += a2 * vv;  ssum[2] += a2;
            acc[3] += a3 * vv;  ssum[3] += a3;
        }
        __syncthreads();
    }
    #pragma unroll
    for (int r = 0; r < 4; r++)
        upd[((size_t)b * S + ty + r * 4) * D + n0 + tx] = acc[r] / ssum[r];
}

// encoder self-attention; reads QKV split-K partials directly
__global__ __launch_bounds__(256)
void enc_attn_kernel(const float* __restrict__ QKVpart,
                     __half* __restrict__ Oh, __half* __restrict__ Ol)
{
    int b = blockIdx.x >> 3, h = blockIdx.x & 7;
    __shared__ float qs[16][65], ks[16][65], vs[16][65];
    __shared__ float p[16][17];
    int tid = threadIdx.x;
    int i = tid >> 4, jj = tid & 15;
    {
        int r = tid >> 4, c = (tid & 15) * 4;
        size_t base = ((size_t)b * S + r) * QKV3 + h * DH + c;
        float4 vq = *(const float4*)&QKVpart[base];
        float4 vk = *(const float4*)&QKVpart[base + HD];
        float4 vv = *(const float4*)&QKVpart[base + 2 * HD];
        #pragma unroll
        for (int sp = 1; sp < 4; sp++) {
            size_t o = (size_t)sp * MS * QKV3 + base;
            float4 w;
            w = *(const float4*)&QKVpart[o];
            vq.x += w.x; vq.y += w.y; vq.z += w.z; vq.w += w.w;
            w = *(const float4*)&QKVpart[o + HD];
            vk.x += w.x; vk.y += w.y; vk.z += w.z; vk.w += w.w;
            w = *(const float4*)&QKVpart[o + 2 * HD];
            vv.x += w.x; vv.y += w.y; vv.z += w.z; vv.w += w.w;
        }
        qs[r][c] = vq.x; qs[r][c+1] = vq.y; qs[r][c+2] = vq.z; qs[r][c+3] = vq.w;
        ks[r][c] = vk.x; ks[r][c+1] = vk.y; ks[r][c+2] = vk.z; ks[r][c+3] = vk.w;
        vs[r][c] = vv.x; vs[r][c+1] = vv.y; vs[r][c+2] = vv.z; vs[r][c+3] = vv.w;
    }
    __syncthreads();
    float s = 0.f;
    #pragma unroll
    for (int d = 0; d < DH; d++) s += qs[i][d] * ks[jj][d];
    s *= 0.125f;
    p[i][jj] = s;
    __syncthreads();
    float m = -1e30f;
    #pragma unroll
    for (int t2 = 0; t2 < 16; t2++) m = fmaxf(m, p[i][t2]);
    __syncthreads();
    float e = expf(s - m);
    p[i][jj] = e;
    __syncthreads();
    float sum = 0.f;
    #pragma unroll
    for (int t2 = 0; t2 < 16; t2++) sum += p[i][t2];
    __syncthreads();
    p[i][jj] = e / sum;
    __syncthreads();
    int io = tid >> 4, dbase = (tid & 15) * 4;
    float o[4] = {0.f, 0.f, 0.f, 0.f};
    #pragma unroll
    for (int t2 = 0; t2 < 16; t2++) {
        float pp = p[io][t2];
        o[0] += pp * vs[t2][dbase + 0];
        o[1] += pp * vs[t2][dbase + 1];
        o[2] += pp * vs[t2][dbase + 2];
        o[3] += pp * vs[t2][dbase + 3];
    }
    size_t base = ((size_t)b * S + io) * HD + h * DH + dbase;
    #pragma unroll
    for (int c = 0; c < 4; c++) {
        __half hb = __float2half_rn(o[c]);
        Oh[base + c] = hb;
        Ol[base + c] = __float2half_rn(o[c] - __half2float(hb));
    }
}

// output map: per (b,i) row — sum over keys then write out[b][j][i] = attn/sum
__global__ __launch_bounds__(256)
void attn_out_kernel(const float* __restrict__ attn, float* __restrict__ out)
{
    int row = blockIdx.x;            // b*S + i
    int b = row >> 4, i = row & 15;
    const float4* p = (const float4*)(attn + (size_t)row * NK);
    int tid = threadIdx.x;
    float4 v = p[tid];
    float s = v.x + v.y + v.z + v.w;
    __shared__ float sa[8];
    #pragma unroll
    for (int o = 16; o > 0; o >>= 1) s += __shfl_down_sync(0xffffffffu, s, o);
    int w = tid >> 5, l = tid & 31;
    if (l == 0) sa[w] = s;
    __syncthreads();
    if (tid == 0) {
        float ts = 0.f;
        #pragma unroll
        for (int k = 0; k < 8; k++) ts += sa[k];
        sa[0] = ts;
    }
    __syncthreads();
    float inv = 1.f / sa[0];
    size_t ob = (size_t)b * NK * S + i;
    int j = tid * 4;
    out[ob + (size_t)(j + 0) * S] = v.x * inv;
    out[ob + (size_t)(j + 1) * S] = v.y * inv;
    out[ob + (size_t)(j + 2) * S] = v.z * inv;
    out[ob + (size_t)(j + 3) * S] = v.w * inv;
}

// ----------------------------------------------------------------------------
// Host orchestration
// ----------------------------------------------------------------------------
extern "C" void kernel_launch(void* const* d_in, const int* in_sizes, int n_in,
                              void* d_out, int out_size)
{
    const float* x       = (const float*)d_in[0];
    const float* noise   = (const float*)d_in[1];
    const float* init_mu = (const float*)d_in[2];
    const float* init_ls = (const float*)d_in[3];
    const float* Wk      = (const float*)d_in[4];
    const float* Wv      = (const float*)d_in[5];
    const float* Wq      = (const float*)d_in[6];
    const float* ni_g    = (const float*)d_in[7];
    const float* ni_b    = (const float*)d_in[8];
    const float* ns_g    = (const float*)d_in[9];
    const float* ns_b    = (const float*)d_in[10];
    const float* nica_g  = (const float*)d_in[11];
    const float* nica_b  = (const float*)d_in[12];
    const float* ln1_g   = (const float*)d_in[13];
    const float* ln1_b   = (const float*)d_in[14];
    const float* Wq_a    = (const float*)d_in[15];
    const float* Wk_a    = (const float*)d_in[16];
    const float* Wv_a    = (const float*)d_in[17];
    const float* Wo_a    = (const float*)d_in[18];
    const float* ln2_g   = (const float*)d_in[19];
    const float* ln2_b   = (const float*)d_in[20];
    const float* W1      = (const float*)d_in[21];
    const float* W2      = (const float*)d_in[22];
    const float* lnf_g   = (const float*)d_in[23];
    const float* lnf_b   = (const float*)d_in[24];

    __half *xnh, *xnl, *wkh, *wkl, *wvh, *wvl, *wqh, *wql;
    __half *wqkh, *wqkl, *woh, *wol, *w1h, *w1l, *w2h, *w2l;
    __half *qnh, *qnl, *abh, *abl, *fbh, *fbl, *innh, *innl, *oah, *oal;
    float *kb, *vb, *slots, *attn, *upd, *hb, *part;
    cudaGetSymbolAddress((void**)&xnh,  g_xnh);  cudaGetSymbolAddress((void**)&xnl,  g_xnl);
    cudaGetSymbolAddress((void**)&wkh,  g_wkh);  cudaGetSymbolAddress((void**)&wkl,  g_wkl);
    cudaGetSymbolAddress((void**)&wvh,  g_wvh);  cudaGetSymbolAddress((void**)&wvl,  g_wvl);
    cudaGetSymbolAddress((void**)&wqh,  g_wqh);  cudaGetSymbolAddress((void**)&wql,  g_wql);
    cudaGetSymbolAddress((void**)&wqkh, g_wqkh); cudaGetSymbolAddress((void**)&wqkl, g_wqkl);
    cudaGetSymbolAddress((void**)&woh,  g_woh);  cudaGetSymbolAddress((void**)&wol,  g_wol);
    cudaGetSymbolAddress((void**)&w1h,  g_w1h);  cudaGetSymbolAddress((void**)&w1l,  g_w1l);
    cudaGetSymbolAddress((void**)&w2h,  g_w2h);  cudaGetSymbolAddress((void**)&w2l,  g_w2l);
    cudaGetSymbolAddress((void**)&qnh,  g_qnh);  cudaGetSymbolAddress((void**)&qnl,  g_qnl);
    cudaGetSymbolAddress((void**)&abh,  g_abh);  cudaGetSymbolAddress((void**)&abl,  g_abl);
    cudaGetSymbolAddress((void**)&fbh,  g_fbh);  cudaGetSymbolAddress((void**)&fbl,  g_fbl);
    cudaGetSymbolAddress((void**)&innh, g_innh); cudaGetSymbolAddress((void**)&innl, g_innl);
    cudaGetSymbolAddress((void**)&oah,  g_oah);  cudaGetSymbolAddress((void**)&oal,  g_oal);
    cudaGetSymbolAddress((void**)&kb,   g_k);
    cudaGetSymbolAddress((void**)&vb,   g_v);
    cudaGetSymbolAddress((void**)&slots,g_slots);
    cudaGetSymbolAddress((void**)&attn, g_attn);
    cudaGetSymbolAddress((void**)&upd,  g_upd);
    cudaGetSymbolAddress((void**)&hb,   g_h);
    cudaGetSymbolAddress((void**)&part, g_part);

    cudaFuncSetAttribute(hgemm_hilo, cudaFuncAttributeMaxDynamicSharedMemorySize, HG_SMEM);
    cudaFuncSetAttribute(hgemm_dual, cudaFuncAttributeMaxDynamicSharedMemorySize, DUAL2_SMEM);
    cudaFuncSetAttribute(hgemm_glu,  cudaFuncAttributeMaxDynamicSharedMemorySize, DUAL2_SMEM);

    // ---- precompute (ordered so launch #5 = hgemm_dual for ncu) ----
    wsplit_kernel<<<dim3(D / 32, D / 32), 256>>>(Wk, wkh, wkl, D, D, 0);       // 0
    wsplit_kernel<<<dim3(D / 32, D / 32), 256>>>(Wv, wvh, wvl, D, D, 0);       // 1
    ln_split_kernel<<<B * NK, 256>>>(x, xnh, xnl, ni_g, ni_b);                 // 2
    init_slots_kernel<<<(MS * D + 255) / 256, 256>>>(noise, init_mu, init_ls, slots); // 3
    wsplit_kernel<<<dim3(D / 32, D / 32), 256>>>(Wq, wqh, wql, D, D, 0);       // 4
    hgemm_dual<<<dim3(D / 128, (B * NK) / 128), 256, DUAL2_SMEM>>>(            // 5
        xnh, xnl, wkh, wkl, wvh, wvl, kb, vb, B * NK, D, D);
    wsplit_kernel<<<dim3(HD / 32, D / 32), 256>>>(Wq_a, wqkh, wqkl, D, HD, 0);
    wsplit_kernel<<<dim3(HD / 32, D / 32), 256>>>(Wk_a, wqkh, wqkl, D, HD, HD);
    wsplit_kernel<<<dim3(HD / 32, D / 32), 256>>>(Wv_a, wqkh, wqkl, D, HD, 2 * HD);
    wsplit_kernel<<<dim3(D / 32, HD / 32), 256>>>(Wo_a, woh, wol, HD, D, 0);
    wsplit_kernel<<<dim3((2 * INNER) / 32, D / 32), 256>>>(W1, w1h, w1l, D, 2 * INNER, 0);
    wsplit_kernel<<<dim3(D / 32, INNER / 32), 256>>>(W2, w2h, w2l, INNER, D, 0);
    ln_split_kernel<<<MS, 256>>>(slots, qnh, qnl, ns_g, ns_b);

    // ---- 4 slot-attention steps (11 launches each) ----
    for (int it = 0; it < N_STEPS; it++) {
        hgemm_hilo<<<dim3(D / 128, MS / 128, 4), 256, HG_SMEM>>>(qnh, qnl, wqh, wql,
                                                                 part, MS, D, D);
        dots_softmax_kernel<<<dim3(NK / 64, B), 256>>>(part, kb, attn);
        updates_kernel<<<dim3(D / 64, B), 256>>>(attn, vb, upd);
        ln_dual_kernel<<<MS, 256>>>(slots, upd, hb, nica_g, nica_b,
                                    ln1_g, ln1_b, abh, abl);
        hgemm_hilo<<<dim3(QKV3 / 128, MS / 128, 4), 256, HG_SMEM>>>(abh, abl, wqkh, wqkl,
                                                                    part, MS, QKV3, D);
        enc_attn_kernel<<<B * H, 256>>>(part, oah, oal);
        hgemm_hilo<<<dim3(D / 128, MS / 128, 4), 256, HG_SMEM>>>(oah, oal, woh, wol,
                                                                 part, MS, D, HD);
        ln_split_red_kernel<<<MS, 256>>>(part, hb, ln2_g, ln2_b, fbh, fbl);
        hgemm_glu<<<dim3(INNER / 128, MS / 128), 256, DUAL2_SMEM>>>(fbh, fbl, w1h, w1l,
                                                                    innh, innl, MS);
        hgemm_hilo<<<dim3(D / 128, MS / 128, 4), 256, HG_SMEM>>>(innh, innl, w2h, w2l,
                                                                 part, MS, D, INNER);
        ln_red_dual_kernel<<<MS, 256>>>(part, hb, slots, lnf_g, lnf_b,
                                        ns_g, ns_b, qnh, qnl);
    }

    // ---- outputs: slots [32,16,768], then attn_map [32,1024,16] ----
    float* out = (float*)d_out;
    cudaMemcpyAsync(out, slots, (size_t)MS * D * sizeof(float),
                    cudaMemcpyDeviceToDevice);
    attn_out_kernel<<<MS, 256>>>(attn, out + (size_t)MS * D);
}

// round 10
// speedup vs baseline: 1.1744x; 1.0905x over previous
#include <cuda_runtime.h>
#include <cuda_fp16.h>
#include <math.h>
#include <stdint.h>

// ----------------------------------------------------------------------------
// Problem constants
// ----------------------------------------------------------------------------
#define B   32
#define NK  1024
#define S   16
#define D   768
#define H   8
#define DH  64
#define HD  (H*DH)    // 512
#define QKV3 (3*HD)   // 1536
#define INNER 3072
#define N_STEPS 4
#define MS  (B*S)     // 512
static __device__ __constant__ float kSCALE = 0.036084391824351615f;  // 768^-0.5

// ----------------------------------------------------------------------------
// Scratch (device globals)
// ----------------------------------------------------------------------------
__device__ __half g_xnh[B*NK*D], g_xnl[B*NK*D];
__device__ __half g_wkh [D*D],        g_wkl [D*D];
__device__ __half g_wvh [D*D],        g_wvl [D*D];
__device__ __half g_wqh [D*D];
__device__ __half g_wqkh[QKV3*D];
__device__ __half g_woh [D*HD];
__device__ __half g_w1h [2*INNER*D];
__device__ __half g_w2h [D*INNER];
__device__ __half g_qnh[MS*D],   g_qnl[MS*D];
__device__ __half g_abh[MS*D],   g_abl[MS*D];
__device__ __half g_fbh[MS*D],   g_fbl[MS*D];
__device__ __half g_innh[MS*INNER], g_innl[MS*INNER];
__device__ __half g_oah[MS*HD],  g_oal[MS*HD];
__device__ float g_k    [B*NK*D];
__device__ float g_v    [B*NK*D];
__device__ float g_slots[MS*D];
__device__ float g_attn [MS*NK];
__device__ float g_upd  [MS*D];
__device__ float g_h    [MS*D];
__device__ float g_part [4*MS*QKV3];

// ----------------------------------------------------------------------------
// HMMA / cp.async helpers (baseline PTX — compiles for plain compute_103)
// ----------------------------------------------------------------------------
__device__ __forceinline__ uint32_t smem_u32(const void* p) {
    uint32_t a;
    asm("{ .reg .u64 t; cvta.to.shared.u64 t, %1; cvt.u32.u64 %0, t; }"
        : "=r"(a) : "l"(p));
    return a;
}
#define LDSM_X4(r0, r1, r2, r3, addr) \
    asm volatile("ldmatrix.sync.aligned.m8n8.x4.shared.b16 {%0,%1,%2,%3}, [%4];" \
                 : "=r"(r0), "=r"(r1), "=r"(r2), "=r"(r3) : "r"(addr))
#define LDSM_X2(r0, r1, addr) \
    asm volatile("ldmatrix.sync.aligned.m8n8.x2.shared.b16 {%0,%1}, [%2];" \
                 : "=r"(r0), "=r"(r1) : "r"(addr))
#define MMA16816(c, a, b) \
    asm volatile("mma.sync.aligned.m16n8k16.row.col.f32.f16.f16.f32 " \
                 "{%0,%1,%2,%3}, {%4,%5,%6,%7}, {%8,%9}, {%0,%1,%2,%3};" \
                 : "+f"((c)[0]), "+f"((c)[1]), "+f"((c)[2]), "+f"((c)[3]) \
                 : "r"((a)[0]), "r"((a)[1]), "r"((a)[2]), "r"((a)[3]), \
                   "r"((b)[0]), "r"((b)[1]))
#define CP_ASYNC16(dst_u32, src_ptr) \
    asm volatile("cp.async.ca.shared.global [%0], [%1], 16;" \
                 :: "r"(dst_u32), "l"(src_ptr))
#define CP_COMMIT() asm volatile("cp.async.commit_group;" ::: "memory")
#define CP_WAIT(n)  asm volatile("cp.async.wait_group %0;" :: "n"(n) : "memory")

#define PITCH 40            // halves per smem row (80 B) — conflict-free ldmatrix
#define TILEH (128 * PITCH) // halves per tile
#define TILEB (TILEH * 2)   // bytes per tile

// ----------------------------------------------------------------------------
// fp16 A-corrected HMMA GEMM (C = Ah·Bh + Al·Bh), split-K, 2-stage cp.async.
// B (weights) uncorrected — 11-bit weight mantissa, rel err ~1e-4.
// ----------------------------------------------------------------------------
__global__ __launch_bounds__(256)
void hgemm_hilo(const __half* __restrict__ Ah, const __half* __restrict__ Al,
                const __half* __restrict__ Bth,
                float* __restrict__ C, int M, int N, int K)
{
    extern __shared__ __align__(16) __half dyn[];
    int tid = threadIdx.x;
    int lane = tid & 31, wid = tid >> 5;
    int wm = wid >> 2, wn = wid & 3;
    int row0 = blockIdx.y * 128, col0 = blockIdx.x * 128;
    int kb   = K / gridDim.z;
    int kbeg = blockIdx.z * kb;
    float* Cz = C + (size_t)blockIdx.z * M * N;
    int nchunk = kb / 32;

    uint32_t base = smem_u32(dyn);

    float acc[4][4][4];
    #pragma unroll
    for (int mf = 0; mf < 4; mf++)
        #pragma unroll
        for (int nf = 0; nf < 4; nf++)
            #pragma unroll
            for (int e = 0; e < 4; e++) acc[mf][nf][e] = 0.f;

    int laneAr = lane & 15, laneAk = (lane & 16) ? 8 : 0;
    int laneBr = lane & 7,  laneBk = (lane & 8)  ? 8 : 0;

    auto load_stage = [&](int c, int s) {
        uint32_t sb = base + (uint32_t)s * 3 * TILEB;
        #pragma unroll
        for (int i = 0; i < 2; i++) {
            int idx = tid + i * 256;
            int row = idx >> 2, sg = idx & 3;
            size_t ga = (size_t)(row0 + row) * K + kbeg + c * 32 + sg * 8;
            size_t gb = (size_t)(col0 + row) * K + kbeg + c * 32 + sg * 8;
            uint32_t so = (uint32_t)(row * PITCH + sg * 8) * 2;
            CP_ASYNC16(sb + 0 * TILEB + so, Ah + ga);
            CP_ASYNC16(sb + 1 * TILEB + so, Al + ga);
            CP_ASYNC16(sb + 2 * TILEB + so, Bth + gb);
        }
    };

    load_stage(0, 0);
    CP_COMMIT();
    for (int c = 0; c < nchunk; c++) {
        int s = c & 1;
        if (c + 1 < nchunk) { load_stage(c + 1, s ^ 1); CP_COMMIT(); CP_WAIT(1); }
        else                { CP_WAIT(0); }
        __syncthreads();
        uint32_t bAh = base + (uint32_t)s * 3 * TILEB;
        uint32_t bAl = bAh + TILEB;
        uint32_t bBh = bAl + TILEB;
        #pragma unroll
        for (int ks = 0; ks < 32; ks += 16) {
            uint32_t bh[4][2];
            #pragma unroll
            for (int nf = 0; nf < 4; nf++) {
                uint32_t off = (uint32_t)((wn * 32 + nf * 8 + laneBr) * PITCH
                                          + ks + laneBk) * 2;
                LDSM_X2(bh[nf][0], bh[nf][1], bBh + off);
            }
            #pragma unroll
            for (int mf = 0; mf < 4; mf++) {
                uint32_t off = (uint32_t)((wm * 64 + mf * 16 + laneAr) * PITCH
                                          + ks + laneAk) * 2;
                uint32_t ah[4], al[4];
                LDSM_X4(ah[0], ah[1], ah[2], ah[3], bAh + off);
                LDSM_X4(al[0], al[1], al[2], al[3], bAl + off);
                #pragma unroll
                for (int nf = 0; nf < 4; nf++) {
                    MMA16816(acc[mf][nf], ah, bh[nf]);
                    MMA16816(acc[mf][nf], al, bh[nf]);
                }
            }
        }
        __syncthreads();
    }
    #pragma unroll
    for (int mf = 0; mf < 4; mf++) {
        int r = row0 + wm * 64 + mf * 16 + (lane >> 2);
        #pragma unroll
        for (int nf = 0; nf < 4; nf++) {
            int c = col0 + wn * 32 + nf * 8 + (lane & 3) * 2;
            *(float2*)(Cz + (size_t)r * N + c) =
                make_float2(acc[mf][nf][0], acc[mf][nf][1]);
            *(float2*)(Cz + (size_t)(r + 8) * N + c) =
                make_float2(acc[mf][nf][2], acc[mf][nf][3]);
        }
    }
}
#define HG_SMEM (2 * 3 * TILEB)     // 61440

// ----------------------------------------------------------------------------
// Dual-output projection (K/V), full 3-term hi/lo, 2-stage pipelined.
// ----------------------------------------------------------------------------
__global__ __launch_bounds__(256)
void hgemm_dual(const __half* __restrict__ Ah, const __half* __restrict__ Al,
                const __half* __restrict__ Bkh, const __half* __restrict__ Bkl,
                const __half* __restrict__ Bvh, const __half* __restrict__ Bvl,
                float* __restrict__ Ck, float* __restrict__ Cv,
                int M, int N, int K)
{
    extern __shared__ __align__(16) __half dyn[];
    int tid = threadIdx.x;
    int lane = tid & 31, wid = tid >> 5;
    int wm = wid >> 2, wn = wid & 3;
    int row0 = blockIdx.y * 128, col0 = blockIdx.x * 128;
    int nchunk = K / 32;
    uint32_t base = smem_u32(dyn);

    float accK[4][4][4], accV[4][4][4];
    #pragma unroll
    for (int mf = 0; mf < 4; mf++)
        #pragma unroll
        for (int nf = 0; nf < 4; nf++)
            #pragma unroll
            for (int e = 0; e < 4; e++) { accK[mf][nf][e] = 0.f; accV[mf][nf][e] = 0.f; }

    int laneAr = lane & 15, laneAk = (lane & 16) ? 8 : 0;
    int laneBr = lane & 7,  laneBk = (lane & 8)  ? 8 : 0;

    auto load_stage = [&](int c, int s) {
        uint32_t sb = base + (uint32_t)s * 6 * TILEB;
        #pragma unroll
        for (int i = 0; i < 2; i++) {
            int idx = tid + i * 256;
            int row = idx >> 2, sg = idx & 3;
            size_t ga = (size_t)(row0 + row) * K + c * 32 + sg * 8;
            size_t gb = (size_t)(col0 + row) * K + c * 32 + sg * 8;
            uint32_t so = (uint32_t)(row * PITCH + sg * 8) * 2;
            CP_ASYNC16(sb + 0 * TILEB + so, Ah + ga);
            CP_ASYNC16(sb + 1 * TILEB + so, Al + ga);
            CP_ASYNC16(sb + 2 * TILEB + so, Bkh + gb);
            CP_ASYNC16(sb + 3 * TILEB + so, Bkl + gb);
            CP_ASYNC16(sb + 4 * TILEB + so, Bvh + gb);
            CP_ASYNC16(sb + 5 * TILEB + so, Bvl + gb);
        }
    };

    load_stage(0, 0);
    CP_COMMIT();
    for (int c = 0; c < nchunk; c++) {
        int s = c & 1;
        if (c + 1 < nchunk) { load_stage(c + 1, s ^ 1); CP_COMMIT(); CP_WAIT(1); }
        else                { CP_WAIT(0); }
        __syncthreads();
        uint32_t bAh = base + (uint32_t)s * 6 * TILEB;
        uint32_t bAl = bAh + TILEB;
        uint32_t bKh = bAl + TILEB;
        uint32_t bKl = bKh + TILEB;
        uint32_t bVh = bKl + TILEB;
        uint32_t bVl = bVh + TILEB;
        #pragma unroll
        for (int ks = 0; ks < 32; ks += 16) {
            uint32_t kh[4][2], kl[4][2], vh[4][2], vl[4][2];
            #pragma unroll
            for (int nf = 0; nf < 4; nf++) {
                uint32_t off = (uint32_t)((wn * 32 + nf * 8 + laneBr) * PITCH
                                          + ks + laneBk) * 2;
                LDSM_X2(kh[nf][0], kh[nf][1], bKh + off);
                LDSM_X2(kl[nf][0], kl[nf][1], bKl + off);
                LDSM_X2(vh[nf][0], vh[nf][1], bVh + off);
                LDSM_X2(vl[nf][0], vl[nf][1], bVl + off);
            }
            #pragma unroll
            for (int mf = 0; mf < 4; mf++) {
                uint32_t off = (uint32_t)((wm * 64 + mf * 16 + laneAr) * PITCH
                                          + ks + laneAk) * 2;
                uint32_t ah[4], al[4];
                LDSM_X4(ah[0], ah[1], ah[2], ah[3], bAh + off);
                LDSM_X4(al[0], al[1], al[2], al[3], bAl + off);
                #pragma unroll
                for (int nf = 0; nf < 4; nf++) {
                    MMA16816(accK[mf][nf], ah, kh[nf]);
                    MMA16816(accK[mf][nf], ah, kl[nf]);
                    MMA16816(accK[mf][nf], al, kh[nf]);
                    MMA16816(accV[mf][nf], ah, vh[nf]);
                    MMA16816(accV[mf][nf], ah, vl[nf]);
                    MMA16816(accV[mf][nf], al, vh[nf]);
                }
            }
        }
        __syncthreads();
    }
    #pragma unroll
    for (int mf = 0; mf < 4; mf++) {
        int r = row0 + wm * 64 + mf * 16 + (lane >> 2);
        #pragma unroll
        for (int nf = 0; nf < 4; nf++) {
            int c = col0 + wn * 32 + nf * 8 + (lane & 3) * 2;
            *(float2*)(Ck + (size_t)r * N + c) =
                make_float2(accK[mf][nf][0], accK[mf][nf][1]);
            *(float2*)(Ck + (size_t)(r + 8) * N + c) =
                make_float2(accK[mf][nf][2], accK[mf][nf][3]);
            *(float2*)(Cv + (size_t)r * N + c) =
                make_float2(accV[mf][nf][0], accV[mf][nf][1]);
            *(float2*)(Cv + (size_t)(r + 8) * N + c) =
                make_float2(accV[mf][nf][2], accV[mf][nf][3]);
        }
    }
}
#define DUAL2_SMEM (2 * 6 * TILEB)   // 122880

// ----------------------------------------------------------------------------
// W1 + GLU fused, A-corrected 2-term, 2-stage pipelined; emits u*silu(g) hi/lo.
// ----------------------------------------------------------------------------
__global__ __launch_bounds__(256)
void hgemm_glu(const __half* __restrict__ Ah, const __half* __restrict__ Al,
               const __half* __restrict__ W1th,
               __half* __restrict__ Ih, __half* __restrict__ Il, int M)
{
    extern __shared__ __align__(16) __half dyn[];
    int tid = threadIdx.x;
    int lane = tid & 31, wid = tid >> 5;
    int wm = wid >> 2, wn = wid & 3;
    int row0 = blockIdx.y * 128, col0 = blockIdx.x * 128;
    int nchunk = D / 32;
    uint32_t base = smem_u32(dyn);

    float accU[4][4][4], accG[4][4][4];
    #pragma unroll
    for (int mf = 0; mf < 4; mf++)
        #pragma unroll
        for (int nf = 0; nf < 4; nf++)
            #pragma unroll
            for (int e = 0; e < 4; e++) { accU[mf][nf][e] = 0.f; accG[mf][nf][e] = 0.f; }

    int laneAr = lane & 15, laneAk = (lane & 16) ? 8 : 0;
    int laneBr = lane & 7,  laneBk = (lane & 8)  ? 8 : 0;

    auto load_stage = [&](int c, int s) {
        uint32_t sb = base + (uint32_t)s * 4 * TILEB;
        #pragma unroll
        for (int i = 0; i < 2; i++) {
            int idx = tid + i * 256;
            int row = idx >> 2, sg = idx & 3;
            size_t ga = (size_t)(row0 + row) * D + c * 32 + sg * 8;
            size_t gu = (size_t)(col0 + row) * D + c * 32 + sg * 8;
            size_t gg = (size_t)(col0 + row + INNER) * D + c * 32 + sg * 8;
            uint32_t so = (uint32_t)(row * PITCH + sg * 8) * 2;
            CP_ASYNC16(sb + 0 * TILEB + so, Ah + ga);
            CP_ASYNC16(sb + 1 * TILEB + so, Al + ga);
            CP_ASYNC16(sb + 2 * TILEB + so, W1th + gu);
            CP_ASYNC16(sb + 3 * TILEB + so, W1th + gg);
        }
    };

    load_stage(0, 0);
    CP_COMMIT();
    for (int c = 0; c < nchunk; c++) {
        int s = c & 1;
        if (c + 1 < nchunk) { load_stage(c + 1, s ^ 1); CP_COMMIT(); CP_WAIT(1); }
        else                { CP_WAIT(0); }
        __syncthreads();
        uint32_t bAh = base + (uint32_t)s * 4 * TILEB;
        uint32_t bAl = bAh + TILEB;
        uint32_t bUh = bAl + TILEB;
        uint32_t bGh = bUh + TILEB;
        #pragma unroll
        for (int ks = 0; ks < 32; ks += 16) {
            uint32_t uh[4][2], gh[4][2];
            #pragma unroll
            for (int nf = 0; nf < 4; nf++) {
                uint32_t off = (uint32_t)((wn * 32 + nf * 8 + laneBr) * PITCH
                                          + ks + laneBk) * 2;
                LDSM_X2(uh[nf][0], uh[nf][1], bUh + off);
                LDSM_X2(gh[nf][0], gh[nf][1], bGh + off);
            }
            #pragma unroll
            for (int mf = 0; mf < 4; mf++) {
                uint32_t off = (uint32_t)((wm * 64 + mf * 16 + laneAr) * PITCH
                                          + ks + laneAk) * 2;
                uint32_t ah[4], al[4];
                LDSM_X4(ah[0], ah[1], ah[2], ah[3], bAh + off);
                LDSM_X4(al[0], al[1], al[2], al[3], bAl + off);
                #pragma unroll
                for (int nf = 0; nf < 4; nf++) {
                    MMA16816(accU[mf][nf], ah, uh[nf]);
                    MMA16816(accU[mf][nf], al, uh[nf]);
                    MMA16816(accG[mf][nf], ah, gh[nf]);
                    MMA16816(accG[mf][nf], al, gh[nf]);
                }
            }
        }
        __syncthreads();
    }
    #pragma unroll
    for (int mf = 0; mf < 4; mf++) {
        int r = row0 + wm * 64 + mf * 16 + (lane >> 2);
        #pragma unroll
        for (int nf = 0; nf < 4; nf++) {
            int c = col0 + wn * 32 + nf * 8 + (lane & 3) * 2;
            #pragma unroll
            for (int half_ = 0; half_ < 2; half_++) {
                int rr = r + half_ * 8;
                float u0 = accU[mf][nf][half_ * 2], u1 = accU[mf][nf][half_ * 2 + 1];
                float gg0 = accG[mf][nf][half_ * 2], gg1 = accG[mf][nf][half_ * 2 + 1];
                float v0 = u0 * (gg0 / (1.f + expf(-gg0)));
                float v1 = u1 * (gg1 / (1.f + expf(-gg1)));
                __half h0 = __float2half_rn(v0), h1 = __float2half_rn(v1);
                __half l0 = __float2half_rn(v0 - __half2float(h0));
                __half l1 = __float2half_rn(v1 - __half2float(h1));
                *(__half2*)(Ih + (size_t)rr * INNER + c) = __halves2half2(h0, h1);
                *(__half2*)(Il + (size_t)rr * INNER + c) = __halves2half2(l0, l1);
            }
        }
    }
}
#define GLU_SMEM (2 * 4 * TILEB)    // 81920

// ----------------------------------------------------------------------------
// LN reduction helper (256 threads over D=768)
// ----------------------------------------------------------------------------
__device__ __forceinline__ void ln_stats(float v0, float v1, float v2,
                                         float* sa, float* sb2,
                                         float& mean, float& rinv)
{
    float s = v0 + v1 + v2;
    float q = v0 * v0 + v1 * v1 + v2 * v2;
    int tid = threadIdx.x;
    #pragma unroll
    for (int o = 16; o > 0; o >>= 1) {
        s += __shfl_down_sync(0xffffffffu, s, o);
        q += __shfl_down_sync(0xffffffffu, q, o);
    }
    int w = tid >> 5, l = tid & 31;
    if (l == 0) { sa[w] = s; sb2[w] = q; }
    __syncthreads();
    if (tid == 0) {
        float ts = 0.f, tq = 0.f;
        #pragma unroll
        for (int k = 0; k < 8; k++) { ts += sa[k]; tq += sb2[k]; }
        sa[0] = ts; sb2[0] = tq;
    }
    __syncthreads();
    mean = sa[0] * (1.0f / D);
    float var = sb2[0] * (1.0f / D) - mean * mean;
    rinv = rsqrtf(var + 1e-5f);
    __syncthreads();
}

// LN(x) -> fp16 hi/lo
__global__ __launch_bounds__(256)
void ln_split_kernel(const float* __restrict__ in,
                     __half* __restrict__ oh, __half* __restrict__ ol,
                     const float* __restrict__ gamma, const float* __restrict__ beta)
{
    int row = blockIdx.x, tid = threadIdx.x;
    const float* x = in + (size_t)row * D;
    float v[3] = {x[tid], x[tid + 256], x[tid + 512]};
    __shared__ float sa[8], sb2[8];
    float mean, r;
    ln_stats(v[0], v[1], v[2], sa, sb2, mean, r);
    #pragma unroll
    for (int e = 0; e < 3; e++) {
        int idx = tid + e * 256;
        float y = (v[e] - mean) * r * gamma[idx] + beta[idx];
        __half hb = __float2half_rn(y);
        oh[(size_t)row * D + idx] = hb;
        ol[(size_t)row * D + idx] = __float2half_rn(y - __half2float(hb));
    }
}

// h = LN_a(slots + upd) -> hb(fp32);  LN_b(h) -> oh/ol(hi/lo)
__global__ __launch_bounds__(256)
void ln_dual_kernel(const float* __restrict__ slots, const float* __restrict__ upd,
                    float* __restrict__ hb,
                    const float* __restrict__ g1, const float* __restrict__ b1,
                    const float* __restrict__ g2, const float* __restrict__ b2,
                    __half* __restrict__ oh, __half* __restrict__ ol)
{
    int row = blockIdx.x, tid = threadIdx.x;
    const float* xs = slots + (size_t)row * D;
    const float* xu = upd + (size_t)row * D;
    float v[3];
    #pragma unroll
    for (int e = 0; e < 3; e++) v[e] = xs[tid + e * 256] + xu[tid + e * 256];
    __shared__ float sa[8], sb2[8];
    float mean, r;
    ln_stats(v[0], v[1], v[2], sa, sb2, mean, r);
    float y[3];
    #pragma unroll
    for (int e = 0; e < 3; e++) {
        int idx = tid + e * 256;
        y[e] = (v[e] - mean) * r * g1[idx] + b1[idx];
        hb[(size_t)row * D + idx] = y[e];
    }
    float mean2, r2;
    ln_stats(y[0], y[1], y[2], sa, sb2, mean2, r2);
    #pragma unroll
    for (int e = 0; e < 3; e++) {
        int idx = tid + e * 256;
        float z = (y[e] - mean2) * r2 * g2[idx] + b2[idx];
        __half hh = __float2half_rn(z);
        oh[(size_t)row * D + idx] = hh;
        ol[(size_t)row * D + idx] = __float2half_rn(z - __half2float(hh));
    }
}

// h = res + sum_{sp<4} part[sp]; res <- h; LN(h) -> oh/ol
__global__ __launch_bounds__(256)
void ln_split_red_kernel(const float* __restrict__ part, float* __restrict__ res,
                         const float* __restrict__ gamma, const float* __restrict__ beta,
                         __half* __restrict__ oh, __half* __restrict__ ol)
{
    int row = blockIdx.x, tid = threadIdx.x;
    float v[3];
    #pragma unroll
    for (int e = 0; e < 3; e++) {
        int idx = tid + e * 256;
        size_t o = (size_t)row * D + idx;
        float s = res[o];
        #pragma unroll
        for (int sp = 0; sp < 4; sp++) s += part[(size_t)sp * MS * D + o];
        v[e] = s;
        res[o] = s;
    }
    __shared__ float sa[8], sb2[8];
    float mean, r;
    ln_stats(v[0], v[1], v[2], sa, sb2, mean, r);
    #pragma unroll
    for (int e = 0; e < 3; e++) {
        int idx = tid + e * 256;
        float y = (v[e] - mean) * r * gamma[idx] + beta[idx];
        __half hb = __float2half_rn(y);
        oh[(size_t)row * D + idx] = hb;
        ol[(size_t)row * D + idx] = __float2half_rn(y - __half2float(hb));
    }
}

// h = res + sum part; slots = LN_f(h);  LN_s(slots) -> qn hi/lo (next step)
__global__ __launch_bounds__(256)
void ln_red_dual_kernel(const float* __restrict__ part, const float* __restrict__ res,
                        float* __restrict__ slots,
                        const float* __restrict__ gf, const float* __restrict__ bf,
                        const float* __restrict__ gs, const float* __restrict__ bs,
                        __half* __restrict__ qh, __half* __restrict__ ql)
{
    int row = blockIdx.x, tid = threadIdx.x;
    float v[3];
    #pragma unroll
    for (int e = 0; e < 3; e++) {
        int idx = tid + e * 256;
        size_t o = (size_t)row * D + idx;
        float s = res[o];
        #pragma unroll
        for (int sp = 0; sp < 4; sp++) s += part[(size_t)sp * MS * D + o];
        v[e] = s;
    }
    __shared__ float sa[8], sb2[8];
    float mean, r;
    ln_stats(v[0], v[1], v[2], sa, sb2, mean, r);
    float y[3];
    #pragma unroll
    for (int e = 0; e < 3; e++) {
        int idx = tid + e * 256;
        y[e] = (v[e] - mean) * r * gf[idx] + bf[idx];
        slots[(size_t)row * D + idx] = y[e];
    }
    float mean2, r2;
    ln_stats(y[0], y[1], y[2], sa, sb2, mean2, r2);
    #pragma unroll
    for (int e = 0; e < 3; e++) {
        int idx = tid + e * 256;
        float z = (y[e] - mean2) * r2 * gs[idx] + bs[idx];
        __half hh = __float2half_rn(z);
        qh[(size_t)row * D + idx] = hh;
        ql[(size_t)row * D + idx] = __float2half_rn(z - __half2float(hh));
    }
}

// transpose + fp16 hi/lo split (lo optional)
__global__ __launch_bounds__(256)
void wsplit_kernel(const float* __restrict__ W,
                   __half* __restrict__ Th, __half* __restrict__ Tl,
                   int Krows, int Ncols, int n_off)
{
    __shared__ float tile[32][33];
    int n0 = blockIdx.x * 32, k0 = blockIdx.y * 32;
    int t = threadIdx.x;
    int tx = t & 31, ty = t >> 5;
    #pragma unroll
    for (int i = 0; i < 4; i++)
        tile[ty + i * 8][tx] = W[(size_t)(k0 + ty + i * 8) * Ncols + n0 + tx];
    __syncthreads();
    #pragma unroll
    for (int i = 0; i < 4; i++) {
        int n = n_off + n0 + ty + i * 8;
        float v = tile[tx][ty + i * 8];
        __half hb = __float2half_rn(v);
        Th[(size_t)n * Krows + k0 + tx] = hb;
        if (Tl)
            Tl[(size_t)n * Krows + k0 + tx] = __float2half_rn(v - __half2float(hb));
    }
}

__global__ void init_slots_kernel(const float* __restrict__ noise,
                                  const float* __restrict__ mu,
                                  const float* __restrict__ ls,
                                  float* __restrict__ slots)
{
    int t = blockIdx.x * blockDim.x + threadIdx.x;
    if (t >= MS * D) return;
    int d = t % D;
    slots[t] = mu[d] + expf(ls[d]) * noise[t];
}

// ----------------------------------------------------------------------------
// dots + softmax over the slot axis; reads Wq split-K partials directly
// ----------------------------------------------------------------------------
__global__ __launch_bounds__(256)
void dots_softmax_kernel(const float* __restrict__ Qpart, const float* __restrict__ Kb,
                         float* __restrict__ attn)
{
    int b  = blockIdx.y;
    int j0 = blockIdx.x * 64;
    __shared__ __align__(16) float qs[16][64];
    __shared__ float ks[64][65];
    __shared__ float red[4][64];
    int tid = threadIdx.x;
    int tx = tid & 63, ty = tid >> 6;
    float acc[4] = {0.f, 0.f, 0.f, 0.f};
    const float* Kp = Kb + ((size_t)b * NK + j0) * D;
    for (int k0 = 0; k0 < D; k0 += 64) {
        {
            int i = tid >> 4, kc = (tid & 15) * 4;
            size_t o = ((size_t)b * S + i) * D + k0 + kc;
            float4 v = *(const float4*)&Qpart[o];
            #pragma unroll
            for (int sp = 1; sp < 4; sp++) {
                float4 w = *(const float4*)&Qpart[(size_t)sp * MS * D + o];
                v.x += w.x; v.y += w.y; v.z += w.z; v.w += w.w;
            }
            *(float4*)&qs[i][kc] = v;
        }
        #pragma unroll
        for (int p = 0; p < 4; p++) {
            int e = tid + p * 256;
            int jj = e >> 4, kc = (e & 15) * 4;
            float4 v = *(const float4*)&Kp[(size_t)jj * D + k0 + kc];
            ks[jj][kc + 0] = v.x; ks[jj][kc + 1] = v.y;
            ks[jj][kc + 2] = v.z; ks[jj][kc + 3] = v.w;
        }
        __syncthreads();
        #pragma unroll
        for (int kk = 0; kk < 64; kk++) {
            float kv = ks[tx][kk];
            acc[0] += qs[ty     ][kk] * kv;
            acc[1] += qs[ty +  4][kk] * kv;
            acc[2] += qs[ty +  8][kk] * kv;
            acc[3] += qs[ty + 12][kk] * kv;
        }
        __syncthreads();
    }
    #pragma unroll
    for (int r = 0; r < 4; r++) acc[r] *= kSCALE;
    float m = fmaxf(fmaxf(acc[0], acc[1]), fmaxf(acc[2], acc[3]));
    red[ty][tx] = m;
    __syncthreads();
    float M = fmaxf(fmaxf(red[0][tx], red[1][tx]), fmaxf(red[2][tx], red[3][tx]));
    __syncthreads();
    float e[4]; float s = 0.f;
    #pragma unroll
    for (int r = 0; r < 4; r++) { e[r] = expf(acc[r] - M); s += e[r]; }
    red[ty][tx] = s;
    __syncthreads();
    float Ssum = red[0][tx] + red[1][tx] + red[2][tx] + red[3][tx];
    float inv = 1.f / Ssum;
    #pragma unroll
    for (int r = 0; r < 4; r++)
        attn[((size_t)b * S + ty + r * 4) * NK + j0 + tx] = e[r] * inv + 1e-8f;
}

// updates[b,i,n] = (sum_j attn * v) / (sum_j attn)
__global__ __launch_bounds__(256)
void updates_kernel(const float* __restrict__ attn, const float* __restrict__ V,
                    float* __restrict__ upd)
{
    int b  = blockIdx.y;
    int n0 = blockIdx.x * 64;
    __shared__ __align__(16) float as_[16][64];
    __shared__ __align__(16) float vs[64][64];
    int tid = threadIdx.x;
    int tx = tid & 63, ty = tid >> 6;
    float acc[4] = {0.f, 0.f, 0.f, 0.f};
    float ssum[4] = {0.f, 0.f, 0.f, 0.f};
    for (int j0 = 0; j0 < NK; j0 += 64) {
        {
            int i = tid >> 4, jc = (tid & 15) * 4;
            *(float4*)&as_[i][jc] =
                *(const float4*)&attn[((size_t)b * S + i) * NK + j0 + jc];
        }
        #pragma unroll
        for (int p = 0; p < 4; p++) {
            int e = tid + p * 256;
            int jj = e >> 4, nc = (e & 15) * 4;
            *(float4*)&vs[jj][nc] =
                *(const float4*)&V[((size_t)b * NK + j0 + jj) * D + n0 + nc];
        }
        __syncthreads();
        #pragma unroll
        for (int jj = 0; jj < 64; jj++) {
            float vv = vs[jj][tx];
            float a0 = as_[ty][jj], a1 = as_[ty + 4][jj];
            float a2 = as_[ty + 8][jj], a3 = as_[ty + 12][jj];
            acc[0] += a0 * vv;  ssum[0] += a0;
            acc[1] += a1 * vv;  ssum[1] += a1;
            acc[2] += a2 * vv;  ssum[2] += a2;
            acc[3] += a3 * vv;  ssum[3] += a3;
        }
        __syncthreads();
    }
    #pragma unroll
    for (int r = 0; r < 4; r++)
        upd[((size_t)b * S + ty + r * 4) * D + n0 + tx] = acc[r] / ssum[r];
}

// encoder self-attention; reads QKV split-K partials directly
__global__ __launch_bounds__(256)
void enc_attn_kernel(const float* __restrict__ QKVpart,
                     __half* __restrict__ Oh, __half* __restrict__ Ol)
{
    int b = blockIdx.x >> 3, h = blockIdx.x & 7;
    __shared__ float qs[16][65], ks[16][65], vs[16][65];
    __shared__ float p[16][17];
    int tid = threadIdx.x;
    int i = tid >> 4, jj = tid & 15;
    {
        int r = tid >> 4, c = (tid & 15) * 4;
        size_t base = ((size_t)b * S + r) * QKV3 + h * DH + c;
        float4 vq = *(const float4*)&QKVpart[base];
        float4 vk = *(const float4*)&QKVpart[base + HD];
        float4 vv = *(const float4*)&QKVpart[base + 2 * HD];
        #pragma unroll
        for (int sp = 1; sp < 4; sp++) {
            size_t o = (size_t)sp * MS * QKV3 + base;
            float4 w;
            w = *(const float4*)&QKVpart[o];
            vq.x += w.x; vq.y += w.y; vq.z += w.z; vq.w += w.w;
            w = *(const float4*)&QKVpart[o + HD];
            vk.x += w.x; vk.y += w.y; vk.z += w.z; vk.w += w.w;
            w = *(const float4*)&QKVpart[o + 2 * HD];
            vv.x += w.x; vv.y += w.y; vv.z += w.z; vv.w += w.w;
        }
        qs[r][c] = vq.x; qs[r][c+1] = vq.y; qs[r][c+2] = vq.z; qs[r][c+3] = vq.w;
        ks[r][c] = vk.x; ks[r][c+1] = vk.y; ks[r][c+2] = vk.z; ks[r][c+3] = vk.w;
        vs[r][c] = vv.x; vs[r][c+1] = vv.y; vs[r][c+2] = vv.z; vs[r][c+3] = vv.w;
    }
    __syncthreads();
    float s = 0.f;
    #pragma unroll
    for (int d = 0; d < DH; d++) s += qs[i][d] * ks[jj][d];
    s *= 0.125f;
    p[i][jj] = s;
    __syncthreads();
    float m = -1e30f;
    #pragma unroll
    for (int t2 = 0; t2 < 16; t2++) m = fmaxf(m, p[i][t2]);
    __syncthreads();
    float e = expf(s - m);
    p[i][jj] = e;
    __syncthreads();
    float sum = 0.f;
    #pragma unroll
    for (int t2 = 0; t2 < 16; t2++) sum += p[i][t2];
    __syncthreads();
    p[i][jj] = e / sum;
    __syncthreads();
    int io = tid >> 4, dbase = (tid & 15) * 4;
    float o[4] = {0.f, 0.f, 0.f, 0.f};
    #pragma unroll
    for (int t2 = 0; t2 < 16; t2++) {
        float pp = p[io][t2];
        o[0] += pp * vs[t2][dbase + 0];
        o[1] += pp * vs[t2][dbase + 1];
        o[2] += pp * vs[t2][dbase + 2];
        o[3] += pp * vs[t2][dbase + 3];
    }
    size_t base = ((size_t)b * S + io) * HD + h * DH + dbase;
    #pragma unroll
    for (int c = 0; c < 4; c++) {
        __half hb = __float2half_rn(o[c]);
        Oh[base + c] = hb;
        Ol[base + c] = __float2half_rn(o[c] - __half2float(hb));
    }
}

// output map: per (b,i) row — sum over keys then write out[b][j][i] = attn/sum
__global__ __launch_bounds__(256)
void attn_out_kernel(const float* __restrict__ attn, float* __restrict__ out)
{
    int row = blockIdx.x;            // b*S + i
    int b = row >> 4, i = row & 15;
    const float4* p = (const float4*)(attn + (size_t)row * NK);
    int tid = threadIdx.x;
    float4 v = p[tid];
    float s = v.x + v.y + v.z + v.w;
    __shared__ float sa[8];
    #pragma unroll
    for (int o = 16; o > 0; o >>= 1) s += __shfl_down_sync(0xffffffffu, s, o);
    int w = tid >> 5, l = tid & 31;
    if (l == 0) sa[w] = s;
    __syncthreads();
    if (tid == 0) {
        float ts = 0.f;
        #pragma unroll
        for (int k = 0; k < 8; k++) ts += sa[k];
        sa[0] = ts;
    }
    __syncthreads();
    float inv = 1.f / sa[0];
    size_t ob = (size_t)b * NK * S + i;
    int j = tid * 4;
    out[ob + (size_t)(j + 0) * S] = v.x * inv;
    out[ob + (size_t)(j + 1) * S] = v.y * inv;
    out[ob + (size_t)(j + 2) * S] = v.z * inv;
    out[ob + (size_t)(j + 3) * S] = v.w * inv;
}

// ----------------------------------------------------------------------------
// Host orchestration
// ----------------------------------------------------------------------------
extern "C" void kernel_launch(void* const* d_in, const int* in_sizes, int n_in,
                              void* d_out, int out_size)
{
    const float* x       = (const float*)d_in[0];
    const float* noise   = (const float*)d_in[1];
    const float* init_mu = (const float*)d_in[2];
    const float* init_ls = (const float*)d_in[3];
    const float* Wk      = (const float*)d_in[4];
    const float* Wv      = (const float*)d_in[5];
    const float* Wq      = (const float*)d_in[6];
    const float* ni_g    = (const float*)d_in[7];
    const float* ni_b    = (const float*)d_in[8];
    const float* ns_g    = (const float*)d_in[9];
    const float* ns_b    = (const float*)d_in[10];
    const float* nica_g  = (const float*)d_in[11];
    const float* nica_b  = (const float*)d_in[12];
    const float* ln1_g   = (const float*)d_in[13];
    const float* ln1_b   = (const float*)d_in[14];
    const float* Wq_a    = (const float*)d_in[15];
    const float* Wk_a    = (const float*)d_in[16];
    const float* Wv_a    = (const float*)d_in[17];
    const float* Wo_a    = (const float*)d_in[18];
    const float* ln2_g   = (const float*)d_in[19];
    const float* ln2_b   = (const float*)d_in[20];
    const float* W1      = (const float*)d_in[21];
    const float* W2      = (const float*)d_in[22];
    const float* lnf_g   = (const float*)d_in[23];
    const float* lnf_b   = (const float*)d_in[24];

    __half *xnh, *xnl, *wkh, *wkl, *wvh, *wvl, *wqh;
    __half *wqkh, *woh, *w1h, *w2h;
    __half *qnh, *qnl, *abh, *abl, *fbh, *fbl, *innh, *innl, *oah, *oal;
    float *kb, *vb, *slots, *attn, *upd, *hb, *part;
    cudaGetSymbolAddress((void**)&xnh,  g_xnh);  cudaGetSymbolAddress((void**)&xnl,  g_xnl);
    cudaGetSymbolAddress((void**)&wkh,  g_wkh);  cudaGetSymbolAddress((void**)&wkl,  g_wkl);
    cudaGetSymbolAddress((void**)&wvh,  g_wvh);  cudaGetSymbolAddress((void**)&wvl,  g_wvl);
    cudaGetSymbolAddress((void**)&wqh,  g_wqh);
    cudaGetSymbolAddress((void**)&wqkh, g_wqkh);
    cudaGetSymbolAddress((void**)&woh,  g_woh);
    cudaGetSymbolAddress((void**)&w1h,  g_w1h);
    cudaGetSymbolAddress((void**)&w2h,  g_w2h);
    cudaGetSymbolAddress((void**)&qnh,  g_qnh);  cudaGetSymbolAddress((void**)&qnl,  g_qnl);
    cudaGetSymbolAddress((void**)&abh,  g_abh);  cudaGetSymbolAddress((void**)&abl,  g_abl);
    cudaGetSymbolAddress((void**)&fbh,  g_fbh);  cudaGetSymbolAddress((void**)&fbl,  g_fbl);
    cudaGetSymbolAddress((void**)&innh, g_innh); cudaGetSymbolAddress((void**)&innl, g_innl);
    cudaGetSymbolAddress((void**)&oah,  g_oah);  cudaGetSymbolAddress((void**)&oal,  g_oal);
    cudaGetSymbolAddress((void**)&kb,   g_k);
    cudaGetSymbolAddress((void**)&vb,   g_v);
    cudaGetSymbolAddress((void**)&slots,g_slots);
    cudaGetSymbolAddress((void**)&attn, g_attn);
    cudaGetSymbolAddress((void**)&upd,  g_upd);
    cudaGetSymbolAddress((void**)&hb,   g_h);
    cudaGetSymbolAddress((void**)&part, g_part);

    cudaFuncSetAttribute(hgemm_hilo, cudaFuncAttributeMaxDynamicSharedMemorySize, HG_SMEM);
    cudaFuncSetAttribute(hgemm_dual, cudaFuncAttributeMaxDynamicSharedMemorySize, DUAL2_SMEM);
    cudaFuncSetAttribute(hgemm_glu,  cudaFuncAttributeMaxDynamicSharedMemorySize, GLU_SMEM);

    // ---- precompute ----
    wsplit_kernel<<<dim3(D / 32, D / 32), 256>>>(Wk, wkh, wkl, D, D, 0);
    wsplit_kernel<<<dim3(D / 32, D / 32), 256>>>(Wv, wvh, wvl, D, D, 0);
    ln_split_kernel<<<B * NK, 256>>>(x, xnh, xnl, ni_g, ni_b);
    init_slots_kernel<<<(MS * D + 255) / 256, 256>>>(noise, init_mu, init_ls, slots);
    wsplit_kernel<<<dim3(D / 32, D / 32), 256>>>(Wq, wqh, nullptr, D, D, 0);
    hgemm_dual<<<dim3(D / 128, (B * NK) / 128), 256, DUAL2_SMEM>>>(
        xnh, xnl, wkh, wkl, wvh, wvl, kb, vb, B * NK, D, D);
    wsplit_kernel<<<dim3(HD / 32, D / 32), 256>>>(Wq_a, wqkh, nullptr, D, HD, 0);
    wsplit_kernel<<<dim3(HD / 32, D / 32), 256>>>(Wk_a, wqkh, nullptr, D, HD, HD);
    wsplit_kernel<<<dim3(HD / 32, D / 32), 256>>>(Wv_a, wqkh, nullptr, D, HD, 2 * HD);
    wsplit_kernel<<<dim3(D / 32, HD / 32), 256>>>(Wo_a, woh, nullptr, HD, D, 0);
    wsplit_kernel<<<dim3((2 * INNER) / 32, D / 32), 256>>>(W1, w1h, nullptr, D, 2 * INNER, 0);
    wsplit_kernel<<<dim3(D / 32, INNER / 32), 256>>>(W2, w2h, nullptr, INNER, D, 0);
    ln_split_kernel<<<MS, 256>>>(slots, qnh, qnl, ns_g, ns_b);

    // ---- 4 slot-attention steps (11 launches each) ----
    for (int it = 0; it < N_STEPS; it++) {
        hgemm_hilo<<<dim3(D / 128, MS / 128, 4), 256, HG_SMEM>>>(qnh, qnl, wqh,
                                                                 part, MS, D, D);
        dots_softmax_kernel<<<dim3(NK / 64, B), 256>>>(part, kb, attn);
        updates_kernel<<<dim3(D / 64, B), 256>>>(attn, vb, upd);
        ln_dual_kernel<<<MS, 256>>>(slots, upd, hb, nica_g, nica_b,
                                    ln1_g, ln1_b, abh, abl);
        hgemm_hilo<<<dim3(QKV3 / 128, MS / 128, 4), 256, HG_SMEM>>>(abh, abl, wqkh,
                                                                    part, MS, QKV3, D);
        enc_attn_kernel<<<B * H, 256>>>(part, oah, oal);
        hgemm_hilo<<<dim3(D / 128, MS / 128, 4), 256, HG_SMEM>>>(oah, oal, woh,
                                                                 part, MS, D, HD);
        ln_split_red_kernel<<<MS, 256>>>(part, hb, ln2_g, ln2_b, fbh, fbl);
        hgemm_glu<<<dim3(INNER / 128, MS / 128), 256, GLU_SMEM>>>(fbh, fbl, w1h,
                                                                  innh, innl, MS);
        hgemm_hilo<<<dim3(D / 128, MS / 128, 4), 256, HG_SMEM>>>(innh, innl, w2h,
                                                                 part, MS, D, INNER);
        ln_red_dual_kernel<<<MS, 256>>>(part, hb, slots, lnf_g, lnf_b,
                                        ns_g, ns_b, qnh, qnl);
    }

    // ---- outputs: slots [32,16,768], then attn_map [32,1024,16] ----
    float* out = (float*)d_out;
    cudaMemcpyAsync(out, slots, (size_t)MS * D * sizeof(float),
                    cudaMemcpyDeviceToDevice);
    attn_out_kernel<<<MS, 256>>>(attn, out + (size_t)MS * D);
}

// round 11
// speedup vs baseline: 1.3400x; 1.1410x over previous
#include <cuda_runtime.h>
#include <cuda_fp16.h>
#include <math.h>
#include <stdint.h>

// ----------------------------------------------------------------------------
// Problem constants
// ----------------------------------------------------------------------------
#define B   32
#define NK  1024
#define S   16
#define D   768
#define H   8
#define DH  64
#define HD  (H*DH)    // 512
#define QKV3 (3*HD)   // 1536
#define INNER 3072
#define N_STEPS 4
#define MS  (B*S)     // 512
static __device__ __constant__ float kSCALE = 0.036084391824351615f;  // 768^-0.5

// ----------------------------------------------------------------------------
// Scratch (device globals)
// ----------------------------------------------------------------------------
__device__ __half g_xnh[B*NK*D], g_xnl[B*NK*D];
__device__ __half g_wkh [D*D];
__device__ __half g_wvh [D*D];
__device__ __half g_wqh [D*D];
__device__ __half g_wqkh[QKV3*D];
__device__ __half g_woh [D*HD];
__device__ __half g_w1h [2*INNER*D];
__device__ __half g_w2h [D*INNER];
__device__ __half g_qnh[MS*D],   g_qnl[MS*D];
__device__ __half g_abh[MS*D],   g_abl[MS*D];
__device__ __half g_fbh[MS*D],   g_fbl[MS*D];
__device__ __half g_innh[MS*INNER], g_innl[MS*INNER];
__device__ __half g_oah[MS*HD],  g_oal[MS*HD];
__device__ float g_k    [B*NK*D];
__device__ float g_v    [B*NK*D];
__device__ float g_slots[MS*D];
__device__ float g_attn [MS*NK];
__device__ float g_upd  [MS*D];
__device__ float g_h    [MS*D];
__device__ float g_part [4*MS*QKV3];

// ----------------------------------------------------------------------------
// HMMA / cp.async helpers (baseline PTX — compiles for plain compute_103)
// ----------------------------------------------------------------------------
__device__ __forceinline__ uint32_t smem_u32(const void* p) {
    uint32_t a;
    asm("{ .reg .u64 t; cvta.to.shared.u64 t, %1; cvt.u32.u64 %0, t; }"
        : "=r"(a) : "l"(p));
    return a;
}
#define LDSM_X4(r0, r1, r2, r3, addr) \
    asm volatile("ldmatrix.sync.aligned.m8n8.x4.shared.b16 {%0,%1,%2,%3}, [%4];" \
                 : "=r"(r0), "=r"(r1), "=r"(r2), "=r"(r3) : "r"(addr))
#define LDSM_X2(r0, r1, addr) \
    asm volatile("ldmatrix.sync.aligned.m8n8.x2.shared.b16 {%0,%1}, [%2];" \
                 : "=r"(r0), "=r"(r1) : "r"(addr))
#define MMA16816(c, a, b) \
    asm volatile("mma.sync.aligned.m16n8k16.row.col.f32.f16.f16.f32 " \
                 "{%0,%1,%2,%3}, {%4,%5,%6,%7}, {%8,%9}, {%0,%1,%2,%3};" \
                 : "+f"((c)[0]), "+f"((c)[1]), "+f"((c)[2]), "+f"((c)[3]) \
                 : "r"((a)[0]), "r"((a)[1]), "r"((a)[2]), "r"((a)[3]), \
                   "r"((b)[0]), "r"((b)[1]))
#define CP_ASYNC16(dst_u32, src_ptr) \
    asm volatile("cp.async.ca.shared.global [%0], [%1], 16;" \
                 :: "r"(dst_u32), "l"(src_ptr))
#define CP_COMMIT() asm volatile("cp.async.commit_group;" ::: "memory")
#define CP_WAIT(n)  asm volatile("cp.async.wait_group %0;" :: "n"(n) : "memory")

#define PITCH 40            // halves per smem row (80 B) — conflict-free ldmatrix
#define TILEH (128 * PITCH) // halves per tile
#define TILEB (TILEH * 2)   // bytes per tile

// ----------------------------------------------------------------------------
// fp16 A-corrected HMMA GEMM (C = Ah·Bh + Al·Bh), split-K, 2-stage cp.async.
// ----------------------------------------------------------------------------
__global__ __launch_bounds__(256)
void hgemm_hilo(const __half* __restrict__ Ah, const __half* __restrict__ Al,
                const __half* __restrict__ Bth,
                float* __restrict__ C, int M, int N, int K)
{
    extern __shared__ __align__(16) __half dyn[];
    int tid = threadIdx.x;
    int lane = tid & 31, wid = tid >> 5;
    int wm = wid >> 2, wn = wid & 3;
    int row0 = blockIdx.y * 128, col0 = blockIdx.x * 128;
    int kb   = K / gridDim.z;
    int kbeg = blockIdx.z * kb;
    float* Cz = C + (size_t)blockIdx.z * M * N;
    int nchunk = kb / 32;

    uint32_t base = smem_u32(dyn);

    float acc[4][4][4];
    #pragma unroll
    for (int mf = 0; mf < 4; mf++)
        #pragma unroll
        for (int nf = 0; nf < 4; nf++)
            #pragma unroll
            for (int e = 0; e < 4; e++) acc[mf][nf][e] = 0.f;

    int laneAr = lane & 15, laneAk = (lane & 16) ? 8 : 0;
    int laneBr = lane & 7,  laneBk = (lane & 8)  ? 8 : 0;

    auto load_stage = [&](int c, int s) {
        uint32_t sb = base + (uint32_t)s * 3 * TILEB;
        #pragma unroll
        for (int i = 0; i < 2; i++) {
            int idx = tid + i * 256;
            int row = idx >> 2, sg = idx & 3;
            size_t ga = (size_t)(row0 + row) * K + kbeg + c * 32 + sg * 8;
            size_t gb = (size_t)(col0 + row) * K + kbeg + c * 32 + sg * 8;
            uint32_t so = (uint32_t)(row * PITCH + sg * 8) * 2;
            CP_ASYNC16(sb + 0 * TILEB + so, Ah + ga);
            CP_ASYNC16(sb + 1 * TILEB + so, Al + ga);
            CP_ASYNC16(sb + 2 * TILEB + so, Bth + gb);
        }
    };

    load_stage(0, 0);
    CP_COMMIT();
    for (int c = 0; c < nchunk; c++) {
        int s = c & 1;
        if (c + 1 < nchunk) { load_stage(c + 1, s ^ 1); CP_COMMIT(); CP_WAIT(1); }
        else                { CP_WAIT(0); }
        __syncthreads();
        uint32_t bAh = base + (uint32_t)s * 3 * TILEB;
        uint32_t bAl = bAh + TILEB;
        uint32_t bBh = bAl + TILEB;
        #pragma unroll
        for (int ks = 0; ks < 32; ks += 16) {
            uint32_t bh[4][2];
            #pragma unroll
            for (int nf = 0; nf < 4; nf++) {
                uint32_t off = (uint32_t)((wn * 32 + nf * 8 + laneBr) * PITCH
                                          + ks + laneBk) * 2;
                LDSM_X2(bh[nf][0], bh[nf][1], bBh + off);
            }
            #pragma unroll
            for (int mf = 0; mf < 4; mf++) {
                uint32_t off = (uint32_t)((wm * 64 + mf * 16 + laneAr) * PITCH
                                          + ks + laneAk) * 2;
                uint32_t ah[4], al[4];
                LDSM_X4(ah[0], ah[1], ah[2], ah[3], bAh + off);
                LDSM_X4(al[0], al[1], al[2], al[3], bAl + off);
                #pragma unroll
                for (int nf = 0; nf < 4; nf++) {
                    MMA16816(acc[mf][nf], ah, bh[nf]);
                    MMA16816(acc[mf][nf], al, bh[nf]);
                }
            }
        }
        __syncthreads();
    }
    #pragma unroll
    for (int mf = 0; mf < 4; mf++) {
        int r = row0 + wm * 64 + mf * 16 + (lane >> 2);
        #pragma unroll
        for (int nf = 0; nf < 4; nf++) {
            int c = col0 + wn * 32 + nf * 8 + (lane & 3) * 2;
            *(float2*)(Cz + (size_t)r * N + c) =
                make_float2(acc[mf][nf][0], acc[mf][nf][1]);
            *(float2*)(Cz + (size_t)(r + 8) * N + c) =
                make_float2(acc[mf][nf][2], acc[mf][nf][3]);
        }
    }
}
#define HG_SMEM (2 * 3 * TILEB)     // 61440

// ----------------------------------------------------------------------------
// Dual-output projection (K/V), A-corrected 2-term, 2-stage pipelined.
// Ck = Ah·Kh + Al·Kh ; Cv = Ah·Vh + Al·Vh   (weights uncorrected)
// ----------------------------------------------------------------------------
__global__ __launch_bounds__(256)
void hgemm_dual(const __half* __restrict__ Ah, const __half* __restrict__ Al,
                const __half* __restrict__ Bkh, const __half* __restrict__ Bvh,
                float* __restrict__ Ck, float* __restrict__ Cv,
                int M, int N, int K)
{
    extern __shared__ __align__(16) __half dyn[];
    int tid = threadIdx.x;
    int lane = tid & 31, wid = tid >> 5;
    int wm = wid >> 2, wn = wid & 3;
    int row0 = blockIdx.y * 128, col0 = blockIdx.x * 128;
    int nchunk = K / 32;
    uint32_t base = smem_u32(dyn);

    float accK[4][4][4], accV[4][4][4];
    #pragma unroll
    for (int mf = 0; mf < 4; mf++)
        #pragma unroll
        for (int nf = 0; nf < 4; nf++)
            #pragma unroll
            for (int e = 0; e < 4; e++) { accK[mf][nf][e] = 0.f; accV[mf][nf][e] = 0.f; }

    int laneAr = lane & 15, laneAk = (lane & 16) ? 8 : 0;
    int laneBr = lane & 7,  laneBk = (lane & 8)  ? 8 : 0;

    auto load_stage = [&](int c, int s) {
        uint32_t sb = base + (uint32_t)s * 4 * TILEB;
        #pragma unroll
        for (int i = 0; i < 2; i++) {
            int idx = tid + i * 256;
            int row = idx >> 2, sg = idx & 3;
            size_t ga = (size_t)(row0 + row) * K + c * 32 + sg * 8;
            size_t gb = (size_t)(col0 + row) * K + c * 32 + sg * 8;
            uint32_t so = (uint32_t)(row * PITCH + sg * 8) * 2;
            CP_ASYNC16(sb + 0 * TILEB + so, Ah + ga);
            CP_ASYNC16(sb + 1 * TILEB + so, Al + ga);
            CP_ASYNC16(sb + 2 * TILEB + so, Bkh + gb);
            CP_ASYNC16(sb + 3 * TILEB + so, Bvh + gb);
        }
    };

    load_stage(0, 0);
    CP_COMMIT();
    for (int c = 0; c < nchunk; c++) {
        int s = c & 1;
        if (c + 1 < nchunk) { load_stage(c + 1, s ^ 1); CP_COMMIT(); CP_WAIT(1); }
        else                { CP_WAIT(0); }
        __syncthreads();
        uint32_t bAh = base + (uint32_t)s * 4 * TILEB;
        uint32_t bAl = bAh + TILEB;
        uint32_t bKh = bAl + TILEB;
        uint32_t bVh = bKh + TILEB;
        #pragma unroll
        for (int ks = 0; ks < 32; ks += 16) {
            uint32_t kh[4][2], vh[4][2];
            #pragma unroll
            for (int nf = 0; nf < 4; nf++) {
                uint32_t off = (uint32_t)((wn * 32 + nf * 8 + laneBr) * PITCH
                                          + ks + laneBk) * 2;
                LDSM_X2(kh[nf][0], kh[nf][1], bKh + off);
                LDSM_X2(vh[nf][0], vh[nf][1], bVh + off);
            }
            #pragma unroll
            for (int mf = 0; mf < 4; mf++) {
                uint32_t off = (uint32_t)((wm * 64 + mf * 16 + laneAr) * PITCH
                                          + ks + laneAk) * 2;
                uint32_t ah[4], al[4];
                LDSM_X4(ah[0], ah[1], ah[2], ah[3], bAh + off);
                LDSM_X4(al[0], al[1], al[2], al[3], bAl + off);
                #pragma unroll
                for (int nf = 0; nf < 4; nf++) {
                    MMA16816(accK[mf][nf], ah, kh[nf]);
                    MMA16816(accK[mf][nf], al, kh[nf]);
                    MMA16816(accV[mf][nf], ah, vh[nf]);
                    MMA16816(accV[mf][nf], al, vh[nf]);
                }
            }
        }
        __syncthreads();
    }
    #pragma unroll
    for (int mf = 0; mf < 4; mf++) {
        int r = row0 + wm * 64 + mf * 16 + (lane >> 2);
        #pragma unroll
        for (int nf = 0; nf < 4; nf++) {
            int c = col0 + wn * 32 + nf * 8 + (lane & 3) * 2;
            *(float2*)(Ck + (size_t)r * N + c) =
                make_float2(accK[mf][nf][0], accK[mf][nf][1]);
            *(float2*)(Ck + (size_t)(r + 8) * N + c) =
                make_float2(accK[mf][nf][2], accK[mf][nf][3]);
            *(float2*)(Cv + (size_t)r * N + c) =
                make_float2(accV[mf][nf][0], accV[mf][nf][1]);
            *(float2*)(Cv + (size_t)(r + 8) * N + c) =
                make_float2(accV[mf][nf][2], accV[mf][nf][3]);
        }
    }
}
#define DUAL_SMEM (2 * 4 * TILEB)   // 81920

// ----------------------------------------------------------------------------
// W1 + GLU fused, A-corrected 2-term, 2-stage pipelined; emits u*silu(g) hi/lo.
// ----------------------------------------------------------------------------
__global__ __launch_bounds__(256)
void hgemm_glu(const __half* __restrict__ Ah, const __half* __restrict__ Al,
               const __half* __restrict__ W1th,
               __half* __restrict__ Ih, __half* __restrict__ Il, int M)
{
    extern __shared__ __align__(16) __half dyn[];
    int tid = threadIdx.x;
    int lane = tid & 31, wid = tid >> 5;
    int wm = wid >> 2, wn = wid & 3;
    int row0 = blockIdx.y * 128, col0 = blockIdx.x * 128;
    int nchunk = D / 32;
    uint32_t base = smem_u32(dyn);

    float accU[4][4][4], accG[4][4][4];
    #pragma unroll
    for (int mf = 0; mf < 4; mf++)
        #pragma unroll
        for (int nf = 0; nf < 4; nf++)
            #pragma unroll
            for (int e = 0; e < 4; e++) { accU[mf][nf][e] = 0.f; accG[mf][nf][e] = 0.f; }

    int laneAr = lane & 15, laneAk = (lane & 16) ? 8 : 0;
    int laneBr = lane & 7,  laneBk = (lane & 8)  ? 8 : 0;

    auto load_stage = [&](int c, int s) {
        uint32_t sb = base + (uint32_t)s * 4 * TILEB;
        #pragma unroll
        for (int i = 0; i < 2; i++) {
            int idx = tid + i * 256;
            int row = idx >> 2, sg = idx & 3;
            size_t ga = (size_t)(row0 + row) * D + c * 32 + sg * 8;
            size_t gu = (size_t)(col0 + row) * D + c * 32 + sg * 8;
            size_t gg = (size_t)(col0 + row + INNER) * D + c * 32 + sg * 8;
            uint32_t so = (uint32_t)(row * PITCH + sg * 8) * 2;
            CP_ASYNC16(sb + 0 * TILEB + so, Ah + ga);
            CP_ASYNC16(sb + 1 * TILEB + so, Al + ga);
            CP_ASYNC16(sb + 2 * TILEB + so, W1th + gu);
            CP_ASYNC16(sb + 3 * TILEB + so, W1th + gg);
        }
    };

    load_stage(0, 0);
    CP_COMMIT();
    for (int c = 0; c < nchunk; c++) {
        int s = c & 1;
        if (c + 1 < nchunk) { load_stage(c + 1, s ^ 1); CP_COMMIT(); CP_WAIT(1); }
        else                { CP_WAIT(0); }
        __syncthreads();
        uint32_t bAh = base + (uint32_t)s * 4 * TILEB;
        uint32_t bAl = bAh + TILEB;
        uint32_t bUh = bAl + TILEB;
        uint32_t bGh = bUh + TILEB;
        #pragma unroll
        for (int ks = 0; ks < 32; ks += 16) {
            uint32_t uh[4][2], gh[4][2];
            #pragma unroll
            for (int nf = 0; nf < 4; nf++) {
                uint32_t off = (uint32_t)((wn * 32 + nf * 8 + laneBr) * PITCH
                                          + ks + laneBk) * 2;
                LDSM_X2(uh[nf][0], uh[nf][1], bUh + off);
                LDSM_X2(gh[nf][0], gh[nf][1], bGh + off);
            }
            #pragma unroll
            for (int mf = 0; mf < 4; mf++) {
                uint32_t off = (uint32_t)((wm * 64 + mf * 16 + laneAr) * PITCH
                                          + ks + laneAk) * 2;
                uint32_t ah[4], al[4];
                LDSM_X4(ah[0], ah[1], ah[2], ah[3], bAh + off);
                LDSM_X4(al[0], al[1], al[2], al[3], bAl + off);
                #pragma unroll
                for (int nf = 0; nf < 4; nf++) {
                    MMA16816(accU[mf][nf], ah, uh[nf]);
                    MMA16816(accU[mf][nf], al, uh[nf]);
                    MMA16816(accG[mf][nf], ah, gh[nf]);
                    MMA16816(accG[mf][nf], al, gh[nf]);
                }
            }
        }
        __syncthreads();
    }
    #pragma unroll
    for (int mf = 0; mf < 4; mf++) {
        int r = row0 + wm * 64 + mf * 16 + (lane >> 2);
        #pragma unroll
        for (int nf = 0; nf < 4; nf++) {
            int c = col0 + wn * 32 + nf * 8 + (lane & 3) * 2;
            #pragma unroll
            for (int half_ = 0; half_ < 2; half_++) {
                int rr = r + half_ * 8;
                float u0 = accU[mf][nf][half_ * 2], u1 = accU[mf][nf][half_ * 2 + 1];
                float gg0 = accG[mf][nf][half_ * 2], gg1 = accG[mf][nf][half_ * 2 + 1];
                float v0 = u0 * (gg0 / (1.f + expf(-gg0)));
                float v1 = u1 * (gg1 / (1.f + expf(-gg1)));
                __half h0 = __float2half_rn(v0), h1 = __float2half_rn(v1);
                __half l0 = __float2half_rn(v0 - __half2float(h0));
                __half l1 = __float2half_rn(v1 - __half2float(h1));
                *(__half2*)(Ih + (size_t)rr * INNER + c) = __halves2half2(h0, h1);
                *(__half2*)(Il + (size_t)rr * INNER + c) = __halves2half2(l0, l1);
            }
        }
    }
}
#define GLU_SMEM (2 * 4 * TILEB)    // 81920

// ----------------------------------------------------------------------------
// LN reduction helper (256 threads over D=768)
// ----------------------------------------------------------------------------
__device__ __forceinline__ void ln_stats(float v0, float v1, float v2,
                                         float* sa, float* sb2,
                                         float& mean, float& rinv)
{
    float s = v0 + v1 + v2;
    float q = v0 * v0 + v1 * v1 + v2 * v2;
    int tid = threadIdx.x;
    #pragma unroll
    for (int o = 16; o > 0; o >>= 1) {
        s += __shfl_down_sync(0xffffffffu, s, o);
        q += __shfl_down_sync(0xffffffffu, q, o);
    }
    int w = tid >> 5, l = tid & 31;
    if (l == 0) { sa[w] = s; sb2[w] = q; }
    __syncthreads();
    if (tid == 0) {
        float ts = 0.f, tq = 0.f;
        #pragma unroll
        for (int k = 0; k < 8; k++) { ts += sa[k]; tq += sb2[k]; }
        sa[0] = ts; sb2[0] = tq;
    }
    __syncthreads();
    mean = sa[0] * (1.0f / D);
    float var = sb2[0] * (1.0f / D) - mean * mean;
    rinv = rsqrtf(var + 1e-5f);
    __syncthreads();
}

// LN(x) -> fp16 hi/lo
__global__ __launch_bounds__(256)
void ln_split_kernel(const float* __restrict__ in,
                     __half* __restrict__ oh, __half* __restrict__ ol,
                     const float* __restrict__ gamma, const float* __restrict__ beta)
{
    int row = blockIdx.x, tid = threadIdx.x;
    const float* x = in + (size_t)row * D;
    float v[3] = {x[tid], x[tid + 256], x[tid + 512]};
    __shared__ float sa[8], sb2[8];
    float mean, r;
    ln_stats(v[0], v[1], v[2], sa, sb2, mean, r);
    #pragma unroll
    for (int e = 0; e < 3; e++) {
        int idx = tid + e * 256;
        float y = (v[e] - mean) * r * gamma[idx] + beta[idx];
        __half hb = __float2half_rn(y);
        oh[(size_t)row * D + idx] = hb;
        ol[(size_t)row * D + idx] = __float2half_rn(y - __half2float(hb));
    }
}

// h = LN_a(slots + upd) -> hb(fp32);  LN_b(h) -> oh/ol(hi/lo)
__global__ __launch_bounds__(256)
void ln_dual_kernel(const float* __restrict__ slots, const float* __restrict__ upd,
                    float* __restrict__ hb,
                    const float* __restrict__ g1, const float* __restrict__ b1,
                    const float* __restrict__ g2, const float* __restrict__ b2,
                    __half* __restrict__ oh, __half* __restrict__ ol)
{
    int row = blockIdx.x, tid = threadIdx.x;
    const float* xs = slots + (size_t)row * D;
    const float* xu = upd + (size_t)row * D;
    float v[3];
    #pragma unroll
    for (int e = 0; e < 3; e++) v[e] = xs[tid + e * 256] + xu[tid + e * 256];
    __shared__ float sa[8], sb2[8];
    float mean, r;
    ln_stats(v[0], v[1], v[2], sa, sb2, mean, r);
    float y[3];
    #pragma unroll
    for (int e = 0; e < 3; e++) {
        int idx = tid + e * 256;
        y[e] = (v[e] - mean) * r * g1[idx] + b1[idx];
        hb[(size_t)row * D + idx] = y[e];
    }
    float mean2, r2;
    ln_stats(y[0], y[1], y[2], sa, sb2, mean2, r2);
    #pragma unroll
    for (int e = 0; e < 3; e++) {
        int idx = tid + e * 256;
        float z = (y[e] - mean2) * r2 * g2[idx] + b2[idx];
        __half hh = __float2half_rn(z);
        oh[(size_t)row * D + idx] = hh;
        ol[(size_t)row * D + idx] = __float2half_rn(z - __half2float(hh));
    }
}

// h = res + sum_{sp<4} part[sp]; res <- h; LN(h) -> oh/ol
__global__ __launch_bounds__(256)
void ln_split_red_kernel(const float* __restrict__ part, float* __restrict__ res,
                         const float* __restrict__ gamma, const float* __restrict__ beta,
                         __half* __restrict__ oh, __half* __restrict__ ol)
{
    int row = blockIdx.x, tid = threadIdx.x;
    float v[3];
    #pragma unroll
    for (int e = 0; e < 3; e++) {
        int idx = tid + e * 256;
        size_t o = (size_t)row * D + idx;
        float s = res[o];
        #pragma unroll
        for (int sp = 0; sp < 4; sp++) s += part[(size_t)sp * MS * D + o];
        v[e] = s;
        res[o] = s;
    }
    __shared__ float sa[8], sb2[8];
    float mean, r;
    ln_stats(v[0], v[1], v[2], sa, sb2, mean, r);
    #pragma unroll
    for (int e = 0; e < 3; e++) {
        int idx = tid + e * 256;
        float y = (v[e] - mean) * r * gamma[idx] + beta[idx];
        __half hb = __float2half_rn(y);
        oh[(size_t)row * D + idx] = hb;
        ol[(size_t)row * D + idx] = __float2half_rn(y - __half2float(hb));
    }
}

// h = res + sum part; slots = LN_f(h);  LN_s(slots) -> qn hi/lo (next step)
__global__ __launch_bounds__(256)
void ln_red_dual_kernel(const float* __restrict__ part, const float* __restrict__ res,
                        float* __restrict__ slots,
                        const float* __restrict__ gf, const float* __restrict__ bf,
                        const float* __restrict__ gs, const float* __restrict__ bs,
                        __half* __restrict__ qh, __half* __restrict__ ql)
{
    int row = blockIdx.x, tid = threadIdx.x;
    float v[3];
    #pragma unroll
    for (int e = 0; e < 3; e++) {
        int idx = tid + e * 256;
        size_t o = (size_t)row * D + idx;
        float s = res[o];
        #pragma unroll
        for (int sp = 0; sp < 4; sp++) s += part[(size_t)sp * MS * D + o];
        v[e] = s;
    }
    __shared__ float sa[8], sb2[8];
    float mean, r;
    ln_stats(v[0], v[1], v[2], sa, sb2, mean, r);
    float y[3];
    #pragma unroll
    for (int e = 0; e < 3; e++) {
        int idx = tid + e * 256;
        y[e] = (v[e] - mean) * r * gf[idx] + bf[idx];
        slots[(size_t)row * D + idx] = y[e];
    }
    float mean2, r2;
    ln_stats(y[0], y[1], y[2], sa, sb2, mean2, r2);
    #pragma unroll
    for (int e = 0; e < 3; e++) {
        int idx = tid + e * 256;
        float z = (y[e] - mean2) * r2 * gs[idx] + bs[idx];
        __half hh = __float2half_rn(z);
        qh[(size_t)row * D + idx] = hh;
        ql[(size_t)row * D + idx] = __float2half_rn(z - __half2float(hh));
    }
}

// transpose + fp16 split (hi only)
__global__ __launch_bounds__(256)
void wsplit_kernel(const float* __restrict__ W,
                   __half* __restrict__ Th,
                   int Krows, int Ncols, int n_off)
{
    __shared__ float tile[32][33];
    int n0 = blockIdx.x * 32, k0 = blockIdx.y * 32;
    int t = threadIdx.x;
    int tx = t & 31, ty = t >> 5;
    #pragma unroll
    for (int i = 0; i < 4; i++)
        tile[ty + i * 8][tx] = W[(size_t)(k0 + ty + i * 8) * Ncols + n0 + tx];
    __syncthreads();
    #pragma unroll
    for (int i = 0; i < 4; i++) {
        int n = n_off + n0 + ty + i * 8;
        float v = tile[tx][ty + i * 8];
        Th[(size_t)n * Krows + k0 + tx] = __float2half_rn(v);
    }
}

__global__ void init_slots_kernel(const float* __restrict__ noise,
                                  const float* __restrict__ mu,
                                  const float* __restrict__ ls,
                                  float* __restrict__ slots)
{
    int t = blockIdx.x * blockDim.x + threadIdx.x;
    if (t >= MS * D) return;
    int d = t % D;
    slots[t] = mu[d] + expf(ls[d]) * noise[t];
}

// ----------------------------------------------------------------------------
// dots + softmax over the slot axis; reads Wq split-K partials directly
// ----------------------------------------------------------------------------
__global__ __launch_bounds__(256)
void dots_softmax_kernel(const float* __restrict__ Qpart, const float* __restrict__ Kb,
                         float* __restrict__ attn)
{
    int b  = blockIdx.y;
    int j0 = blockIdx.x * 64;
    __shared__ __align__(16) float qs[16][64];
    __shared__ float ks[64][65];
    __shared__ float red[4][64];
    int tid = threadIdx.x;
    int tx = tid & 63, ty = tid >> 6;
    float acc[4] = {0.f, 0.f, 0.f, 0.f};
    const float* Kp = Kb + ((size_t)b * NK + j0) * D;
    for (int k0 = 0; k0 < D; k0 += 64) {
        {
            int i = tid >> 4, kc = (tid & 15) * 4;
            size_t o = ((size_t)b * S + i) * D + k0 + kc;
            float4 v = *(const float4*)&Qpart[o];
            #pragma unroll
            for (int sp = 1; sp < 4; sp++) {
                float4 w = *(const float4*)&Qpart[(size_t)sp * MS * D + o];
                v.x += w.x; v.y += w.y; v.z += w.z; v.w += w.w;
            }
            *(float4*)&qs[i][kc] = v;
        }
        #pragma unroll
        for (int p = 0; p < 4; p++) {
            int e = tid + p * 256;
            int jj = e >> 4, kc = (e & 15) * 4;
            float4 v = *(const float4*)&Kp[(size_t)jj * D + k0 + kc];
            ks[jj][kc + 0] = v.x; ks[jj][kc + 1] = v.y;
            ks[jj][kc + 2] = v.z; ks[jj][kc + 3] = v.w;
        }
        __syncthreads();
        #pragma unroll
        for (int kk = 0; kk < 64; kk++) {
            float kv = ks[tx][kk];
            acc[0] += qs[ty     ][kk] * kv;
            acc[1] += qs[ty +  4][kk] * kv;
            acc[2] += qs[ty +  8][kk] * kv;
            acc[3] += qs[ty + 12][kk] * kv;
        }
        __syncthreads();
    }
    #pragma unroll
    for (int r = 0; r < 4; r++) acc[r] *= kSCALE;
    float m = fmaxf(fmaxf(acc[0], acc[1]), fmaxf(acc[2], acc[3]));
    red[ty][tx] = m;
    __syncthreads();
    float M = fmaxf(fmaxf(red[0][tx], red[1][tx]), fmaxf(red[2][tx], red[3][tx]));
    __syncthreads();
    float e[4]; float s = 0.f;
    #pragma unroll
    for (int r = 0; r < 4; r++) { e[r] = expf(acc[r] - M); s += e[r]; }
    red[ty][tx] = s;
    __syncthreads();
    float Ssum = red[0][tx] + red[1][tx] + red[2][tx] + red[3][tx];
    float inv = 1.f / Ssum;
    #pragma unroll
    for (int r = 0; r < 4; r++)
        attn[((size_t)b * S + ty + r * 4) * NK + j0 + tx] = e[r] * inv + 1e-8f;
}

// updates[b,i,n] = (sum_j attn * v) / (sum_j attn)
__global__ __launch_bounds__(256)
void updates_kernel(const float* __restrict__ attn, const float* __restrict__ V,
                    float* __restrict__ upd)
{
    int b  = blockIdx.y;
    int n0 = blockIdx.x * 64;
    __shared__ __align__(16) float as_[16][64];
    __shared__ __align__(16) float vs[64][64];
    int tid = threadIdx.x;
    int tx = tid & 63, ty = tid >> 6;
    float acc[4] = {0.f, 0.f, 0.f, 0.f};
    float ssum[4] = {0.f, 0.f, 0.f, 0.f};
    for (int j0 = 0; j0 < NK; j0 += 64) {
        {
            int i = tid >> 4, jc = (tid & 15) * 4;
            *(float4*)&as_[i][jc] =
                *(const float4*)&attn[((size_t)b * S + i) * NK + j0 + jc];
        }
        #pragma unroll
        for (int p = 0; p < 4; p++) {
            int e = tid + p * 256;
            int jj = e >> 4, nc = (e & 15) * 4;
            *(float4*)&vs[jj][nc] =
                *(const float4*)&V[((size_t)b * NK + j0 + jj) * D + n0 + nc];
        }
        __syncthreads();
        #pragma unroll
        for (int jj = 0; jj < 64; jj++) {
            float vv = vs[jj][tx];
            float a0 = as_[ty][jj], a1 = as_[ty + 4][jj];
            float a2 = as_[ty + 8][jj], a3 = as_[ty + 12][jj];
            acc[0] += a0 * vv;  ssum[0] += a0;
            acc[1] += a1 * vv;  ssum[1] += a1;
            acc[2] += a2 * vv;  ssum[2] += a2;
            acc[3] += a3 * vv;  ssum[3] += a3;
        }
        __syncthreads();
    }
    #pragma unroll
    for (int r = 0; r < 4; r++)
        upd[((size_t)b * S + ty + r * 4) * D + n0 + tx] = acc[r] / ssum[r];
}

// encoder self-attention; reads QKV split-K partials directly
__global__ __launch_bounds__(256)
void enc_attn_kernel(const float* __restrict__ QKVpart,
                     __half* __restrict__ Oh, __half* __restrict__ Ol)
{
    int b = blockIdx.x >> 3, h = blockIdx.x & 7;
    __shared__ float qs[16][65], ks[16][65], vs[16][65];
    __shared__ float p[16][17];
    int tid = threadIdx.x;
    int i = tid >> 4, jj = tid & 15;
    {
        int r = tid >> 4, c = (tid & 15) * 4;
        size_t base = ((size_t)b * S + r) * QKV3 + h * DH + c;
        float4 vq = *(const float4*)&QKVpart[base];
        float4 vk = *(const float4*)&QKVpart[base + HD];
        float4 vv = *(const float4*)&QKVpart[base + 2 * HD];
        #pragma unroll
        for (int sp = 1; sp < 4; sp++) {
            size_t o = (size_t)sp * MS * QKV3 + base;
            float4 w;
            w = *(const float4*)&QKVpart[o];
            vq.x += w.x; vq.y += w.y; vq.z += w.z; vq.w += w.w;
            w = *(const float4*)&QKVpart[o + HD];
            vk.x += w.x; vk.y += w.y; vk.z += w.z; vk.w += w.w;
            w = *(const float4*)&QKVpart[o + 2 * HD];
            vv.x += w.x; vv.y += w.y; vv.z += w.z; vv.w += w.w;
        }
        qs[r][c] = vq.x; qs[r][c+1] = vq.y; qs[r][c+2] = vq.z; qs[r][c+3] = vq.w;
        ks[r][c] = vk.x; ks[r][c+1] = vk.y; ks[r][c+2] = vk.z; ks[r][c+3] = vk.w;
        vs[r][c] = vv.x; vs[r][c+1] = vv.y; vs[r][c+2] = vv.z; vs[r][c+3] = vv.w;
    }
    __syncthreads();
    float s = 0.f;
    #pragma unroll
    for (int d = 0; d < DH; d++) s += qs[i][d] * ks[jj][d];
    s *= 0.125f;
    p[i][jj] = s;
    __syncthreads();
    float m = -1e30f;
    #pragma unroll
    for (int t2 = 0; t2 < 16; t2++) m = fmaxf(m, p[i][t2]);
    __syncthreads();
    float e = expf(s - m);
    p[i][jj] = e;
    __syncthreads();
    float sum = 0.f;
    #pragma unroll
    for (int t2 = 0; t2 < 16; t2++) sum += p[i][t2];
    __syncthreads();
    p[i][jj] = e / sum;
    __syncthreads();
    int io = tid >> 4, dbase = (tid & 15) * 4;
    float o[4] = {0.f, 0.f, 0.f, 0.f};
    #pragma unroll
    for (int t2 = 0; t2 < 16; t2++) {
        float pp = p[io][t2];
        o[0] += pp * vs[t2][dbase + 0];
        o[1] += pp * vs[t2][dbase + 1];
        o[2] += pp * vs[t2][dbase + 2];
        o[3] += pp * vs[t2][dbase + 3];
    }
    size_t base = ((size_t)b * S + io) * HD + h * DH + dbase;
    #pragma unroll
    for (int c = 0; c < 4; c++) {
        __half hb = __float2half_rn(o[c]);
        Oh[base + c] = hb;
        Ol[base + c] = __float2half_rn(o[c] - __half2float(hb));
    }
}

// output map: per (b,i) row — sum over keys then write out[b][j][i] = attn/sum
__global__ __launch_bounds__(256)
void attn_out_kernel(const float* __restrict__ attn, float* __restrict__ out)
{
    int row = blockIdx.x;            // b*S + i
    int b = row >> 4, i = row & 15;
    const float4* p = (const float4*)(attn + (size_t)row * NK);
    int tid = threadIdx.x;
    float4 v = p[tid];
    float s = v.x + v.y + v.z + v.w;
    __shared__ float sa[8];
    #pragma unroll
    for (int o = 16; o > 0; o >>= 1) s += __shfl_down_sync(0xffffffffu, s, o);
    int w = tid >> 5, l = tid & 31;
    if (l == 0) sa[w] = s;
    __syncthreads();
    if (tid == 0) {
        float ts = 0.f;
        #pragma unroll
        for (int k = 0; k < 8; k++) ts += sa[k];
        sa[0] = ts;
    }
    __syncthreads();
    float inv = 1.f / sa[0];
    size_t ob = (size_t)b * NK * S + i;
    int j = tid * 4;
    out[ob + (size_t)(j + 0) * S] = v.x * inv;
    out[ob + (size_t)(j + 1) * S] = v.y * inv;
    out[ob + (size_t)(j + 2) * S] = v.z * inv;
    out[ob + (size_t)(j + 3) * S] = v.w * inv;
}

// ----------------------------------------------------------------------------
// Host orchestration
// ----------------------------------------------------------------------------
extern "C" void kernel_launch(void* const* d_in, const int* in_sizes, int n_in,
                              void* d_out, int out_size)
{
    const float* x       = (const float*)d_in[0];
    const float* noise   = (const float*)d_in[1];
    const float* init_mu = (const float*)d_in[2];
    const float* init_ls = (const float*)d_in[3];
    const float* Wk      = (const float*)d_in[4];
    const float* Wv      = (const float*)d_in[5];
    const float* Wq      = (const float*)d_in[6];
    const float* ni_g    = (const float*)d_in[7];
    const float* ni_b    = (const float*)d_in[8];
    const float* ns_g    = (const float*)d_in[9];
    const float* ns_b    = (const float*)d_in[10];
    const float* nica_g  = (const float*)d_in[11];
    const float* nica_b  = (const float*)d_in[12];
    const float* ln1_g   = (const float*)d_in[13];
    const float* ln1_b   = (const float*)d_in[14];
    const float* Wq_a    = (const float*)d_in[15];
    const float* Wk_a    = (const float*)d_in[16];
    const float* Wv_a    = (const float*)d_in[17];
    const float* Wo_a    = (const float*)d_in[18];
    const float* ln2_g   = (const float*)d_in[19];
    const float* ln2_b   = (const float*)d_in[20];
    const float* W1      = (const float*)d_in[21];
    const float* W2      = (const float*)d_in[22];
    const float* lnf_g   = (const float*)d_in[23];
    const float* lnf_b   = (const float*)d_in[24];

    __half *xnh, *xnl, *wkh, *wvh, *wqh;
    __half *wqkh, *woh, *w1h, *w2h;
    __half *qnh, *qnl, *abh, *abl, *fbh, *fbl, *innh, *innl, *oah, *oal;
    float *kb, *vb, *slots, *attn, *upd, *hb, *part;
    cudaGetSymbolAddress((void**)&xnh,  g_xnh);  cudaGetSymbolAddress((void**)&xnl,  g_xnl);
    cudaGetSymbolAddress((void**)&wkh,  g_wkh);
    cudaGetSymbolAddress((void**)&wvh,  g_wvh);
    cudaGetSymbolAddress((void**)&wqh,  g_wqh);
    cudaGetSymbolAddress((void**)&wqkh, g_wqkh);
    cudaGetSymbolAddress((void**)&woh,  g_woh);
    cudaGetSymbolAddress((void**)&w1h,  g_w1h);
    cudaGetSymbolAddress((void**)&w2h,  g_w2h);
    cudaGetSymbolAddress((void**)&qnh,  g_qnh);  cudaGetSymbolAddress((void**)&qnl,  g_qnl);
    cudaGetSymbolAddress((void**)&abh,  g_abh);  cudaGetSymbolAddress((void**)&abl,  g_abl);
    cudaGetSymbolAddress((void**)&fbh,  g_fbh);  cudaGetSymbolAddress((void**)&fbl,  g_fbl);
    cudaGetSymbolAddress((void**)&innh, g_innh); cudaGetSymbolAddress((void**)&innl, g_innl);
    cudaGetSymbolAddress((void**)&oah,  g_oah);  cudaGetSymbolAddress((void**)&oal,  g_oal);
    cudaGetSymbolAddress((void**)&kb,   g_k);
    cudaGetSymbolAddress((void**)&vb,   g_v);
    cudaGetSymbolAddress((void**)&slots,g_slots);
    cudaGetSymbolAddress((void**)&attn, g_attn);
    cudaGetSymbolAddress((void**)&upd,  g_upd);
    cudaGetSymbolAddress((void**)&hb,   g_h);
    cudaGetSymbolAddress((void**)&part, g_part);

    cudaFuncSetAttribute(hgemm_hilo, cudaFuncAttributeMaxDynamicSharedMemorySize, HG_SMEM);
    cudaFuncSetAttribute(hgemm_dual, cudaFuncAttributeMaxDynamicSharedMemorySize, DUAL_SMEM);
    cudaFuncSetAttribute(hgemm_glu,  cudaFuncAttributeMaxDynamicSharedMemorySize, GLU_SMEM);

    // ---- precompute ----
    wsplit_kernel<<<dim3(D / 32, D / 32), 256>>>(Wk, wkh, D, D, 0);
    wsplit_kernel<<<dim3(D / 32, D / 32), 256>>>(Wv, wvh, D, D, 0);
    ln_split_kernel<<<B * NK, 256>>>(x, xnh, xnl, ni_g, ni_b);
    init_slots_kernel<<<(MS * D + 255) / 256, 256>>>(noise, init_mu, init_ls, slots);
    wsplit_kernel<<<dim3(D / 32, D / 32), 256>>>(Wq, wqh, D, D, 0);
    hgemm_dual<<<dim3(D / 128, (B * NK) / 128), 256, DUAL_SMEM>>>(
        xnh, xnl, wkh, wvh, kb, vb, B * NK, D, D);
    wsplit_kernel<<<dim3(HD / 32, D / 32), 256>>>(Wq_a, wqkh, D, HD, 0);
    wsplit_kernel<<<dim3(HD / 32, D / 32), 256>>>(Wk_a, wqkh, D, HD, HD);
    wsplit_kernel<<<dim3(HD / 32, D / 32), 256>>>(Wv_a, wqkh, D, HD, 2 * HD);
    wsplit_kernel<<<dim3(D / 32, HD / 32), 256>>>(Wo_a, woh, HD, D, 0);
    wsplit_kernel<<<dim3((2 * INNER) / 32, D / 32), 256>>>(W1, w1h, D, 2 * INNER, 0);
    wsplit_kernel<<<dim3(D / 32, INNER / 32), 256>>>(W2, w2h, INNER, D, 0);
    ln_split_kernel<<<MS, 256>>>(slots, qnh, qnl, ns_g, ns_b);

    // ---- 4 slot-attention steps (11 launches each) ----
    for (int it = 0; it < N_STEPS; it++) {
        hgemm_hilo<<<dim3(D / 128, MS / 128, 4), 256, HG_SMEM>>>(qnh, qnl, wqh,
                                                                 part, MS, D, D);
        dots_softmax_kernel<<<dim3(NK / 64, B), 256>>>(part, kb, attn);
        updates_kernel<<<dim3(D / 64, B), 256>>>(attn, vb, upd);
        ln_dual_kernel<<<MS, 256>>>(slots, upd, hb, nica_g, nica_b,
                                    ln1_g, ln1_b, abh, abl);
        hgemm_hilo<<<dim3(QKV3 / 128, MS / 128, 4), 256, HG_SMEM>>>(abh, abl, wqkh,
                                                                    part, MS, QKV3, D);
        enc_attn_kernel<<<B * H, 256>>>(part, oah, oal);
        hgemm_hilo<<<dim3(D / 128, MS / 128, 4), 256, HG_SMEM>>>(oah, oal, woh,
                                                                 part, MS, D, HD);
        ln_split_red_kernel<<<MS, 256>>>(part, hb, ln2_g, ln2_b, fbh, fbl);
        hgemm_glu<<<dim3(INNER / 128, MS / 128), 256, GLU_SMEM>>>(fbh, fbl, w1h,
                                                                  innh, innl, MS);
        hgemm_hilo<<<dim3(D / 128, MS / 128, 4), 256, HG_SMEM>>>(innh, innl, w2h,
                                                                 part, MS, D, INNER);
        ln_red_dual_kernel<<<MS, 256>>>(part, hb, slots, lnf_g, lnf_b,
                                        ns_g, ns_b, qnh, qnl);
    }

    // ---- outputs: slots [32,16,768], then attn_map [32,1024,16] ----
    float* out = (float*)d_out;
    cudaMemcpyAsync(out, slots, (size_t)MS * D * sizeof(float),
                    cudaMemcpyDeviceToDevice);
    attn_out_kernel<<<MS, 256>>>(attn, out + (size_t)MS * D);
}

// round 12
// speedup vs baseline: 1.5235x; 1.1369x over previous
#include <cuda_runtime.h>
#include <cuda_fp16.h>
#include <math.h>
#include <stdint.h>

// ----------------------------------------------------------------------------
// Problem constants
// ----------------------------------------------------------------------------
#define B   32
#define NK  1024
#define S   16
#define D   768
#define H   8
#define DH  64
#define HD  (H*DH)    // 512
#define QKV3 (3*HD)   // 1536
#define INNER 3072
#define N_STEPS 4
#define MS  (B*S)     // 512
static __device__ __constant__ float kSCALE = 0.036084391824351615f;  // 768^-0.5

// ----------------------------------------------------------------------------
// Scratch (device globals)
// ----------------------------------------------------------------------------
__device__ __half g_xnh[B*NK*D];
__device__ __half g_wkh [D*D];
__device__ __half g_wvh [D*D];
__device__ __half g_wqh [D*D];
__device__ __half g_wqkh[QKV3*D];
__device__ __half g_woh [D*HD];
__device__ __half g_w1h [2*INNER*D];
__device__ __half g_w2h [D*INNER];
__device__ __half g_qnh[MS*D],   g_qnl[MS*D];
__device__ __half g_abh[MS*D],   g_abl[MS*D];
__device__ __half g_fbh[MS*D],   g_fbl[MS*D];
__device__ __half g_innh[MS*INNER], g_innl[MS*INNER];
__device__ __half g_oah[MS*HD],  g_oal[MS*HD];
__device__ float g_k    [B*NK*D];
__device__ float g_v    [B*NK*D];
__device__ float g_slots[MS*D];
__device__ float g_attn [MS*NK];
__device__ float g_upd  [MS*D];
__device__ float g_h    [MS*D];
__device__ float g_part [4*MS*QKV3];

// ----------------------------------------------------------------------------
// HMMA / cp.async helpers (baseline PTX — compiles for plain compute_103)
// ----------------------------------------------------------------------------
__device__ __forceinline__ uint32_t smem_u32(const void* p) {
    uint32_t a;
    asm("{ .reg .u64 t; cvta.to.shared.u64 t, %1; cvt.u32.u64 %0, t; }"
        : "=r"(a) : "l"(p));
    return a;
}
#define LDSM_X4(r0, r1, r2, r3, addr) \
    asm volatile("ldmatrix.sync.aligned.m8n8.x4.shared.b16 {%0,%1,%2,%3}, [%4];" \
                 : "=r"(r0), "=r"(r1), "=r"(r2), "=r"(r3) : "r"(addr))
#define LDSM_X2(r0, r1, addr) \
    asm volatile("ldmatrix.sync.aligned.m8n8.x2.shared.b16 {%0,%1}, [%2];" \
                 : "=r"(r0), "=r"(r1) : "r"(addr))
#define MMA16816(c, a, b) \
    asm volatile("mma.sync.aligned.m16n8k16.row.col.f32.f16.f16.f32 " \
                 "{%0,%1,%2,%3}, {%4,%5,%6,%7}, {%8,%9}, {%0,%1,%2,%3};" \
                 : "+f"((c)[0]), "+f"((c)[1]), "+f"((c)[2]), "+f"((c)[3]) \
                 : "r"((a)[0]), "r"((a)[1]), "r"((a)[2]), "r"((a)[3]), \
                   "r"((b)[0]), "r"((b)[1]))
#define CP_ASYNC16(dst_u32, src_ptr) \
    asm volatile("cp.async.ca.shared.global [%0], [%1], 16;" \
                 :: "r"(dst_u32), "l"(src_ptr))
#define CP_COMMIT() asm volatile("cp.async.commit_group;" ::: "memory")
#define CP_WAIT(n)  asm volatile("cp.async.wait_group %0;" :: "n"(n) : "memory")

#define PITCH 40            // halves per smem row (80 B) — conflict-free ldmatrix
#define TILEH (128 * PITCH) // halves per tile
#define TILEB (TILEH * 2)   // bytes per tile

// ----------------------------------------------------------------------------
// fp16 A-corrected HMMA GEMM (C = Ah·Bh + Al·Bh), split-K, 2-stage cp.async.
// ----------------------------------------------------------------------------
__global__ __launch_bounds__(256)
void hgemm_hilo(const __half* __restrict__ Ah, const __half* __restrict__ Al,
                const __half* __restrict__ Bth,
                float* __restrict__ C, int M, int N, int K)
{
    extern __shared__ __align__(16) __half dyn[];
    int tid = threadIdx.x;
    int lane = tid & 31, wid = tid >> 5;
    int wm = wid >> 2, wn = wid & 3;
    int row0 = blockIdx.y * 128, col0 = blockIdx.x * 128;
    int kb   = K / gridDim.z;
    int kbeg = blockIdx.z * kb;
    float* Cz = C + (size_t)blockIdx.z * M * N;
    int nchunk = kb / 32;

    uint32_t base = smem_u32(dyn);

    float acc[4][4][4];
    #pragma unroll
    for (int mf = 0; mf < 4; mf++)
        #pragma unroll
        for (int nf = 0; nf < 4; nf++)
            #pragma unroll
            for (int e = 0; e < 4; e++) acc[mf][nf][e] = 0.f;

    int laneAr = lane & 15, laneAk = (lane & 16) ? 8 : 0;
    int laneBr = lane & 7,  laneBk = (lane & 8)  ? 8 : 0;

    auto load_stage = [&](int c, int s) {
        uint32_t sb = base + (uint32_t)s * 3 * TILEB;
        #pragma unroll
        for (int i = 0; i < 2; i++) {
            int idx = tid + i * 256;
            int row = idx >> 2, sg = idx & 3;
            size_t ga = (size_t)(row0 + row) * K + kbeg + c * 32 + sg * 8;
            size_t gb = (size_t)(col0 + row) * K + kbeg + c * 32 + sg * 8;
            uint32_t so = (uint32_t)(row * PITCH + sg * 8) * 2;
            CP_ASYNC16(sb + 0 * TILEB + so, Ah + ga);
            CP_ASYNC16(sb + 1 * TILEB + so, Al + ga);
            CP_ASYNC16(sb + 2 * TILEB + so, Bth + gb);
        }
    };

    load_stage(0, 0);
    CP_COMMIT();
    for (int c = 0; c < nchunk; c++) {
        int s = c & 1;
        if (c + 1 < nchunk) { load_stage(c + 1, s ^ 1); CP_COMMIT(); CP_WAIT(1); }
        else                { CP_WAIT(0); }
        __syncthreads();
        uint32_t bAh = base + (uint32_t)s * 3 * TILEB;
        uint32_t bAl = bAh + TILEB;
        uint32_t bBh = bAl + TILEB;
        #pragma unroll
        for (int ks = 0; ks < 32; ks += 16) {
            uint32_t bh[4][2];
            #pragma unroll
            for (int nf = 0; nf < 4; nf++) {
                uint32_t off = (uint32_t)((wn * 32 + nf * 8 + laneBr) * PITCH
                                          + ks + laneBk) * 2;
                LDSM_X2(bh[nf][0], bh[nf][1], bBh + off);
            }
            #pragma unroll
            for (int mf = 0; mf < 4; mf++) {
                uint32_t off = (uint32_t)((wm * 64 + mf * 16 + laneAr) * PITCH
                                          + ks + laneAk) * 2;
                uint32_t ah[4], al[4];
                LDSM_X4(ah[0], ah[1], ah[2], ah[3], bAh + off);
                LDSM_X4(al[0], al[1], al[2], al[3], bAl + off);
                #pragma unroll
                for (int nf = 0; nf < 4; nf++) {
                    MMA16816(acc[mf][nf], ah, bh[nf]);
                    MMA16816(acc[mf][nf], al, bh[nf]);
                }
            }
        }
        __syncthreads();
    }
    #pragma unroll
    for (int mf = 0; mf < 4; mf++) {
        int r = row0 + wm * 64 + mf * 16 + (lane >> 2);
        #pragma unroll
        for (int nf = 0; nf < 4; nf++) {
            int c = col0 + wn * 32 + nf * 8 + (lane & 3) * 2;
            *(float2*)(Cz + (size_t)r * N + c) =
                make_float2(acc[mf][nf][0], acc[mf][nf][1]);
            *(float2*)(Cz + (size_t)(r + 8) * N + c) =
                make_float2(acc[mf][nf][2], acc[mf][nf][3]);
        }
    }
}
#define HG_SMEM (2 * 3 * TILEB)     // 61440

// ----------------------------------------------------------------------------
// Dual-output projection (K/V), pure fp16 (C = Ah·Bh), 2-stage pipelined.
// ----------------------------------------------------------------------------
__global__ __launch_bounds__(256)
void hgemm_dual(const __half* __restrict__ Ah,
                const __half* __restrict__ Bkh, const __half* __restrict__ Bvh,
                float* __restrict__ Ck, float* __restrict__ Cv,
                int M, int N, int K)
{
    extern __shared__ __align__(16) __half dyn[];
    int tid = threadIdx.x;
    int lane = tid & 31, wid = tid >> 5;
    int wm = wid >> 2, wn = wid & 3;
    int row0 = blockIdx.y * 128, col0 = blockIdx.x * 128;
    int nchunk = K / 32;
    uint32_t base = smem_u32(dyn);

    float accK[4][4][4], accV[4][4][4];
    #pragma unroll
    for (int mf = 0; mf < 4; mf++)
        #pragma unroll
        for (int nf = 0; nf < 4; nf++)
            #pragma unroll
            for (int e = 0; e < 4; e++) { accK[mf][nf][e] = 0.f; accV[mf][nf][e] = 0.f; }

    int laneAr = lane & 15, laneAk = (lane & 16) ? 8 : 0;
    int laneBr = lane & 7,  laneBk = (lane & 8)  ? 8 : 0;

    auto load_stage = [&](int c, int s) {
        uint32_t sb = base + (uint32_t)s * 3 * TILEB;
        #pragma unroll
        for (int i = 0; i < 2; i++) {
            int idx = tid + i * 256;
            int row = idx >> 2, sg = idx & 3;
            size_t ga = (size_t)(row0 + row) * K + c * 32 + sg * 8;
            size_t gb = (size_t)(col0 + row) * K + c * 32 + sg * 8;
            uint32_t so = (uint32_t)(row * PITCH + sg * 8) * 2;
            CP_ASYNC16(sb + 0 * TILEB + so, Ah + ga);
            CP_ASYNC16(sb + 1 * TILEB + so, Bkh + gb);
            CP_ASYNC16(sb + 2 * TILEB + so, Bvh + gb);
        }
    };

    load_stage(0, 0);
    CP_COMMIT();
    for (int c = 0; c < nchunk; c++) {
        int s = c & 1;
        if (c + 1 < nchunk) { load_stage(c + 1, s ^ 1); CP_COMMIT(); CP_WAIT(1); }
        else                { CP_WAIT(0); }
        __syncthreads();
        uint32_t bAh = base + (uint32_t)s * 3 * TILEB;
        uint32_t bKh = bAh + TILEB;
        uint32_t bVh = bKh + TILEB;
        #pragma unroll
        for (int ks = 0; ks < 32; ks += 16) {
            uint32_t kh[4][2], vh[4][2];
            #pragma unroll
            for (int nf = 0; nf < 4; nf++) {
                uint32_t off = (uint32_t)((wn * 32 + nf * 8 + laneBr) * PITCH
                                          + ks + laneBk) * 2;
                LDSM_X2(kh[nf][0], kh[nf][1], bKh + off);
                LDSM_X2(vh[nf][0], vh[nf][1], bVh + off);
            }
            #pragma unroll
            for (int mf = 0; mf < 4; mf++) {
                uint32_t off = (uint32_t)((wm * 64 + mf * 16 + laneAr) * PITCH
                                          + ks + laneAk) * 2;
                uint32_t ah[4];
                LDSM_X4(ah[0], ah[1], ah[2], ah[3], bAh + off);
                #pragma unroll
                for (int nf = 0; nf < 4; nf++) {
                    MMA16816(accK[mf][nf], ah, kh[nf]);
                    MMA16816(accV[mf][nf], ah, vh[nf]);
                }
            }
        }
        __syncthreads();
    }
    #pragma unroll
    for (int mf = 0; mf < 4; mf++) {
        int r = row0 + wm * 64 + mf * 16 + (lane >> 2);
        #pragma unroll
        for (int nf = 0; nf < 4; nf++) {
            int c = col0 + wn * 32 + nf * 8 + (lane & 3) * 2;
            *(float2*)(Ck + (size_t)r * N + c) =
                make_float2(accK[mf][nf][0], accK[mf][nf][1]);
            *(float2*)(Ck + (size_t)(r + 8) * N + c) =
                make_float2(accK[mf][nf][2], accK[mf][nf][3]);
            *(float2*)(Cv + (size_t)r * N + c) =
                make_float2(accV[mf][nf][0], accV[mf][nf][1]);
            *(float2*)(Cv + (size_t)(r + 8) * N + c) =
                make_float2(accV[mf][nf][2], accV[mf][nf][3]);
        }
    }
}
#define DUAL_SMEM (2 * 3 * TILEB)   // 61440

// ----------------------------------------------------------------------------
// W1 + GLU fused, A-corrected 2-term, 2-stage pipelined; emits u*silu(g) hi/lo.
// ----------------------------------------------------------------------------
__global__ __launch_bounds__(256)
void hgemm_glu(const __half* __restrict__ Ah, const __half* __restrict__ Al,
               const __half* __restrict__ W1th,
               __half* __restrict__ Ih, __half* __restrict__ Il, int M)
{
    extern __shared__ __align__(16) __half dyn[];
    int tid = threadIdx.x;
    int lane = tid & 31, wid = tid >> 5;
    int wm = wid >> 2, wn = wid & 3;
    int row0 = blockIdx.y * 128, col0 = blockIdx.x * 128;
    int nchunk = D / 32;
    uint32_t base = smem_u32(dyn);

    float accU[4][4][4], accG[4][4][4];
    #pragma unroll
    for (int mf = 0; mf < 4; mf++)
        #pragma unroll
        for (int nf = 0; nf < 4; nf++)
            #pragma unroll
            for (int e = 0; e < 4; e++) { accU[mf][nf][e] = 0.f; accG[mf][nf][e] = 0.f; }

    int laneAr = lane & 15, laneAk = (lane & 16) ? 8 : 0;
    int laneBr = lane & 7,  laneBk = (lane & 8)  ? 8 : 0;

    auto load_stage = [&](int c, int s) {
        uint32_t sb = base + (uint32_t)s * 4 * TILEB;
        #pragma unroll
        for (int i = 0; i < 2; i++) {
            int idx = tid + i * 256;
            int row = idx >> 2, sg = idx & 3;
            size_t ga = (size_t)(row0 + row) * D + c * 32 + sg * 8;
            size_t gu = (size_t)(col0 + row) * D + c * 32 + sg * 8;
            size_t gg = (size_t)(col0 + row + INNER) * D + c * 32 + sg * 8;
            uint32_t so = (uint32_t)(row * PITCH + sg * 8) * 2;
            CP_ASYNC16(sb + 0 * TILEB + so, Ah + ga);
            CP_ASYNC16(sb + 1 * TILEB + so, Al + ga);
            CP_ASYNC16(sb + 2 * TILEB + so, W1th + gu);
            CP_ASYNC16(sb + 3 * TILEB + so, W1th + gg);
        }
    };

    load_stage(0, 0);
    CP_COMMIT();
    for (int c = 0; c < nchunk; c++) {
        int s = c & 1;
        if (c + 1 < nchunk) { load_stage(c + 1, s ^ 1); CP_COMMIT(); CP_WAIT(1); }
        else                { CP_WAIT(0); }
        __syncthreads();
        uint32_t bAh = base + (uint32_t)s * 4 * TILEB;
        uint32_t bAl = bAh + TILEB;
        uint32_t bUh = bAl + TILEB;
        uint32_t bGh = bUh + TILEB;
        #pragma unroll
        for (int ks = 0; ks < 32; ks += 16) {
            uint32_t uh[4][2], gh[4][2];
            #pragma unroll
            for (int nf = 0; nf < 4; nf++) {
                uint32_t off = (uint32_t)((wn * 32 + nf * 8 + laneBr) * PITCH
                                          + ks + laneBk) * 2;
                LDSM_X2(uh[nf][0], uh[nf][1], bUh + off);
                LDSM_X2(gh[nf][0], gh[nf][1], bGh + off);
            }
            #pragma unroll
            for (int mf = 0; mf < 4; mf++) {
                uint32_t off = (uint32_t)((wm * 64 + mf * 16 + laneAr) * PITCH
                                          + ks + laneAk) * 2;
                uint32_t ah[4], al[4];
                LDSM_X4(ah[0], ah[1], ah[2], ah[3], bAh + off);
                LDSM_X4(al[0], al[1], al[2], al[3], bAl + off);
                #pragma unroll
                for (int nf = 0; nf < 4; nf++) {
                    MMA16816(accU[mf][nf], ah, uh[nf]);
                    MMA16816(accU[mf][nf], al, uh[nf]);
                    MMA16816(accG[mf][nf], ah, gh[nf]);
                    MMA16816(accG[mf][nf], al, gh[nf]);
                }
            }
        }
        __syncthreads();
    }
    #pragma unroll
    for (int mf = 0; mf < 4; mf++) {
        int r = row0 + wm * 64 + mf * 16 + (lane >> 2);
        #pragma unroll
        for (int nf = 0; nf < 4; nf++) {
            int c = col0 + wn * 32 + nf * 8 + (lane & 3) * 2;
            #pragma unroll
            for (int half_ = 0; half_ < 2; half_++) {
                int rr = r + half_ * 8;
                float u0 = accU[mf][nf][half_ * 2], u1 = accU[mf][nf][half_ * 2 + 1];
                float gg0 = accG[mf][nf][half_ * 2], gg1 = accG[mf][nf][half_ * 2 + 1];
                float v0 = u0 * (gg0 / (1.f + expf(-gg0)));
                float v1 = u1 * (gg1 / (1.f + expf(-gg1)));
                __half h0 = __float2half_rn(v0), h1 = __float2half_rn(v1);
                __half l0 = __float2half_rn(v0 - __half2float(h0));
                __half l1 = __float2half_rn(v1 - __half2float(h1));
                *(__half2*)(Ih + (size_t)rr * INNER + c) = __halves2half2(h0, h1);
                *(__half2*)(Il + (size_t)rr * INNER + c) = __halves2half2(l0, l1);
            }
        }
    }
}
#define GLU_SMEM (2 * 4 * TILEB)    // 81920

// ----------------------------------------------------------------------------
// LN reduction helper (256 threads over D=768)
// ----------------------------------------------------------------------------
__device__ __forceinline__ void ln_stats(float v0, float v1, float v2,
                                         float* sa, float* sb2,
                                         float& mean, float& rinv)
{
    float s = v0 + v1 + v2;
    float q = v0 * v0 + v1 * v1 + v2 * v2;
    int tid = threadIdx.x;
    #pragma unroll
    for (int o = 16; o > 0; o >>= 1) {
        s += __shfl_down_sync(0xffffffffu, s, o);
        q += __shfl_down_sync(0xffffffffu, q, o);
    }
    int w = tid >> 5, l = tid & 31;
    if (l == 0) { sa[w] = s; sb2[w] = q; }
    __syncthreads();
    if (tid == 0) {
        float ts = 0.f, tq = 0.f;
        #pragma unroll
        for (int k = 0; k < 8; k++) { ts += sa[k]; tq += sb2[k]; }
        sa[0] = ts; sb2[0] = tq;
    }
    __syncthreads();
    mean = sa[0] * (1.0f / D);
    float var = sb2[0] * (1.0f / D) - mean * mean;
    rinv = rsqrtf(var + 1e-5f);
    __syncthreads();
}

// LN(x) -> fp16 hi (+ optional lo)
__global__ __launch_bounds__(256)
void ln_split_kernel(const float* __restrict__ in,
                     __half* __restrict__ oh, __half* __restrict__ ol,
                     const float* __restrict__ gamma, const float* __restrict__ beta)
{
    int row = blockIdx.x, tid = threadIdx.x;
    const float* x = in + (size_t)row * D;
    float v[3] = {x[tid], x[tid + 256], x[tid + 512]};
    __shared__ float sa[8], sb2[8];
    float mean, r;
    ln_stats(v[0], v[1], v[2], sa, sb2, mean, r);
    #pragma unroll
    for (int e = 0; e < 3; e++) {
        int idx = tid + e * 256;
        float y = (v[e] - mean) * r * gamma[idx] + beta[idx];
        __half hb = __float2half_rn(y);
        oh[(size_t)row * D + idx] = hb;
        if (ol)
            ol[(size_t)row * D + idx] = __float2half_rn(y - __half2float(hb));
    }
}

// h = LN_a(slots + upd) -> hb(fp32);  LN_b(h) -> oh/ol(hi/lo)
__global__ __launch_bounds__(256)
void ln_dual_kernel(const float* __restrict__ slots, const float* __restrict__ upd,
                    float* __restrict__ hb,
                    const float* __restrict__ g1, const float* __restrict__ b1,
                    const float* __restrict__ g2, const float* __restrict__ b2,
                    __half* __restrict__ oh, __half* __restrict__ ol)
{
    int row = blockIdx.x, tid = threadIdx.x;
    const float* xs = slots + (size_t)row * D;
    const float* xu = upd + (size_t)row * D;
    float v[3];
    #pragma unroll
    for (int e = 0; e < 3; e++) v[e] = xs[tid + e * 256] + xu[tid + e * 256];
    __shared__ float sa[8], sb2[8];
    float mean, r;
    ln_stats(v[0], v[1], v[2], sa, sb2, mean, r);
    float y[3];
    #pragma unroll
    for (int e = 0; e < 3; e++) {
        int idx = tid + e * 256;
        y[e] = (v[e] - mean) * r * g1[idx] + b1[idx];
        hb[(size_t)row * D + idx] = y[e];
    }
    float mean2, r2;
    ln_stats(y[0], y[1], y[2], sa, sb2, mean2, r2);
    #pragma unroll
    for (int e = 0; e < 3; e++) {
        int idx = tid + e * 256;
        float z = (y[e] - mean2) * r2 * g2[idx] + b2[idx];
        __half hh = __float2half_rn(z);
        oh[(size_t)row * D + idx] = hh;
        ol[(size_t)row * D + idx] = __float2half_rn(z - __half2float(hh));
    }
}

// h = res + sum_{sp<4} part[sp]; res <- h; LN(h) -> oh/ol
__global__ __launch_bounds__(256)
void ln_split_red_kernel(const float* __restrict__ part, float* __restrict__ res,
                         const float* __restrict__ gamma, const float* __restrict__ beta,
                         __half* __restrict__ oh, __half* __restrict__ ol)
{
    int row = blockIdx.x, tid = threadIdx.x;
    float v[3];
    #pragma unroll
    for (int e = 0; e < 3; e++) {
        int idx = tid + e * 256;
        size_t o = (size_t)row * D + idx;
        float s = res[o];
        #pragma unroll
        for (int sp = 0; sp < 4; sp++) s += part[(size_t)sp * MS * D + o];
        v[e] = s;
        res[o] = s;
    }
    __shared__ float sa[8], sb2[8];
    float mean, r;
    ln_stats(v[0], v[1], v[2], sa, sb2, mean, r);
    #pragma unroll
    for (int e = 0; e < 3; e++) {
        int idx = tid + e * 256;
        float y = (v[e] - mean) * r * gamma[idx] + beta[idx];
        __half hb = __float2half_rn(y);
        oh[(size_t)row * D + idx] = hb;
        ol[(size_t)row * D + idx] = __float2half_rn(y - __half2float(hb));
    }
}

// h = res + sum part; slots = LN_f(h);  LN_s(slots) -> qn hi/lo (next step)
__global__ __launch_bounds__(256)
void ln_red_dual_kernel(const float* __restrict__ part, const float* __restrict__ res,
                        float* __restrict__ slots,
                        const float* __restrict__ gf, const float* __restrict__ bf,
                        const float* __restrict__ gs, const float* __restrict__ bs,
                        __half* __restrict__ qh, __half* __restrict__ ql)
{
    int row = blockIdx.x, tid = threadIdx.x;
    float v[3];
    #pragma unroll
    for (int e = 0; e < 3; e++) {
        int idx = tid + e * 256;
        size_t o = (size_t)row * D + idx;
        float s = res[o];
        #pragma unroll
        for (int sp = 0; sp < 4; sp++) s += part[(size_t)sp * MS * D + o];
        v[e] = s;
    }
    __shared__ float sa[8], sb2[8];
    float mean, r;
    ln_stats(v[0], v[1], v[2], sa, sb2, mean, r);
    float y[3];
    #pragma unroll
    for (int e = 0; e < 3; e++) {
        int idx = tid + e * 256;
        y[e] = (v[e] - mean) * r * gf[idx] + bf[idx];
        slots[(size_t)row * D + idx] = y[e];
    }
    float mean2, r2;
    ln_stats(y[0], y[1], y[2], sa, sb2, mean2, r2);
    #pragma unroll
    for (int e = 0; e < 3; e++) {
        int idx = tid + e * 256;
        float z = (y[e] - mean2) * r2 * gs[idx] + bs[idx];
        __half hh = __float2half_rn(z);
        qh[(size_t)row * D + idx] = hh;
        ql[(size_t)row * D + idx] = __float2half_rn(z - __half2float(hh));
    }
}

// transpose + fp16 (hi only)
__global__ __launch_bounds__(256)
void wsplit_kernel(const float* __restrict__ W,
                   __half* __restrict__ Th,
                   int Krows, int Ncols, int n_off)
{
    __shared__ float tile[32][33];
    int n0 = blockIdx.x * 32, k0 = blockIdx.y * 32;
    int t = threadIdx.x;
    int tx = t & 31, ty = t >> 5;
    #pragma unroll
    for (int i = 0; i < 4; i++)
        tile[ty + i * 8][tx] = W[(size_t)(k0 + ty + i * 8) * Ncols + n0 + tx];
    __syncthreads();
    #pragma unroll
    for (int i = 0; i < 4; i++) {
        int n = n_off + n0 + ty + i * 8;
        float v = tile[tx][ty + i * 8];
        Th[(size_t)n * Krows + k0 + tx] = __float2half_rn(v);
    }
}

__global__ void init_slots_kernel(const float* __restrict__ noise,
                                  const float* __restrict__ mu,
                                  const float* __restrict__ ls,
                                  float* __restrict__ slots)
{
    int t = blockIdx.x * blockDim.x + threadIdx.x;
    if (t >= MS * D) return;
    int d = t % D;
    slots[t] = mu[d] + expf(ls[d]) * noise[t];
}

// ----------------------------------------------------------------------------
// dots + softmax over the slot axis; reads Wq split-K partials directly
// ----------------------------------------------------------------------------
__global__ __launch_bounds__(256)
void dots_softmax_kernel(const float* __restrict__ Qpart, const float* __restrict__ Kb,
                         float* __restrict__ attn)
{
    int b  = blockIdx.y;
    int j0 = blockIdx.x * 64;
    __shared__ __align__(16) float qs[16][64];
    __shared__ float ks[64][65];
    __shared__ float red[4][64];
    int tid = threadIdx.x;
    int tx = tid & 63, ty = tid >> 6;
    float acc[4] = {0.f, 0.f, 0.f, 0.f};
    const float* Kp = Kb + ((size_t)b * NK + j0) * D;
    for (int k0 = 0; k0 < D; k0 += 64) {
        {
            int i = tid >> 4, kc = (tid & 15) * 4;
            size_t o = ((size_t)b * S + i) * D + k0 + kc;
            float4 v = *(const float4*)&Qpart[o];
            #pragma unroll
            for (int sp = 1; sp < 4; sp++) {
                float4 w = *(const float4*)&Qpart[(size_t)sp * MS * D + o];
                v.x += w.x; v.y += w.y; v.z += w.z; v.w += w.w;
            }
            *(float4*)&qs[i][kc] = v;
        }
        #pragma unroll
        for (int p = 0; p < 4; p++) {
            int e = tid + p * 256;
            int jj = e >> 4, kc = (e & 15) * 4;
            float4 v = *(const float4*)&Kp[(size_t)jj * D + k0 + kc];
            ks[jj][kc + 0] = v.x; ks[jj][kc + 1] = v.y;
            ks[jj][kc + 2] = v.z; ks[jj][kc + 3] = v.w;
        }
        __syncthreads();
        #pragma unroll
        for (int kk = 0; kk < 64; kk++) {
            float kv = ks[tx][kk];
            acc[0] += qs[ty     ][kk] * kv;
            acc[1] += qs[ty +  4][kk] * kv;
            acc[2] += qs[ty +  8][kk] * kv;
            acc[3] += qs[ty + 12][kk] * kv;
        }
        __syncthreads();
    }
    #pragma unroll
    for (int r = 0; r < 4; r++) acc[r] *= kSCALE;
    float m = fmaxf(fmaxf(acc[0], acc[1]), fmaxf(acc[2], acc[3]));
    red[ty][tx] = m;
    __syncthreads();
    float M = fmaxf(fmaxf(red[0][tx], red[1][tx]), fmaxf(red[2][tx], red[3][tx]));
    __syncthreads();
    float e[4]; float s = 0.f;
    #pragma unroll
    for (int r = 0; r < 4; r++) { e[r] = expf(acc[r] - M); s += e[r]; }
    red[ty][tx] = s;
    __syncthreads();
    float Ssum = red[0][tx] + red[1][tx] + red[2][tx] + red[3][tx];
    float inv = 1.f / Ssum;
    #pragma unroll
    for (int r = 0; r < 4; r++)
        attn[((size_t)b * S + ty + r * 4) * NK + j0 + tx] = e[r] * inv + 1e-8f;
}

// updates[b,i,n] = (sum_j attn * v) / (sum_j attn)
__global__ __launch_bounds__(256)
void updates_kernel(const float* __restrict__ attn, const float* __restrict__ V,
                    float* __restrict__ upd)
{
    int b  = blockIdx.y;
    int n0 = blockIdx.x * 64;
    __shared__ __align__(16) float as_[16][64];
    __shared__ __align__(16) float vs[64][64];
    int tid = threadIdx.x;
    int tx = tid & 63, ty = tid >> 6;
    float acc[4] = {0.f, 0.f, 0.f, 0.f};
    float ssum[4] = {0.f, 0.f, 0.f, 0.f};
    for (int j0 = 0; j0 < NK; j0 += 64) {
        {
            int i = tid >> 4, jc = (tid & 15) * 4;
            *(float4*)&as_[i][jc] =
                *(const float4*)&attn[((size_t)b * S + i) * NK + j0 + jc];
        }
        #pragma unroll
        for (int p = 0; p < 4; p++) {
            int e = tid + p * 256;
            int jj = e >> 4, nc = (e & 15) * 4;
            *(float4*)&vs[jj][nc] =
                *(const float4*)&V[((size_t)b * NK + j0 + jj) * D + n0 + nc];
        }
        __syncthreads();
        #pragma unroll
        for (int jj = 0; jj < 64; jj++) {
            float vv = vs[jj][tx];
            float a0 = as_[ty][jj], a1 = as_[ty + 4][jj];
            float a2 = as_[ty + 8][jj], a3 = as_[ty + 12][jj];
            acc[0] += a0 * vv;  ssum[0] += a0;
            acc[1] += a1 * vv;  ssum[1] += a1;
            acc[2] += a2 * vv;  ssum[2] += a2;
            acc[3] += a3 * vv;  ssum[3] += a3;
        }
        __syncthreads();
    }
    #pragma unroll
    for (int r = 0; r < 4; r++)
        upd[((size_t)b * S + ty + r * 4) * D + n0 + tx] = acc[r] / ssum[r];
}

// encoder self-attention; reads QKV split-K partials directly
__global__ __launch_bounds__(256)
void enc_attn_kernel(const float* __restrict__ QKVpart,
                     __half* __restrict__ Oh, __half* __restrict__ Ol)
{
    int b = blockIdx.x >> 3, h = blockIdx.x & 7;
    __shared__ float qs[16][65], ks[16][65], vs[16][65];
    __shared__ float p[16][17];
    int tid = threadIdx.x;
    int i = tid >> 4, jj = tid & 15;
    {
        int r = tid >> 4, c = (tid & 15) * 4;
        size_t base = ((size_t)b * S + r) * QKV3 + h * DH + c;
        float4 vq = *(const float4*)&QKVpart[base];
        float4 vk = *(const float4*)&QKVpart[base + HD];
        float4 vv = *(const float4*)&QKVpart[base + 2 * HD];
        #pragma unroll
        for (int sp = 1; sp < 4; sp++) {
            size_t o = (size_t)sp * MS * QKV3 + base;
            float4 w;
            w = *(const float4*)&QKVpart[o];
            vq.x += w.x; vq.y += w.y; vq.z += w.z; vq.w += w.w;
            w = *(const float4*)&QKVpart[o + HD];
            vk.x += w.x; vk.y += w.y; vk.z += w.z; vk.w += w.w;
            w = *(const float4*)&QKVpart[o + 2 * HD];
            vv.x += w.x; vv.y += w.y; vv.z += w.z; vv.w += w.w;
        }
        qs[r][c] = vq.x; qs[r][c+1] = vq.y; qs[r][c+2] = vq.z; qs[r][c+3] = vq.w;
        ks[r][c] = vk.x; ks[r][c+1] = vk.y; ks[r][c+2] = vk.z; ks[r][c+3] = vk.w;
        vs[r][c] = vv.x; vs[r][c+1] = vv.y; vs[r][c+2] = vv.z; vs[r][c+3] = vv.w;
    }
    __syncthreads();
    float s = 0.f;
    #pragma unroll
    for (int d = 0; d < DH; d++) s += qs[i][d] * ks[jj][d];
    s *= 0.125f;
    p[i][jj] = s;
    __syncthreads();
    float m = -1e30f;
    #pragma unroll
    for (int t2 = 0; t2 < 16; t2++) m = fmaxf(m, p[i][t2]);
    __syncthreads();
    float e = expf(s - m);
    p[i][jj] = e;
    __syncthreads();
    float sum = 0.f;
    #pragma unroll
    for (int t2 = 0; t2 < 16; t2++) sum += p[i][t2];
    __syncthreads();
    p[i][jj] = e / sum;
    __syncthreads();
    int io = tid >> 4, dbase = (tid & 15) * 4;
    float o[4] = {0.f, 0.f, 0.f, 0.f};
    #pragma unroll
    for (int t2 = 0; t2 < 16; t2++) {
        float pp = p[io][t2];
        o[0] += pp * vs[t2][dbase + 0];
        o[1] += pp * vs[t2][dbase + 1];
        o[2] += pp * vs[t2][dbase + 2];
        o[3] += pp * vs[t2][dbase + 3];
    }
    size_t base = ((size_t)b * S + io) * HD + h * DH + dbase;
    #pragma unroll
    for (int c = 0; c < 4; c++) {
        __half hb = __float2half_rn(o[c]);
        Oh[base + c] = hb;
        Ol[base + c] = __float2half_rn(o[c] - __half2float(hb));
    }
}

// output map: per (b,i) row — sum over keys then write out[b][j][i] = attn/sum
__global__ __launch_bounds__(256)
void attn_out_kernel(const float* __restrict__ attn, float* __restrict__ out)
{
    int row = blockIdx.x;            // b*S + i
    int b = row >> 4, i = row & 15;
    const float4* p = (const float4*)(attn + (size_t)row * NK);
    int tid = threadIdx.x;
    float4 v = p[tid];
    float s = v.x + v.y + v.z + v.w;
    __shared__ float sa[8];
    #pragma unroll
    for (int o = 16; o > 0; o >>= 1) s += __shfl_down_sync(0xffffffffu, s, o);
    int w = tid >> 5, l = tid & 31;
    if (l == 0) sa[w] = s;
    __syncthreads();
    if (tid == 0) {
        float ts = 0.f;
        #pragma unroll
        for (int k = 0; k < 8; k++) ts += sa[k];
        sa[0] = ts;
    }
    __syncthreads();
    float inv = 1.f / sa[0];
    size_t ob = (size_t)b * NK * S + i;
    int j = tid * 4;
    out[ob + (size_t)(j + 0) * S] = v.x * inv;
    out[ob + (size_t)(j + 1) * S] = v.y * inv;
    out[ob + (size_t)(j + 2) * S] = v.z * inv;
    out[ob + (size_t)(j + 3) * S] = v.w * inv;
}

// ----------------------------------------------------------------------------
// Host orchestration
// ----------------------------------------------------------------------------
extern "C" void kernel_launch(void* const* d_in, const int* in_sizes, int n_in,
                              void* d_out, int out_size)
{
    const float* x       = (const float*)d_in[0];
    const float* noise   = (const float*)d_in[1];
    const float* init_mu = (const float*)d_in[2];
    const float* init_ls = (const float*)d_in[3];
    const float* Wk      = (const float*)d_in[4];
    const float* Wv      = (const float*)d_in[5];
    const float* Wq      = (const float*)d_in[6];
    const float* ni_g    = (const float*)d_in[7];
    const float* ni_b    = (const float*)d_in[8];
    const float* ns_g    = (const float*)d_in[9];
    const float* ns_b    = (const float*)d_in[10];
    const float* nica_g  = (const float*)d_in[11];
    const float* nica_b  = (const float*)d_in[12];
    const float* ln1_g   = (const float*)d_in[13];
    const float* ln1_b   = (const float*)d_in[14];
    const float* Wq_a    = (const float*)d_in[15];
    const float* Wk_a    = (const float*)d_in[16];
    const float* Wv_a    = (const float*)d_in[17];
    const float* Wo_a    = (const float*)d_in[18];
    const float* ln2_g   = (const float*)d_in[19];
    const float* ln2_b   = (const float*)d_in[20];
    const float* W1      = (const float*)d_in[21];
    const float* W2      = (const float*)d_in[22];
    const float* lnf_g   = (const float*)d_in[23];
    const float* lnf_b   = (const float*)d_in[24];

    __half *xnh, *wkh, *wvh, *wqh;
    __half *wqkh, *woh, *w1h, *w2h;
    __half *qnh, *qnl, *abh, *abl, *fbh, *fbl, *innh, *innl, *oah, *oal;
    float *kb, *vb, *slots, *attn, *upd, *hb, *part;
    cudaGetSymbolAddress((void**)&xnh,  g_xnh);
    cudaGetSymbolAddress((void**)&wkh,  g_wkh);
    cudaGetSymbolAddress((void**)&wvh,  g_wvh);
    cudaGetSymbolAddress((void**)&wqh,  g_wqh);
    cudaGetSymbolAddress((void**)&wqkh, g_wqkh);
    cudaGetSymbolAddress((void**)&woh,  g_woh);
    cudaGetSymbolAddress((void**)&w1h,  g_w1h);
    cudaGetSymbolAddress((void**)&w2h,  g_w2h);
    cudaGetSymbolAddress((void**)&qnh,  g_qnh);  cudaGetSymbolAddress((void**)&qnl,  g_qnl);
    cudaGetSymbolAddress((void**)&abh,  g_abh);  cudaGetSymbolAddress((void**)&abl,  g_abl);
    cudaGetSymbolAddress((void**)&fbh,  g_fbh);  cudaGetSymbolAddress((void**)&fbl,  g_fbl);
    cudaGetSymbolAddress((void**)&innh, g_innh); cudaGetSymbolAddress((void**)&innl, g_innl);
    cudaGetSymbolAddress((void**)&oah,  g_oah);  cudaGetSymbolAddress((void**)&oal,  g_oal);
    cudaGetSymbolAddress((void**)&kb,   g_k);
    cudaGetSymbolAddress((void**)&vb,   g_v);
    cudaGetSymbolAddress((void**)&slots,g_slots);
    cudaGetSymbolAddress((void**)&attn, g_attn);
    cudaGetSymbolAddress((void**)&upd,  g_upd);
    cudaGetSymbolAddress((void**)&hb,   g_h);
    cudaGetSymbolAddress((void**)&part, g_part);

    cudaFuncSetAttribute(hgemm_hilo, cudaFuncAttributeMaxDynamicSharedMemorySize, HG_SMEM);
    cudaFuncSetAttribute(hgemm_dual, cudaFuncAttributeMaxDynamicSharedMemorySize, DUAL_SMEM);
    cudaFuncSetAttribute(hgemm_glu,  cudaFuncAttributeMaxDynamicSharedMemorySize, GLU_SMEM);

    // ---- precompute ----
    wsplit_kernel<<<dim3(D / 32, D / 32), 256>>>(Wk, wkh, D, D, 0);
    wsplit_kernel<<<dim3(D / 32, D / 32), 256>>>(Wv, wvh, D, D, 0);
    ln_split_kernel<<<B * NK, 256>>>(x, xnh, nullptr, ni_g, ni_b);
    init_slots_kernel<<<(MS * D + 255) / 256, 256>>>(noise, init_mu, init_ls, slots);
    wsplit_kernel<<<dim3(D / 32, D / 32), 256>>>(Wq, wqh, D, D, 0);
    hgemm_dual<<<dim3(D / 128, (B * NK) / 128), 256, DUAL_SMEM>>>(
        xnh, wkh, wvh, kb, vb, B * NK, D, D);
    wsplit_kernel<<<dim3(HD / 32, D / 32), 256>>>(Wq_a, wqkh, D, HD, 0);
    wsplit_kernel<<<dim3(HD / 32, D / 32), 256>>>(Wk_a, wqkh, D, HD, HD);
    wsplit_kernel<<<dim3(HD / 32, D / 32), 256>>>(Wv_a, wqkh, D, HD, 2 * HD);
    wsplit_kernel<<<dim3(D / 32, HD / 32), 256>>>(Wo_a, woh, HD, D, 0);
    wsplit_kernel<<<dim3((2 * INNER) / 32, D / 32), 256>>>(W1, w1h, D, 2 * INNER, 0);
    wsplit_kernel<<<dim3(D / 32, INNER / 32), 256>>>(W2, w2h, INNER, D, 0);
    ln_split_kernel<<<MS, 256>>>(slots, qnh, qnl, ns_g, ns_b);

    // ---- 4 slot-attention steps (11 launches each) ----
    for (int it = 0; it < N_STEPS; it++) {
        hgemm_hilo<<<dim3(D / 128, MS / 128, 4), 256, HG_SMEM>>>(qnh, qnl, wqh,
                                                                 part, MS, D, D);
        dots_softmax_kernel<<<dim3(NK / 64, B), 256>>>(part, kb, attn);
        updates_kernel<<<dim3(D / 64, B), 256>>>(attn, vb, upd);
        ln_dual_kernel<<<MS, 256>>>(slots, upd, hb, nica_g, nica_b,
                                    ln1_g, ln1_b, abh, abl);
        hgemm_hilo<<<dim3(QKV3 / 128, MS / 128, 4), 256, HG_SMEM>>>(abh, abl, wqkh,
                                                                    part, MS, QKV3, D);
        enc_attn_kernel<<<B * H, 256>>>(part, oah, oal);
        hgemm_hilo<<<dim3(D / 128, MS / 128, 4), 256, HG_SMEM>>>(oah, oal, woh,
                                                                 part, MS, D, HD);
        ln_split_red_kernel<<<MS, 256>>>(part, hb, ln2_g, ln2_b, fbh, fbl);
        hgemm_glu<<<dim3(INNER / 128, MS / 128), 256, GLU_SMEM>>>(fbh, fbl, w1h,
                                                                  innh, innl, MS);
        hgemm_hilo<<<dim3(D / 128, MS / 128, 4), 256, HG_SMEM>>>(innh, innl, w2h,
                                                                 part, MS, D, INNER);
        ln_red_dual_kernel<<<MS, 256>>>(part, hb, slots, lnf_g, lnf_b,
                                        ns_g, ns_b, qnh, qnl);
    }

    // ---- outputs: slots [32,16,768], then attn_map [32,1024,16] ----
    float* out = (float*)d_out;
    cudaMemcpyAsync(out, slots, (size_t)MS * D * sizeof(float),
                    cudaMemcpyDeviceToDevice);
    attn_out_kernel<<<MS, 256>>>(attn, out + (size_t)MS * D);
}

// round 13
// speedup vs baseline: 1.6974x; 1.1142x over previous
#include <cuda_runtime.h>
#include <cuda_fp16.h>
#include <math.h>
#include <stdint.h>

// ----------------------------------------------------------------------------
// Problem constants
// ----------------------------------------------------------------------------
#define B   32
#define NK  1024
#define S   16
#define D   768
#define H   8
#define DH  64
#define HD  (H*DH)    // 512
#define QKV3 (3*HD)   // 1536
#define INNER 3072
#define N_STEPS 4
#define MS  (B*S)     // 512
static __device__ __constant__ float kSCALE = 0.036084391824351615f;  // 768^-0.5

// ----------------------------------------------------------------------------
// Scratch (device globals)
// ----------------------------------------------------------------------------
__device__ __half g_xnh[B*NK*D];
__device__ __half g_wkh [D*D];
__device__ __half g_wvh [D*D];
__device__ __half g_wqh [D*D];
__device__ __half g_wqkh[QKV3*D];
__device__ __half g_woh [D*HD];
__device__ __half g_w1h [2*INNER*D];
__device__ __half g_w2h [D*INNER];
__device__ __half g_qnh[MS*D];
__device__ __half g_abh[MS*D];
__device__ __half g_fbh[MS*D];
__device__ __half g_innh[MS*INNER];
__device__ __half g_oah[MS*HD];
__device__ __half g_k  [B*NK*D];
__device__ __half g_v  [B*NK*D];
__device__ float g_slots[MS*D];
__device__ float g_attn [MS*NK];
__device__ float g_upd  [MS*D];
__device__ float g_h    [MS*D];
__device__ float g_part [4*MS*QKV3];

// ----------------------------------------------------------------------------
// HMMA / cp.async helpers (baseline PTX — compiles for plain compute_103)
// ----------------------------------------------------------------------------
__device__ __forceinline__ uint32_t smem_u32(const void* p) {
    uint32_t a;
    asm("{ .reg .u64 t; cvta.to.shared.u64 t, %1; cvt.u32.u64 %0, t; }"
        : "=r"(a) : "l"(p));
    return a;
}
#define LDSM_X4(r0, r1, r2, r3, addr) \
    asm volatile("ldmatrix.sync.aligned.m8n8.x4.shared.b16 {%0,%1,%2,%3}, [%4];" \
                 : "=r"(r0), "=r"(r1), "=r"(r2), "=r"(r3) : "r"(addr))
#define LDSM_X2(r0, r1, addr) \
    asm volatile("ldmatrix.sync.aligned.m8n8.x2.shared.b16 {%0,%1}, [%2];" \
                 : "=r"(r0), "=r"(r1) : "r"(addr))
#define MMA16816(c, a, b) \
    asm volatile("mma.sync.aligned.m16n8k16.row.col.f32.f16.f16.f32 " \
                 "{%0,%1,%2,%3}, {%4,%5,%6,%7}, {%8,%9}, {%0,%1,%2,%3};" \
                 : "+f"((c)[0]), "+f"((c)[1]), "+f"((c)[2]), "+f"((c)[3]) \
                 : "r"((a)[0]), "r"((a)[1]), "r"((a)[2]), "r"((a)[3]), \
                   "r"((b)[0]), "r"((b)[1]))
#define CP_ASYNC16(dst_u32, src_ptr) \
    asm volatile("cp.async.ca.shared.global [%0], [%1], 16;" \
                 :: "r"(dst_u32), "l"(src_ptr))
#define CP_COMMIT() asm volatile("cp.async.commit_group;" ::: "memory")
#define CP_WAIT(n)  asm volatile("cp.async.wait_group %0;" :: "n"(n) : "memory")

#define PITCH 40            // halves per smem row (80 B) — conflict-free ldmatrix
#define TILEH (128 * PITCH) // halves per tile
#define TILEB (TILEH * 2)   // bytes per tile

// ----------------------------------------------------------------------------
// Pure fp16 HMMA GEMM (C = A·B), split-K, 2-stage cp.async.
// ----------------------------------------------------------------------------
__global__ __launch_bounds__(256)
void hgemm_fp16(const __half* __restrict__ Ah, const __half* __restrict__ Bth,
                float* __restrict__ C, int M, int N, int K)
{
    extern __shared__ __align__(16) __half dyn[];
    int tid = threadIdx.x;
    int lane = tid & 31, wid = tid >> 5;
    int wm = wid >> 2, wn = wid & 3;
    int row0 = blockIdx.y * 128, col0 = blockIdx.x * 128;
    int kb   = K / gridDim.z;
    int kbeg = blockIdx.z * kb;
    float* Cz = C + (size_t)blockIdx.z * M * N;
    int nchunk = kb / 32;

    uint32_t base = smem_u32(dyn);

    float acc[4][4][4];
    #pragma unroll
    for (int mf = 0; mf < 4; mf++)
        #pragma unroll
        for (int nf = 0; nf < 4; nf++)
            #pragma unroll
            for (int e = 0; e < 4; e++) acc[mf][nf][e] = 0.f;

    int laneAr = lane & 15, laneAk = (lane & 16) ? 8 : 0;
    int laneBr = lane & 7,  laneBk = (lane & 8)  ? 8 : 0;

    auto load_stage = [&](int c, int s) {
        uint32_t sb = base + (uint32_t)s * 2 * TILEB;
        #pragma unroll
        for (int i = 0; i < 2; i++) {
            int idx = tid + i * 256;
            int row = idx >> 2, sg = idx & 3;
            size_t ga = (size_t)(row0 + row) * K + kbeg + c * 32 + sg * 8;
            size_t gb = (size_t)(col0 + row) * K + kbeg + c * 32 + sg * 8;
            uint32_t so = (uint32_t)(row * PITCH + sg * 8) * 2;
            CP_ASYNC16(sb + 0 * TILEB + so, Ah + ga);
            CP_ASYNC16(sb + 1 * TILEB + so, Bth + gb);
        }
    };

    load_stage(0, 0);
    CP_COMMIT();
    for (int c = 0; c < nchunk; c++) {
        int s = c & 1;
        if (c + 1 < nchunk) { load_stage(c + 1, s ^ 1); CP_COMMIT(); CP_WAIT(1); }
        else                { CP_WAIT(0); }
        __syncthreads();
        uint32_t bAh = base + (uint32_t)s * 2 * TILEB;
        uint32_t bBh = bAh + TILEB;
        #pragma unroll
        for (int ks = 0; ks < 32; ks += 16) {
            uint32_t bh[4][2];
            #pragma unroll
            for (int nf = 0; nf < 4; nf++) {
                uint32_t off = (uint32_t)((wn * 32 + nf * 8 + laneBr) * PITCH
                                          + ks + laneBk) * 2;
                LDSM_X2(bh[nf][0], bh[nf][1], bBh + off);
            }
            #pragma unroll
            for (int mf = 0; mf < 4; mf++) {
                uint32_t off = (uint32_t)((wm * 64 + mf * 16 + laneAr) * PITCH
                                          + ks + laneAk) * 2;
                uint32_t ah[4];
                LDSM_X4(ah[0], ah[1], ah[2], ah[3], bAh + off);
                #pragma unroll
                for (int nf = 0; nf < 4; nf++)
                    MMA16816(acc[mf][nf], ah, bh[nf]);
            }
        }
        __syncthreads();
    }
    #pragma unroll
    for (int mf = 0; mf < 4; mf++) {
        int r = row0 + wm * 64 + mf * 16 + (lane >> 2);
        #pragma unroll
        for (int nf = 0; nf < 4; nf++) {
            int c = col0 + wn * 32 + nf * 8 + (lane & 3) * 2;
            *(float2*)(Cz + (size_t)r * N + c) =
                make_float2(acc[mf][nf][0], acc[mf][nf][1]);
            *(float2*)(Cz + (size_t)(r + 8) * N + c) =
                make_float2(acc[mf][nf][2], acc[mf][nf][3]);
        }
    }
}
#define HG_SMEM (2 * 2 * TILEB)     // 40960

// ----------------------------------------------------------------------------
// Dual-output projection (K/V), pure fp16, emits __half K/V.
// ----------------------------------------------------------------------------
__global__ __launch_bounds__(256)
void hgemm_dual(const __half* __restrict__ Ah,
                const __half* __restrict__ Bkh, const __half* __restrict__ Bvh,
                __half* __restrict__ Ck, __half* __restrict__ Cv,
                int M, int N, int K)
{
    extern __shared__ __align__(16) __half dyn[];
    int tid = threadIdx.x;
    int lane = tid & 31, wid = tid >> 5;
    int wm = wid >> 2, wn = wid & 3;
    int row0 = blockIdx.y * 128, col0 = blockIdx.x * 128;
    int nchunk = K / 32;
    uint32_t base = smem_u32(dyn);

    float accK[4][4][4], accV[4][4][4];
    #pragma unroll
    for (int mf = 0; mf < 4; mf++)
        #pragma unroll
        for (int nf = 0; nf < 4; nf++)
            #pragma unroll
            for (int e = 0; e < 4; e++) { accK[mf][nf][e] = 0.f; accV[mf][nf][e] = 0.f; }

    int laneAr = lane & 15, laneAk = (lane & 16) ? 8 : 0;
    int laneBr = lane & 7,  laneBk = (lane & 8)  ? 8 : 0;

    auto load_stage = [&](int c, int s) {
        uint32_t sb = base + (uint32_t)s * 3 * TILEB;
        #pragma unroll
        for (int i = 0; i < 2; i++) {
            int idx = tid + i * 256;
            int row = idx >> 2, sg = idx & 3;
            size_t ga = (size_t)(row0 + row) * K + c * 32 + sg * 8;
            size_t gb = (size_t)(col0 + row) * K + c * 32 + sg * 8;
            uint32_t so = (uint32_t)(row * PITCH + sg * 8) * 2;
            CP_ASYNC16(sb + 0 * TILEB + so, Ah + ga);
            CP_ASYNC16(sb + 1 * TILEB + so, Bkh + gb);
            CP_ASYNC16(sb + 2 * TILEB + so, Bvh + gb);
        }
    };

    load_stage(0, 0);
    CP_COMMIT();
    for (int c = 0; c < nchunk; c++) {
        int s = c & 1;
        if (c + 1 < nchunk) { load_stage(c + 1, s ^ 1); CP_COMMIT(); CP_WAIT(1); }
        else                { CP_WAIT(0); }
        __syncthreads();
        uint32_t bAh = base + (uint32_t)s * 3 * TILEB;
        uint32_t bKh = bAh + TILEB;
        uint32_t bVh = bKh + TILEB;
        #pragma unroll
        for (int ks = 0; ks < 32; ks += 16) {
            uint32_t kh[4][2], vh[4][2];
            #pragma unroll
            for (int nf = 0; nf < 4; nf++) {
                uint32_t off = (uint32_t)((wn * 32 + nf * 8 + laneBr) * PITCH
                                          + ks + laneBk) * 2;
                LDSM_X2(kh[nf][0], kh[nf][1], bKh + off);
                LDSM_X2(vh[nf][0], vh[nf][1], bVh + off);
            }
            #pragma unroll
            for (int mf = 0; mf < 4; mf++) {
                uint32_t off = (uint32_t)((wm * 64 + mf * 16 + laneAr) * PITCH
                                          + ks + laneAk) * 2;
                uint32_t ah[4];
                LDSM_X4(ah[0], ah[1], ah[2], ah[3], bAh + off);
                #pragma unroll
                for (int nf = 0; nf < 4; nf++) {
                    MMA16816(accK[mf][nf], ah, kh[nf]);
                    MMA16816(accV[mf][nf], ah, vh[nf]);
                }
            }
        }
        __syncthreads();
    }
    #pragma unroll
    for (int mf = 0; mf < 4; mf++) {
        int r = row0 + wm * 64 + mf * 16 + (lane >> 2);
        #pragma unroll
        for (int nf = 0; nf < 4; nf++) {
            int c = col0 + wn * 32 + nf * 8 + (lane & 3) * 2;
            *(__half2*)(Ck + (size_t)r * N + c) =
                __floats2half2_rn(accK[mf][nf][0], accK[mf][nf][1]);
            *(__half2*)(Ck + (size_t)(r + 8) * N + c) =
                __floats2half2_rn(accK[mf][nf][2], accK[mf][nf][3]);
            *(__half2*)(Cv + (size_t)r * N + c) =
                __floats2half2_rn(accV[mf][nf][0], accV[mf][nf][1]);
            *(__half2*)(Cv + (size_t)(r + 8) * N + c) =
                __floats2half2_rn(accV[mf][nf][2], accV[mf][nf][3]);
        }
    }
}
#define DUAL_SMEM (2 * 3 * TILEB)   // 61440

// ----------------------------------------------------------------------------
// W1 + GLU fused, pure fp16, 2-stage pipelined; emits fp16 u*silu(g).
// ----------------------------------------------------------------------------
__global__ __launch_bounds__(256)
void hgemm_glu(const __half* __restrict__ Ah, const __half* __restrict__ W1th,
               __half* __restrict__ Ih, int M)
{
    extern __shared__ __align__(16) __half dyn[];
    int tid = threadIdx.x;
    int lane = tid & 31, wid = tid >> 5;
    int wm = wid >> 2, wn = wid & 3;
    int row0 = blockIdx.y * 128, col0 = blockIdx.x * 128;
    int nchunk = D / 32;
    uint32_t base = smem_u32(dyn);

    float accU[4][4][4], accG[4][4][4];
    #pragma unroll
    for (int mf = 0; mf < 4; mf++)
        #pragma unroll
        for (int nf = 0; nf < 4; nf++)
            #pragma unroll
            for (int e = 0; e < 4; e++) { accU[mf][nf][e] = 0.f; accG[mf][nf][e] = 0.f; }

    int laneAr = lane & 15, laneAk = (lane & 16) ? 8 : 0;
    int laneBr = lane & 7,  laneBk = (lane & 8)  ? 8 : 0;

    auto load_stage = [&](int c, int s) {
        uint32_t sb = base + (uint32_t)s * 3 * TILEB;
        #pragma unroll
        for (int i = 0; i < 2; i++) {
            int idx = tid + i * 256;
            int row = idx >> 2, sg = idx & 3;
            size_t ga = (size_t)(row0 + row) * D + c * 32 + sg * 8;
            size_t gu = (size_t)(col0 + row) * D + c * 32 + sg * 8;
            size_t gg = (size_t)(col0 + row + INNER) * D + c * 32 + sg * 8;
            uint32_t so = (uint32_t)(row * PITCH + sg * 8) * 2;
            CP_ASYNC16(sb + 0 * TILEB + so, Ah + ga);
            CP_ASYNC16(sb + 1 * TILEB + so, W1th + gu);
            CP_ASYNC16(sb + 2 * TILEB + so, W1th + gg);
        }
    };

    load_stage(0, 0);
    CP_COMMIT();
    for (int c = 0; c < nchunk; c++) {
        int s = c & 1;
        if (c + 1 < nchunk) { load_stage(c + 1, s ^ 1); CP_COMMIT(); CP_WAIT(1); }
        else                { CP_WAIT(0); }
        __syncthreads();
        uint32_t bAh = base + (uint32_t)s * 3 * TILEB;
        uint32_t bUh = bAh + TILEB;
        uint32_t bGh = bUh + TILEB;
        #pragma unroll
        for (int ks = 0; ks < 32; ks += 16) {
            uint32_t uh[4][2], gh[4][2];
            #pragma unroll
            for (int nf = 0; nf < 4; nf++) {
                uint32_t off = (uint32_t)((wn * 32 + nf * 8 + laneBr) * PITCH
                                          + ks + laneBk) * 2;
                LDSM_X2(uh[nf][0], uh[nf][1], bUh + off);
                LDSM_X2(gh[nf][0], gh[nf][1], bGh + off);
            }
            #pragma unroll
            for (int mf = 0; mf < 4; mf++) {
                uint32_t off = (uint32_t)((wm * 64 + mf * 16 + laneAr) * PITCH
                                          + ks + laneAk) * 2;
                uint32_t ah[4];
                LDSM_X4(ah[0], ah[1], ah[2], ah[3], bAh + off);
                #pragma unroll
                for (int nf = 0; nf < 4; nf++) {
                    MMA16816(accU[mf][nf], ah, uh[nf]);
                    MMA16816(accG[mf][nf], ah, gh[nf]);
                }
            }
        }
        __syncthreads();
    }
    #pragma unroll
    for (int mf = 0; mf < 4; mf++) {
        int r = row0 + wm * 64 + mf * 16 + (lane >> 2);
        #pragma unroll
        for (int nf = 0; nf < 4; nf++) {
            int c = col0 + wn * 32 + nf * 8 + (lane & 3) * 2;
            #pragma unroll
            for (int half_ = 0; half_ < 2; half_++) {
                int rr = r + half_ * 8;
                float u0 = accU[mf][nf][half_ * 2], u1 = accU[mf][nf][half_ * 2 + 1];
                float g0 = accG[mf][nf][half_ * 2], g1 = accG[mf][nf][half_ * 2 + 1];
                float v0 = u0 * (g0 / (1.f + expf(-g0)));
                float v1 = u1 * (g1 / (1.f + expf(-g1)));
                *(__half2*)(Ih + (size_t)rr * INNER + c) = __floats2half2_rn(v0, v1);
            }
        }
    }
}
#define GLU_SMEM (2 * 3 * TILEB)    // 61440

// ----------------------------------------------------------------------------
// LN reduction helper (256 threads over D=768)
// ----------------------------------------------------------------------------
__device__ __forceinline__ void ln_stats(float v0, float v1, float v2,
                                         float* sa, float* sb2,
                                         float& mean, float& rinv)
{
    float s = v0 + v1 + v2;
    float q = v0 * v0 + v1 * v1 + v2 * v2;
    int tid = threadIdx.x;
    #pragma unroll
    for (int o = 16; o > 0; o >>= 1) {
        s += __shfl_down_sync(0xffffffffu, s, o);
        q += __shfl_down_sync(0xffffffffu, q, o);
    }
    int w = tid >> 5, l = tid & 31;
    if (l == 0) { sa[w] = s; sb2[w] = q; }
    __syncthreads();
    if (tid == 0) {
        float ts = 0.f, tq = 0.f;
        #pragma unroll
        for (int k = 0; k < 8; k++) { ts += sa[k]; tq += sb2[k]; }
        sa[0] = ts; sb2[0] = tq;
    }
    __syncthreads();
    mean = sa[0] * (1.0f / D);
    float var = sb2[0] * (1.0f / D) - mean * mean;
    rinv = rsqrtf(var + 1e-5f);
    __syncthreads();
}

// LN(x) -> fp16
__global__ __launch_bounds__(256)
void ln_h_kernel(const float* __restrict__ in, __half* __restrict__ oh,
                 const float* __restrict__ gamma, const float* __restrict__ beta)
{
    int row = blockIdx.x, tid = threadIdx.x;
    const float* x = in + (size_t)row * D;
    float v[3] = {x[tid], x[tid + 256], x[tid + 512]};
    __shared__ float sa[8], sb2[8];
    float mean, r;
    ln_stats(v[0], v[1], v[2], sa, sb2, mean, r);
    #pragma unroll
    for (int e = 0; e < 3; e++) {
        int idx = tid + e * 256;
        float y = (v[e] - mean) * r * gamma[idx] + beta[idx];
        oh[(size_t)row * D + idx] = __float2half_rn(y);
    }
}

// h = LN_a(slots + upd) -> hb(fp32);  LN_b(h) -> oh(fp16)
__global__ __launch_bounds__(256)
void ln_dual_kernel(const float* __restrict__ slots, const float* __restrict__ upd,
                    float* __restrict__ hb,
                    const float* __restrict__ g1, const float* __restrict__ b1,
                    const float* __restrict__ g2, const float* __restrict__ b2,
                    __half* __restrict__ oh)
{
    int row = blockIdx.x, tid = threadIdx.x;
    const float* xs = slots + (size_t)row * D;
    const float* xu = upd + (size_t)row * D;
    float v[3];
    #pragma unroll
    for (int e = 0; e < 3; e++) v[e] = xs[tid + e * 256] + xu[tid + e * 256];
    __shared__ float sa[8], sb2[8];
    float mean, r;
    ln_stats(v[0], v[1], v[2], sa, sb2, mean, r);
    float y[3];
    #pragma unroll
    for (int e = 0; e < 3; e++) {
        int idx = tid + e * 256;
        y[e] = (v[e] - mean) * r * g1[idx] + b1[idx];
        hb[(size_t)row * D + idx] = y[e];
    }
    float mean2, r2;
    ln_stats(y[0], y[1], y[2], sa, sb2, mean2, r2);
    #pragma unroll
    for (int e = 0; e < 3; e++) {
        int idx = tid + e * 256;
        float z = (y[e] - mean2) * r2 * g2[idx] + b2[idx];
        oh[(size_t)row * D + idx] = __float2half_rn(z);
    }
}

// h = res + sum_{sp<4} part[sp]; res <- h; LN(h) -> oh(fp16)
__global__ __launch_bounds__(256)
void ln_red_kernel(const float* __restrict__ part, float* __restrict__ res,
                   const float* __restrict__ gamma, const float* __restrict__ beta,
                   __half* __restrict__ oh)
{
    int row = blockIdx.x, tid = threadIdx.x;
    float v[3];
    #pragma unroll
    for (int e = 0; e < 3; e++) {
        int idx = tid + e * 256;
        size_t o = (size_t)row * D + idx;
        float s = res[o];
        #pragma unroll
        for (int sp = 0; sp < 4; sp++) s += part[(size_t)sp * MS * D + o];
        v[e] = s;
        res[o] = s;
    }
    __shared__ float sa[8], sb2[8];
    float mean, r;
    ln_stats(v[0], v[1], v[2], sa, sb2, mean, r);
    #pragma unroll
    for (int e = 0; e < 3; e++) {
        int idx = tid + e * 256;
        float y = (v[e] - mean) * r * gamma[idx] + beta[idx];
        oh[(size_t)row * D + idx] = __float2half_rn(y);
    }
}

// h = res + sum part; slots = LN_f(h);  LN_s(slots) -> qn(fp16) (next step)
__global__ __launch_bounds__(256)
void ln_red_dual_kernel(const float* __restrict__ part, const float* __restrict__ res,
                        float* __restrict__ slots,
                        const float* __restrict__ gf, const float* __restrict__ bf,
                        const float* __restrict__ gs, const float* __restrict__ bs,
                        __half* __restrict__ qh)
{
    int row = blockIdx.x, tid = threadIdx.x;
    float v[3];
    #pragma unroll
    for (int e = 0; e < 3; e++) {
        int idx = tid + e * 256;
        size_t o = (size_t)row * D + idx;
        float s = res[o];
        #pragma unroll
        for (int sp = 0; sp < 4; sp++) s += part[(size_t)sp * MS * D + o];
        v[e] = s;
    }
    __shared__ float sa[8], sb2[8];
    float mean, r;
    ln_stats(v[0], v[1], v[2], sa, sb2, mean, r);
    float y[3];
    #pragma unroll
    for (int e = 0; e < 3; e++) {
        int idx = tid + e * 256;
        y[e] = (v[e] - mean) * r * gf[idx] + bf[idx];
        slots[(size_t)row * D + idx] = y[e];
    }
    float mean2, r2;
    ln_stats(y[0], y[1], y[2], sa, sb2, mean2, r2);
    #pragma unroll
    for (int e = 0; e < 3; e++) {
        int idx = tid + e * 256;
        float z = (y[e] - mean2) * r2 * gs[idx] + bs[idx];
        qh[(size_t)row * D + idx] = __float2half_rn(z);
    }
}

// transpose + fp16
__global__ __launch_bounds__(256)
void wsplit_kernel(const float* __restrict__ W,
                   __half* __restrict__ Th,
                   int Krows, int Ncols, int n_off)
{
    __shared__ float tile[32][33];
    int n0 = blockIdx.x * 32, k0 = blockIdx.y * 32;
    int t = threadIdx.x;
    int tx = t & 31, ty = t >> 5;
    #pragma unroll
    for (int i = 0; i < 4; i++)
        tile[ty + i * 8][tx] = W[(size_t)(k0 + ty + i * 8) * Ncols + n0 + tx];
    __syncthreads();
    #pragma unroll
    for (int i = 0; i < 4; i++) {
        int n = n_off + n0 + ty + i * 8;
        Th[(size_t)n * Krows + k0 + tx] = __float2half_rn(tile[tx][ty + i * 8]);
    }
}

__global__ void init_slots_kernel(const float* __restrict__ noise,
                                  const float* __restrict__ mu,
                                  const float* __restrict__ ls,
                                  float* __restrict__ slots)
{
    int t = blockIdx.x * blockDim.x + threadIdx.x;
    if (t >= MS * D) return;
    int d = t % D;
    slots[t] = mu[d] + expf(ls[d]) * noise[t];
}

// ----------------------------------------------------------------------------
// dots + softmax over the slot axis; Q from split-K partials, K stored fp16
// ----------------------------------------------------------------------------
__global__ __launch_bounds__(256)
void dots_softmax_kernel(const float* __restrict__ Qpart, const __half* __restrict__ Kb,
                         float* __restrict__ attn)
{
    int b  = blockIdx.y;
    int j0 = blockIdx.x * 64;
    __shared__ __align__(16) float qs[16][64];
    __shared__ float ks[64][65];
    __shared__ float red[4][64];
    int tid = threadIdx.x;
    int tx = tid & 63, ty = tid >> 6;
    float acc[4] = {0.f, 0.f, 0.f, 0.f};
    const __half* Kp = Kb + ((size_t)b * NK + j0) * D;
    for (int k0 = 0; k0 < D; k0 += 64) {
        {
            int i = tid >> 4, kc = (tid & 15) * 4;
            size_t o = ((size_t)b * S + i) * D + k0 + kc;
            float4 v = *(const float4*)&Qpart[o];
            #pragma unroll
            for (int sp = 1; sp < 4; sp++) {
                float4 w = *(const float4*)&Qpart[(size_t)sp * MS * D + o];
                v.x += w.x; v.y += w.y; v.z += w.z; v.w += w.w;
            }
            *(float4*)&qs[i][kc] = v;
        }
        #pragma unroll
        for (int p = 0; p < 2; p++) {
            int e = tid + p * 256;
            int jj = e >> 3, kc = (e & 7) * 8;
            uint4 raw = *(const uint4*)&Kp[(size_t)jj * D + k0 + kc];
            const __half2* hp = (const __half2*)&raw;
            #pragma unroll
            for (int q = 0; q < 4; q++) {
                float2 f = __half22float2(hp[q]);
                ks[jj][kc + q * 2]     = f.x;
                ks[jj][kc + q * 2 + 1] = f.y;
            }
        }
        __syncthreads();
        #pragma unroll
        for (int kk = 0; kk < 64; kk++) {
            float kv = ks[tx][kk];
            acc[0] += qs[ty     ][kk] * kv;
            acc[1] += qs[ty +  4][kk] * kv;
            acc[2] += qs[ty +  8][kk] * kv;
            acc[3] += qs[ty + 12][kk] * kv;
        }
        __syncthreads();
    }
    #pragma unroll
    for (int r = 0; r < 4; r++) acc[r] *= kSCALE;
    float m = fmaxf(fmaxf(acc[0], acc[1]), fmaxf(acc[2], acc[3]));
    red[ty][tx] = m;
    __syncthreads();
    float M = fmaxf(fmaxf(red[0][tx], red[1][tx]), fmaxf(red[2][tx], red[3][tx]));
    __syncthreads();
    float e[4]; float s = 0.f;
    #pragma unroll
    for (int r = 0; r < 4; r++) { e[r] = expf(acc[r] - M); s += e[r]; }
    red[ty][tx] = s;
    __syncthreads();
    float Ssum = red[0][tx] + red[1][tx] + red[2][tx] + red[3][tx];
    float inv = 1.f / Ssum;
    #pragma unroll
    for (int r = 0; r < 4; r++)
        attn[((size_t)b * S + ty + r * 4) * NK + j0 + tx] = e[r] * inv + 1e-8f;
}

// updates[b,i,n] = (sum_j attn * v) / (sum_j attn) ; V stored fp16
__global__ __launch_bounds__(256)
void updates_kernel(const float* __restrict__ attn, const __half* __restrict__ V,
                    float* __restrict__ upd)
{
    int b  = blockIdx.y;
    int n0 = blockIdx.x * 64;
    __shared__ __align__(16) float as_[16][64];
    __shared__ __align__(16) float vs[64][64];
    int tid = threadIdx.x;
    int tx = tid & 63, ty = tid >> 6;
    float acc[4] = {0.f, 0.f, 0.f, 0.f};
    float ssum[4] = {0.f, 0.f, 0.f, 0.f};
    for (int j0 = 0; j0 < NK; j0 += 64) {
        {
            int i = tid >> 4, jc = (tid & 15) * 4;
            *(float4*)&as_[i][jc] =
                *(const float4*)&attn[((size_t)b * S + i) * NK + j0 + jc];
        }
        #pragma unroll
        for (int p = 0; p < 2; p++) {
            int e = tid + p * 256;
            int jj = e >> 3, nc = (e & 7) * 8;
            uint4 raw = *(const uint4*)&V[((size_t)b * NK + j0 + jj) * D + n0 + nc];
            const __half2* hp = (const __half2*)&raw;
            #pragma unroll
            for (int q = 0; q < 4; q++) {
                float2 f = __half22float2(hp[q]);
                vs[jj][nc + q * 2]     = f.x;
                vs[jj][nc + q * 2 + 1] = f.y;
            }
        }
        __syncthreads();
        #pragma unroll
        for (int jj = 0; jj < 64; jj++) {
            float vv = vs[jj][tx];
            float a0 = as_[ty][jj], a1 = as_[ty + 4][jj];
            float a2 = as_[ty + 8][jj], a3 = as_[ty + 12][jj];
            acc[0] += a0 * vv;  ssum[0] += a0;
            acc[1] += a1 * vv;  ssum[1] += a1;
            acc[2] += a2 * vv;  ssum[2] += a2;
            acc[3] += a3 * vv;  ssum[3] += a3;
        }
        __syncthreads();
    }
    #pragma unroll
    for (int r = 0; r < 4; r++)
        upd[((size_t)b * S + ty + r * 4) * D + n0 + tx] = acc[r] / ssum[r];
}

// encoder self-attention; reads QKV split-K partials; emits fp16 O
__global__ __launch_bounds__(256)
void enc_attn_kernel(const float* __restrict__ QKVpart, __half* __restrict__ Oh)
{
    int b = blockIdx.x >> 3, h = blockIdx.x & 7;
    __shared__ float qs[16][65], ks[16][65], vs[16][65];
    __shared__ float p[16][17];
    int tid = threadIdx.x;
    int i = tid >> 4, jj = tid & 15;
    {
        int r = tid >> 4, c = (tid & 15) * 4;
        size_t base = ((size_t)b * S + r) * QKV3 + h * DH + c;
        float4 vq = *(const float4*)&QKVpart[base];
        float4 vk = *(const float4*)&QKVpart[base + HD];
        float4 vv = *(const float4*)&QKVpart[base + 2 * HD];
        #pragma unroll
        for (int sp = 1; sp < 4; sp++) {
            size_t o = (size_t)sp * MS * QKV3 + base;
            float4 w;
            w = *(const float4*)&QKVpart[o];
            vq.x += w.x; vq.y += w.y; vq.z += w.z; vq.w += w.w;
            w = *(const float4*)&QKVpart[o + HD];
            vk.x += w.x; vk.y += w.y; vk.z += w.z; vk.w += w.w;
            w = *(const float4*)&QKVpart[o + 2 * HD];
            vv.x += w.x; vv.y += w.y; vv.z += w.z; vv.w += w.w;
        }
        qs[r][c] = vq.x; qs[r][c+1] = vq.y; qs[r][c+2] = vq.z; qs[r][c+3] = vq.w;
        ks[r][c] = vk.x; ks[r][c+1] = vk.y; ks[r][c+2] = vk.z; ks[r][c+3] = vk.w;
        vs[r][c] = vv.x; vs[r][c+1] = vv.y; vs[r][c+2] = vv.z; vs[r][c+3] = vv.w;
    }
    __syncthreads();
    float s = 0.f;
    #pragma unroll
    for (int d = 0; d < DH; d++) s += qs[i][d] * ks[jj][d];
    s *= 0.125f;
    p[i][jj] = s;
    __syncthreads();
    float m = -1e30f;
    #pragma unroll
    for (int t2 = 0; t2 < 16; t2++) m = fmaxf(m, p[i][t2]);
    __syncthreads();
    float e = expf(s - m);
    p[i][jj] = e;
    __syncthreads();
    float sum = 0.f;
    #pragma unroll
    for (int t2 = 0; t2 < 16; t2++) sum += p[i][t2];
    __syncthreads();
    p[i][jj] = e / sum;
    __syncthreads();
    int io = tid >> 4, dbase = (tid & 15) * 4;
    float o[4] = {0.f, 0.f, 0.f, 0.f};
    #pragma unroll
    for (int t2 = 0; t2 < 16; t2++) {
        float pp = p[io][t2];
        o[0] += pp * vs[t2][dbase + 0];
        o[1] += pp * vs[t2][dbase + 1];
        o[2] += pp * vs[t2][dbase + 2];
        o[3] += pp * vs[t2][dbase + 3];
    }
    size_t base = ((size_t)b * S + io) * HD + h * DH + dbase;
    *(__half2*)(Oh + base)     = __floats2half2_rn(o[0], o[1]);
    *(__half2*)(Oh + base + 2) = __floats2half2_rn(o[2], o[3]);
}

// output map: per (b,i) row — sum over keys then write out[b][j][i] = attn/sum
__global__ __launch_bounds__(256)
void attn_out_kernel(const float* __restrict__ attn, float* __restrict__ out)
{
    int row = blockIdx.x;            // b*S + i
    int b = row >> 4, i = row & 15;
    const float4* p = (const float4*)(attn + (size_t)row * NK);
    int tid = threadIdx.x;
    float4 v = p[tid];
    float s = v.x + v.y + v.z + v.w;
    __shared__ float sa[8];
    #pragma unroll
    for (int o = 16; o > 0; o >>= 1) s += __shfl_down_sync(0xffffffffu, s, o);
    int w = tid >> 5, l = tid & 31;
    if (l == 0) sa[w] = s;
    __syncthreads();
    if (tid == 0) {
        float ts = 0.f;
        #pragma unroll
        for (int k = 0; k < 8; k++) ts += sa[k];
        sa[0] = ts;
    }
    __syncthreads();
    float inv = 1.f / sa[0];
    size_t ob = (size_t)b * NK * S + i;
    int j = tid * 4;
    out[ob + (size_t)(j + 0) * S] = v.x * inv;
    out[ob + (size_t)(j + 1) * S] = v.y * inv;
    out[ob + (size_t)(j + 2) * S] = v.z * inv;
    out[ob + (size_t)(j + 3) * S] = v.w * inv;
}

// ----------------------------------------------------------------------------
// Host orchestration
// ----------------------------------------------------------------------------
extern "C" void kernel_launch(void* const* d_in, const int* in_sizes, int n_in,
                              void* d_out, int out_size)
{
    const float* x       = (const float*)d_in[0];
    const float* noise   = (const float*)d_in[1];
    const float* init_mu = (const float*)d_in[2];
    const float* init_ls = (const float*)d_in[3];
    const float* Wk      = (const float*)d_in[4];
    const float* Wv      = (const float*)d_in[5];
    const float* Wq      = (const float*)d_in[6];
    const float* ni_g    = (const float*)d_in[7];
    const float* ni_b    = (const float*)d_in[8];
    const float* ns_g    = (const float*)d_in[9];
    const float* ns_b    = (const float*)d_in[10];
    const float* nica_g  = (const float*)d_in[11];
    const float* nica_b  = (const float*)d_in[12];
    const float* ln1_g   = (const float*)d_in[13];
    const float* ln1_b   = (const float*)d_in[14];
    const float* Wq_a    = (const float*)d_in[15];
    const float* Wk_a    = (const float*)d_in[16];
    const float* Wv_a    = (const float*)d_in[17];
    const float* Wo_a    = (const float*)d_in[18];
    const float* ln2_g   = (const float*)d_in[19];
    const float* ln2_b   = (const float*)d_in[20];
    const float* W1      = (const float*)d_in[21];
    const float* W2      = (const float*)d_in[22];
    const float* lnf_g   = (const float*)d_in[23];
    const float* lnf_b   = (const float*)d_in[24];

    __half *xnh, *wkh, *wvh, *wqh, *wqkh, *woh, *w1h, *w2h;
    __half *qnh, *abh, *fbh, *innh, *oah, *kb, *vb;
    float *slots, *attn, *upd, *hb, *part;
    cudaGetSymbolAddress((void**)&xnh,  g_xnh);
    cudaGetSymbolAddress((void**)&wkh,  g_wkh);
    cudaGetSymbolAddress((void**)&wvh,  g_wvh);
    cudaGetSymbolAddress((void**)&wqh,  g_wqh);
    cudaGetSymbolAddress((void**)&wqkh, g_wqkh);
    cudaGetSymbolAddress((void**)&woh,  g_woh);
    cudaGetSymbolAddress((void**)&w1h,  g_w1h);
    cudaGetSymbolAddress((void**)&w2h,  g_w2h);
    cudaGetSymbolAddress((void**)&qnh,  g_qnh);
    cudaGetSymbolAddress((void**)&abh,  g_abh);
    cudaGetSymbolAddress((void**)&fbh,  g_fbh);
    cudaGetSymbolAddress((void**)&innh, g_innh);
    cudaGetSymbolAddress((void**)&oah,  g_oah);
    cudaGetSymbolAddress((void**)&kb,   g_k);
    cudaGetSymbolAddress((void**)&vb,   g_v);
    cudaGetSymbolAddress((void**)&slots,g_slots);
    cudaGetSymbolAddress((void**)&attn, g_attn);
    cudaGetSymbolAddress((void**)&upd,  g_upd);
    cudaGetSymbolAddress((void**)&hb,   g_h);
    cudaGetSymbolAddress((void**)&part, g_part);

    cudaFuncSetAttribute(hgemm_fp16, cudaFuncAttributeMaxDynamicSharedMemorySize, HG_SMEM);
    cudaFuncSetAttribute(hgemm_dual, cudaFuncAttributeMaxDynamicSharedMemorySize, DUAL_SMEM);
    cudaFuncSetAttribute(hgemm_glu,  cudaFuncAttributeMaxDynamicSharedMemorySize, GLU_SMEM);

    // ---- precompute ----
    wsplit_kernel<<<dim3(D / 32, D / 32), 256>>>(Wk, wkh, D, D, 0);
    wsplit_kernel<<<dim3(D / 32, D / 32), 256>>>(Wv, wvh, D, D, 0);
    ln_h_kernel<<<B * NK, 256>>>(x, xnh, ni_g, ni_b);
    init_slots_kernel<<<(MS * D + 255) / 256, 256>>>(noise, init_mu, init_ls, slots);
    wsplit_kernel<<<dim3(D / 32, D / 32), 256>>>(Wq, wqh, D, D, 0);
    hgemm_dual<<<dim3(D / 128, (B * NK) / 128), 256, DUAL_SMEM>>>(
        xnh, wkh, wvh, kb, vb, B * NK, D, D);
    wsplit_kernel<<<dim3(HD / 32, D / 32), 256>>>(Wq_a, wqkh, D, HD, 0);
    wsplit_kernel<<<dim3(HD / 32, D / 32), 256>>>(Wk_a, wqkh, D, HD, HD);
    wsplit_kernel<<<dim3(HD / 32, D / 32), 256>>>(Wv_a, wqkh, D, HD, 2 * HD);
    wsplit_kernel<<<dim3(D / 32, HD / 32), 256>>>(Wo_a, woh, HD, D, 0);
    wsplit_kernel<<<dim3((2 * INNER) / 32, D / 32), 256>>>(W1, w1h, D, 2 * INNER, 0);
    wsplit_kernel<<<dim3(D / 32, INNER / 32), 256>>>(W2, w2h, INNER, D, 0);
    ln_h_kernel<<<MS, 256>>>(slots, qnh, ns_g, ns_b);

    // ---- 4 slot-attention steps (11 launches each) ----
    for (int it = 0; it < N_STEPS; it++) {
        hgemm_fp16<<<dim3(D / 128, MS / 128, 4), 256, HG_SMEM>>>(qnh, wqh,
                                                                 part, MS, D, D);
        dots_softmax_kernel<<<dim3(NK / 64, B), 256>>>(part, kb, attn);
        updates_kernel<<<dim3(D / 64, B), 256>>>(attn, vb, upd);
        ln_dual_kernel<<<MS, 256>>>(slots, upd, hb, nica_g, nica_b,
                                    ln1_g, ln1_b, abh);
        hgemm_fp16<<<dim3(QKV3 / 128, MS / 128, 4), 256, HG_SMEM>>>(abh, wqkh,
                                                                    part, MS, QKV3, D);
        enc_attn_kernel<<<B * H, 256>>>(part, oah);
        hgemm_fp16<<<dim3(D / 128, MS / 128, 4), 256, HG_SMEM>>>(oah, woh,
                                                                 part, MS, D, HD);
        ln_red_kernel<<<MS, 256>>>(part, hb, ln2_g, ln2_b, fbh);
        hgemm_glu<<<dim3(INNER / 128, MS / 128), 256, GLU_SMEM>>>(fbh, w1h,
                                                                  innh, MS);
        hgemm_fp16<<<dim3(D / 128, MS / 128, 4), 256, HG_SMEM>>>(innh, w2h,
                                                                 part, MS, D, INNER);
        ln_red_dual_kernel<<<MS, 256>>>(part, hb, slots, lnf_g, lnf_b,
                                        ns_g, ns_b, qnh);
    }

    // ---- outputs: slots [32,16,768], then attn_map [32,1024,16] ----
    float* out = (float*)d_out;
    cudaMemcpyAsync(out, slots, (size_t)MS * D * sizeof(float),
                    cudaMemcpyDeviceToDevice);
    attn_out_kernel<<<MS, 256>>>(attn, out + (size_t)MS * D);
}

// round 14
// speedup vs baseline: 2.1959x; 1.2936x over previous
#include <cuda_runtime.h>
#include <cuda_fp16.h>
#include <math.h>
#include <stdint.h>

// ----------------------------------------------------------------------------
// Problem constants
// ----------------------------------------------------------------------------
#define B   32
#define NK  1024
#define S   16
#define D   768
#define H   8
#define DH  64
#define HD  (H*DH)    // 512
#define QKV3 (3*HD)   // 1536
#define INNER 3072
#define N_STEPS 4
#define MS  (B*S)     // 512
static __device__ __constant__ float kSCALE = 0.036084391824351615f;  // 768^-0.5

// ----------------------------------------------------------------------------
// Scratch (device globals)
// ----------------------------------------------------------------------------
__device__ __half g_xnh[B*NK*D];
__device__ __half g_wkh [D*D];
__device__ __half g_wvh [D*D];
__device__ __half g_wqh [D*D];
__device__ __half g_wqkh[QKV3*D];
__device__ __half g_woh [D*HD];
__device__ __half g_w1h [2*INNER*D];
__device__ __half g_w2h [D*INNER];
__device__ __half g_qnh[MS*D];
__device__ __half g_qf [MS*D];        // reduced q, fp16
__device__ __half g_abh[MS*D];
__device__ __half g_fbh[MS*D];
__device__ __half g_innh[MS*INNER];
__device__ __half g_oah[MS*HD];
__device__ __half g_k  [B*NK*D];      // [b*NK + j][d]
__device__ __half g_vt [B*D*NK];      // [b*D + n][j]  (transposed V)
__device__ __half g_attnh[MS*NK];     // fp16 attn for updates GEMM
__device__ float g_slots[MS*D];
__device__ float g_attn [MS*NK];
__device__ float g_sums [MS];
__device__ float g_upd  [MS*D];
__device__ float g_h    [MS*D];
__device__ float g_part [4*MS*QKV3];

// ----------------------------------------------------------------------------
// HMMA / cp.async helpers (baseline PTX — compiles for plain compute_103)
// ----------------------------------------------------------------------------
__device__ __forceinline__ uint32_t smem_u32(const void* p) {
    uint32_t a;
    asm("{ .reg .u64 t; cvta.to.shared.u64 t, %1; cvt.u32.u64 %0, t; }"
        : "=r"(a) : "l"(p));
    return a;
}
#define LDSM_X4(r0, r1, r2, r3, addr) \
    asm volatile("ldmatrix.sync.aligned.m8n8.x4.shared.b16 {%0,%1,%2,%3}, [%4];" \
                 : "=r"(r0), "=r"(r1), "=r"(r2), "=r"(r3) : "r"(addr))
#define LDSM_X2(r0, r1, addr) \
    asm volatile("ldmatrix.sync.aligned.m8n8.x2.shared.b16 {%0,%1}, [%2];" \
                 : "=r"(r0), "=r"(r1) : "r"(addr))
#define MMA16816(c, a, b) \
    asm volatile("mma.sync.aligned.m16n8k16.row.col.f32.f16.f16.f32 " \
                 "{%0,%1,%2,%3}, {%4,%5,%6,%7}, {%8,%9}, {%0,%1,%2,%3};" \
                 : "+f"((c)[0]), "+f"((c)[1]), "+f"((c)[2]), "+f"((c)[3]) \
                 : "r"((a)[0]), "r"((a)[1]), "r"((a)[2]), "r"((a)[3]), \
                   "r"((b)[0]), "r"((b)[1]))
#define CP_ASYNC16(dst_u32, src_ptr) \
    asm volatile("cp.async.ca.shared.global [%0], [%1], 16;" \
                 :: "r"(dst_u32), "l"(src_ptr))
#define CP_COMMIT() asm volatile("cp.async.commit_group;" ::: "memory")
#define CP_WAIT(n)  asm volatile("cp.async.wait_group %0;" :: "n"(n) : "memory")

#define PITCH 40            // halves per smem row (80 B) — conflict-free ldmatrix
#define TILEH (128 * PITCH) // halves per 128-row tile
#define TILEB (TILEH * 2)   // bytes per tile
#define ATILEB (16 * PITCH * 2)  // bytes per 16-row A tile (1280)

// ----------------------------------------------------------------------------
// Pure fp16 HMMA GEMM (C = A·B), split-K, 2-stage cp.async.
// ----------------------------------------------------------------------------
__global__ __launch_bounds__(256)
void hgemm_fp16(const __half* __restrict__ Ah, const __half* __restrict__ Bth,
                float* __restrict__ C, int M, int N, int K)
{
    extern __shared__ __align__(16) __half dyn[];
    int tid = threadIdx.x;
    int lane = tid & 31, wid = tid >> 5;
    int wm = wid >> 2, wn = wid & 3;
    int row0 = blockIdx.y * 128, col0 = blockIdx.x * 128;
    int kb   = K / gridDim.z;
    int kbeg = blockIdx.z * kb;
    float* Cz = C + (size_t)blockIdx.z * M * N;
    int nchunk = kb / 32;

    uint32_t base = smem_u32(dyn);

    float acc[4][4][4];
    #pragma unroll
    for (int mf = 0; mf < 4; mf++)
        #pragma unroll
        for (int nf = 0; nf < 4; nf++)
            #pragma unroll
            for (int e = 0; e < 4; e++) acc[mf][nf][e] = 0.f;

    int laneAr = lane & 15, laneAk = (lane & 16) ? 8 : 0;
    int laneBr = lane & 7,  laneBk = (lane & 8)  ? 8 : 0;

    auto load_stage = [&](int c, int s) {
        uint32_t sb = base + (uint32_t)s * 2 * TILEB;
        #pragma unroll
        for (int i = 0; i < 2; i++) {
            int idx = tid + i * 256;
            int row = idx >> 2, sg = idx & 3;
            size_t ga = (size_t)(row0 + row) * K + kbeg + c * 32 + sg * 8;
            size_t gb = (size_t)(col0 + row) * K + kbeg + c * 32 + sg * 8;
            uint32_t so = (uint32_t)(row * PITCH + sg * 8) * 2;
            CP_ASYNC16(sb + 0 * TILEB + so, Ah + ga);
            CP_ASYNC16(sb + 1 * TILEB + so, Bth + gb);
        }
    };

    load_stage(0, 0);
    CP_COMMIT();
    for (int c = 0; c < nchunk; c++) {
        int s = c & 1;
        if (c + 1 < nchunk) { load_stage(c + 1, s ^ 1); CP_COMMIT(); CP_WAIT(1); }
        else                { CP_WAIT(0); }
        __syncthreads();
        uint32_t bAh = base + (uint32_t)s * 2 * TILEB;
        uint32_t bBh = bAh + TILEB;
        #pragma unroll
        for (int ks = 0; ks < 32; ks += 16) {
            uint32_t bh[4][2];
            #pragma unroll
            for (int nf = 0; nf < 4; nf++) {
                uint32_t off = (uint32_t)((wn * 32 + nf * 8 + laneBr) * PITCH
                                          + ks + laneBk) * 2;
                LDSM_X2(bh[nf][0], bh[nf][1], bBh + off);
            }
            #pragma unroll
            for (int mf = 0; mf < 4; mf++) {
                uint32_t off = (uint32_t)((wm * 64 + mf * 16 + laneAr) * PITCH
                                          + ks + laneAk) * 2;
                uint32_t ah[4];
                LDSM_X4(ah[0], ah[1], ah[2], ah[3], bAh + off);
                #pragma unroll
                for (int nf = 0; nf < 4; nf++)
                    MMA16816(acc[mf][nf], ah, bh[nf]);
            }
        }
        __syncthreads();
    }
    #pragma unroll
    for (int mf = 0; mf < 4; mf++) {
        int r = row0 + wm * 64 + mf * 16 + (lane >> 2);
        #pragma unroll
        for (int nf = 0; nf < 4; nf++) {
            int c = col0 + wn * 32 + nf * 8 + (lane & 3) * 2;
            *(float2*)(Cz + (size_t)r * N + c) =
                make_float2(acc[mf][nf][0], acc[mf][nf][1]);
            *(float2*)(Cz + (size_t)(r + 8) * N + c) =
                make_float2(acc[mf][nf][2], acc[mf][nf][3]);
        }
    }
}
#define HG_SMEM (2 * 2 * TILEB)     // 40960

// ----------------------------------------------------------------------------
// Dual-output projection (K/V), pure fp16; K stored [row][n], V stored
// TRANSPOSED [b*D + n][j] for the updates HMMA GEMM.
// ----------------------------------------------------------------------------
__global__ __launch_bounds__(256)
void hgemm_dual(const __half* __restrict__ Ah,
                const __half* __restrict__ Bkh, const __half* __restrict__ Bvh,
                __half* __restrict__ Ck, __half* __restrict__ Cvt,
                int M, int N, int K)
{
    extern __shared__ __align__(16) __half dyn[];
    int tid = threadIdx.x;
    int lane = tid & 31, wid = tid >> 5;
    int wm = wid >> 2, wn = wid & 3;
    int row0 = blockIdx.y * 128, col0 = blockIdx.x * 128;
    int nchunk = K / 32;
    uint32_t base = smem_u32(dyn);

    float accK[4][4][4], accV[4][4][4];
    #pragma unroll
    for (int mf = 0; mf < 4; mf++)
        #pragma unroll
        for (int nf = 0; nf < 4; nf++)
            #pragma unroll
            for (int e = 0; e < 4; e++) { accK[mf][nf][e] = 0.f; accV[mf][nf][e] = 0.f; }

    int laneAr = lane & 15, laneAk = (lane & 16) ? 8 : 0;
    int laneBr = lane & 7,  laneBk = (lane & 8)  ? 8 : 0;

    auto load_stage = [&](int c, int s) {
        uint32_t sb = base + (uint32_t)s * 3 * TILEB;
        #pragma unroll
        for (int i = 0; i < 2; i++) {
            int idx = tid + i * 256;
            int row = idx >> 2, sg = idx & 3;
            size_t ga = (size_t)(row0 + row) * K + c * 32 + sg * 8;
            size_t gb = (size_t)(col0 + row) * K + c * 32 + sg * 8;
            uint32_t so = (uint32_t)(row * PITCH + sg * 8) * 2;
            CP_ASYNC16(sb + 0 * TILEB + so, Ah + ga);
            CP_ASYNC16(sb + 1 * TILEB + so, Bkh + gb);
            CP_ASYNC16(sb + 2 * TILEB + so, Bvh + gb);
        }
    };

    load_stage(0, 0);
    CP_COMMIT();
    for (int c = 0; c < nchunk; c++) {
        int s = c & 1;
        if (c + 1 < nchunk) { load_stage(c + 1, s ^ 1); CP_COMMIT(); CP_WAIT(1); }
        else                { CP_WAIT(0); }
        __syncthreads();
        uint32_t bAh = base + (uint32_t)s * 3 * TILEB;
        uint32_t bKh = bAh + TILEB;
        uint32_t bVh = bKh + TILEB;
        #pragma unroll
        for (int ks = 0; ks < 32; ks += 16) {
            uint32_t kh[4][2], vh[4][2];
            #pragma unroll
            for (int nf = 0; nf < 4; nf++) {
                uint32_t off = (uint32_t)((wn * 32 + nf * 8 + laneBr) * PITCH
                                          + ks + laneBk) * 2;
                LDSM_X2(kh[nf][0], kh[nf][1], bKh + off);
                LDSM_X2(vh[nf][0], vh[nf][1], bVh + off);
            }
            #pragma unroll
            for (int mf = 0; mf < 4; mf++) {
                uint32_t off = (uint32_t)((wm * 64 + mf * 16 + laneAr) * PITCH
                                          + ks + laneAk) * 2;
                uint32_t ah[4];
                LDSM_X4(ah[0], ah[1], ah[2], ah[3], bAh + off);
                #pragma unroll
                for (int nf = 0; nf < 4; nf++) {
                    MMA16816(accK[mf][nf], ah, kh[nf]);
                    MMA16816(accV[mf][nf], ah, vh[nf]);
                }
            }
        }
        __syncthreads();
    }
    #pragma unroll
    for (int mf = 0; mf < 4; mf++) {
        int r = row0 + wm * 64 + mf * 16 + (lane >> 2);
        int b0 = r >> 10, j0 = r & (NK - 1);
        int b1 = (r + 8) >> 10, j1 = (r + 8) & (NK - 1);
        #pragma unroll
        for (int nf = 0; nf < 4; nf++) {
            int c = col0 + wn * 32 + nf * 8 + (lane & 3) * 2;
            *(__half2*)(Ck + (size_t)r * N + c) =
                __floats2half2_rn(accK[mf][nf][0], accK[mf][nf][1]);
            *(__half2*)(Ck + (size_t)(r + 8) * N + c) =
                __floats2half2_rn(accK[mf][nf][2], accK[mf][nf][3]);
            // transposed V
            Cvt[((size_t)b0 * D + c    ) * NK + j0] = __float2half_rn(accV[mf][nf][0]);
            Cvt[((size_t)b0 * D + c + 1) * NK + j0] = __float2half_rn(accV[mf][nf][1]);
            Cvt[((size_t)b1 * D + c    ) * NK + j1] = __float2half_rn(accV[mf][nf][2]);
            Cvt[((size_t)b1 * D + c + 1) * NK + j1] = __float2half_rn(accV[mf][nf][3]);
        }
    }
}
#define DUAL_SMEM (2 * 3 * TILEB)   // 61440

// ----------------------------------------------------------------------------
// W1 + GLU fused, pure fp16, 2-stage pipelined; emits fp16 u*silu(g).
// ----------------------------------------------------------------------------
__global__ __launch_bounds__(256)
void hgemm_glu(const __half* __restrict__ Ah, const __half* __restrict__ W1th,
               __half* __restrict__ Ih, int M)
{
    extern __shared__ __align__(16) __half dyn[];
    int tid = threadIdx.x;
    int lane = tid & 31, wid = tid >> 5;
    int wm = wid >> 2, wn = wid & 3;
    int row0 = blockIdx.y * 128, col0 = blockIdx.x * 128;
    int nchunk = D / 32;
    uint32_t base = smem_u32(dyn);

    float accU[4][4][4], accG[4][4][4];
    #pragma unroll
    for (int mf = 0; mf < 4; mf++)
        #pragma unroll
        for (int nf = 0; nf < 4; nf++)
            #pragma unroll
            for (int e = 0; e < 4; e++) { accU[mf][nf][e] = 0.f; accG[mf][nf][e] = 0.f; }

    int laneAr = lane & 15, laneAk = (lane & 16) ? 8 : 0;
    int laneBr = lane & 7,  laneBk = (lane & 8)  ? 8 : 0;

    auto load_stage = [&](int c, int s) {
        uint32_t sb = base + (uint32_t)s * 3 * TILEB;
        #pragma unroll
        for (int i = 0; i < 2; i++) {
            int idx = tid + i * 256;
            int row = idx >> 2, sg = idx & 3;
            size_t ga = (size_t)(row0 + row) * D + c * 32 + sg * 8;
            size_t gu = (size_t)(col0 + row) * D + c * 32 + sg * 8;
            size_t gg = (size_t)(col0 + row + INNER) * D + c * 32 + sg * 8;
            uint32_t so = (uint32_t)(row * PITCH + sg * 8) * 2;
            CP_ASYNC16(sb + 0 * TILEB + so, Ah + ga);
            CP_ASYNC16(sb + 1 * TILEB + so, W1th + gu);
            CP_ASYNC16(sb + 2 * TILEB + so, W1th + gg);
        }
    };

    load_stage(0, 0);
    CP_COMMIT();
    for (int c = 0; c < nchunk; c++) {
        int s = c & 1;
        if (c + 1 < nchunk) { load_stage(c + 1, s ^ 1); CP_COMMIT(); CP_WAIT(1); }
        else                { CP_WAIT(0); }
        __syncthreads();
        uint32_t bAh = base + (uint32_t)s * 3 * TILEB;
        uint32_t bUh = bAh + TILEB;
        uint32_t bGh = bUh + TILEB;
        #pragma unroll
        for (int ks = 0; ks < 32; ks += 16) {
            uint32_t uh[4][2], gh[4][2];
            #pragma unroll
            for (int nf = 0; nf < 4; nf++) {
                uint32_t off = (uint32_t)((wn * 32 + nf * 8 + laneBr) * PITCH
                                          + ks + laneBk) * 2;
                LDSM_X2(uh[nf][0], uh[nf][1], bUh + off);
                LDSM_X2(gh[nf][0], gh[nf][1], bGh + off);
            }
            #pragma unroll
            for (int mf = 0; mf < 4; mf++) {
                uint32_t off = (uint32_t)((wm * 64 + mf * 16 + laneAr) * PITCH
                                          + ks + laneAk) * 2;
                uint32_t ah[4];
                LDSM_X4(ah[0], ah[1], ah[2], ah[3], bAh + off);
                #pragma unroll
                for (int nf = 0; nf < 4; nf++) {
                    MMA16816(accU[mf][nf], ah, uh[nf]);
                    MMA16816(accG[mf][nf], ah, gh[nf]);
                }
            }
        }
        __syncthreads();
    }
    #pragma unroll
    for (int mf = 0; mf < 4; mf++) {
        int r = row0 + wm * 64 + mf * 16 + (lane >> 2);
        #pragma unroll
        for (int nf = 0; nf < 4; nf++) {
            int c = col0 + wn * 32 + nf * 8 + (lane & 3) * 2;
            #pragma unroll
            for (int half_ = 0; half_ < 2; half_++) {
                int rr = r + half_ * 8;
                float u0 = accU[mf][nf][half_ * 2], u1 = accU[mf][nf][half_ * 2 + 1];
                float g0 = accG[mf][nf][half_ * 2], g1 = accG[mf][nf][half_ * 2 + 1];
                float v0 = u0 * (g0 / (1.f + expf(-g0)));
                float v1 = u1 * (g1 / (1.f + expf(-g1)));
                *(__half2*)(Ih + (size_t)rr * INNER + c) = __floats2half2_rn(v0, v1);
            }
        }
    }
}
#define GLU_SMEM (2 * 3 * TILEB)    // 61440

// ----------------------------------------------------------------------------
// dots + softmax, HMMA: per (b, 128-key tile). A = q fp16 [16xD], B = K rows.
// Softmax over the 16-slot axis via shfl_xor (C-fragment row layout).
// Emits attn fp32 + fp16.
// ----------------------------------------------------------------------------
#define DOTS_STAGE (ATILEB + TILEB)
__global__ __launch_bounds__(256)
void dots_hmma(const __half* __restrict__ Qh, const __half* __restrict__ Kb,
               float* __restrict__ attn, __half* __restrict__ attnh)
{
    extern __shared__ __align__(16) __half dyn[];
    int tid = threadIdx.x;
    int lane = tid & 31, wn = tid >> 5;     // 8 warps, each 16 cols
    int b = blockIdx.y, j0 = blockIdx.x * 128;
    uint32_t base = smem_u32(dyn);
    int nchunk = D / 32;                    // 24

    float acc[2][4];
    #pragma unroll
    for (int nf = 0; nf < 2; nf++)
        #pragma unroll
        for (int e = 0; e < 4; e++) acc[nf][e] = 0.f;

    int laneAr = lane & 15, laneAk = (lane & 16) ? 8 : 0;
    int laneBr = lane & 7,  laneBk = (lane & 8)  ? 8 : 0;

    auto load_stage = [&](int c, int s) {
        uint32_t sb = base + (uint32_t)s * DOTS_STAGE;
        if (tid < 64) {
            int row = tid >> 2, sg = tid & 3;
            size_t ga = ((size_t)b * S + row) * D + c * 32 + sg * 8;
            CP_ASYNC16(sb + (uint32_t)(row * PITCH + sg * 8) * 2, Qh + ga);
        }
        #pragma unroll
        for (int i = 0; i < 2; i++) {
            int idx = tid + i * 256;
            int row = idx >> 2, sg = idx & 3;
            size_t gb = ((size_t)b * NK + j0 + row) * D + c * 32 + sg * 8;
            CP_ASYNC16(sb + ATILEB + (uint32_t)(row * PITCH + sg * 8) * 2, Kb + gb);
        }
    };

    load_stage(0, 0);
    CP_COMMIT();
    for (int c = 0; c < nchunk; c++) {
        int s = c & 1;
        if (c + 1 < nchunk) { load_stage(c + 1, s ^ 1); CP_COMMIT(); CP_WAIT(1); }
        else                { CP_WAIT(0); }
        __syncthreads();
        uint32_t bA = base + (uint32_t)s * DOTS_STAGE;
        uint32_t bB = bA + ATILEB;
        #pragma unroll
        for (int ks = 0; ks < 32; ks += 16) {
            uint32_t ah[4];
            LDSM_X4(ah[0], ah[1], ah[2], ah[3],
                    bA + (uint32_t)(laneAr * PITCH + ks + laneAk) * 2);
            #pragma unroll
            for (int nf = 0; nf < 2; nf++) {
                uint32_t bh[2];
                LDSM_X2(bh[0], bh[1],
                        bB + (uint32_t)((wn * 16 + nf * 8 + laneBr) * PITCH
                                        + ks + laneBk) * 2);
                MMA16816(acc[nf], ah, bh);
            }
        }
        __syncthreads();
    }

    // softmax over slot axis (16 rows per column) in registers
    int r = lane >> 2;
    #pragma unroll
    for (int nf = 0; nf < 2; nf++) {
        float s0 = acc[nf][0] * kSCALE, s1 = acc[nf][1] * kSCALE;
        float s2 = acc[nf][2] * kSCALE, s3 = acc[nf][3] * kSCALE;
        // column maxima (over lanes xor 4,8,16 and the two local rows)
        float m0 = fmaxf(s0, s2), m1 = fmaxf(s1, s3);
        #pragma unroll
        for (int o = 4; o <= 16; o <<= 1) {
            m0 = fmaxf(m0, __shfl_xor_sync(0xffffffffu, m0, o));
            m1 = fmaxf(m1, __shfl_xor_sync(0xffffffffu, m1, o));
        }
        float e0 = expf(s0 - m0), e1 = expf(s1 - m1);
        float e2 = expf(s2 - m0), e3 = expf(s3 - m1);
        float t0 = e0 + e2, t1 = e1 + e3;
        #pragma unroll
        for (int o = 4; o <= 16; o <<= 1) {
            t0 += __shfl_xor_sync(0xffffffffu, t0, o);
            t1 += __shfl_xor_sync(0xffffffffu, t1, o);
        }
        float a0 = e0 / t0 + 1e-8f, a1 = e1 / t1 + 1e-8f;
        float a2 = e2 / t0 + 1e-8f, a3 = e3 / t1 + 1e-8f;
        int col = j0 + wn * 16 + nf * 8 + (lane & 3) * 2;
        size_t o0 = ((size_t)b * S + r) * NK + col;
        size_t o1 = ((size_t)b * S + r + 8) * NK + col;
        *(float2*)(attn + o0) = make_float2(a0, a1);
        *(float2*)(attn + o1) = make_float2(a2, a3);
        *(__half2*)(attnh + o0) = __floats2half2_rn(a0, a1);
        *(__half2*)(attnh + o1) = __floats2half2_rn(a2, a3);
    }
}
#define DOTS_SMEM (2 * DOTS_STAGE)   // 23040

// per-(b,i) key-sum of attn (for renormalization)
__global__ __launch_bounds__(256)
void attn_sums_kernel(const float* __restrict__ attn, float* __restrict__ sums)
{
    int row = blockIdx.x;
    const float4* p = (const float4*)(attn + (size_t)row * NK);
    int tid = threadIdx.x;
    float4 v = p[tid];
    float s = v.x + v.y + v.z + v.w;
    __shared__ float sa[8];
    #pragma unroll
    for (int o = 16; o > 0; o >>= 1) s += __shfl_down_sync(0xffffffffu, s, o);
    int w = tid >> 5, l = tid & 31;
    if (l == 0) sa[w] = s;
    __syncthreads();
    if (tid == 0) {
        float ts = 0.f;
        #pragma unroll
        for (int k = 0; k < 8; k++) ts += sa[k];
        sums[row] = ts;
    }
}

// ----------------------------------------------------------------------------
// updates, HMMA: per (b, 128-d tile). A = attn fp16 [16xNK], B = Vt rows.
// upd = (attn @ V) / ssum.
// ----------------------------------------------------------------------------
__global__ __launch_bounds__(256)
void updates_hmma(const __half* __restrict__ Ath, const __half* __restrict__ Vt,
                  const float* __restrict__ sums, float* __restrict__ upd)
{
    extern __shared__ __align__(16) __half dyn[];
    int tid = threadIdx.x;
    int lane = tid & 31, wn = tid >> 5;
    int b = blockIdx.y, n0 = blockIdx.x * 128;
    uint32_t base = smem_u32(dyn);
    int nchunk = NK / 32;                   // 32

    float acc[2][4];
    #pragma unroll
    for (int nf = 0; nf < 2; nf++)
        #pragma unroll
        for (int e = 0; e < 4; e++) acc[nf][e] = 0.f;

    int laneAr = lane & 15, laneAk = (lane & 16) ? 8 : 0;
    int laneBr = lane & 7,  laneBk = (lane & 8)  ? 8 : 0;

    auto load_stage = [&](int c, int s) {
        uint32_t sb = base + (uint32_t)s * DOTS_STAGE;
        if (tid < 64) {
            int row = tid >> 2, sg = tid & 3;
            size_t ga = ((size_t)b * S + row) * NK + c * 32 + sg * 8;
            CP_ASYNC16(sb + (uint32_t)(row * PITCH + sg * 8) * 2, Ath + ga);
        }
        #pragma unroll
        for (int i = 0; i < 2; i++) {
            int idx = tid + i * 256;
            int row = idx >> 2, sg = idx & 3;
            size_t gb = ((size_t)b * D + n0 + row) * NK + c * 32 + sg * 8;
            CP_ASYNC16(sb + ATILEB + (uint32_t)(row * PITCH + sg * 8) * 2, Vt + gb);
        }
    };

    load_stage(0, 0);
    CP_COMMIT();
    for (int c = 0; c < nchunk; c++) {
        int s = c & 1;
        if (c + 1 < nchunk) { load_stage(c + 1, s ^ 1); CP_COMMIT(); CP_WAIT(1); }
        else                { CP_WAIT(0); }
        __syncthreads();
        uint32_t bA = base + (uint32_t)s * DOTS_STAGE;
        uint32_t bB = bA + ATILEB;
        #pragma unroll
        for (int ks = 0; ks < 32; ks += 16) {
            uint32_t ah[4];
            LDSM_X4(ah[0], ah[1], ah[2], ah[3],
                    bA + (uint32_t)(laneAr * PITCH + ks + laneAk) * 2);
            #pragma unroll
            for (int nf = 0; nf < 2; nf++) {
                uint32_t bh[2];
                LDSM_X2(bh[0], bh[1],
                        bB + (uint32_t)((wn * 16 + nf * 8 + laneBr) * PITCH
                                        + ks + laneBk) * 2);
                MMA16816(acc[nf], ah, bh);
            }
        }
        __syncthreads();
    }

    int r = lane >> 2;
    float inv0 = 1.f / sums[b * S + r];
    float inv1 = 1.f / sums[b * S + r + 8];
    #pragma unroll
    for (int nf = 0; nf < 2; nf++) {
        int col = n0 + wn * 16 + nf * 8 + (lane & 3) * 2;
        *(float2*)(upd + ((size_t)b * S + r) * D + col) =
            make_float2(acc[nf][0] * inv0, acc[nf][1] * inv0);
        *(float2*)(upd + ((size_t)b * S + r + 8) * D + col) =
            make_float2(acc[nf][2] * inv1, acc[nf][3] * inv1);
    }
}

// reduce 4 Wq split-K partials -> fp16 q
__global__ __launch_bounds__(256)
void red_h_kernel(const float* __restrict__ part, __half* __restrict__ qh)
{
    int t = blockIdx.x * blockDim.x + threadIdx.x;
    if (t * 2 >= MS * D) return;
    float2 s = ((const float2*)part)[t];
    #pragma unroll
    for (int sp = 1; sp < 4; sp++) {
        float2 v = ((const float2*)(part + (size_t)sp * MS * D))[t];
        s.x += v.x; s.y += v.y;
    }
    ((__half2*)qh)[t] = __floats2half2_rn(s.x, s.y);
}

// ----------------------------------------------------------------------------
// LN reduction helper (256 threads over D=768)
// ----------------------------------------------------------------------------
__device__ __forceinline__ void ln_stats(float v0, float v1, float v2,
                                         float* sa, float* sb2,
                                         float& mean, float& rinv)
{
    float s = v0 + v1 + v2;
    float q = v0 * v0 + v1 * v1 + v2 * v2;
    int tid = threadIdx.x;
    #pragma unroll
    for (int o = 16; o > 0; o >>= 1) {
        s += __shfl_down_sync(0xffffffffu, s, o);
        q += __shfl_down_sync(0xffffffffu, q, o);
    }
    int w = tid >> 5, l = tid & 31;
    if (l == 0) { sa[w] = s; sb2[w] = q; }
    __syncthreads();
    if (tid == 0) {
        float ts = 0.f, tq = 0.f;
        #pragma unroll
        for (int k = 0; k < 8; k++) { ts += sa[k]; tq += sb2[k]; }
        sa[0] = ts; sb2[0] = tq;
    }
    __syncthreads();
    mean = sa[0] * (1.0f / D);
    float var = sb2[0] * (1.0f / D) - mean * mean;
    rinv = rsqrtf(var + 1e-5f);
    __syncthreads();
}

__global__ __launch_bounds__(256)
void ln_h_kernel(const float* __restrict__ in, __half* __restrict__ oh,
                 const float* __restrict__ gamma, const float* __restrict__ beta)
{
    int row = blockIdx.x, tid = threadIdx.x;
    const float* x = in + (size_t)row * D;
    float v[3] = {x[tid], x[tid + 256], x[tid + 512]};
    __shared__ float sa[8], sb2[8];
    float mean, r;
    ln_stats(v[0], v[1], v[2], sa, sb2, mean, r);
    #pragma unroll
    for (int e = 0; e < 3; e++) {
        int idx = tid + e * 256;
        float y = (v[e] - mean) * r * gamma[idx] + beta[idx];
        oh[(size_t)row * D + idx] = __float2half_rn(y);
    }
}

__global__ __launch_bounds__(256)
void ln_dual_kernel(const float* __restrict__ slots, const float* __restrict__ upd,
                    float* __restrict__ hb,
                    const float* __restrict__ g1, const float* __restrict__ b1,
                    const float* __restrict__ g2, const float* __restrict__ b2,
                    __half* __restrict__ oh)
{
    int row = blockIdx.x, tid = threadIdx.x;
    const float* xs = slots + (size_t)row * D;
    const float* xu = upd + (size_t)row * D;
    float v[3];
    #pragma unroll
    for (int e = 0; e < 3; e++) v[e] = xs[tid + e * 256] + xu[tid + e * 256];
    __shared__ float sa[8], sb2[8];
    float mean, r;
    ln_stats(v[0], v[1], v[2], sa, sb2, mean, r);
    float y[3];
    #pragma unroll
    for (int e = 0; e < 3; e++) {
        int idx = tid + e * 256;
        y[e] = (v[e] - mean) * r * g1[idx] + b1[idx];
        hb[(size_t)row * D + idx] = y[e];
    }
    float mean2, r2;
    ln_stats(y[0], y[1], y[2], sa, sb2, mean2, r2);
    #pragma unroll
    for (int e = 0; e < 3; e++) {
        int idx = tid + e * 256;
        float z = (y[e] - mean2) * r2 * g2[idx] + b2[idx];
        oh[(size_t)row * D + idx] = __float2half_rn(z);
    }
}

__global__ __launch_bounds__(256)
void ln_red_kernel(const float* __restrict__ part, float* __restrict__ res,
                   const float* __restrict__ gamma, const float* __restrict__ beta,
                   __half* __restrict__ oh)
{
    int row = blockIdx.x, tid = threadIdx.x;
    float v[3];
    #pragma unroll
    for (int e = 0; e < 3; e++) {
        int idx = tid + e * 256;
        size_t o = (size_t)row * D + idx;
        float s = res[o];
        #pragma unroll
        for (int sp = 0; sp < 4; sp++) s += part[(size_t)sp * MS * D + o];
        v[e] = s;
        res[o] = s;
    }
    __shared__ float sa[8], sb2[8];
    float mean, r;
    ln_stats(v[0], v[1], v[2], sa, sb2, mean, r);
    #pragma unroll
    for (int e = 0; e < 3; e++) {
        int idx = tid + e * 256;
        float y = (v[e] - mean) * r * gamma[idx] + beta[idx];
        oh[(size_t)row * D + idx] = __float2half_rn(y);
    }
}

__global__ __launch_bounds__(256)
void ln_red_dual_kernel(const float* __restrict__ part, const float* __restrict__ res,
                        float* __restrict__ slots,
                        const float* __restrict__ gf, const float* __restrict__ bf,
                        const float* __restrict__ gs, const float* __restrict__ bs,
                        __half* __restrict__ qh)
{
    int row = blockIdx.x, tid = threadIdx.x;
    float v[3];
    #pragma unroll
    for (int e = 0; e < 3; e++) {
        int idx = tid + e * 256;
        size_t o = (size_t)row * D + idx;
        float s = res[o];
        #pragma unroll
        for (int sp = 0; sp < 4; sp++) s += part[(size_t)sp * MS * D + o];
        v[e] = s;
    }
    __shared__ float sa[8], sb2[8];
    float mean, r;
    ln_stats(v[0], v[1], v[2], sa, sb2, mean, r);
    float y[3];
    #pragma unroll
    for (int e = 0; e < 3; e++) {
        int idx = tid + e * 256;
        y[e] = (v[e] - mean) * r * gf[idx] + bf[idx];
        slots[(size_t)row * D + idx] = y[e];
    }
    float mean2, r2;
    ln_stats(y[0], y[1], y[2], sa, sb2, mean2, r2);
    #pragma unroll
    for (int e = 0; e < 3; e++) {
        int idx = tid + e * 256;
        float z = (y[e] - mean2) * r2 * gs[idx] + bs[idx];
        qh[(size_t)row * D + idx] = __float2half_rn(z);
    }
}

__global__ __launch_bounds__(256)
void wsplit_kernel(const float* __restrict__ W,
                   __half* __restrict__ Th,
                   int Krows, int Ncols, int n_off)
{
    __shared__ float tile[32][33];
    int n0 = blockIdx.x * 32, k0 = blockIdx.y * 32;
    int t = threadIdx.x;
    int tx = t & 31, ty = t >> 5;
    #pragma unroll
    for (int i = 0; i < 4; i++)
        tile[ty + i * 8][tx] = W[(size_t)(k0 + ty + i * 8) * Ncols + n0 + tx];
    __syncthreads();
    #pragma unroll
    for (int i = 0; i < 4; i++) {
        int n = n_off + n0 + ty + i * 8;
        Th[(size_t)n * Krows + k0 + tx] = __float2half_rn(tile[tx][ty + i * 8]);
    }
}

__global__ void init_slots_kernel(const float* __restrict__ noise,
                                  const float* __restrict__ mu,
                                  const float* __restrict__ ls,
                                  float* __restrict__ slots)
{
    int t = blockIdx.x * blockDim.x + threadIdx.x;
    if (t >= MS * D) return;
    int d = t % D;
    slots[t] = mu[d] + expf(ls[d]) * noise[t];
}

// encoder self-attention; reads QKV split-K partials; emits fp16 O
__global__ __launch_bounds__(256)
void enc_attn_kernel(const float* __restrict__ QKVpart, __half* __restrict__ Oh)
{
    int b = blockIdx.x >> 3, h = blockIdx.x & 7;
    __shared__ float qs[16][65], ks[16][65], vs[16][65];
    __shared__ float p[16][17];
    int tid = threadIdx.x;
    int i = tid >> 4, jj = tid & 15;
    {
        int r = tid >> 4, c = (tid & 15) * 4;
        size_t base = ((size_t)b * S + r) * QKV3 + h * DH + c;
        float4 vq = *(const float4*)&QKVpart[base];
        float4 vk = *(const float4*)&QKVpart[base + HD];
        float4 vv = *(const float4*)&QKVpart[base + 2 * HD];
        #pragma unroll
        for (int sp = 1; sp < 4; sp++) {
            size_t o = (size_t)sp * MS * QKV3 + base;
            float4 w;
            w = *(const float4*)&QKVpart[o];
            vq.x += w.x; vq.y += w.y; vq.z += w.z; vq.w += w.w;
            w = *(const float4*)&QKVpart[o + HD];
            vk.x += w.x; vk.y += w.y; vk.z += w.z; vk.w += w.w;
            w = *(const float4*)&QKVpart[o + 2 * HD];
            vv.x += w.x; vv.y += w.y; vv.z += w.z; vv.w += w.w;
        }
        qs[r][c] = vq.x; qs[r][c+1] = vq.y; qs[r][c+2] = vq.z; qs[r][c+3] = vq.w;
        ks[r][c] = vk.x; ks[r][c+1] = vk.y; ks[r][c+2] = vk.z; ks[r][c+3] = vk.w;
        vs[r][c] = vv.x; vs[r][c+1] = vv.y; vs[r][c+2] = vv.z; vs[r][c+3] = vv.w;
    }
    __syncthreads();
    float s = 0.f;
    #pragma unroll
    for (int d = 0; d < DH; d++) s += qs[i][d] * ks[jj][d];
    s *= 0.125f;
    p[i][jj] = s;
    __syncthreads();
    float m = -1e30f;
    #pragma unroll
    for (int t2 = 0; t2 < 16; t2++) m = fmaxf(m, p[i][t2]);
    __syncthreads();
    float e = expf(s - m);
    p[i][jj] = e;
    __syncthreads();
    float sum = 0.f;
    #pragma unroll
    for (int t2 = 0; t2 < 16; t2++) sum += p[i][t2];
    __syncthreads();
    p[i][jj] = e / sum;
    __syncthreads();
    int io = tid >> 4, dbase = (tid & 15) * 4;
    float o[4] = {0.f, 0.f, 0.f, 0.f};
    #pragma unroll
    for (int t2 = 0; t2 < 16; t2++) {
        float pp = p[io][t2];
        o[0] += pp * vs[t2][dbase + 0];
        o[1] += pp * vs[t2][dbase + 1];
        o[2] += pp * vs[t2][dbase + 2];
        o[3] += pp * vs[t2][dbase + 3];
    }
    size_t base = ((size_t)b * S + io) * HD + h * DH + dbase;
    *(__half2*)(Oh + base)     = __floats2half2_rn(o[0], o[1]);
    *(__half2*)(Oh + base + 2) = __floats2half2_rn(o[2], o[3]);
}

// output map: per (b,i) row — sum over keys then write out[b][j][i] = attn/sum
__global__ __launch_bounds__(256)
void attn_out_kernel(const float* __restrict__ attn, float* __restrict__ out)
{
    int row = blockIdx.x;            // b*S + i
    int b = row >> 4, i = row & 15;
    const float4* p = (const float4*)(attn + (size_t)row * NK);
    int tid = threadIdx.x;
    float4 v = p[tid];
    float s = v.x + v.y + v.z + v.w;
    __shared__ float sa[8];
    #pragma unroll
    for (int o = 16; o > 0; o >>= 1) s += __shfl_down_sync(0xffffffffu, s, o);
    int w = tid >> 5, l = tid & 31;
    if (l == 0) sa[w] = s;
    __syncthreads();
    if (tid == 0) {
        float ts = 0.f;
        #pragma unroll
        for (int k = 0; k < 8; k++) ts += sa[k];
        sa[0] = ts;
    }
    __syncthreads();
    float inv = 1.f / sa[0];
    size_t ob = (size_t)b * NK * S + i;
    int j = tid * 4;
    out[ob + (size_t)(j + 0) * S] = v.x * inv;
    out[ob + (size_t)(j + 1) * S] = v.y * inv;
    out[ob + (size_t)(j + 2) * S] = v.z * inv;
    out[ob + (size_t)(j + 3) * S] = v.w * inv;
}

// ----------------------------------------------------------------------------
// Host orchestration
// ----------------------------------------------------------------------------
extern "C" void kernel_launch(void* const* d_in, const int* in_sizes, int n_in,
                              void* d_out, int out_size)
{
    const float* x       = (const float*)d_in[0];
    const float* noise   = (const float*)d_in[1];
    const float* init_mu = (const float*)d_in[2];
    const float* init_ls = (const float*)d_in[3];
    const float* Wk      = (const float*)d_in[4];
    const float* Wv      = (const float*)d_in[5];
    const float* Wq      = (const float*)d_in[6];
    const float* ni_g    = (const float*)d_in[7];
    const float* ni_b    = (const float*)d_in[8];
    const float* ns_g    = (const float*)d_in[9];
    const float* ns_b    = (const float*)d_in[10];
    const float* nica_g  = (const float*)d_in[11];
    const float* nica_b  = (const float*)d_in[12];
    const float* ln1_g   = (const float*)d_in[13];
    const float* ln1_b   = (const float*)d_in[14];
    const float* Wq_a    = (const float*)d_in[15];
    const float* Wk_a    = (const float*)d_in[16];
    const float* Wv_a    = (const float*)d_in[17];
    const float* Wo_a    = (const float*)d_in[18];
    const float* ln2_g   = (const float*)d_in[19];
    const float* ln2_b   = (const float*)d_in[20];
    const float* W1      = (const float*)d_in[21];
    const float* W2      = (const float*)d_in[22];
    const float* lnf_g   = (const float*)d_in[23];
    const float* lnf_b   = (const float*)d_in[24];

    __half *xnh, *wkh, *wvh, *wqh, *wqkh, *woh, *w1h, *w2h;
    __half *qnh, *qf, *abh, *fbh, *innh, *oah, *kb, *vt, *attnh;
    float *slots, *attn, *sums, *upd, *hb, *part;
    cudaGetSymbolAddress((void**)&xnh,  g_xnh);
    cudaGetSymbolAddress((void**)&wkh,  g_wkh);
    cudaGetSymbolAddress((void**)&wvh,  g_wvh);
    cudaGetSymbolAddress((void**)&wqh,  g_wqh);
    cudaGetSymbolAddress((void**)&wqkh, g_wqkh);
    cudaGetSymbolAddress((void**)&woh,  g_woh);
    cudaGetSymbolAddress((void**)&w1h,  g_w1h);
    cudaGetSymbolAddress((void**)&w2h,  g_w2h);
    cudaGetSymbolAddress((void**)&qnh,  g_qnh);
    cudaGetSymbolAddress((void**)&qf,   g_qf);
    cudaGetSymbolAddress((void**)&abh,  g_abh);
    cudaGetSymbolAddress((void**)&fbh,  g_fbh);
    cudaGetSymbolAddress((void**)&innh, g_innh);
    cudaGetSymbolAddress((void**)&oah,  g_oah);
    cudaGetSymbolAddress((void**)&kb,   g_k);
    cudaGetSymbolAddress((void**)&vt,   g_vt);
    cudaGetSymbolAddress((void**)&attnh,g_attnh);
    cudaGetSymbolAddress((void**)&slots,g_slots);
    cudaGetSymbolAddress((void**)&attn, g_attn);
    cudaGetSymbolAddress((void**)&sums, g_sums);
    cudaGetSymbolAddress((void**)&upd,  g_upd);
    cudaGetSymbolAddress((void**)&hb,   g_h);
    cudaGetSymbolAddress((void**)&part, g_part);

    cudaFuncSetAttribute(hgemm_fp16, cudaFuncAttributeMaxDynamicSharedMemorySize, HG_SMEM);
    cudaFuncSetAttribute(hgemm_dual, cudaFuncAttributeMaxDynamicSharedMemorySize, DUAL_SMEM);
    cudaFuncSetAttribute(hgemm_glu,  cudaFuncAttributeMaxDynamicSharedMemorySize, GLU_SMEM);
    cudaFuncSetAttribute(dots_hmma,  cudaFuncAttributeMaxDynamicSharedMemorySize, DOTS_SMEM);
    cudaFuncSetAttribute(updates_hmma, cudaFuncAttributeMaxDynamicSharedMemorySize, DOTS_SMEM);

    // ---- precompute ----
    wsplit_kernel<<<dim3(D / 32, D / 32), 256>>>(Wk, wkh, D, D, 0);
    wsplit_kernel<<<dim3(D / 32, D / 32), 256>>>(Wv, wvh, D, D, 0);
    ln_h_kernel<<<B * NK, 256>>>(x, xnh, ni_g, ni_b);
    init_slots_kernel<<<(MS * D + 255) / 256, 256>>>(noise, init_mu, init_ls, slots);
    wsplit_kernel<<<dim3(D / 32, D / 32), 256>>>(Wq, wqh, D, D, 0);
    hgemm_dual<<<dim3(D / 128, (B * NK) / 128), 256, DUAL_SMEM>>>(
        xnh, wkh, wvh, kb, vt, B * NK, D, D);
    wsplit_kernel<<<dim3(HD / 32, D / 32), 256>>>(Wq_a, wqkh, D, HD, 0);
    wsplit_kernel<<<dim3(HD / 32, D / 32), 256>>>(Wk_a, wqkh, D, HD, HD);
    wsplit_kernel<<<dim3(HD / 32, D / 32), 256>>>(Wv_a, wqkh, D, HD, 2 * HD);
    wsplit_kernel<<<dim3(D / 32, HD / 32), 256>>>(Wo_a, woh, HD, D, 0);
    wsplit_kernel<<<dim3((2 * INNER) / 32, D / 32), 256>>>(W1, w1h, D, 2 * INNER, 0);
    wsplit_kernel<<<dim3(D / 32, INNER / 32), 256>>>(W2, w2h, INNER, D, 0);
    ln_h_kernel<<<MS, 256>>>(slots, qnh, ns_g, ns_b);

    // ---- 4 slot-attention steps ----
    for (int it = 0; it < N_STEPS; it++) {
        hgemm_fp16<<<dim3(D / 128, MS / 128, 4), 256, HG_SMEM>>>(qnh, wqh,
                                                                 part, MS, D, D);
        red_h_kernel<<<(MS * D / 2 + 255) / 256, 256>>>(part, qf);
        dots_hmma<<<dim3(NK / 128, B), 256, DOTS_SMEM>>>(qf, kb, attn, attnh);
        attn_sums_kernel<<<MS, 256>>>(attn, sums);
        updates_hmma<<<dim3(D / 128, B), 256, DOTS_SMEM>>>(attnh, vt, sums, upd);
        ln_dual_kernel<<<MS, 256>>>(slots, upd, hb, nica_g, nica_b,
                                    ln1_g, ln1_b, abh);
        hgemm_fp16<<<dim3(QKV3 / 128, MS / 128, 4), 256, HG_SMEM>>>(abh, wqkh,
                                                                    part, MS, QKV3, D);
        enc_attn_kernel<<<B * H, 256>>>(part, oah);
        hgemm_fp16<<<dim3(D / 128, MS / 128, 4), 256, HG_SMEM>>>(oah, woh,
                                                                 part, MS, D, HD);
        ln_red_kernel<<<MS, 256>>>(part, hb, ln2_g, ln2_b, fbh);
        hgemm_glu<<<dim3(INNER / 128, MS / 128), 256, GLU_SMEM>>>(fbh, w1h,
                                                                  innh, MS);
        hgemm_fp16<<<dim3(D / 128, MS / 128, 4), 256, HG_SMEM>>>(innh, w2h,
                                                                 part, MS, D, INNER);
        ln_red_dual_kernel<<<MS, 256>>>(part, hb, slots, lnf_g, lnf_b,
                                        ns_g, ns_b, qnh);
    }

    // ---- outputs: slots [32,16,768], then attn_map [32,1024,16] ----
    float* out = (float*)d_out;
    cudaMemcpyAsync(out, slots, (size_t)MS * D * sizeof(float),
                    cudaMemcpyDeviceToDevice);
    attn_out_kernel<<<MS, 256>>>(attn, out + (size_t)MS * D);
}

// round 15
// speedup vs baseline: 2.2965x; 1.0458x over previous
#include <cuda_runtime.h>
#include <cuda_fp16.h>
#include <math.h>
#include <stdint.h>

// ----------------------------------------------------------------------------
// Problem constants
// ----------------------------------------------------------------------------
#define B   32
#define NK  1024
#define S   16
#define D   768
#define H   8
#define DH  64
#define HD  (H*DH)    // 512
#define QKV3 (3*HD)   // 1536
#define INNER 3072
#define N_STEPS 4
#define MS  (B*S)     // 512
static __device__ __constant__ float kSCALE = 0.036084391824351615f;  // 768^-0.5

// ----------------------------------------------------------------------------
// Scratch (device globals)
// ----------------------------------------------------------------------------
__device__ __half g_xnh[B*NK*D];
__device__ __half g_wkh [D*D];
__device__ __half g_wvh [D*D];
__device__ __half g_wqh [D*D];
__device__ __half g_wqkh[QKV3*D];
__device__ __half g_woh [D*HD];
__device__ __half g_w1h [2*INNER*D];
__device__ __half g_w2h [D*INNER];
__device__ __half g_qnh[MS*D];
__device__ __half g_qf [MS*D];        // reduced q, fp16
__device__ __half g_abh[MS*D];
__device__ __half g_fbh[MS*D];
__device__ __half g_innh[MS*INNER];
__device__ __half g_oah[MS*HD];
__device__ __half g_k  [B*NK*D];      // [b*NK + j][d]
__device__ __half g_vt [B*D*NK];      // [b*D + n][j]  (transposed V)
__device__ __half g_attnh[MS*NK];     // fp16 attn
__device__ float g_slots[MS*D];
__device__ float g_upd  [MS*D];
__device__ float g_h    [MS*D];
__device__ float g_part [4*MS*QKV3];

// ----------------------------------------------------------------------------
// HMMA / cp.async helpers (baseline PTX — compiles for plain compute_103)
// ----------------------------------------------------------------------------
__device__ __forceinline__ uint32_t smem_u32(const void* p) {
    uint32_t a;
    asm("{ .reg .u64 t; cvta.to.shared.u64 t, %1; cvt.u32.u64 %0, t; }"
        : "=r"(a) : "l"(p));
    return a;
}
#define LDSM_X4(r0, r1, r2, r3, addr) \
    asm volatile("ldmatrix.sync.aligned.m8n8.x4.shared.b16 {%0,%1,%2,%3}, [%4];" \
                 : "=r"(r0), "=r"(r1), "=r"(r2), "=r"(r3) : "r"(addr))
#define LDSM_X2(r0, r1, addr) \
    asm volatile("ldmatrix.sync.aligned.m8n8.x2.shared.b16 {%0,%1}, [%2];" \
                 : "=r"(r0), "=r"(r1) : "r"(addr))
#define MMA16816(c, a, b) \
    asm volatile("mma.sync.aligned.m16n8k16.row.col.f32.f16.f16.f32 " \
                 "{%0,%1,%2,%3}, {%4,%5,%6,%7}, {%8,%9}, {%0,%1,%2,%3};" \
                 : "+f"((c)[0]), "+f"((c)[1]), "+f"((c)[2]), "+f"((c)[3]) \
                 : "r"((a)[0]), "r"((a)[1]), "r"((a)[2]), "r"((a)[3]), \
                   "r"((b)[0]), "r"((b)[1]))
#define CP_ASYNC16(dst_u32, src_ptr) \
    asm volatile("cp.async.ca.shared.global [%0], [%1], 16;" \
                 :: "r"(dst_u32), "l"(src_ptr))
#define CP_COMMIT() asm volatile("cp.async.commit_group;" ::: "memory")
#define CP_WAIT(n)  asm volatile("cp.async.wait_group %0;" :: "n"(n) : "memory")

#define PITCH 40            // halves per smem row (80 B) — conflict-free ldmatrix
#define TILEH (128 * PITCH) // halves per 128-row tile
#define TILEB (TILEH * 2)   // bytes per tile
#define ATILEB (16 * PITCH * 2)  // bytes per 16-row A tile (1280)
#define TP 136              // transpose-tile pitch in halves (272 B, 16B-aligned)

// ----------------------------------------------------------------------------
// Pure fp16 HMMA GEMM (C = A·B), split-K, 2-stage cp.async.
// ----------------------------------------------------------------------------
__global__ __launch_bounds__(256)
void hgemm_fp16(const __half* __restrict__ Ah, const __half* __restrict__ Bth,
                float* __restrict__ C, int M, int N, int K)
{
    extern __shared__ __align__(16) __half dyn[];
    int tid = threadIdx.x;
    int lane = tid & 31, wid = tid >> 5;
    int wm = wid >> 2, wn = wid & 3;
    int row0 = blockIdx.y * 128, col0 = blockIdx.x * 128;
    int kb   = K / gridDim.z;
    int kbeg = blockIdx.z * kb;
    float* Cz = C + (size_t)blockIdx.z * M * N;
    int nchunk = kb / 32;

    uint32_t base = smem_u32(dyn);

    float acc[4][4][4];
    #pragma unroll
    for (int mf = 0; mf < 4; mf++)
        #pragma unroll
        for (int nf = 0; nf < 4; nf++)
            #pragma unroll
            for (int e = 0; e < 4; e++) acc[mf][nf][e] = 0.f;

    int laneAr = lane & 15, laneAk = (lane & 16) ? 8 : 0;
    int laneBr = lane & 7,  laneBk = (lane & 8)  ? 8 : 0;

    auto load_stage = [&](int c, int s) {
        uint32_t sb = base + (uint32_t)s * 2 * TILEB;
        #pragma unroll
        for (int i = 0; i < 2; i++) {
            int idx = tid + i * 256;
            int row = idx >> 2, sg = idx & 3;
            size_t ga = (size_t)(row0 + row) * K + kbeg + c * 32 + sg * 8;
            size_t gb = (size_t)(col0 + row) * K + kbeg + c * 32 + sg * 8;
            uint32_t so = (uint32_t)(row * PITCH + sg * 8) * 2;
            CP_ASYNC16(sb + 0 * TILEB + so, Ah + ga);
            CP_ASYNC16(sb + 1 * TILEB + so, Bth + gb);
        }
    };

    load_stage(0, 0);
    CP_COMMIT();
    for (int c = 0; c < nchunk; c++) {
        int s = c & 1;
        if (c + 1 < nchunk) { load_stage(c + 1, s ^ 1); CP_COMMIT(); CP_WAIT(1); }
        else                { CP_WAIT(0); }
        __syncthreads();
        uint32_t bAh = base + (uint32_t)s * 2 * TILEB;
        uint32_t bBh = bAh + TILEB;
        #pragma unroll
        for (int ks = 0; ks < 32; ks += 16) {
            uint32_t bh[4][2];
            #pragma unroll
            for (int nf = 0; nf < 4; nf++) {
                uint32_t off = (uint32_t)((wn * 32 + nf * 8 + laneBr) * PITCH
                                          + ks + laneBk) * 2;
                LDSM_X2(bh[nf][0], bh[nf][1], bBh + off);
            }
            #pragma unroll
            for (int mf = 0; mf < 4; mf++) {
                uint32_t off = (uint32_t)((wm * 64 + mf * 16 + laneAr) * PITCH
                                          + ks + laneAk) * 2;
                uint32_t ah[4];
                LDSM_X4(ah[0], ah[1], ah[2], ah[3], bAh + off);
                #pragma unroll
                for (int nf = 0; nf < 4; nf++)
                    MMA16816(acc[mf][nf], ah, bh[nf]);
            }
        }
        __syncthreads();
    }
    #pragma unroll
    for (int mf = 0; mf < 4; mf++) {
        int r = row0 + wm * 64 + mf * 16 + (lane >> 2);
        #pragma unroll
        for (int nf = 0; nf < 4; nf++) {
            int c = col0 + wn * 32 + nf * 8 + (lane & 3) * 2;
            *(float2*)(Cz + (size_t)r * N + c) =
                make_float2(acc[mf][nf][0], acc[mf][nf][1]);
            *(float2*)(Cz + (size_t)(r + 8) * N + c) =
                make_float2(acc[mf][nf][2], acc[mf][nf][3]);
        }
    }
}
#define HG_SMEM (2 * 2 * TILEB)     // 40960

// ----------------------------------------------------------------------------
// Dual-output projection (K/V), pure fp16; K stored [row][n], V stored
// TRANSPOSED [b*D + n][j]. Both exit through an smem staging tile so every
// global store is a full-width coalesced row.
// ----------------------------------------------------------------------------
__global__ __launch_bounds__(256)
void hgemm_dual(const __half* __restrict__ Ah,
                const __half* __restrict__ Bkh, const __half* __restrict__ Bvh,
                __half* __restrict__ Ck, __half* __restrict__ Cvt,
                int M, int N, int K)
{
    extern __shared__ __align__(16) __half dyn[];
    int tid = threadIdx.x;
    int lane = tid & 31, wid = tid >> 5;
    int wm = wid >> 2, wn = wid & 3;
    int row0 = blockIdx.y * 128, col0 = blockIdx.x * 128;
    int nchunk = K / 32;
    uint32_t base = smem_u32(dyn);

    float accK[4][4][4], accV[4][4][4];
    #pragma unroll
    for (int mf = 0; mf < 4; mf++)
        #pragma unroll
        for (int nf = 0; nf < 4; nf++)
            #pragma unroll
            for (int e = 0; e < 4; e++) { accK[mf][nf][e] = 0.f; accV[mf][nf][e] = 0.f; }

    int laneAr = lane & 15, laneAk = (lane & 16) ? 8 : 0;
    int laneBr = lane & 7,  laneBk = (lane & 8)  ? 8 : 0;

    auto load_stage = [&](int c, int s) {
        uint32_t sb = base + (uint32_t)s * 3 * TILEB;
        #pragma unroll
        for (int i = 0; i < 2; i++) {
            int idx = tid + i * 256;
            int row = idx >> 2, sg = idx & 3;
            size_t ga = (size_t)(row0 + row) * K + c * 32 + sg * 8;
            size_t gb = (size_t)(col0 + row) * K + c * 32 + sg * 8;
            uint32_t so = (uint32_t)(row * PITCH + sg * 8) * 2;
            CP_ASYNC16(sb + 0 * TILEB + so, Ah + ga);
            CP_ASYNC16(sb + 1 * TILEB + so, Bkh + gb);
            CP_ASYNC16(sb + 2 * TILEB + so, Bvh + gb);
        }
    };

    load_stage(0, 0);
    CP_COMMIT();
    for (int c = 0; c < nchunk; c++) {
        int s = c & 1;
        if (c + 1 < nchunk) { load_stage(c + 1, s ^ 1); CP_COMMIT(); CP_WAIT(1); }
        else                { CP_WAIT(0); }
        __syncthreads();
        uint32_t bAh = base + (uint32_t)s * 3 * TILEB;
        uint32_t bKh = bAh + TILEB;
        uint32_t bVh = bKh + TILEB;
        #pragma unroll
        for (int ks = 0; ks < 32; ks += 16) {
            uint32_t kh[4][2], vh[4][2];
            #pragma unroll
            for (int nf = 0; nf < 4; nf++) {
                uint32_t off = (uint32_t)((wn * 32 + nf * 8 + laneBr) * PITCH
                                          + ks + laneBk) * 2;
                LDSM_X2(kh[nf][0], kh[nf][1], bKh + off);
                LDSM_X2(vh[nf][0], vh[nf][1], bVh + off);
            }
            #pragma unroll
            for (int mf = 0; mf < 4; mf++) {
                uint32_t off = (uint32_t)((wm * 64 + mf * 16 + laneAr) * PITCH
                                          + ks + laneAk) * 2;
                uint32_t ah[4];
                LDSM_X4(ah[0], ah[1], ah[2], ah[3], bAh + off);
                #pragma unroll
                for (int nf = 0; nf < 4; nf++) {
                    MMA16816(accK[mf][nf], ah, kh[nf]);
                    MMA16816(accV[mf][nf], ah, vh[nf]);
                }
            }
        }
        __syncthreads();
    }

    // ---- epilogue via smem staging (coalesced stores) ----
    __half* tile = dyn;                 // 128 x TP halves = 34816 B
    int bb = row0 >> 10, jbase = row0 & (NK - 1);

    // V transposed: tile[n_local][r_local]
    #pragma unroll
    for (int mf = 0; mf < 4; mf++) {
        int rl = wm * 64 + mf * 16 + (lane >> 2);
        #pragma unroll
        for (int nf = 0; nf < 4; nf++) {
            int cl = wn * 32 + nf * 8 + (lane & 3) * 2;
            tile[(size_t)cl * TP + rl]           = __float2half_rn(accV[mf][nf][0]);
            tile[(size_t)(cl + 1) * TP + rl]     = __float2half_rn(accV[mf][nf][1]);
            tile[(size_t)cl * TP + rl + 8]       = __float2half_rn(accV[mf][nf][2]);
            tile[(size_t)(cl + 1) * TP + rl + 8] = __float2half_rn(accV[mf][nf][3]);
        }
    }
    __syncthreads();
    for (int idx = tid; idx < 128 * 16; idx += 256) {
        int n = idx >> 4, seg = idx & 15;
        uint4 v = *(const uint4*)&tile[(size_t)n * TP + seg * 8];
        *(uint4*)&Cvt[((size_t)bb * D + col0 + n) * NK + jbase + seg * 8] = v;
    }
    __syncthreads();

    // K: tile[r_local][n_local]
    #pragma unroll
    for (int mf = 0; mf < 4; mf++) {
        int rl = wm * 64 + mf * 16 + (lane >> 2);
        #pragma unroll
        for (int nf = 0; nf < 4; nf++) {
            int cl = wn * 32 + nf * 8 + (lane & 3) * 2;
            *(__half2*)&tile[(size_t)rl * TP + cl] =
                __floats2half2_rn(accK[mf][nf][0], accK[mf][nf][1]);
            *(__half2*)&tile[(size_t)(rl + 8) * TP + cl] =
                __floats2half2_rn(accK[mf][nf][2], accK[mf][nf][3]);
        }
    }
    __syncthreads();
    for (int idx = tid; idx < 128 * 16; idx += 256) {
        int r = idx >> 4, seg = idx & 15;
        uint4 v = *(const uint4*)&tile[(size_t)r * TP + seg * 8];
        *(uint4*)&Ck[(size_t)(row0 + r) * N + col0 + seg * 8] = v;
    }
}
#define DUAL_SMEM (2 * 3 * TILEB)   // 61440

// ----------------------------------------------------------------------------
// W1 + GLU fused, pure fp16, 2-stage pipelined; emits fp16 u*silu(g).
// ----------------------------------------------------------------------------
__global__ __launch_bounds__(256)
void hgemm_glu(const __half* __restrict__ Ah, const __half* __restrict__ W1th,
               __half* __restrict__ Ih, int M)
{
    extern __shared__ __align__(16) __half dyn[];
    int tid = threadIdx.x;
    int lane = tid & 31, wid = tid >> 5;
    int wm = wid >> 2, wn = wid & 3;
    int row0 = blockIdx.y * 128, col0 = blockIdx.x * 128;
    int nchunk = D / 32;
    uint32_t base = smem_u32(dyn);

    float accU[4][4][4], accG[4][4][4];
    #pragma unroll
    for (int mf = 0; mf < 4; mf++)
        #pragma unroll
        for (int nf = 0; nf < 4; nf++)
            #pragma unroll
            for (int e = 0; e < 4; e++) { accU[mf][nf][e] = 0.f; accG[mf][nf][e] = 0.f; }

    int laneAr = lane & 15, laneAk = (lane & 16) ? 8 : 0;
    int laneBr = lane & 7,  laneBk = (lane & 8)  ? 8 : 0;

    auto load_stage = [&](int c, int s) {
        uint32_t sb = base + (uint32_t)s * 3 * TILEB;
        #pragma unroll
        for (int i = 0; i < 2; i++) {
            int idx = tid + i * 256;
            int row = idx >> 2, sg = idx & 3;
            size_t ga = (size_t)(row0 + row) * D + c * 32 + sg * 8;
            size_t gu = (size_t)(col0 + row) * D + c * 32 + sg * 8;
            size_t gg = (size_t)(col0 + row + INNER) * D + c * 32 + sg * 8;
            uint32_t so = (uint32_t)(row * PITCH + sg * 8) * 2;
            CP_ASYNC16(sb + 0 * TILEB + so, Ah + ga);
            CP_ASYNC16(sb + 1 * TILEB + so, W1th + gu);
            CP_ASYNC16(sb + 2 * TILEB + so, W1th + gg);
        }
    };

    load_stage(0, 0);
    CP_COMMIT();
    for (int c = 0; c < nchunk; c++) {
        int s = c & 1;
        if (c + 1 < nchunk) { load_stage(c + 1, s ^ 1); CP_COMMIT(); CP_WAIT(1); }
        else                { CP_WAIT(0); }
        __syncthreads();
        uint32_t bAh = base + (uint32_t)s * 3 * TILEB;
        uint32_t bUh = bAh + TILEB;
        uint32_t bGh = bUh + TILEB;
        #pragma unroll
        for (int ks = 0; ks < 32; ks += 16) {
            uint32_t uh[4][2], gh[4][2];
            #pragma unroll
            for (int nf = 0; nf < 4; nf++) {
                uint32_t off = (uint32_t)((wn * 32 + nf * 8 + laneBr) * PITCH
                                          + ks + laneBk) * 2;
                LDSM_X2(uh[nf][0], uh[nf][1], bUh + off);
                LDSM_X2(gh[nf][0], gh[nf][1], bGh + off);
            }
            #pragma unroll
            for (int mf = 0; mf < 4; mf++) {
                uint32_t off = (uint32_t)((wm * 64 + mf * 16 + laneAr) * PITCH
                                          + ks + laneAk) * 2;
                uint32_t ah[4];
                LDSM_X4(ah[0], ah[1], ah[2], ah[3], bAh + off);
                #pragma unroll
                for (int nf = 0; nf < 4; nf++) {
                    MMA16816(accU[mf][nf], ah, uh[nf]);
                    MMA16816(accG[mf][nf], ah, gh[nf]);
                }
            }
        }
        __syncthreads();
    }
    #pragma unroll
    for (int mf = 0; mf < 4; mf++) {
        int r = row0 + wm * 64 + mf * 16 + (lane >> 2);
        #pragma unroll
        for (int nf = 0; nf < 4; nf++) {
            int c = col0 + wn * 32 + nf * 8 + (lane & 3) * 2;
            #pragma unroll
            for (int half_ = 0; half_ < 2; half_++) {
                int rr = r + half_ * 8;
                float u0 = accU[mf][nf][half_ * 2], u1 = accU[mf][nf][half_ * 2 + 1];
                float g0 = accG[mf][nf][half_ * 2], g1 = accG[mf][nf][half_ * 2 + 1];
                float v0 = u0 * (g0 / (1.f + expf(-g0)));
                float v1 = u1 * (g1 / (1.f + expf(-g1)));
                *(__half2*)(Ih + (size_t)rr * INNER + c) = __floats2half2_rn(v0, v1);
            }
        }
    }
}
#define GLU_SMEM (2 * 3 * TILEB)    // 61440

// ----------------------------------------------------------------------------
// dots + softmax, HMMA: per (b, 128-key tile). A = q fp16 [16xD], B = K rows.
// Softmax over the 16-slot axis via shfl_xor; emits attn fp16 only.
// ----------------------------------------------------------------------------
#define DOTS_STAGE (ATILEB + TILEB)
__global__ __launch_bounds__(256)
void dots_hmma(const __half* __restrict__ Qh, const __half* __restrict__ Kb,
               __half* __restrict__ attnh)
{
    extern __shared__ __align__(16) __half dyn[];
    int tid = threadIdx.x;
    int lane = tid & 31, wn = tid >> 5;     // 8 warps, each 16 cols
    int b = blockIdx.y, j0 = blockIdx.x * 128;
    uint32_t base = smem_u32(dyn);
    int nchunk = D / 32;                    // 24

    float acc[2][4];
    #pragma unroll
    for (int nf = 0; nf < 2; nf++)
        #pragma unroll
        for (int e = 0; e < 4; e++) acc[nf][e] = 0.f;

    int laneAr = lane & 15, laneAk = (lane & 16) ? 8 : 0;
    int laneBr = lane & 7,  laneBk = (lane & 8)  ? 8 : 0;

    auto load_stage = [&](int c, int s) {
        uint32_t sb = base + (uint32_t)s * DOTS_STAGE;
        if (tid < 64) {
            int row = tid >> 2, sg = tid & 3;
            size_t ga = ((size_t)b * S + row) * D + c * 32 + sg * 8;
            CP_ASYNC16(sb + (uint32_t)(row * PITCH + sg * 8) * 2, Qh + ga);
        }
        #pragma unroll
        for (int i = 0; i < 2; i++) {
            int idx = tid + i * 256;
            int row = idx >> 2, sg = idx & 3;
            size_t gb = ((size_t)b * NK + j0 + row) * D + c * 32 + sg * 8;
            CP_ASYNC16(sb + ATILEB + (uint32_t)(row * PITCH + sg * 8) * 2, Kb + gb);
        }
    };

    load_stage(0, 0);
    CP_COMMIT();
    for (int c = 0; c < nchunk; c++) {
        int s = c & 1;
        if (c + 1 < nchunk) { load_stage(c + 1, s ^ 1); CP_COMMIT(); CP_WAIT(1); }
        else                { CP_WAIT(0); }
        __syncthreads();
        uint32_t bA = base + (uint32_t)s * DOTS_STAGE;
        uint32_t bB = bA + ATILEB;
        #pragma unroll
        for (int ks = 0; ks < 32; ks += 16) {
            uint32_t ah[4];
            LDSM_X4(ah[0], ah[1], ah[2], ah[3],
                    bA + (uint32_t)(laneAr * PITCH + ks + laneAk) * 2);
            #pragma unroll
            for (int nf = 0; nf < 2; nf++) {
                uint32_t bh[2];
                LDSM_X2(bh[0], bh[1],
                        bB + (uint32_t)((wn * 16 + nf * 8 + laneBr) * PITCH
                                        + ks + laneBk) * 2);
                MMA16816(acc[nf], ah, bh);
            }
        }
        __syncthreads();
    }

    // softmax over slot axis (16 rows per column) in registers
    int r = lane >> 2;
    #pragma unroll
    for (int nf = 0; nf < 2; nf++) {
        float s0 = acc[nf][0] * kSCALE, s1 = acc[nf][1] * kSCALE;
        float s2 = acc[nf][2] * kSCALE, s3 = acc[nf][3] * kSCALE;
        float m0 = fmaxf(s0, s2), m1 = fmaxf(s1, s3);
        #pragma unroll
        for (int o = 4; o <= 16; o <<= 1) {
            m0 = fmaxf(m0, __shfl_xor_sync(0xffffffffu, m0, o));
            m1 = fmaxf(m1, __shfl_xor_sync(0xffffffffu, m1, o));
        }
        float e0 = expf(s0 - m0), e1 = expf(s1 - m1);
        float e2 = expf(s2 - m0), e3 = expf(s3 - m1);
        float t0 = e0 + e2, t1 = e1 + e3;
        #pragma unroll
        for (int o = 4; o <= 16; o <<= 1) {
            t0 += __shfl_xor_sync(0xffffffffu, t0, o);
            t1 += __shfl_xor_sync(0xffffffffu, t1, o);
        }
        float a0 = e0 / t0 + 1e-8f, a1 = e1 / t1 + 1e-8f;
        float a2 = e2 / t0 + 1e-8f, a3 = e3 / t1 + 1e-8f;
        int col = j0 + wn * 16 + nf * 8 + (lane & 3) * 2;
        size_t o0 = ((size_t)b * S + r) * NK + col;
        size_t o1 = ((size_t)b * S + r + 8) * NK + col;
        *(__half2*)(attnh + o0) = __floats2half2_rn(a0, a1);
        *(__half2*)(attnh + o1) = __floats2half2_rn(a2, a3);
    }
}
#define DOTS_SMEM (2 * DOTS_STAGE)   // 23040

// ----------------------------------------------------------------------------
// updates, HMMA: per (b, 128-d tile). A = attn fp16 [16xNK], B = Vt rows.
// Row sums via an all-ones B fragment; upd = (attn @ V) / rowsum.
// ----------------------------------------------------------------------------
__global__ __launch_bounds__(256)
void updates_hmma(const __half* __restrict__ Ath, const __half* __restrict__ Vt,
                  float* __restrict__ upd)
{
    extern __shared__ __align__(16) __half dyn[];
    int tid = threadIdx.x;
    int lane = tid & 31, wn = tid >> 5;
    int b = blockIdx.y, n0 = blockIdx.x * 128;
    uint32_t base = smem_u32(dyn);
    int nchunk = NK / 32;                   // 32

    float acc[2][4];
    float accS[4] = {0.f, 0.f, 0.f, 0.f};
    #pragma unroll
    for (int nf = 0; nf < 2; nf++)
        #pragma unroll
        for (int e = 0; e < 4; e++) acc[nf][e] = 0.f;

    int laneAr = lane & 15, laneAk = (lane & 16) ? 8 : 0;
    int laneBr = lane & 7,  laneBk = (lane & 8)  ? 8 : 0;
    uint32_t ones[2] = {0x3C003C00u, 0x3C003C00u};

    auto load_stage = [&](int c, int s) {
        uint32_t sb = base + (uint32_t)s * DOTS_STAGE;
        if (tid < 64) {
            int row = tid >> 2, sg = tid & 3;
            size_t ga = ((size_t)b * S + row) * NK + c * 32 + sg * 8;
            CP_ASYNC16(sb + (uint32_t)(row * PITCH + sg * 8) * 2, Ath + ga);
        }
        #pragma unroll
        for (int i = 0; i < 2; i++) {
            int idx = tid + i * 256;
            int row = idx >> 2, sg = idx & 3;
            size_t gb = ((size_t)b * D + n0 + row) * NK + c * 32 + sg * 8;
            CP_ASYNC16(sb + ATILEB + (uint32_t)(row * PITCH + sg * 8) * 2, Vt + gb);
        }
    };

    load_stage(0, 0);
    CP_COMMIT();
    for (int c = 0; c < nchunk; c++) {
        int s = c & 1;
        if (c + 1 < nchunk) { load_stage(c + 1, s ^ 1); CP_COMMIT(); CP_WAIT(1); }
        else                { CP_WAIT(0); }
        __syncthreads();
        uint32_t bA = base + (uint32_t)s * DOTS_STAGE;
        uint32_t bB = bA + ATILEB;
        #pragma unroll
        for (int ks = 0; ks < 32; ks += 16) {
            uint32_t ah[4];
            LDSM_X4(ah[0], ah[1], ah[2], ah[3],
                    bA + (uint32_t)(laneAr * PITCH + ks + laneAk) * 2);
            MMA16816(accS, ah, ones);
            #pragma unroll
            for (int nf = 0; nf < 2; nf++) {
                uint32_t bh[2];
                LDSM_X2(bh[0], bh[1],
                        bB + (uint32_t)((wn * 16 + nf * 8 + laneBr) * PITCH
                                        + ks + laneBk) * 2);
                MMA16816(acc[nf], ah, bh);
            }
        }
        __syncthreads();
    }

    int r = lane >> 2;
    float inv0 = 1.f / accS[0];
    float inv1 = 1.f / accS[2];
    #pragma unroll
    for (int nf = 0; nf < 2; nf++) {
        int col = n0 + wn * 16 + nf * 8 + (lane & 3) * 2;
        *(float2*)(upd + ((size_t)b * S + r) * D + col) =
            make_float2(acc[nf][0] * inv0, acc[nf][1] * inv0);
        *(float2*)(upd + ((size_t)b * S + r + 8) * D + col) =
            make_float2(acc[nf][2] * inv1, acc[nf][3] * inv1);
    }
}

// reduce 4 Wq split-K partials -> fp16 q
__global__ __launch_bounds__(256)
void red_h_kernel(const float* __restrict__ part, __half* __restrict__ qh)
{
    int t = blockIdx.x * blockDim.x + threadIdx.x;
    if (t * 2 >= MS * D) return;
    float2 s = ((const float2*)part)[t];
    #pragma unroll
    for (int sp = 1; sp < 4; sp++) {
        float2 v = ((const float2*)(part + (size_t)sp * MS * D))[t];
        s.x += v.x; s.y += v.y;
    }
    ((__half2*)qh)[t] = __floats2half2_rn(s.x, s.y);
}

// ----------------------------------------------------------------------------
// LN reduction helper (256 threads over D=768)
// ----------------------------------------------------------------------------
__device__ __forceinline__ void ln_stats(float v0, float v1, float v2,
                                         float* sa, float* sb2,
                                         float& mean, float& rinv)
{
    float s = v0 + v1 + v2;
    float q = v0 * v0 + v1 * v1 + v2 * v2;
    int tid = threadIdx.x;
    #pragma unroll
    for (int o = 16; o > 0; o >>= 1) {
        s += __shfl_down_sync(0xffffffffu, s, o);
        q += __shfl_down_sync(0xffffffffu, q, o);
    }
    int w = tid >> 5, l = tid & 31;
    if (l == 0) { sa[w] = s; sb2[w] = q; }
    __syncthreads();
    if (tid == 0) {
        float ts = 0.f, tq = 0.f;
        #pragma unroll
        for (int k = 0; k < 8; k++) { ts += sa[k]; tq += sb2[k]; }
        sa[0] = ts; sb2[0] = tq;
    }
    __syncthreads();
    mean = sa[0] * (1.0f / D);
    float var = sb2[0] * (1.0f / D) - mean * mean;
    rinv = rsqrtf(var + 1e-5f);
    __syncthreads();
}

__global__ __launch_bounds__(256)
void ln_h_kernel(const float* __restrict__ in, __half* __restrict__ oh,
                 const float* __restrict__ gamma, const float* __restrict__ beta)
{
    int row = blockIdx.x, tid = threadIdx.x;
    const float* x = in + (size_t)row * D;
    float v[3] = {x[tid], x[tid + 256], x[tid + 512]};
    __shared__ float sa[8], sb2[8];
    float mean, r;
    ln_stats(v[0], v[1], v[2], sa, sb2, mean, r);
    #pragma unroll
    for (int e = 0; e < 3; e++) {
        int idx = tid + e * 256;
        float y = (v[e] - mean) * r * gamma[idx] + beta[idx];
        oh[(size_t)row * D + idx] = __float2half_rn(y);
    }
}

__global__ __launch_bounds__(256)
void ln_dual_kernel(const float* __restrict__ slots, const float* __restrict__ upd,
                    float* __restrict__ hb,
                    const float* __restrict__ g1, const float* __restrict__ b1,
                    const float* __restrict__ g2, const float* __restrict__ b2,
                    __half* __restrict__ oh)
{
    int row = blockIdx.x, tid = threadIdx.x;
    const float* xs = slots + (size_t)row * D;
    const float* xu = upd + (size_t)row * D;
    float v[3];
    #pragma unroll
    for (int e = 0; e < 3; e++) v[e] = xs[tid + e * 256] + xu[tid + e * 256];
    __shared__ float sa[8], sb2[8];
    float mean, r;
    ln_stats(v[0], v[1], v[2], sa, sb2, mean, r);
    float y[3];
    #pragma unroll
    for (int e = 0; e < 3; e++) {
        int idx = tid + e * 256;
        y[e] = (v[e] - mean) * r * g1[idx] + b1[idx];
        hb[(size_t)row * D + idx] = y[e];
    }
    float mean2, r2;
    ln_stats(y[0], y[1], y[2], sa, sb2, mean2, r2);
    #pragma unroll
    for (int e = 0; e < 3; e++) {
        int idx = tid + e * 256;
        float z = (y[e] - mean2) * r2 * g2[idx] + b2[idx];
        oh[(size_t)row * D + idx] = __float2half_rn(z);
    }
}

__global__ __launch_bounds__(256)
void ln_red_kernel(const float* __restrict__ part, float* __restrict__ res,
                   const float* __restrict__ gamma, const float* __restrict__ beta,
                   __half* __restrict__ oh)
{
    int row = blockIdx.x, tid = threadIdx.x;
    float v[3];
    #pragma unroll
    for (int e = 0; e < 3; e++) {
        int idx = tid + e * 256;
        size_t o = (size_t)row * D + idx;
        float s = res[o];
        #pragma unroll
        for (int sp = 0; sp < 4; sp++) s += part[(size_t)sp * MS * D + o];
        v[e] = s;
        res[o] = s;
    }
    __shared__ float sa[8], sb2[8];
    float mean, r;
    ln_stats(v[0], v[1], v[2], sa, sb2, mean, r);
    #pragma unroll
    for (int e = 0; e < 3; e++) {
        int idx = tid + e * 256;
        float y = (v[e] - mean) * r * gamma[idx] + beta[idx];
        oh[(size_t)row * D + idx] = __float2half_rn(y);
    }
}

__global__ __launch_bounds__(256)
void ln_red_dual_kernel(const float* __restrict__ part, const float* __restrict__ res,
                        float* __restrict__ slots,
                        const float* __restrict__ gf, const float* __restrict__ bf,
                        const float* __restrict__ gs, const float* __restrict__ bs,
                        __half* __restrict__ qh)
{
    int row = blockIdx.x, tid = threadIdx.x;
    float v[3];
    #pragma unroll
    for (int e = 0; e < 3; e++) {
        int idx = tid + e * 256;
        size_t o = (size_t)row * D + idx;
        float s = res[o];
        #pragma unroll
        for (int sp = 0; sp < 4; sp++) s += part[(size_t)sp * MS * D + o];
        v[e] = s;
    }
    __shared__ float sa[8], sb2[8];
    float mean, r;
    ln_stats(v[0], v[1], v[2], sa, sb2, mean, r);
    float y[3];
    #pragma unroll
    for (int e = 0; e < 3; e++) {
        int idx = tid + e * 256;
        y[e] = (v[e] - mean) * r * gf[idx] + bf[idx];
        slots[(size_t)row * D + idx] = y[e];
    }
    float mean2, r2;
    ln_stats(y[0], y[1], y[2], sa, sb2, mean2, r2);
    #pragma unroll
    for (int e = 0; e < 3; e++) {
        int idx = tid + e * 256;
        float z = (y[e] - mean2) * r2 * gs[idx] + bs[idx];
        qh[(size_t)row * D + idx] = __float2half_rn(z);
    }
}

__global__ __launch_bounds__(256)
void wsplit_kernel(const float* __restrict__ W,
                   __half* __restrict__ Th,
                   int Krows, int Ncols, int n_off)
{
    __shared__ float tile[32][33];
    int n0 = blockIdx.x * 32, k0 = blockIdx.y * 32;
    int t = threadIdx.x;
    int tx = t & 31, ty = t >> 5;
    #pragma unroll
    for (int i = 0; i < 4; i++)
        tile[ty + i * 8][tx] = W[(size_t)(k0 + ty + i * 8) * Ncols + n0 + tx];
    __syncthreads();
    #pragma unroll
    for (int i = 0; i < 4; i++) {
        int n = n_off + n0 + ty + i * 8;
        Th[(size_t)n * Krows + k0 + tx] = __float2half_rn(tile[tx][ty + i * 8]);
    }
}

__global__ void init_slots_kernel(const float* __restrict__ noise,
                                  const float* __restrict__ mu,
                                  const float* __restrict__ ls,
                                  float* __restrict__ slots)
{
    int t = blockIdx.x * blockDim.x + threadIdx.x;
    if (t >= MS * D) return;
    int d = t % D;
    slots[t] = mu[d] + expf(ls[d]) * noise[t];
}

// encoder self-attention; reads QKV split-K partials; emits fp16 O
__global__ __launch_bounds__(256)
void enc_attn_kernel(const float* __restrict__ QKVpart, __half* __restrict__ Oh)
{
    int b = blockIdx.x >> 3, h = blockIdx.x & 7;
    __shared__ float qs[16][65], ks[16][65], vs[16][65];
    __shared__ float p[16][17];
    int tid = threadIdx.x;
    int i = tid >> 4, jj = tid & 15;
    {
        int r = tid >> 4, c = (tid & 15) * 4;
        size_t base = ((size_t)b * S + r) * QKV3 + h * DH + c;
        float4 vq = *(const float4*)&QKVpart[base];
        float4 vk = *(const float4*)&QKVpart[base + HD];
        float4 vv = *(const float4*)&QKVpart[base + 2 * HD];
        #pragma unroll
        for (int sp = 1; sp < 4; sp++) {
            size_t o = (size_t)sp * MS * QKV3 + base;
            float4 w;
            w = *(const float4*)&QKVpart[o];
            vq.x += w.x; vq.y += w.y; vq.z += w.z; vq.w += w.w;
            w = *(const float4*)&QKVpart[o + HD];
            vk.x += w.x; vk.y += w.y; vk.z += w.z; vk.w += w.w;
            w = *(const float4*)&QKVpart[o + 2 * HD];
            vv.x += w.x; vv.y += w.y; vv.z += w.z; vv.w += w.w;
        }
        qs[r][c] = vq.x; qs[r][c+1] = vq.y; qs[r][c+2] = vq.z; qs[r][c+3] = vq.w;
        ks[r][c] = vk.x; ks[r][c+1] = vk.y; ks[r][c+2] = vk.z; ks[r][c+3] = vk.w;
        vs[r][c] = vv.x; vs[r][c+1] = vv.y; vs[r][c+2] = vv.z; vs[r][c+3] = vv.w;
    }
    __syncthreads();
    float s = 0.f;
    #pragma unroll
    for (int d = 0; d < DH; d++) s += qs[i][d] * ks[jj][d];
    s *= 0.125f;
    p[i][jj] = s;
    __syncthreads();
    float m = -1e30f;
    #pragma unroll
    for (int t2 = 0; t2 < 16; t2++) m = fmaxf(m, p[i][t2]);
    __syncthreads();
    float e = expf(s - m);
    p[i][jj] = e;
    __syncthreads();
    float sum = 0.f;
    #pragma unroll
    for (int t2 = 0; t2 < 16; t2++) sum += p[i][t2];
    __syncthreads();
    p[i][jj] = e / sum;
    __syncthreads();
    int io = tid >> 4, dbase = (tid & 15) * 4;
    float o[4] = {0.f, 0.f, 0.f, 0.f};
    #pragma unroll
    for (int t2 = 0; t2 < 16; t2++) {
        float pp = p[io][t2];
        o[0] += pp * vs[t2][dbase + 0];
        o[1] += pp * vs[t2][dbase + 1];
        o[2] += pp * vs[t2][dbase + 2];
        o[3] += pp * vs[t2][dbase + 3];
    }
    size_t base = ((size_t)b * S + io) * HD + h * DH + dbase;
    *(__half2*)(Oh + base)     = __floats2half2_rn(o[0], o[1]);
    *(__half2*)(Oh + base + 2) = __floats2half2_rn(o[2], o[3]);
}

// output map from fp16 attn: per (b,i) row — sum keys, write out[b][j][i]
__global__ __launch_bounds__(256)
void attn_out_kernel(const __half* __restrict__ attnh, float* __restrict__ out)
{
    int row = blockIdx.x;            // b*S + i
    int b = row >> 4, i = row & 15;
    const __half2* p = (const __half2*)(attnh + (size_t)row * NK);
    int tid = threadIdx.x;
    float2 v0 = __half22float2(p[tid * 2]);
    float2 v1 = __half22float2(p[tid * 2 + 1]);
    float s = v0.x + v0.y + v1.x + v1.y;
    __shared__ float sa[8];
    #pragma unroll
    for (int o = 16; o > 0; o >>= 1) s += __shfl_down_sync(0xffffffffu, s, o);
    int w = tid >> 5, l = tid & 31;
    if (l == 0) sa[w] = s;
    __syncthreads();
    if (tid == 0) {
        float ts = 0.f;
        #pragma unroll
        for (int k = 0; k < 8; k++) ts += sa[k];
        sa[0] = ts;
    }
    __syncthreads();
    float inv = 1.f / sa[0];
    size_t ob = (size_t)b * NK * S + i;
    int j = tid * 4;
    out[ob + (size_t)(j + 0) * S] = v0.x * inv;
    out[ob + (size_t)(j + 1) * S] = v0.y * inv;
    out[ob + (size_t)(j + 2) * S] = v1.x * inv;
    out[ob + (size_t)(j + 3) * S] = v1.y * inv;
}

// ----------------------------------------------------------------------------
// Host orchestration
// ----------------------------------------------------------------------------
extern "C" void kernel_launch(void* const* d_in, const int* in_sizes, int n_in,
                              void* d_out, int out_size)
{
    const float* x       = (const float*)d_in[0];
    const float* noise   = (const float*)d_in[1];
    const float* init_mu = (const float*)d_in[2];
    const float* init_ls = (const float*)d_in[3];
    const float* Wk      = (const float*)d_in[4];
    const float* Wv      = (const float*)d_in[5];
    const float* Wq      = (const float*)d_in[6];
    const float* ni_g    = (const float*)d_in[7];
    const float* ni_b    = (const float*)d_in[8];
    const float* ns_g    = (const float*)d_in[9];
    const float* ns_b    = (const float*)d_in[10];
    const float* nica_g  = (const float*)d_in[11];
    const float* nica_b  = (const float*)d_in[12];
    const float* ln1_g   = (const float*)d_in[13];
    const float* ln1_b   = (const float*)d_in[14];
    const float* Wq_a    = (const float*)d_in[15];
    const float* Wk_a    = (const float*)d_in[16];
    const float* Wv_a    = (const float*)d_in[17];
    const float* Wo_a    = (const float*)d_in[18];
    const float* ln2_g   = (const float*)d_in[19];
    const float* ln2_b   = (const float*)d_in[20];
    const float* W1      = (const float*)d_in[21];
    const float* W2      = (const float*)d_in[22];
    const float* lnf_g   = (const float*)d_in[23];
    const float* lnf_b   = (const float*)d_in[24];

    __half *xnh, *wkh, *wvh, *wqh, *wqkh, *woh, *w1h, *w2h;
    __half *qnh, *qf, *abh, *fbh, *innh, *oah, *kb, *vt, *attnh;
    float *slots, *upd, *hb, *part;
    cudaGetSymbolAddress((void**)&xnh,  g_xnh);
    cudaGetSymbolAddress((void**)&wkh,  g_wkh);
    cudaGetSymbolAddress((void**)&wvh,  g_wvh);
    cudaGetSymbolAddress((void**)&wqh,  g_wqh);
    cudaGetSymbolAddress((void**)&wqkh, g_wqkh);
    cudaGetSymbolAddress((void**)&woh,  g_woh);
    cudaGetSymbolAddress((void**)&w1h,  g_w1h);
    cudaGetSymbolAddress((void**)&w2h,  g_w2h);
    cudaGetSymbolAddress((void**)&qnh,  g_qnh);
    cudaGetSymbolAddress((void**)&qf,   g_qf);
    cudaGetSymbolAddress((void**)&abh,  g_abh);
    cudaGetSymbolAddress((void**)&fbh,  g_fbh);
    cudaGetSymbolAddress((void**)&innh, g_innh);
    cudaGetSymbolAddress((void**)&oah,  g_oah);
    cudaGetSymbolAddress((void**)&kb,   g_k);
    cudaGetSymbolAddress((void**)&vt,   g_vt);
    cudaGetSymbolAddress((void**)&attnh,g_attnh);
    cudaGetSymbolAddress((void**)&slots,g_slots);
    cudaGetSymbolAddress((void**)&upd,  g_upd);
    cudaGetSymbolAddress((void**)&hb,   g_h);
    cudaGetSymbolAddress((void**)&part, g_part);

    cudaFuncSetAttribute(hgemm_fp16, cudaFuncAttributeMaxDynamicSharedMemorySize, HG_SMEM);
    cudaFuncSetAttribute(hgemm_dual, cudaFuncAttributeMaxDynamicSharedMemorySize, DUAL_SMEM);
    cudaFuncSetAttribute(hgemm_glu,  cudaFuncAttributeMaxDynamicSharedMemorySize, GLU_SMEM);
    cudaFuncSetAttribute(dots_hmma,  cudaFuncAttributeMaxDynamicSharedMemorySize, DOTS_SMEM);
    cudaFuncSetAttribute(updates_hmma, cudaFuncAttributeMaxDynamicSharedMemorySize, DOTS_SMEM);

    // ---- precompute ----
    wsplit_kernel<<<dim3(D / 32, D / 32), 256>>>(Wk, wkh, D, D, 0);
    wsplit_kernel<<<dim3(D / 32, D / 32), 256>>>(Wv, wvh, D, D, 0);
    ln_h_kernel<<<B * NK, 256>>>(x, xnh, ni_g, ni_b);
    init_slots_kernel<<<(MS * D + 255) / 256, 256>>>(noise, init_mu, init_ls, slots);
    wsplit_kernel<<<dim3(D / 32, D / 32), 256>>>(Wq, wqh, D, D, 0);
    hgemm_dual<<<dim3(D / 128, (B * NK) / 128), 256, DUAL_SMEM>>>(
        xnh, wkh, wvh, kb, vt, B * NK, D, D);
    wsplit_kernel<<<dim3(HD / 32, D / 32), 256>>>(Wq_a, wqkh, D, HD, 0);
    wsplit_kernel<<<dim3(HD / 32, D / 32), 256>>>(Wk_a, wqkh, D, HD, HD);
    wsplit_kernel<<<dim3(HD / 32, D / 32), 256>>>(Wv_a, wqkh, D, HD, 2 * HD);
    wsplit_kernel<<<dim3(D / 32, HD / 32), 256>>>(Wo_a, woh, HD, D, 0);
    wsplit_kernel<<<dim3((2 * INNER) / 32, D / 32), 256>>>(W1, w1h, D, 2 * INNER, 0);
    wsplit_kernel<<<dim3(D / 32, INNER / 32), 256>>>(W2, w2h, INNER, D, 0);
    ln_h_kernel<<<MS, 256>>>(slots, qnh, ns_g, ns_b);

    // ---- 4 slot-attention steps (12 launches each) ----
    for (int it = 0; it < N_STEPS; it++) {
        hgemm_fp16<<<dim3(D / 128, MS / 128, 4), 256, HG_SMEM>>>(qnh, wqh,
                                                                 part, MS, D, D);
        red_h_kernel<<<(MS * D / 2 + 255) / 256, 256>>>(part, qf);
        dots_hmma<<<dim3(NK / 128, B), 256, DOTS_SMEM>>>(qf, kb, attnh);
        updates_hmma<<<dim3(D / 128, B), 256, DOTS_SMEM>>>(attnh, vt, upd);
        ln_dual_kernel<<<MS, 256>>>(slots, upd, hb, nica_g, nica_b,
                                    ln1_g, ln1_b, abh);
        hgemm_fp16<<<dim3(QKV3 / 128, MS / 128, 4), 256, HG_SMEM>>>(abh, wqkh,
                                                                    part, MS, QKV3, D);
        enc_attn_kernel<<<B * H, 256>>>(part, oah);
        hgemm_fp16<<<dim3(D / 128, MS / 128, 4), 256, HG_SMEM>>>(oah, woh,
                                                                 part, MS, D, HD);
        ln_red_kernel<<<MS, 256>>>(part, hb, ln2_g, ln2_b, fbh);
        hgemm_glu<<<dim3(INNER / 128, MS / 128), 256, GLU_SMEM>>>(fbh, w1h,
                                                                  innh, MS);
        hgemm_fp16<<<dim3(D / 128, MS / 128, 4), 256, HG_SMEM>>>(innh, w2h,
                                                                 part, MS, D, INNER);
        ln_red_dual_kernel<<<MS, 256>>>(part, hb, slots, lnf_g, lnf_b,
                                        ns_g, ns_b, qnh);
    }

    // ---- outputs: slots [32,16,768], then attn_map [32,1024,16] ----
    float* out = (float*)d_out;
    cudaMemcpyAsync(out, slots, (size_t)MS * D * sizeof(float),
                    cudaMemcpyDeviceToDevice);
    attn_out_kernel<<<MS, 256>>>(attnh, out + (size_t)MS * D);
}

// round 16
// speedup vs baseline: 2.2966x; 1.0000x over previous
#include <cuda_runtime.h>
#include <cuda_fp16.h>
#include <math.h>
#include <stdint.h>

// ----------------------------------------------------------------------------
// Problem constants
// ----------------------------------------------------------------------------
#define B   32
#define NK  1024
#define S   16
#define D   768
#define H   8
#define DH  64
#define HD  (H*DH)    // 512
#define QKV3 (3*HD)   // 1536
#define INNER 3072
#define N_STEPS 4
#define MS  (B*S)     // 512
static __device__ __constant__ float kSCALE = 0.036084391824351615f;  // 768^-0.5

// ----------------------------------------------------------------------------
// Scratch (device globals)
// ----------------------------------------------------------------------------
__device__ __half g_xnh[B*NK*D];
__device__ __half g_wkh [D*D];
__device__ __half g_wvh [D*D];
__device__ __half g_wqh [D*D];
__device__ __half g_wqkh[QKV3*D];
__device__ __half g_woh [D*HD];
__device__ __half g_w1h [2*INNER*D];
__device__ __half g_w2h [D*INNER];
__device__ __half g_qnh[MS*D];
__device__ __half g_abh[MS*D];
__device__ __half g_fbh[MS*D];
__device__ __half g_innh[MS*INNER];
__device__ __half g_oah[MS*HD];
__device__ __half g_k  [B*NK*D];      // [b*NK + j][d]
__device__ __half g_vt [B*D*NK];      // [b*D + n][j]  (transposed V)
__device__ __half g_attnh[MS*NK];     // fp16 attn
__device__ float g_slots[MS*D];
__device__ float g_upd  [MS*D];
__device__ float g_h    [MS*D];
__device__ float g_part [4*MS*QKV3];  // 12.58 MB (>= 6*MS*D fp32)

// ----------------------------------------------------------------------------
// HMMA / cp.async helpers (baseline PTX — compiles for plain compute_103)
// ----------------------------------------------------------------------------
__device__ __forceinline__ uint32_t smem_u32(const void* p) {
    uint32_t a;
    asm("{ .reg .u64 t; cvta.to.shared.u64 t, %1; cvt.u32.u64 %0, t; }"
        : "=r"(a) : "l"(p));
    return a;
}
#define LDSM_X4(r0, r1, r2, r3, addr) \
    asm volatile("ldmatrix.sync.aligned.m8n8.x4.shared.b16 {%0,%1,%2,%3}, [%4];" \
                 : "=r"(r0), "=r"(r1), "=r"(r2), "=r"(r3) : "r"(addr))
#define LDSM_X2(r0, r1, addr) \
    asm volatile("ldmatrix.sync.aligned.m8n8.x2.shared.b16 {%0,%1}, [%2];" \
                 : "=r"(r0), "=r"(r1) : "r"(addr))
#define MMA16816(c, a, b) \
    asm volatile("mma.sync.aligned.m16n8k16.row.col.f32.f16.f16.f32 " \
                 "{%0,%1,%2,%3}, {%4,%5,%6,%7}, {%8,%9}, {%0,%1,%2,%3};" \
                 : "+f"((c)[0]), "+f"((c)[1]), "+f"((c)[2]), "+f"((c)[3]) \
                 : "r"((a)[0]), "r"((a)[1]), "r"((a)[2]), "r"((a)[3]), \
                   "r"((b)[0]), "r"((b)[1]))
#define CP_ASYNC16(dst_u32, src_ptr) \
    asm volatile("cp.async.ca.shared.global [%0], [%1], 16;" \
                 :: "r"(dst_u32), "l"(src_ptr))
#define CP_COMMIT() asm volatile("cp.async.commit_group;" ::: "memory")
#define CP_WAIT(n)  asm volatile("cp.async.wait_group %0;" :: "n"(n) : "memory")

#define PITCH 40            // halves per smem row (80 B) — conflict-free ldmatrix
#define TILEH (128 * PITCH) // halves per 128-row tile
#define TILEB (TILEH * 2)   // bytes per tile
#define ATILEB (16 * PITCH * 2)  // bytes per 16-row A tile (1280)
#define TP 136              // transpose-tile pitch in halves

// ----------------------------------------------------------------------------
// Pure fp16 HMMA GEMM (C = A·B), split-K, 2-stage cp.async.
// ----------------------------------------------------------------------------
__global__ __launch_bounds__(256)
void hgemm_fp16(const __half* __restrict__ Ah, const __half* __restrict__ Bth,
                float* __restrict__ C, int M, int N, int K)
{
    extern __shared__ __align__(16) __half dyn[];
    int tid = threadIdx.x;
    int lane = tid & 31, wid = tid >> 5;
    int wm = wid >> 2, wn = wid & 3;
    int row0 = blockIdx.y * 128, col0 = blockIdx.x * 128;
    int kb   = K / gridDim.z;
    int kbeg = blockIdx.z * kb;
    float* Cz = C + (size_t)blockIdx.z * M * N;
    int nchunk = kb / 32;

    uint32_t base = smem_u32(dyn);

    float acc[4][4][4];
    #pragma unroll
    for (int mf = 0; mf < 4; mf++)
        #pragma unroll
        for (int nf = 0; nf < 4; nf++)
            #pragma unroll
            for (int e = 0; e < 4; e++) acc[mf][nf][e] = 0.f;

    int laneAr = lane & 15, laneAk = (lane & 16) ? 8 : 0;
    int laneBr = lane & 7,  laneBk = (lane & 8)  ? 8 : 0;

    auto load_stage = [&](int c, int s) {
        uint32_t sb = base + (uint32_t)s * 2 * TILEB;
        #pragma unroll
        for (int i = 0; i < 2; i++) {
            int idx = tid + i * 256;
            int row = idx >> 2, sg = idx & 3;
            size_t ga = (size_t)(row0 + row) * K + kbeg + c * 32 + sg * 8;
            size_t gb = (size_t)(col0 + row) * K + kbeg + c * 32 + sg * 8;
            uint32_t so = (uint32_t)(row * PITCH + sg * 8) * 2;
            CP_ASYNC16(sb + 0 * TILEB + so, Ah + ga);
            CP_ASYNC16(sb + 1 * TILEB + so, Bth + gb);
        }
    };

    load_stage(0, 0);
    CP_COMMIT();
    for (int c = 0; c < nchunk; c++) {
        int s = c & 1;
        if (c + 1 < nchunk) { load_stage(c + 1, s ^ 1); CP_COMMIT(); CP_WAIT(1); }
        else                { CP_WAIT(0); }
        __syncthreads();
        uint32_t bAh = base + (uint32_t)s * 2 * TILEB;
        uint32_t bBh = bAh + TILEB;
        #pragma unroll
        for (int ks = 0; ks < 32; ks += 16) {
            uint32_t bh[4][2];
            #pragma unroll
            for (int nf = 0; nf < 4; nf++) {
                uint32_t off = (uint32_t)((wn * 32 + nf * 8 + laneBr) * PITCH
                                          + ks + laneBk) * 2;
                LDSM_X2(bh[nf][0], bh[nf][1], bBh + off);
            }
            #pragma unroll
            for (int mf = 0; mf < 4; mf++) {
                uint32_t off = (uint32_t)((wm * 64 + mf * 16 + laneAr) * PITCH
                                          + ks + laneAk) * 2;
                uint32_t ah[4];
                LDSM_X4(ah[0], ah[1], ah[2], ah[3], bAh + off);
                #pragma unroll
                for (int nf = 0; nf < 4; nf++)
                    MMA16816(acc[mf][nf], ah, bh[nf]);
            }
        }
        __syncthreads();
    }
    #pragma unroll
    for (int mf = 0; mf < 4; mf++) {
        int r = row0 + wm * 64 + mf * 16 + (lane >> 2);
        #pragma unroll
        for (int nf = 0; nf < 4; nf++) {
            int c = col0 + wn * 32 + nf * 8 + (lane & 3) * 2;
            *(float2*)(Cz + (size_t)r * N + c) =
                make_float2(acc[mf][nf][0], acc[mf][nf][1]);
            *(float2*)(Cz + (size_t)(r + 8) * N + c) =
                make_float2(acc[mf][nf][2], acc[mf][nf][3]);
        }
    }
}
#define HG_SMEM (2 * 2 * TILEB)     // 40960

// ----------------------------------------------------------------------------
// Dual-output projection (K/V), pure fp16; K [row][n], V transposed [b*D+n][j];
// smem-staged coalesced epilogue.
// ----------------------------------------------------------------------------
__global__ __launch_bounds__(256)
void hgemm_dual(const __half* __restrict__ Ah,
                const __half* __restrict__ Bkh, const __half* __restrict__ Bvh,
                __half* __restrict__ Ck, __half* __restrict__ Cvt,
                int M, int N, int K)
{
    extern __shared__ __align__(16) __half dyn[];
    int tid = threadIdx.x;
    int lane = tid & 31, wid = tid >> 5;
    int wm = wid >> 2, wn = wid & 3;
    int row0 = blockIdx.y * 128, col0 = blockIdx.x * 128;
    int nchunk = K / 32;
    uint32_t base = smem_u32(dyn);

    float accK[4][4][4], accV[4][4][4];
    #pragma unroll
    for (int mf = 0; mf < 4; mf++)
        #pragma unroll
        for (int nf = 0; nf < 4; nf++)
            #pragma unroll
            for (int e = 0; e < 4; e++) { accK[mf][nf][e] = 0.f; accV[mf][nf][e] = 0.f; }

    int laneAr = lane & 15, laneAk = (lane & 16) ? 8 : 0;
    int laneBr = lane & 7,  laneBk = (lane & 8)  ? 8 : 0;

    auto load_stage = [&](int c, int s) {
        uint32_t sb = base + (uint32_t)s * 3 * TILEB;
        #pragma unroll
        for (int i = 0; i < 2; i++) {
            int idx = tid + i * 256;
            int row = idx >> 2, sg = idx & 3;
            size_t ga = (size_t)(row0 + row) * K + c * 32 + sg * 8;
            size_t gb = (size_t)(col0 + row) * K + c * 32 + sg * 8;
            uint32_t so = (uint32_t)(row * PITCH + sg * 8) * 2;
            CP_ASYNC16(sb + 0 * TILEB + so, Ah + ga);
            CP_ASYNC16(sb + 1 * TILEB + so, Bkh + gb);
            CP_ASYNC16(sb + 2 * TILEB + so, Bvh + gb);
        }
    };

    load_stage(0, 0);
    CP_COMMIT();
    for (int c = 0; c < nchunk; c++) {
        int s = c & 1;
        if (c + 1 < nchunk) { load_stage(c + 1, s ^ 1); CP_COMMIT(); CP_WAIT(1); }
        else                { CP_WAIT(0); }
        __syncthreads();
        uint32_t bAh = base + (uint32_t)s * 3 * TILEB;
        uint32_t bKh = bAh + TILEB;
        uint32_t bVh = bKh + TILEB;
        #pragma unroll
        for (int ks = 0; ks < 32; ks += 16) {
            uint32_t kh[4][2], vh[4][2];
            #pragma unroll
            for (int nf = 0; nf < 4; nf++) {
                uint32_t off = (uint32_t)((wn * 32 + nf * 8 + laneBr) * PITCH
                                          + ks + laneBk) * 2;
                LDSM_X2(kh[nf][0], kh[nf][1], bKh + off);
                LDSM_X2(vh[nf][0], vh[nf][1], bVh + off);
            }
            #pragma unroll
            for (int mf = 0; mf < 4; mf++) {
                uint32_t off = (uint32_t)((wm * 64 + mf * 16 + laneAr) * PITCH
                                          + ks + laneAk) * 2;
                uint32_t ah[4];
                LDSM_X4(ah[0], ah[1], ah[2], ah[3], bAh + off);
                #pragma unroll
                for (int nf = 0; nf < 4; nf++) {
                    MMA16816(accK[mf][nf], ah, kh[nf]);
                    MMA16816(accV[mf][nf], ah, vh[nf]);
                }
            }
        }
        __syncthreads();
    }

    // ---- epilogue via smem staging (coalesced stores) ----
    __half* tile = dyn;
    int bb = row0 >> 10, jbase = row0 & (NK - 1);

    #pragma unroll
    for (int mf = 0; mf < 4; mf++) {
        int rl = wm * 64 + mf * 16 + (lane >> 2);
        #pragma unroll
        for (int nf = 0; nf < 4; nf++) {
            int cl = wn * 32 + nf * 8 + (lane & 3) * 2;
            tile[(size_t)cl * TP + rl]           = __float2half_rn(accV[mf][nf][0]);
            tile[(size_t)(cl + 1) * TP + rl]     = __float2half_rn(accV[mf][nf][1]);
            tile[(size_t)cl * TP + rl + 8]       = __float2half_rn(accV[mf][nf][2]);
            tile[(size_t)(cl + 1) * TP + rl + 8] = __float2half_rn(accV[mf][nf][3]);
        }
    }
    __syncthreads();
    for (int idx = tid; idx < 128 * 16; idx += 256) {
        int n = idx >> 4, seg = idx & 15;
        uint4 v = *(const uint4*)&tile[(size_t)n * TP + seg * 8];
        *(uint4*)&Cvt[((size_t)bb * D + col0 + n) * NK + jbase + seg * 8] = v;
    }
    __syncthreads();

    #pragma unroll
    for (int mf = 0; mf < 4; mf++) {
        int rl = wm * 64 + mf * 16 + (lane >> 2);
        #pragma unroll
        for (int nf = 0; nf < 4; nf++) {
            int cl = wn * 32 + nf * 8 + (lane & 3) * 2;
            *(__half2*)&tile[(size_t)rl * TP + cl] =
                __floats2half2_rn(accK[mf][nf][0], accK[mf][nf][1]);
            *(__half2*)&tile[(size_t)(rl + 8) * TP + cl] =
                __floats2half2_rn(accK[mf][nf][2], accK[mf][nf][3]);
        }
    }
    __syncthreads();
    for (int idx = tid; idx < 128 * 16; idx += 256) {
        int r = idx >> 4, seg = idx & 15;
        uint4 v = *(const uint4*)&tile[(size_t)r * TP + seg * 8];
        *(uint4*)&Ck[(size_t)(row0 + r) * N + col0 + seg * 8] = v;
    }
}
#define DUAL_SMEM (2 * 3 * TILEB)   // 61440

// ----------------------------------------------------------------------------
// W1 + GLU fused, pure fp16, 2-stage pipelined; emits fp16 u*silu(g).
// ----------------------------------------------------------------------------
__global__ __launch_bounds__(256)
void hgemm_glu(const __half* __restrict__ Ah, const __half* __restrict__ W1th,
               __half* __restrict__ Ih, int M)
{
    extern __shared__ __align__(16) __half dyn[];
    int tid = threadIdx.x;
    int lane = tid & 31, wid = tid >> 5;
    int wm = wid >> 2, wn = wid & 3;
    int row0 = blockIdx.y * 128, col0 = blockIdx.x * 128;
    int nchunk = D / 32;
    uint32_t base = smem_u32(dyn);

    float accU[4][4][4], accG[4][4][4];
    #pragma unroll
    for (int mf = 0; mf < 4; mf++)
        #pragma unroll
        for (int nf = 0; nf < 4; nf++)
            #pragma unroll
            for (int e = 0; e < 4; e++) { accU[mf][nf][e] = 0.f; accG[mf][nf][e] = 0.f; }

    int laneAr = lane & 15, laneAk = (lane & 16) ? 8 : 0;
    int laneBr = lane & 7,  laneBk = (lane & 8)  ? 8 : 0;

    auto load_stage = [&](int c, int s) {
        uint32_t sb = base + (uint32_t)s * 3 * TILEB;
        #pragma unroll
        for (int i = 0; i < 2; i++) {
            int idx = tid + i * 256;
            int row = idx >> 2, sg = idx & 3;
            size_t ga = (size_t)(row0 + row) * D + c * 32 + sg * 8;
            size_t gu = (size_t)(col0 + row) * D + c * 32 + sg * 8;
            size_t gg = (size_t)(col0 + row + INNER) * D + c * 32 + sg * 8;
            uint32_t so = (uint32_t)(row * PITCH + sg * 8) * 2;
            CP_ASYNC16(sb + 0 * TILEB + so, Ah + ga);
            CP_ASYNC16(sb + 1 * TILEB + so, W1th + gu);
            CP_ASYNC16(sb + 2 * TILEB + so, W1th + gg);
        }
    };

    load_stage(0, 0);
    CP_COMMIT();
    for (int c = 0; c < nchunk; c++) {
        int s = c & 1;
        if (c + 1 < nchunk) { load_stage(c + 1, s ^ 1); CP_COMMIT(); CP_WAIT(1); }
        else                { CP_WAIT(0); }
        __syncthreads();
        uint32_t bAh = base + (uint32_t)s * 3 * TILEB;
        uint32_t bUh = bAh + TILEB;
        uint32_t bGh = bUh + TILEB;
        #pragma unroll
        for (int ks = 0; ks < 32; ks += 16) {
            uint32_t uh[4][2], gh[4][2];
            #pragma unroll
            for (int nf = 0; nf < 4; nf++) {
                uint32_t off = (uint32_t)((wn * 32 + nf * 8 + laneBr) * PITCH
                                          + ks + laneBk) * 2;
                LDSM_X2(uh[nf][0], uh[nf][1], bUh + off);
                LDSM_X2(gh[nf][0], gh[nf][1], bGh + off);
            }
            #pragma unroll
            for (int mf = 0; mf < 4; mf++) {
                uint32_t off = (uint32_t)((wm * 64 + mf * 16 + laneAr) * PITCH
                                          + ks + laneAk) * 2;
                uint32_t ah[4];
                LDSM_X4(ah[0], ah[1], ah[2], ah[3], bAh + off);
                #pragma unroll
                for (int nf = 0; nf < 4; nf++) {
                    MMA16816(accU[mf][nf], ah, uh[nf]);
                    MMA16816(accG[mf][nf], ah, gh[nf]);
                }
            }
        }
        __syncthreads();
    }
    #pragma unroll
    for (int mf = 0; mf < 4; mf++) {
        int r = row0 + wm * 64 + mf * 16 + (lane >> 2);
        #pragma unroll
        for (int nf = 0; nf < 4; nf++) {
            int c = col0 + wn * 32 + nf * 8 + (lane & 3) * 2;
            #pragma unroll
            for (int half_ = 0; half_ < 2; half_++) {
                int rr = r + half_ * 8;
                float u0 = accU[mf][nf][half_ * 2], u1 = accU[mf][nf][half_ * 2 + 1];
                float g0 = accG[mf][nf][half_ * 2], g1 = accG[mf][nf][half_ * 2 + 1];
                float v0 = u0 * (g0 / (1.f + expf(-g0)));
                float v1 = u1 * (g1 / (1.f + expf(-g1)));
                *(__half2*)(Ih + (size_t)rr * INNER + c) = __floats2half2_rn(v0, v1);
            }
        }
    }
}
#define GLU_SMEM (2 * 3 * TILEB)    // 61440

// ----------------------------------------------------------------------------
// dots + softmax, HMMA; Wq split-K partials summed once into a persistent
// fp16 q smem tile (done under the first K cp.async). Emits fp16 attn.
// ----------------------------------------------------------------------------
#define QP 776                        // q smem pitch (halves); 776*2 = 16*97
#define DOTS_Q_BYTES (16 * QP * 2)    // 24832
#define DOTS_SMEM (DOTS_Q_BYTES + 2 * TILEB)   // 45312
__global__ __launch_bounds__(256)
void dots_hmma(const float* __restrict__ Qpart, const __half* __restrict__ Kb,
               __half* __restrict__ attnh)
{
    extern __shared__ __align__(16) __half dyn[];
    __half* qs = dyn;
    uint32_t qbase = smem_u32(qs);
    uint32_t kbase = qbase + DOTS_Q_BYTES;
    int tid = threadIdx.x;
    int lane = tid & 31, wn = tid >> 5;
    int b = blockIdx.y, j0 = blockIdx.x * 128;
    int nchunk = D / 32;                    // 24

    int laneAr = lane & 15, laneAk = (lane & 16) ? 8 : 0;
    int laneBr = lane & 7,  laneBk = (lane & 8)  ? 8 : 0;

    auto load_stage = [&](int c, int s) {
        uint32_t sb = kbase + (uint32_t)s * TILEB;
        #pragma unroll
        for (int i = 0; i < 2; i++) {
            int idx = tid + i * 256;
            int row = idx >> 2, sg = idx & 3;
            size_t gb = ((size_t)b * NK + j0 + row) * D + c * 32 + sg * 8;
            CP_ASYNC16(sb + (uint32_t)(row * PITCH + sg * 8) * 2, Kb + gb);
        }
    };

    load_stage(0, 0);
    CP_COMMIT();
    load_stage(1, 1);
    CP_COMMIT();

    // sum 4 Wq partials -> fp16 q (overlaps with the K cp.asyncs above)
    #pragma unroll
    for (int k = 0; k < 12; k++) {
        int idx4 = tid + k * 256;           // float4 group index (0..3071)
        int row = idx4 / 192, col = (idx4 % 192) * 4;
        size_t o = ((size_t)b * S + row) * D + col;
        float4 v = *(const float4*)&Qpart[o];
        #pragma unroll
        for (int sp = 1; sp < 4; sp++) {
            float4 w = *(const float4*)&Qpart[(size_t)sp * MS * D + o];
            v.x += w.x; v.y += w.y; v.z += w.z; v.w += w.w;
        }
        *(__half2*)&qs[row * QP + col]     = __floats2half2_rn(v.x, v.y);
        *(__half2*)&qs[row * QP + col + 2] = __floats2half2_rn(v.z, v.w);
    }

    float acc[2][4];
    #pragma unroll
    for (int nf = 0; nf < 2; nf++)
        #pragma unroll
        for (int e = 0; e < 4; e++) acc[nf][e] = 0.f;

    for (int c = 0; c < nchunk; c++) {
        int s = c & 1;
        if (c + 2 < nchunk) { CP_WAIT(1); }
        else                { CP_WAIT(0); }
        __syncthreads();
        uint32_t bB = kbase + (uint32_t)s * TILEB;
        #pragma unroll
        for (int ks = 0; ks < 32; ks += 16) {
            uint32_t ah[4];
            LDSM_X4(ah[0], ah[1], ah[2], ah[3],
                    qbase + (uint32_t)(laneAr * QP + c * 32 + ks + laneAk) * 2);
            #pragma unroll
            for (int nf = 0; nf < 2; nf++) {
                uint32_t bh[2];
                LDSM_X2(bh[0], bh[1],
                        bB + (uint32_t)((wn * 16 + nf * 8 + laneBr) * PITCH
                                        + ks + laneBk) * 2);
                MMA16816(acc[nf], ah, bh);
            }
        }
        __syncthreads();
        if (c + 2 < nchunk) { load_stage(c + 2, s); CP_COMMIT(); }
    }

    // softmax over slot axis in registers
    int r = lane >> 2;
    #pragma unroll
    for (int nf = 0; nf < 2; nf++) {
        float s0 = acc[nf][0] * kSCALE, s1 = acc[nf][1] * kSCALE;
        float s2 = acc[nf][2] * kSCALE, s3 = acc[nf][3] * kSCALE;
        float m0 = fmaxf(s0, s2), m1 = fmaxf(s1, s3);
        #pragma unroll
        for (int o = 4; o <= 16; o <<= 1) {
            m0 = fmaxf(m0, __shfl_xor_sync(0xffffffffu, m0, o));
            m1 = fmaxf(m1, __shfl_xor_sync(0xffffffffu, m1, o));
        }
        float e0 = expf(s0 - m0), e1 = expf(s1 - m1);
        float e2 = expf(s2 - m0), e3 = expf(s3 - m1);
        float t0 = e0 + e2, t1 = e1 + e3;
        #pragma unroll
        for (int o = 4; o <= 16; o <<= 1) {
            t0 += __shfl_xor_sync(0xffffffffu, t0, o);
            t1 += __shfl_xor_sync(0xffffffffu, t1, o);
        }
        float a0 = e0 / t0 + 1e-8f, a1 = e1 / t1 + 1e-8f;
        float a2 = e2 / t0 + 1e-8f, a3 = e3 / t1 + 1e-8f;
        int col = j0 + wn * 16 + nf * 8 + (lane & 3) * 2;
        size_t o0 = ((size_t)b * S + r) * NK + col;
        size_t o1 = ((size_t)b * S + r + 8) * NK + col;
        *(__half2*)(attnh + o0) = __floats2half2_rn(a0, a1);
        *(__half2*)(attnh + o1) = __floats2half2_rn(a2, a3);
    }
}

// ----------------------------------------------------------------------------
// updates, HMMA: A = attn fp16 [16xNK], B = Vt rows; row sums via all-ones
// fragment; upd = (attn @ V) / rowsum.
// ----------------------------------------------------------------------------
#define UPD_STAGE (ATILEB + TILEB)
#define UPD_SMEM (2 * UPD_STAGE)     // 23040
__global__ __launch_bounds__(256)
void updates_hmma(const __half* __restrict__ Ath, const __half* __restrict__ Vt,
                  float* __restrict__ upd)
{
    extern __shared__ __align__(16) __half dyn[];
    int tid = threadIdx.x;
    int lane = tid & 31, wn = tid >> 5;
    int b = blockIdx.y, n0 = blockIdx.x * 128;
    uint32_t base = smem_u32(dyn);
    int nchunk = NK / 32;                   // 32

    float acc[2][4];
    float accS[4] = {0.f, 0.f, 0.f, 0.f};
    #pragma unroll
    for (int nf = 0; nf < 2; nf++)
        #pragma unroll
        for (int e = 0; e < 4; e++) acc[nf][e] = 0.f;

    int laneAr = lane & 15, laneAk = (lane & 16) ? 8 : 0;
    int laneBr = lane & 7,  laneBk = (lane & 8)  ? 8 : 0;
    uint32_t ones[2] = {0x3C003C00u, 0x3C003C00u};

    auto load_stage = [&](int c, int s) {
        uint32_t sb = base + (uint32_t)s * UPD_STAGE;
        if (tid < 64) {
            int row = tid >> 2, sg = tid & 3;
            size_t ga = ((size_t)b * S + row) * NK + c * 32 + sg * 8;
            CP_ASYNC16(sb + (uint32_t)(row * PITCH + sg * 8) * 2, Ath + ga);
        }
        #pragma unroll
        for (int i = 0; i < 2; i++) {
            int idx = tid + i * 256;
            int row = idx >> 2, sg = idx & 3;
            size_t gb = ((size_t)b * D + n0 + row) * NK + c * 32 + sg * 8;
            CP_ASYNC16(sb + ATILEB + (uint32_t)(row * PITCH + sg * 8) * 2, Vt + gb);
        }
    };

    load_stage(0, 0);
    CP_COMMIT();
    for (int c = 0; c < nchunk; c++) {
        int s = c & 1;
        if (c + 1 < nchunk) { load_stage(c + 1, s ^ 1); CP_COMMIT(); CP_WAIT(1); }
        else                { CP_WAIT(0); }
        __syncthreads();
        uint32_t bA = base + (uint32_t)s * UPD_STAGE;
        uint32_t bB = bA + ATILEB;
        #pragma unroll
        for (int ks = 0; ks < 32; ks += 16) {
            uint32_t ah[4];
            LDSM_X4(ah[0], ah[1], ah[2], ah[3],
                    bA + (uint32_t)(laneAr * PITCH + ks + laneAk) * 2);
            MMA16816(accS, ah, ones);
            #pragma unroll
            for (int nf = 0; nf < 2; nf++) {
                uint32_t bh[2];
                LDSM_X2(bh[0], bh[1],
                        bB + (uint32_t)((wn * 16 + nf * 8 + laneBr) * PITCH
                                        + ks + laneBk) * 2);
                MMA16816(acc[nf], ah, bh);
            }
        }
        __syncthreads();
    }

    int r = lane >> 2;
    float inv0 = 1.f / accS[0];
    float inv1 = 1.f / accS[2];
    #pragma unroll
    for (int nf = 0; nf < 2; nf++) {
        int col = n0 + wn * 16 + nf * 8 + (lane & 3) * 2;
        *(float2*)(upd + ((size_t)b * S + r) * D + col) =
            make_float2(acc[nf][0] * inv0, acc[nf][1] * inv0);
        *(float2*)(upd + ((size_t)b * S + r + 8) * D + col) =
            make_float2(acc[nf][2] * inv1, acc[nf][3] * inv1);
    }
}

// ----------------------------------------------------------------------------
// LN reduction helper (256 threads over D=768)
// ----------------------------------------------------------------------------
__device__ __forceinline__ void ln_stats(float v0, float v1, float v2,
                                         float* sa, float* sb2,
                                         float& mean, float& rinv)
{
    float s = v0 + v1 + v2;
    float q = v0 * v0 + v1 * v1 + v2 * v2;
    int tid = threadIdx.x;
    #pragma unroll
    for (int o = 16; o > 0; o >>= 1) {
        s += __shfl_down_sync(0xffffffffu, s, o);
        q += __shfl_down_sync(0xffffffffu, q, o);
    }
    int w = tid >> 5, l = tid & 31;
    if (l == 0) { sa[w] = s; sb2[w] = q; }
    __syncthreads();
    if (tid == 0) {
        float ts = 0.f, tq = 0.f;
        #pragma unroll
        for (int k = 0; k < 8; k++) { ts += sa[k]; tq += sb2[k]; }
        sa[0] = ts; sb2[0] = tq;
    }
    __syncthreads();
    mean = sa[0] * (1.0f / D);
    float var = sb2[0] * (1.0f / D) - mean * mean;
    rinv = rsqrtf(var + 1e-5f);
    __syncthreads();
}

__global__ __launch_bounds__(256)
void ln_h_kernel(const float* __restrict__ in, __half* __restrict__ oh,
                 const float* __restrict__ gamma, const float* __restrict__ beta)
{
    int row = blockIdx.x, tid = threadIdx.x;
    const float* x = in + (size_t)row * D;
    float v[3] = {x[tid], x[tid + 256], x[tid + 512]};
    __shared__ float sa[8], sb2[8];
    float mean, r;
    ln_stats(v[0], v[1], v[2], sa, sb2, mean, r);
    #pragma unroll
    for (int e = 0; e < 3; e++) {
        int idx = tid + e * 256;
        float y = (v[e] - mean) * r * gamma[idx] + beta[idx];
        oh[(size_t)row * D + idx] = __float2half_rn(y);
    }
}

__global__ __launch_bounds__(256)
void ln_dual_kernel(const float* __restrict__ slots, const float* __restrict__ upd,
                    float* __restrict__ hb,
                    const float* __restrict__ g1, const float* __restrict__ b1,
                    const float* __restrict__ g2, const float* __restrict__ b2,
                    __half* __restrict__ oh)
{
    int row = blockIdx.x, tid = threadIdx.x;
    const float* xs = slots + (size_t)row * D;
    const float* xu = upd + (size_t)row * D;
    float v[3];
    #pragma unroll
    for (int e = 0; e < 3; e++) v[e] = xs[tid + e * 256] + xu[tid + e * 256];
    __shared__ float sa[8], sb2[8];
    float mean, r;
    ln_stats(v[0], v[1], v[2], sa, sb2, mean, r);
    float y[3];
    #pragma unroll
    for (int e = 0; e < 3; e++) {
        int idx = tid + e * 256;
        y[e] = (v[e] - mean) * r * g1[idx] + b1[idx];
        hb[(size_t)row * D + idx] = y[e];
    }
    float mean2, r2;
    ln_stats(y[0], y[1], y[2], sa, sb2, mean2, r2);
    #pragma unroll
    for (int e = 0; e < 3; e++) {
        int idx = tid + e * 256;
        float z = (y[e] - mean2) * r2 * g2[idx] + b2[idx];
        oh[(size_t)row * D + idx] = __float2half_rn(z);
    }
}

// h = res + sum_{sp<4} part[sp]; res <- h; LN(h) -> oh(fp16)
__global__ __launch_bounds__(256)
void ln_red_kernel(const float* __restrict__ part, float* __restrict__ res,
                   const float* __restrict__ gamma, const float* __restrict__ beta,
                   __half* __restrict__ oh)
{
    int row = blockIdx.x, tid = threadIdx.x;
    float v[3];
    #pragma unroll
    for (int e = 0; e < 3; e++) {
        int idx = tid + e * 256;
        size_t o = (size_t)row * D + idx;
        float s = res[o];
        #pragma unroll
        for (int sp = 0; sp < 4; sp++) s += part[(size_t)sp * MS * D + o];
        v[e] = s;
        res[o] = s;
    }
    __shared__ float sa[8], sb2[8];
    float mean, r;
    ln_stats(v[0], v[1], v[2], sa, sb2, mean, r);
    #pragma unroll
    for (int e = 0; e < 3; e++) {
        int idx = tid + e * 256;
        float y = (v[e] - mean) * r * gamma[idx] + beta[idx];
        oh[(size_t)row * D + idx] = __float2half_rn(y);
    }
}

// h = res + sum_{sp<6} part[sp]; slots = LN_f(h); LN_s(slots) -> qn(fp16)
__global__ __launch_bounds__(256)
void ln_red_dual_kernel(const float* __restrict__ part, const float* __restrict__ res,
                        float* __restrict__ slots,
                        const float* __restrict__ gf, const float* __restrict__ bf,
                        const float* __restrict__ gs, const float* __restrict__ bs,
                        __half* __restrict__ qh)
{
    int row = blockIdx.x, tid = threadIdx.x;
    float v[3];
    #pragma unroll
    for (int e = 0; e < 3; e++) {
        int idx = tid + e * 256;
        size_t o = (size_t)row * D + idx;
        float s = res[o];
        #pragma unroll
        for (int sp = 0; sp < 6; sp++) s += part[(size_t)sp * MS * D + o];
        v[e] = s;
    }
    __shared__ float sa[8], sb2[8];
    float mean, r;
    ln_stats(v[0], v[1], v[2], sa, sb2, mean, r);
    float y[3];
    #pragma unroll
    for (int e = 0; e < 3; e++) {
        int idx = tid + e * 256;
        y[e] = (v[e] - mean) * r * gf[idx] + bf[idx];
        slots[(size_t)row * D + idx] = y[e];
    }
    float mean2, r2;
    ln_stats(y[0], y[1], y[2], sa, sb2, mean2, r2);
    #pragma unroll
    for (int e = 0; e < 3; e++) {
        int idx = tid + e * 256;
        float z = (y[e] - mean2) * r2 * gs[idx] + bs[idx];
        qh[(size_t)row * D + idx] = __float2half_rn(z);
    }
}

__global__ __launch_bounds__(256)
void wsplit_kernel(const float* __restrict__ W,
                   __half* __restrict__ Th,
                   int Krows, int Ncols, int n_off)
{
    __shared__ float tile[32][33];
    int n0 = blockIdx.x * 32, k0 = blockIdx.y * 32;
    int t = threadIdx.x;
    int tx = t & 31, ty = t >> 5;
    #pragma unroll
    for (int i = 0; i < 4; i++)
        tile[ty + i * 8][tx] = W[(size_t)(k0 + ty + i * 8) * Ncols + n0 + tx];
    __syncthreads();
    #pragma unroll
    for (int i = 0; i < 4; i++) {
        int n = n_off + n0 + ty + i * 8;
        Th[(size_t)n * Krows + k0 + tx] = __float2half_rn(tile[tx][ty + i * 8]);
    }
}

__global__ void init_slots_kernel(const float* __restrict__ noise,
                                  const float* __restrict__ mu,
                                  const float* __restrict__ ls,
                                  float* __restrict__ slots)
{
    int t = blockIdx.x * blockDim.x + threadIdx.x;
    if (t >= MS * D) return;
    int d = t % D;
    slots[t] = mu[d] + expf(ls[d]) * noise[t];
}

// encoder self-attention; reads 2 QKV split-K partials; emits fp16 O
__global__ __launch_bounds__(256)
void enc_attn_kernel(const float* __restrict__ QKVpart, __half* __restrict__ Oh)
{
    int b = blockIdx.x >> 3, h = blockIdx.x & 7;
    __shared__ float qs[16][65], ks[16][65], vs[16][65];
    __shared__ float p[16][17];
    int tid = threadIdx.x;
    int i = tid >> 4, jj = tid & 15;
    {
        int r = tid >> 4, c = (tid & 15) * 4;
        size_t base = ((size_t)b * S + r) * QKV3 + h * DH + c;
        float4 vq = *(const float4*)&QKVpart[base];
        float4 vk = *(const float4*)&QKVpart[base + HD];
        float4 vv = *(const float4*)&QKVpart[base + 2 * HD];
        #pragma unroll
        for (int sp = 1; sp < 2; sp++) {
            size_t o = (size_t)sp * MS * QKV3 + base;
            float4 w;
            w = *(const float4*)&QKVpart[o];
            vq.x += w.x; vq.y += w.y; vq.z += w.z; vq.w += w.w;
            w = *(const float4*)&QKVpart[o + HD];
            vk.x += w.x; vk.y += w.y; vk.z += w.z; vk.w += w.w;
            w = *(const float4*)&QKVpart[o + 2 * HD];
            vv.x += w.x; vv.y += w.y; vv.z += w.z; vv.w += w.w;
        }
        qs[r][c] = vq.x; qs[r][c+1] = vq.y; qs[r][c+2] = vq.z; qs[r][c+3] = vq.w;
        ks[r][c] = vk.x; ks[r][c+1] = vk.y; ks[r][c+2] = vk.z; ks[r][c+3] = vk.w;
        vs[r][c] = vv.x; vs[r][c+1] = vv.y; vs[r][c+2] = vv.z; vs[r][c+3] = vv.w;
    }
    __syncthreads();
    float s = 0.f;
    #pragma unroll
    for (int d = 0; d < DH; d++) s += qs[i][d] * ks[jj][d];
    s *= 0.125f;
    p[i][jj] = s;
    __syncthreads();
    float m = -1e30f;
    #pragma unroll
    for (int t2 = 0; t2 < 16; t2++) m = fmaxf(m, p[i][t2]);
    __syncthreads();
    float e = expf(s - m);
    p[i][jj] = e;
    __syncthreads();
    float sum = 0.f;
    #pragma unroll
    for (int t2 = 0; t2 < 16; t2++) sum += p[i][t2];
    __syncthreads();
    p[i][jj] = e / sum;
    __syncthreads();
    int io = tid >> 4, dbase = (tid & 15) * 4;
    float o[4] = {0.f, 0.f, 0.f, 0.f};
    #pragma unroll
    for (int t2 = 0; t2 < 16; t2++) {
        float pp = p[io][t2];
        o[0] += pp * vs[t2][dbase + 0];
        o[1] += pp * vs[t2][dbase + 1];
        o[2] += pp * vs[t2][dbase + 2];
        o[3] += pp * vs[t2][dbase + 3];
    }
    size_t base = ((size_t)b * S + io) * HD + h * DH + dbase;
    *(__half2*)(Oh + base)     = __floats2half2_rn(o[0], o[1]);
    *(__half2*)(Oh + base + 2) = __floats2half2_rn(o[2], o[3]);
}

// output map from fp16 attn: per (b,i) row — sum keys, write out[b][j][i]
__global__ __launch_bounds__(256)
void attn_out_kernel(const __half* __restrict__ attnh, float* __restrict__ out)
{
    int row = blockIdx.x;            // b*S + i
    int b = row >> 4, i = row & 15;
    const __half2* p = (const __half2*)(attnh + (size_t)row * NK);
    int tid = threadIdx.x;
    float2 v0 = __half22float2(p[tid * 2]);
    float2 v1 = __half22float2(p[tid * 2 + 1]);
    float s = v0.x + v0.y + v1.x + v1.y;
    __shared__ float sa[8];
    #pragma unroll
    for (int o = 16; o > 0; o >>= 1) s += __shfl_down_sync(0xffffffffu, s, o);
    int w = tid >> 5, l = tid & 31;
    if (l == 0) sa[w] = s;
    __syncthreads();
    if (tid == 0) {
        float ts = 0.f;
        #pragma unroll
        for (int k = 0; k < 8; k++) ts += sa[k];
        sa[0] = ts;
    }
    __syncthreads();
    float inv = 1.f / sa[0];
    size_t ob = (size_t)b * NK * S + i;
    int j = tid * 4;
    out[ob + (size_t)(j + 0) * S] = v0.x * inv;
    out[ob + (size_t)(j + 1) * S] = v0.y * inv;
    out[ob + (size_t)(j + 2) * S] = v1.x * inv;
    out[ob + (size_t)(j + 3) * S] = v1.y * inv;
}

// ----------------------------------------------------------------------------
// Host orchestration
// ----------------------------------------------------------------------------
extern "C" void kernel_launch(void* const* d_in, const int* in_sizes, int n_in,
                              void* d_out, int out_size)
{
    const float* x       = (const float*)d_in[0];
    const float* noise   = (const float*)d_in[1];
    const float* init_mu = (const float*)d_in[2];
    const float* init_ls = (const float*)d_in[3];
    const float* Wk      = (const float*)d_in[4];
    const float* Wv      = (const float*)d_in[5];
    const float* Wq      = (const float*)d_in[6];
    const float* ni_g    = (const float*)d_in[7];
    const float* ni_b    = (const float*)d_in[8];
    const float* ns_g    = (const float*)d_in[9];
    const float* ns_b    = (const float*)d_in[10];
    const float* nica_g  = (const float*)d_in[11];
    const float* nica_b  = (const float*)d_in[12];
    const float* ln1_g   = (const float*)d_in[13];
    const float* ln1_b   = (const float*)d_in[14];
    const float* Wq_a    = (const float*)d_in[15];
    const float* Wk_a    = (const float*)d_in[16];
    const float* Wv_a    = (const float*)d_in[17];
    const float* Wo_a    = (const float*)d_in[18];
    const float* ln2_g   = (const float*)d_in[19];
    const float* ln2_b   = (const float*)d_in[20];
    const float* W1      = (const float*)d_in[21];
    const float* W2      = (const float*)d_in[22];
    const float* lnf_g   = (const float*)d_in[23];
    const float* lnf_b   = (const float*)d_in[24];

    __half *xnh, *wkh, *wvh, *wqh, *wqkh, *woh, *w1h, *w2h;
    __half *qnh, *abh, *fbh, *innh, *oah, *kb, *vt, *attnh;
    float *slots, *upd, *hb, *part;
    cudaGetSymbolAddress((void**)&xnh,  g_xnh);
    cudaGetSymbolAddress((void**)&wkh,  g_wkh);
    cudaGetSymbolAddress((void**)&wvh,  g_wvh);
    cudaGetSymbolAddress((void**)&wqh,  g_wqh);
    cudaGetSymbolAddress((void**)&wqkh, g_wqkh);
    cudaGetSymbolAddress((void**)&woh,  g_woh);
    cudaGetSymbolAddress((void**)&w1h,  g_w1h);
    cudaGetSymbolAddress((void**)&w2h,  g_w2h);
    cudaGetSymbolAddress((void**)&qnh,  g_qnh);
    cudaGetSymbolAddress((void**)&abh,  g_abh);
    cudaGetSymbolAddress((void**)&fbh,  g_fbh);
    cudaGetSymbolAddress((void**)&innh, g_innh);
    cudaGetSymbolAddress((void**)&oah,  g_oah);
    cudaGetSymbolAddress((void**)&kb,   g_k);
    cudaGetSymbolAddress((void**)&vt,   g_vt);
    cudaGetSymbolAddress((void**)&attnh,g_attnh);
    cudaGetSymbolAddress((void**)&slots,g_slots);
    cudaGetSymbolAddress((void**)&upd,  g_upd);
    cudaGetSymbolAddress((void**)&hb,   g_h);
    cudaGetSymbolAddress((void**)&part, g_part);

    cudaFuncSetAttribute(hgemm_fp16, cudaFuncAttributeMaxDynamicSharedMemorySize, HG_SMEM);
    cudaFuncSetAttribute(hgemm_dual, cudaFuncAttributeMaxDynamicSharedMemorySize, DUAL_SMEM);
    cudaFuncSetAttribute(hgemm_glu,  cudaFuncAttributeMaxDynamicSharedMemorySize, GLU_SMEM);
    cudaFuncSetAttribute(dots_hmma,  cudaFuncAttributeMaxDynamicSharedMemorySize, DOTS_SMEM);
    cudaFuncSetAttribute(updates_hmma, cudaFuncAttributeMaxDynamicSharedMemorySize, UPD_SMEM);

    // ---- precompute ----
    wsplit_kernel<<<dim3(D / 32, D / 32), 256>>>(Wk, wkh, D, D, 0);
    wsplit_kernel<<<dim3(D / 32, D / 32), 256>>>(Wv, wvh, D, D, 0);
    ln_h_kernel<<<B * NK, 256>>>(x, xnh, ni_g, ni_b);
    init_slots_kernel<<<(MS * D + 255) / 256, 256>>>(noise, init_mu, init_ls, slots);
    wsplit_kernel<<<dim3(D / 32, D / 32), 256>>>(Wq, wqh, D, D, 0);
    hgemm_dual<<<dim3(D / 128, (B * NK) / 128), 256, DUAL_SMEM>>>(
        xnh, wkh, wvh, kb, vt, B * NK, D, D);
    wsplit_kernel<<<dim3(HD / 32, D / 32), 256>>>(Wq_a, wqkh, D, HD, 0);
    wsplit_kernel<<<dim3(HD / 32, D / 32), 256>>>(Wk_a, wqkh, D, HD, HD);
    wsplit_kernel<<<dim3(HD / 32, D / 32), 256>>>(Wv_a, wqkh, D, HD, 2 * HD);
    wsplit_kernel<<<dim3(D / 32, HD / 32), 256>>>(Wo_a, woh, HD, D, 0);
    wsplit_kernel<<<dim3((2 * INNER) / 32, D / 32), 256>>>(W1, w1h, D, 2 * INNER, 0);
    wsplit_kernel<<<dim3(D / 32, INNER / 32), 256>>>(W2, w2h, INNER, D, 0);
    ln_h_kernel<<<MS, 256>>>(slots, qnh, ns_g, ns_b);

    // ---- 4 slot-attention steps (11 launches each) ----
    for (int it = 0; it < N_STEPS; it++) {
        hgemm_fp16<<<dim3(D / 128, MS / 128, 4), 256, HG_SMEM>>>(qnh, wqh,
                                                                 part, MS, D, D);
        dots_hmma<<<dim3(NK / 128, B), 256, DOTS_SMEM>>>(part, kb, attnh);
        updates_hmma<<<dim3(D / 128, B), 256, UPD_SMEM>>>(attnh, vt, upd);
        ln_dual_kernel<<<MS, 256>>>(slots, upd, hb, nica_g, nica_b,
                                    ln1_g, ln1_b, abh);
        hgemm_fp16<<<dim3(QKV3 / 128, MS / 128, 2), 256, HG_SMEM>>>(abh, wqkh,
                                                                    part, MS, QKV3, D);
        enc_attn_kernel<<<B * H, 256>>>(part, oah);
        hgemm_fp16<<<dim3(D / 128, MS / 128, 4), 256, HG_SMEM>>>(oah, woh,
                                                                 part, MS, D, HD);
        ln_red_kernel<<<MS, 256>>>(part, hb, ln2_g, ln2_b, fbh);
        hgemm_glu<<<dim3(INNER / 128, MS / 128), 256, GLU_SMEM>>>(fbh, w1h,
                                                                  innh, MS);
        hgemm_fp16<<<dim3(D / 128, MS / 128, 6), 256, HG_SMEM>>>(innh, w2h,
                                                                 part, MS, D, INNER);
        ln_red_dual_kernel<<<MS, 256>>>(part, hb, slots, lnf_g, lnf_b,
                                        ns_g, ns_b, qnh);
    }

    // ---- outputs: slots [32,16,768], then attn_map [32,1024,16] ----
    float* out = (float*)d_out;
    cudaMemcpyAsync(out, slots, (size_t)MS * D * sizeof(float),
                    cudaMemcpyDeviceToDevice);
    attn_out_kernel<<<MS, 256>>>(attnh, out + (size_t)MS * D);
}